// round 3
// baseline (speedup 1.0000x reference)
#include <cuda_runtime.h>

#define Bn 32
#define Ln 512
#define Dn 512
#define Hn 8
#define DHn 64
#define Kn 7
#define Mn (Bn*Ln)            // 16384 rows for the big GEMMs
#define NEGV (-1e30f)

// ---------------- scratch (device globals; no runtime allocation) ----------------
__device__ float g_x1[Mn*Dn];
__device__ float g_x2[Mn*Dn];
__device__ float g_t [Mn*Dn];
__device__ float g_q [Mn*Dn];
__device__ float g_k [Mn*Dn];
__device__ float g_v [Mn*Dn];
__device__ float g_o [Mn*Dn];
__device__ float g_att[Bn*Hn*Ln*Ln];     // 268 MB
__device__ float g_wq[Dn*Dn];
__device__ float g_wk[Dn*Dn];
__device__ float g_wv[Dn*Dn];
__device__ float g_mu[Bn];
__device__ float g_rstd[Bn];

// ---------------- elementwise: x + pe ----------------
__global__ void add_pe_k(const float* __restrict__ x, const float* __restrict__ pe,
                         float* __restrict__ y)
{
    int idx = blockIdx.x * blockDim.x + threadIdx.x;
    y[idx] = x[idx] + pe[idx & (Ln*Dn - 1)];
}

// ---------------- per-batch LayerNorm([L,D]) stats -> g_mu, g_rstd ----------------
__global__ void ln_stats(const float* __restrict__ x)
{
    int b = blockIdx.x;
    const float4* p = (const float4*)(x + (size_t)b * Ln * Dn);
    float s = 0.f, s2 = 0.f;
    for (int i = threadIdx.x; i < Ln*Dn/4; i += blockDim.x) {
        float4 v = p[i];
        s  += v.x + v.y + v.z + v.w;
        s2 += v.x*v.x + v.y*v.y + v.z*v.z + v.w*v.w;
    }
#pragma unroll
    for (int o = 16; o > 0; o >>= 1) {
        s  += __shfl_xor_sync(0xffffffffu, s,  o);
        s2 += __shfl_xor_sync(0xffffffffu, s2, o);
    }
    __shared__ float sh[32], sh2[32];
    int w = threadIdx.x >> 5, lane = threadIdx.x & 31;
    if (lane == 0) { sh[w] = s; sh2[w] = s2; }
    __syncthreads();
    if (w == 0) {
        int nw = blockDim.x >> 5;
        s  = (lane < nw) ? sh[lane]  : 0.f;
        s2 = (lane < nw) ? sh2[lane] : 0.f;
#pragma unroll
        for (int o = 16; o > 0; o >>= 1) {
            s  += __shfl_xor_sync(0xffffffffu, s,  o);
            s2 += __shfl_xor_sync(0xffffffffu, s2, o);
        }
        if (lane == 0) {
            float inv = 1.f / (float)(Ln*Dn);
            float m   = s * inv;
            float var = s2 * inv - m*m;
            g_mu[b]   = m;
            g_rstd[b] = rsqrtf(var + 1e-5f);
        }
    }
}

// ---------------- depthwise conv (K=7, pad 3) + bias + relu ----------------
__global__ void dwconv_relu(const float* __restrict__ x, const float* __restrict__ w,
                            const float* __restrict__ bias, float* __restrict__ y)
{
    int idx = blockIdx.x * blockDim.x + threadIdx.x;     // over B*L*D
    int d = idx & (Dn - 1);
    int l = (idx >> 9) & (Ln - 1);
    int b = idx >> 18;
    float acc = bias[d];
    const float* wr = w + d * Kn;
#pragma unroll
    for (int kk = 0; kk < Kn; kk++) {
        int ll = l + kk - 3;
        if (ll >= 0 && ll < Ln)
            acc = fmaf(x[((size_t)(b*Ln + ll))*Dn + d], wr[kk], acc);
    }
    y[idx] = fmaxf(acc, 0.f);
}

// ---------------- repack qkv weights [H,D,DH] -> W'[n,d] (n = h*64+dh) ----------------
__global__ void repack_qkv(const float* __restrict__ wq, const float* __restrict__ wk,
                           const float* __restrict__ wv)
{
    int idx = blockIdx.x * blockDim.x + threadIdx.x;     // over D*D
    int n = idx >> 9, d = idx & 511;
    int src = (n >> 6) * (Dn * DHn) + d * DHn + (n & 63);
    g_wq[idx] = wq[src];
    g_wk[idx] = wk[src];
    g_wv[idx] = wv[src];
}

// ---------------- main SGEMM: C[M,512] = A[M,512] * W[512,512]^T (+bias, relu?, +LN(res)?) ----
// 128x128 block tile, Ktile 8, double-buffered smem, 8x8 per thread.
template<bool RELU, bool ADDLN>
__global__ __launch_bounds__(256, 2) void gemm_ep(
    const float* __restrict__ A, const float* __restrict__ W,
    const float* __restrict__ bias, float* __restrict__ C,
    const float* __restrict__ res, const float* __restrict__ lng,
    const float* __restrict__ lnb)
{
    __shared__ float As[2][8][128];
    __shared__ float Bs[2][8][128];
    const int tid = threadIdx.x;
    const int lr = tid >> 1;
    const int lc = (tid & 1) << 2;
    const int bx = blockIdx.x, by = blockIdx.y;
    const int arow = by*128 + lr;
    const int wrow = bx*128 + lr;
    const int tx = tid & 15, ty = tid >> 4;

    float acc[8][8];
#pragma unroll
    for (int i = 0; i < 8; i++)
#pragma unroll
        for (int j = 0; j < 8; j++) acc[i][j] = 0.f;

    float4 ar = *(const float4*)(A + (size_t)arow*Dn + lc);
    float4 br = *(const float4*)(W + (size_t)wrow*Dn + lc);
    As[0][lc+0][lr]=ar.x; As[0][lc+1][lr]=ar.y; As[0][lc+2][lr]=ar.z; As[0][lc+3][lr]=ar.w;
    Bs[0][lc+0][lr]=br.x; Bs[0][lc+1][lr]=br.y; Bs[0][lc+2][lr]=br.z; Bs[0][lc+3][lr]=br.w;
    __syncthreads();
    int buf = 0;
#pragma unroll 1
    for (int kt = 0; kt < Dn/8; kt++) {
        if (kt + 1 < Dn/8) {
            int k0 = (kt+1)*8 + lc;
            ar = *(const float4*)(A + (size_t)arow*Dn + k0);
            br = *(const float4*)(W + (size_t)wrow*Dn + k0);
        }
#pragma unroll
        for (int kk = 0; kk < 8; kk++) {
            float4 a0 = *(const float4*)&As[buf][kk][ty*4];
            float4 a1 = *(const float4*)&As[buf][kk][64 + ty*4];
            float4 b0 = *(const float4*)&Bs[buf][kk][tx*4];
            float4 b1 = *(const float4*)&Bs[buf][kk][64 + tx*4];
            float a[8] = {a0.x,a0.y,a0.z,a0.w,a1.x,a1.y,a1.z,a1.w};
            float b[8] = {b0.x,b0.y,b0.z,b0.w,b1.x,b1.y,b1.z,b1.w};
#pragma unroll
            for (int i = 0; i < 8; i++)
#pragma unroll
                for (int j = 0; j < 8; j++) acc[i][j] = fmaf(a[i], b[j], acc[i][j]);
        }
        if (kt + 1 < Dn/8) {
            int nb = buf ^ 1;
            As[nb][lc+0][lr]=ar.x; As[nb][lc+1][lr]=ar.y; As[nb][lc+2][lr]=ar.z; As[nb][lc+3][lr]=ar.w;
            Bs[nb][lc+0][lr]=br.x; Bs[nb][lc+1][lr]=br.y; Bs[nb][lc+2][lr]=br.z; Bs[nb][lc+3][lr]=br.w;
        }
        __syncthreads();
        buf ^= 1;
    }

    float muv = 0.f, rsv = 0.f;
    if (ADDLN) { int bb = (by*128) / Ln; muv = g_mu[bb]; rsv = g_rstd[bb]; }
#pragma unroll
    for (int i = 0; i < 8; i++) {
        int row  = by*128 + ((i < 4) ? (ty*4 + i) : (64 + ty*4 + i - 4));
        int lrow = row & (Ln - 1);
#pragma unroll
        for (int j = 0; j < 8; j++) {
            int col = bx*128 + ((j < 4) ? (tx*4 + j) : (64 + tx*4 + j - 4));
            float v = acc[i][j] + bias[col];
            if (RELU) v = fmaxf(v, 0.f);
            if (ADDLN) {
                float r = res[(size_t)row*Dn + col];
                v += (r - muv) * rsv * lng[lrow*Dn + col] + lnb[lrow*Dn + col];
            }
            C[(size_t)row*Dn + col] = v;
        }
    }
}

// ---------------- attention scores: att[bh,i,j] = mask-adjusted (q.k)*scale ----------------
__global__ __launch_bounds__(256, 2) void qk_scores(
    const float* __restrict__ q, const float* __restrict__ kx,
    const float* __restrict__ mask, float* __restrict__ att)
{
    int bh = blockIdx.z; int b = bh >> 3, h = bh & 7;
    const float* Qb = q  + (size_t)b*Ln*Dn + h*DHn;
    const float* Kb = kx + (size_t)b*Ln*Dn + h*DHn;
    float* Cb = att + (size_t)bh*Ln*Ln;

    __shared__ float As[2][8][128];
    __shared__ float Bs[2][8][128];
    const int tid = threadIdx.x;
    const int lr = tid >> 1;
    const int lc = (tid & 1) << 2;
    const int i0 = blockIdx.y*128, j0 = blockIdx.x*128;
    const int tx = tid & 15, ty = tid >> 4;

    float acc[8][8];
#pragma unroll
    for (int i = 0; i < 8; i++)
#pragma unroll
        for (int j = 0; j < 8; j++) acc[i][j] = 0.f;

    float4 ar = *(const float4*)(Qb + (size_t)(i0 + lr)*Dn + lc);
    float4 br = *(const float4*)(Kb + (size_t)(j0 + lr)*Dn + lc);
    As[0][lc+0][lr]=ar.x; As[0][lc+1][lr]=ar.y; As[0][lc+2][lr]=ar.z; As[0][lc+3][lr]=ar.w;
    Bs[0][lc+0][lr]=br.x; Bs[0][lc+1][lr]=br.y; Bs[0][lc+2][lr]=br.z; Bs[0][lc+3][lr]=br.w;
    __syncthreads();
    int buf = 0;
#pragma unroll 1
    for (int kt = 0; kt < DHn/8; kt++) {
        if (kt + 1 < DHn/8) {
            int k0 = (kt+1)*8 + lc;
            ar = *(const float4*)(Qb + (size_t)(i0 + lr)*Dn + k0);
            br = *(const float4*)(Kb + (size_t)(j0 + lr)*Dn + k0);
        }
#pragma unroll
        for (int kk = 0; kk < 8; kk++) {
            float4 a0 = *(const float4*)&As[buf][kk][ty*4];
            float4 a1 = *(const float4*)&As[buf][kk][64 + ty*4];
            float4 b0 = *(const float4*)&Bs[buf][kk][tx*4];
            float4 b1 = *(const float4*)&Bs[buf][kk][64 + tx*4];
            float a[8] = {a0.x,a0.y,a0.z,a0.w,a1.x,a1.y,a1.z,a1.w};
            float bb[8] = {b0.x,b0.y,b0.z,b0.w,b1.x,b1.y,b1.z,b1.w};
#pragma unroll
            for (int i = 0; i < 8; i++)
#pragma unroll
                for (int j = 0; j < 8; j++) acc[i][j] = fmaf(a[i], bb[j], acc[i][j]);
        }
        if (kt + 1 < DHn/8) {
            int nb = buf ^ 1;
            As[nb][lc+0][lr]=ar.x; As[nb][lc+1][lr]=ar.y; As[nb][lc+2][lr]=ar.z; As[nb][lc+3][lr]=ar.w;
            Bs[nb][lc+0][lr]=br.x; Bs[nb][lc+1][lr]=br.y; Bs[nb][lc+2][lr]=br.z; Bs[nb][lc+3][lr]=br.w;
        }
        __syncthreads();
        buf ^= 1;
    }

    const float* mb = mask + b * Ln;
    const float scale = 0.125f;   // 1/sqrt(D/8) = 1/8
#pragma unroll
    for (int i = 0; i < 8; i++) {
        int row = i0 + ((i < 4) ? (ty*4 + i) : (64 + ty*4 + i - 4));
        float mi = mb[row];
#pragma unroll
        for (int j = 0; j < 8; j++) {
            int col = j0 + ((j < 4) ? (tx*4 + j) : (64 + tx*4 + j - 4));
            float m = mi * mb[col];
            float s = acc[i][j] * scale;
            s = s * m + NEGV * (1.f - m);
            Cb[(size_t)row*Ln + col] = s;
        }
    }
}

// ---------------- softmax over last dim of att (one warp per 512-row) ----------------
__global__ void softmax_rows(float* __restrict__ att)
{
    int row  = blockIdx.x * 8 + (threadIdx.x >> 5);
    int lane = threadIdx.x & 31;
    float* p = att + (size_t)row * Ln;
    float vals[16];
    float mx = -3.4e38f;
#pragma unroll
    for (int i = 0; i < 16; i++) { vals[i] = p[lane + i*32]; mx = fmaxf(mx, vals[i]); }
#pragma unroll
    for (int o = 16; o > 0; o >>= 1) mx = fmaxf(mx, __shfl_xor_sync(0xffffffffu, mx, o));
    float s = 0.f;
#pragma unroll
    for (int i = 0; i < 16; i++) { vals[i] = __expf(vals[i] - mx); s += vals[i]; }
#pragma unroll
    for (int o = 16; o > 0; o >>= 1) s += __shfl_xor_sync(0xffffffffu, s, o);
    float inv = 1.f / s;
#pragma unroll
    for (int i = 0; i < 16; i++) p[lane + i*32] = vals[i] * inv;
}

// ---------------- attention output: o[bh] = P[512x512] @ V[512x64] ----------------
// block: 128 rows x 64 cols, thread 8x4, Ktile 8, double-buffered.
__global__ __launch_bounds__(256, 2) void attn_av(
    const float* __restrict__ att, const float* __restrict__ v, float* __restrict__ o)
{
    int bh = blockIdx.y; int b = bh >> 3, h = bh & 7;
    const float* P  = att + (size_t)bh*Ln*Ln;
    const float* Vb = v + (size_t)b*Ln*Dn + h*DHn;
    float* Ob = o + (size_t)b*Ln*Dn + h*DHn;
    int m0 = blockIdx.x * 128;

    __shared__ float Ps[2][8][128];
    __shared__ float Vs[2][8][64];
    const int tid = threadIdx.x;
    const int pr = tid >> 1;
    const int pc = (tid & 1) << 2;
    const int vk = tid >> 4;          // valid 0..7 when tid < 128
    const int vn = (tid & 15) << 2;
    const int tx = tid & 15, ty = tid >> 4;

    float acc[8][4];
#pragma unroll
    for (int i = 0; i < 8; i++)
#pragma unroll
        for (int j = 0; j < 4; j++) acc[i][j] = 0.f;

    float4 pa = *(const float4*)(P + (size_t)(m0 + pr)*Ln + pc);
    float4 va = make_float4(0.f,0.f,0.f,0.f);
    if (tid < 128) va = *(const float4*)(Vb + (size_t)vk*Dn + vn);
    Ps[0][pc+0][pr]=pa.x; Ps[0][pc+1][pr]=pa.y; Ps[0][pc+2][pr]=pa.z; Ps[0][pc+3][pr]=pa.w;
    if (tid < 128) *(float4*)&Vs[0][vk][vn] = va;
    __syncthreads();
    int buf = 0;
#pragma unroll 1
    for (int kt = 0; kt < Ln/8; kt++) {
        if (kt + 1 < Ln/8) {
            int k0 = (kt+1)*8;
            pa = *(const float4*)(P + (size_t)(m0 + pr)*Ln + k0 + pc);
            if (tid < 128) va = *(const float4*)(Vb + (size_t)(k0 + vk)*Dn + vn);
        }
#pragma unroll
        for (int kk = 0; kk < 8; kk++) {
            float4 a0 = *(const float4*)&Ps[buf][kk][ty*8];
            float4 a1 = *(const float4*)&Ps[buf][kk][ty*8 + 4];
            float4 bv = *(const float4*)&Vs[buf][kk][tx*4];
            float a[8]  = {a0.x,a0.y,a0.z,a0.w,a1.x,a1.y,a1.z,a1.w};
            float bb[4] = {bv.x,bv.y,bv.z,bv.w};
#pragma unroll
            for (int i = 0; i < 8; i++)
#pragma unroll
                for (int j = 0; j < 4; j++) acc[i][j] = fmaf(a[i], bb[j], acc[i][j]);
        }
        if (kt + 1 < Ln/8) {
            int nb = buf ^ 1;
            Ps[nb][pc+0][pr]=pa.x; Ps[nb][pc+1][pr]=pa.y; Ps[nb][pc+2][pr]=pa.z; Ps[nb][pc+3][pr]=pa.w;
            if (tid < 128) *(float4*)&Vs[nb][vk][vn] = va;
        }
        __syncthreads();
        buf ^= 1;
    }
#pragma unroll
    for (int i = 0; i < 8; i++) {
        int row = m0 + ty*8 + i;
#pragma unroll
        for (int j = 0; j < 4; j++)
            Ob[(size_t)row*Dn + tx*4 + j] = acc[i][j];
    }
}

// ---------------- host orchestration ----------------
extern "C" void kernel_launch(void* const* d_in, const int* in_sizes, int n_in,
                              void* d_out, int out_size)
{
    (void)in_sizes; (void)n_in; (void)out_size;
    const float* x     = (const float*)d_in[0];
    const float* mask  = (const float*)d_in[1];
    const float* pe    = (const float*)d_in[2];
    const float* dw_w  = (const float*)d_in[3];
    const float* dw_b  = (const float*)d_in[4];
    const float* pw_w  = (const float*)d_in[5];
    const float* pw_b  = (const float*)d_in[6];
    const float* wq    = (const float*)d_in[7];
    const float* bq    = (const float*)d_in[8];
    const float* wk    = (const float*)d_in[9];
    const float* bk    = (const float*)d_in[10];
    const float* wv    = (const float*)d_in[11];
    const float* bv    = (const float*)d_in[12];
    const float* fc_w  = (const float*)d_in[13];
    const float* fc_b  = (const float*)d_in[14];
    const float* out_w = (const float*)d_in[15];
    const float* out_b = (const float*)d_in[16];
    const float* lnc_g = (const float*)d_in[17];
    const float* lnc_b = (const float*)d_in[18];
    const float* lna_g = (const float*)d_in[19];
    const float* lna_b = (const float*)d_in[20];
    const float* lno_g = (const float*)d_in[21];
    const float* lno_b = (const float*)d_in[22];
    float* out = (float*)d_out;

    float *x1, *x2, *t, *q, *k, *v, *o, *att, *wqp, *wkp, *wvp;
    cudaGetSymbolAddress((void**)&x1,  g_x1);
    cudaGetSymbolAddress((void**)&x2,  g_x2);
    cudaGetSymbolAddress((void**)&t,   g_t);
    cudaGetSymbolAddress((void**)&q,   g_q);
    cudaGetSymbolAddress((void**)&k,   g_k);
    cudaGetSymbolAddress((void**)&v,   g_v);
    cudaGetSymbolAddress((void**)&o,   g_o);
    cudaGetSymbolAddress((void**)&att, g_att);
    cudaGetSymbolAddress((void**)&wqp, g_wq);
    cudaGetSymbolAddress((void**)&wkp, g_wk);
    cudaGetSymbolAddress((void**)&wvp, g_wv);

    const int NE = Mn * Dn;                 // 8388608
    dim3 gemmGrid(Dn/128, Mn/128);          // (4, 128)

    // x = x + pe
    add_pe_k<<<NE/256, 256>>>(x, pe, x1);

    // conv layer 0 (no residual LN)
    dwconv_relu<<<NE/256, 256>>>(x1, dw_w + 0*Dn*Kn, dw_b + 0*Dn, t);
    gemm_ep<true, false><<<gemmGrid, 256>>>(t, pw_w + 0*Dn*Dn, pw_b + 0*Dn, x2,
                                            nullptr, nullptr, nullptr);
    // conv layer 1: x = dsconv(x2) + LN(x2; lnc[0])
    ln_stats<<<Bn, 1024>>>(x2);
    dwconv_relu<<<NE/256, 256>>>(x2, dw_w + 1*Dn*Kn, dw_b + 1*Dn, t);
    gemm_ep<true, true><<<gemmGrid, 256>>>(t, pw_w + 1*Dn*Dn, pw_b + 1*Dn, x1,
                                           x2, lnc_g + 0, lnc_b + 0);
    // conv layer 2: x = dsconv(x1) + LN(x1; lnc[1])
    ln_stats<<<Bn, 1024>>>(x1);
    dwconv_relu<<<NE/256, 256>>>(x1, dw_w + 2*Dn*Kn, dw_b + 2*Dn, t);
    gemm_ep<true, true><<<gemmGrid, 256>>>(t, pw_w + 2*Dn*Dn, pw_b + 2*Dn, x2,
                                           x1, lnc_g + Ln*Dn, lnc_b + Ln*Dn);

    // attention on x2
    repack_qkv<<<(Dn*Dn)/256, 256>>>(wq, wk, wv);
    gemm_ep<false, false><<<gemmGrid, 256>>>(x2, wqp, bq, q, nullptr, nullptr, nullptr);
    gemm_ep<false, false><<<gemmGrid, 256>>>(x2, wkp, bk, k, nullptr, nullptr, nullptr);
    gemm_ep<false, false><<<gemmGrid, 256>>>(x2, wvp, bv, v, nullptr, nullptr, nullptr);

    qk_scores<<<dim3(Ln/128, Ln/128, Bn*Hn), 256>>>(q, k, mask, att);
    softmax_rows<<<(Bn*Hn*Ln)/8, 256>>>(att);
    attn_av<<<dim3(Ln/128, Bn*Hn), 256>>>(att, v, o);

    // fc + residual LN(x2; lna)
    ln_stats<<<Bn, 1024>>>(x2);
    gemm_ep<false, true><<<gemmGrid, 256>>>(o, fc_w, fc_b, x1, x2, lna_g, lna_b);

    // output linear + residual LN(x1; lno) -> d_out
    ln_stats<<<Bn, 1024>>>(x1);
    gemm_ep<false, true><<<gemmGrid, 256>>>(x1, out_w, out_b, out, x1, lno_g, lno_b);
}

// round 5
// speedup vs baseline: 1.5169x; 1.5169x over previous
#include <cuda_runtime.h>
#include <cuda_bf16.h>
#include <cstdint>

#define Bn 32
#define Ln 512
#define Dn 512
#define Hn 8
#define DHn 64
#define Kn 7
#define Mn (Bn*Ln)
#define NEGV (-1e30f)

// ---- MMA GEMM tiling ----
#define BK 32
#define PITCH 40                    // bf16 elems per smem row (80 bytes, 16B-aligned, conflict-light)
#define TB (128*PITCH*2)            // one tile: 128 rows * 80B = 10240 B
#define BUFB (4*TB)                 // 4 tiles (Ahi, Alo, Whi, Wlo) per buffer
#define SMEM_SZ (2*BUFB)            // double buffer = 81920 B

// ======================= PTX helpers (base-target only) =======================
__device__ __forceinline__ uint32_t smem_u32(const void* p){
    uint32_t a;
    asm("{ .reg .u64 t; cvta.to.shared.u64 t, %1; cvt.u32.u64 %0, t; }" : "=r"(a) : "l"(p));
    return a;
}
__device__ __forceinline__ void cpasync16(uint32_t dst, const void* src){
    asm volatile("cp.async.cg.shared.global [%0], [%1], 16;" :: "r"(dst), "l"(src) : "memory");
}
#define CP_COMMIT() asm volatile("cp.async.commit_group;" ::: "memory")
#define CP_WAIT(N)  asm volatile("cp.async.wait_group %0;" :: "n"(N) : "memory")
__device__ __forceinline__ void ldsm4(uint32_t* r, uint32_t addr){
    asm volatile("ldmatrix.sync.aligned.m8n8.x4.shared.b16 {%0,%1,%2,%3}, [%4];"
        : "=r"(r[0]), "=r"(r[1]), "=r"(r[2]), "=r"(r[3]) : "r"(addr));
}
__device__ __forceinline__ void mma16816(float* d, const uint32_t* a, const uint32_t* b){
    asm volatile("mma.sync.aligned.m16n8k16.row.col.f32.bf16.bf16.f32 "
        "{%0,%1,%2,%3}, {%4,%5,%6,%7}, {%8,%9}, {%0,%1,%2,%3};"
        : "+f"(d[0]), "+f"(d[1]), "+f"(d[2]), "+f"(d[3])
        : "r"(a[0]), "r"(a[1]), "r"(a[2]), "r"(a[3]), "r"(b[0]), "r"(b[1]));
}

// ======================= scratch (device globals) =======================
__device__ float g_x1[Mn*Dn];
__device__ float g_x2[Mn*Dn];
__device__ float g_q [Mn*Dn];
__device__ float g_k [Mn*Dn];
__device__ float g_v [Mn*Dn];
__device__ float g_att[Bn*Hn*Ln*Ln];
__device__ float g_mu[Bn];
__device__ float g_rstd[Bn];
__device__ __nv_bfloat16 g_pt[2][Mn*Dn];      // activation pair T (hi, lo)
__device__ __nv_bfloat16 g_px[2][Mn*Dn];      // activation pair X (hi, lo)
__device__ __nv_bfloat16 g_wspl[8*2*Dn*Dn];   // 8 weights x (hi, lo)

// ======================= small kernels =======================
__global__ void add_pe_k(const float* __restrict__ x, const float* __restrict__ pe,
                         float* __restrict__ y)
{
    int idx = blockIdx.x * blockDim.x + threadIdx.x;
    y[idx] = x[idx] + pe[idx & (Ln*Dn - 1)];
}

__global__ void ln_stats(const float* __restrict__ x)
{
    int b = blockIdx.x;
    const float4* p = (const float4*)(x + (size_t)b * Ln * Dn);
    float s = 0.f, s2 = 0.f;
    for (int i = threadIdx.x; i < Ln*Dn/4; i += blockDim.x) {
        float4 v = p[i];
        s  += v.x + v.y + v.z + v.w;
        s2 += v.x*v.x + v.y*v.y + v.z*v.z + v.w*v.w;
    }
#pragma unroll
    for (int o = 16; o > 0; o >>= 1) {
        s  += __shfl_xor_sync(0xffffffffu, s,  o);
        s2 += __shfl_xor_sync(0xffffffffu, s2, o);
    }
    __shared__ float sh[32], sh2[32];
    int w = threadIdx.x >> 5, lane = threadIdx.x & 31;
    if (lane == 0) { sh[w] = s; sh2[w] = s2; }
    __syncthreads();
    if (w == 0) {
        int nw = blockDim.x >> 5;
        s  = (lane < nw) ? sh[lane]  : 0.f;
        s2 = (lane < nw) ? sh2[lane] : 0.f;
#pragma unroll
        for (int o = 16; o > 0; o >>= 1) {
            s  += __shfl_xor_sync(0xffffffffu, s,  o);
            s2 += __shfl_xor_sync(0xffffffffu, s2, o);
        }
        if (lane == 0) {
            float inv = 1.f / (float)(Ln*Dn);
            float m   = s * inv;
            float var = s2 * inv - m*m;
            g_mu[b]   = m;
            g_rstd[b] = rsqrtf(var + 1e-5f);
        }
    }
}

// depthwise conv + relu, emits bf16 hi/lo pair directly
__global__ void dwconv_relu(const float* __restrict__ x, const float* __restrict__ w,
                            const float* __restrict__ bias,
                            __nv_bfloat16* __restrict__ hi, __nv_bfloat16* __restrict__ lo)
{
    int idx = blockIdx.x * blockDim.x + threadIdx.x;
    int d = idx & (Dn - 1);
    int l = (idx >> 9) & (Ln - 1);
    int b = idx >> 18;
    float acc = bias[d];
    const float* wr = w + d * Kn;
#pragma unroll
    for (int kk = 0; kk < Kn; kk++) {
        int ll = l + kk - 3;
        if (ll >= 0 && ll < Ln)
            acc = fmaf(x[((size_t)(b*Ln + ll))*Dn + d], wr[kk], acc);
    }
    float r = fmaxf(acc, 0.f);
    __nv_bfloat16 h = __float2bfloat16_rn(r);
    hi[idx] = h;
    lo[idx] = __float2bfloat16_rn(r - __bfloat162float(h));
}

__global__ void split_w(const float* __restrict__ w,
                        __nv_bfloat16* __restrict__ hi, __nv_bfloat16* __restrict__ lo)
{
    int idx = blockIdx.x * blockDim.x + threadIdx.x;
    float a = w[idx];
    __nv_bfloat16 h = __float2bfloat16_rn(a);
    hi[idx] = h;
    lo[idx] = __float2bfloat16_rn(a - __bfloat162float(h));
}

__global__ void repack_split(const float* __restrict__ wq, const float* __restrict__ wk,
                             const float* __restrict__ wv,
                             __nv_bfloat16* __restrict__ qh, __nv_bfloat16* __restrict__ ql,
                             __nv_bfloat16* __restrict__ kh, __nv_bfloat16* __restrict__ kl,
                             __nv_bfloat16* __restrict__ vh, __nv_bfloat16* __restrict__ vl)
{
    int idx = blockIdx.x * blockDim.x + threadIdx.x;
    int n = idx >> 9, d = idx & 511;
    int src = (n >> 6) * (Dn * DHn) + d * DHn + (n & 63);
    float a;
    __nv_bfloat16 h;
    a = wq[src]; h = __float2bfloat16_rn(a); qh[idx] = h; ql[idx] = __float2bfloat16_rn(a - __bfloat162float(h));
    a = wk[src]; h = __float2bfloat16_rn(a); kh[idx] = h; kl[idx] = __float2bfloat16_rn(a - __bfloat162float(h));
    a = wv[src]; h = __float2bfloat16_rn(a); vh[idx] = h; vl[idx] = __float2bfloat16_rn(a - __bfloat162float(h));
}

// ======================= mma.sync GEMM: C[M,512] = A*W^T (3-term bf16) =======================
// CTA 128x128, BK=32, 8 warps (2x4), warp tile 64x32, cp.async double-buffered.
template<bool RELU, bool ADDLN, bool SPLIT>
__global__ __launch_bounds__(256, 2) void gemm_mma(
    const __nv_bfloat16* __restrict__ Ahi, const __nv_bfloat16* __restrict__ Alo,
    const __nv_bfloat16* __restrict__ Whi, const __nv_bfloat16* __restrict__ Wlo,
    const float* __restrict__ bias, float* __restrict__ C,
    const float* __restrict__ res, const float* __restrict__ lng,
    const float* __restrict__ lnb,
    __nv_bfloat16* __restrict__ Chi, __nv_bfloat16* __restrict__ Clo)
{
    extern __shared__ __align__(16) char dsm[];
    const uint32_t sb = smem_u32(dsm);
    const int tid = threadIdx.x;
    const int wid = tid >> 5, lane = tid & 31;
    const int warpRow = wid >> 2, warpCol = wid & 3;
    const int bx = blockIdx.x, by = blockIdx.y;

    const __nv_bfloat16* srcs[4] = {Ahi, Alo, Whi, Wlo};
    const int rowb[2] = { by*128, bx*128 };

    // prefetch one k-step into buffer (kt&1)
    auto PREF = [&](int kt){
        uint32_t bufb = sb + (uint32_t)(kt & 1) * BUFB;
#pragma unroll
        for (int t = 0; t < 4; t++){
            const __nv_bfloat16* src = srcs[t] + (size_t)rowb[t >> 1]*Dn + kt*BK;
            uint32_t tb = bufb + (uint32_t)t*TB;
#pragma unroll
            for (int i = 0; i < 2; i++){
                int id  = tid + i*256;
                int row = id >> 2, c = id & 3;
                cpasync16(tb + (uint32_t)(row*(PITCH*2) + c*16),
                          src + (size_t)row*Dn + c*8);
            }
        }
        CP_COMMIT();
    };

    float acc[4][4][4];
#pragma unroll
    for (int i = 0; i < 4; i++)
#pragma unroll
        for (int j = 0; j < 4; j++)
#pragma unroll
            for (int q = 0; q < 4; q++) acc[i][j][q] = 0.f;

    // ldmatrix lane address components
    const uint32_t aRow = (uint32_t)(warpRow*64 + (lane & 15));
    const uint32_t aColB = (uint32_t)(((lane >> 4) << 4));                // 0 or 16 bytes
    const uint32_t bRow = (uint32_t)(warpCol*32 + (lane & 7) + ((lane >> 4) << 3));
    const uint32_t bColB = (uint32_t)((((lane >> 3) & 1) << 4));          // 0 or 16 bytes

    PREF(0);
#pragma unroll 1
    for (int kt = 0; kt < Dn/BK; kt++){
        if (kt + 1 < Dn/BK) { PREF(kt + 1); CP_WAIT(1); }
        else                { CP_WAIT(0); }
        __syncthreads();

        uint32_t bufb = sb + (uint32_t)(kt & 1) * BUFB;
        uint32_t tAhi = bufb, tAlo = bufb + TB, tWhi = bufb + 2*TB, tWlo = bufb + 3*TB;
#pragma unroll
        for (int term = 0; term < 3; term++){
            uint32_t aB = (term == 1) ? tAlo : tAhi;
            uint32_t wB = (term == 2) ? tWlo : tWhi;
#pragma unroll
            for (int kk = 0; kk < 2; kk++){
                uint32_t a[4][4], b[2][4];
#pragma unroll
                for (int mi = 0; mi < 4; mi++)
                    ldsm4(a[mi], aB + (aRow + mi*16)*(PITCH*2) + aColB + kk*32);
#pragma unroll
                for (int nt = 0; nt < 2; nt++)
                    ldsm4(b[nt], wB + (bRow + nt*16)*(PITCH*2) + bColB + kk*32);
#pragma unroll
                for (int mi = 0; mi < 4; mi++)
#pragma unroll
                    for (int nj = 0; nj < 4; nj++)
                        mma16816(acc[mi][nj], a[mi], &b[nj >> 1][(nj & 1) << 1]);
            }
        }
        __syncthreads();
    }

    // ---------------- fused epilogue straight from registers ----------------
    float muv = 0.f, rsv = 0.f;
    if (ADDLN) { int bb = (by*128) >> 9; muv = g_mu[bb]; rsv = g_rstd[bb]; }
    const int r0base = by*128 + warpRow*64;
    const int c0base = bx*128 + warpCol*32;
#pragma unroll
    for (int mi = 0; mi < 4; mi++){
#pragma unroll
        for (int rp = 0; rp < 2; rp++){
            int grow = r0base + mi*16 + (lane >> 2) + rp*8;
            int lrow = grow & (Ln - 1);
#pragma unroll
            for (int nj = 0; nj < 4; nj++){
                int col = c0base + nj*8 + (lane & 3)*2;
                float vx = acc[mi][nj][rp*2 + 0];
                float vy = acc[mi][nj][rp*2 + 1];
                float2 bs = *(const float2*)(bias + col);
                vx += bs.x; vy += bs.y;
                if (RELU) { vx = fmaxf(vx, 0.f); vy = fmaxf(vy, 0.f); }
                if (ADDLN) {
                    float2 rr = *(const float2*)(res + (size_t)grow*Dn + col);
                    float2 gg = *(const float2*)(lng + (size_t)lrow*Dn + col);
                    float2 bb = *(const float2*)(lnb + (size_t)lrow*Dn + col);
                    vx += (rr.x - muv)*rsv*gg.x + bb.x;
                    vy += (rr.y - muv)*rsv*gg.y + bb.y;
                }
                float2 o; o.x = vx; o.y = vy;
                *(float2*)(C + (size_t)grow*Dn + col) = o;
                if (SPLIT) {
                    size_t off = (size_t)grow*Dn + col;
                    __nv_bfloat16 h0 = __float2bfloat16_rn(vx);
                    __nv_bfloat16 h1 = __float2bfloat16_rn(vy);
                    __nv_bfloat162 hh; hh.x = h0; hh.y = h1;
                    __nv_bfloat162 ll;
                    ll.x = __float2bfloat16_rn(vx - __bfloat162float(h0));
                    ll.y = __float2bfloat16_rn(vy - __bfloat162float(h1));
                    *(__nv_bfloat162*)(Chi + off) = hh;
                    *(__nv_bfloat162*)(Clo + off) = ll;
                }
            }
        }
    }
}

// ======================= fp32 attention kernels =======================
__global__ __launch_bounds__(256, 2) void qk_scores(
    const float* __restrict__ q, const float* __restrict__ kx,
    const float* __restrict__ mask, float* __restrict__ att)
{
    int bh = blockIdx.z; int b = bh >> 3, h = bh & 7;
    const float* Qb = q  + (size_t)b*Ln*Dn + h*DHn;
    const float* Kb = kx + (size_t)b*Ln*Dn + h*DHn;
    float* Cb = att + (size_t)bh*Ln*Ln;

    __shared__ float As[2][8][128];
    __shared__ float Bs[2][8][128];
    const int tid = threadIdx.x;
    const int lr = tid >> 1;
    const int lc = (tid & 1) << 2;
    const int i0 = blockIdx.y*128, j0 = blockIdx.x*128;
    const int tx = tid & 15, ty = tid >> 4;

    float acc[8][8];
#pragma unroll
    for (int i = 0; i < 8; i++)
#pragma unroll
        for (int j = 0; j < 8; j++) acc[i][j] = 0.f;

    float4 ar = *(const float4*)(Qb + (size_t)(i0 + lr)*Dn + lc);
    float4 br = *(const float4*)(Kb + (size_t)(j0 + lr)*Dn + lc);
    As[0][lc+0][lr]=ar.x; As[0][lc+1][lr]=ar.y; As[0][lc+2][lr]=ar.z; As[0][lc+3][lr]=ar.w;
    Bs[0][lc+0][lr]=br.x; Bs[0][lc+1][lr]=br.y; Bs[0][lc+2][lr]=br.z; Bs[0][lc+3][lr]=br.w;
    __syncthreads();
    int buf = 0;
#pragma unroll 1
    for (int kt = 0; kt < DHn/8; kt++) {
        if (kt + 1 < DHn/8) {
            int k0 = (kt+1)*8 + lc;
            ar = *(const float4*)(Qb + (size_t)(i0 + lr)*Dn + k0);
            br = *(const float4*)(Kb + (size_t)(j0 + lr)*Dn + k0);
        }
#pragma unroll
        for (int kk = 0; kk < 8; kk++) {
            float4 a0 = *(const float4*)&As[buf][kk][ty*4];
            float4 a1 = *(const float4*)&As[buf][kk][64 + ty*4];
            float4 b0 = *(const float4*)&Bs[buf][kk][tx*4];
            float4 b1 = *(const float4*)&Bs[buf][kk][64 + tx*4];
            float a[8] = {a0.x,a0.y,a0.z,a0.w,a1.x,a1.y,a1.z,a1.w};
            float bb[8] = {b0.x,b0.y,b0.z,b0.w,b1.x,b1.y,b1.z,b1.w};
#pragma unroll
            for (int i = 0; i < 8; i++)
#pragma unroll
                for (int j = 0; j < 8; j++) acc[i][j] = fmaf(a[i], bb[j], acc[i][j]);
        }
        if (kt + 1 < DHn/8) {
            int nb = buf ^ 1;
            As[nb][lc+0][lr]=ar.x; As[nb][lc+1][lr]=ar.y; As[nb][lc+2][lr]=ar.z; As[nb][lc+3][lr]=ar.w;
            Bs[nb][lc+0][lr]=br.x; Bs[nb][lc+1][lr]=br.y; Bs[nb][lc+2][lr]=br.z; Bs[nb][lc+3][lr]=br.w;
        }
        __syncthreads();
        buf ^= 1;
    }

    const float* mb = mask + b * Ln;
    const float scale = 0.125f;
#pragma unroll
    for (int i = 0; i < 8; i++) {
        int row = i0 + ((i < 4) ? (ty*4 + i) : (64 + ty*4 + i - 4));
        float mi = mb[row];
#pragma unroll
        for (int j = 0; j < 8; j++) {
            int col = j0 + ((j < 4) ? (tx*4 + j) : (64 + tx*4 + j - 4));
            float m = mi * mb[col];
            float s = acc[i][j] * scale;
            s = s * m + NEGV * (1.f - m);
            Cb[(size_t)row*Ln + col] = s;
        }
    }
}

__global__ void softmax_rows(float* __restrict__ att)
{
    int row  = blockIdx.x * 8 + (threadIdx.x >> 5);
    int lane = threadIdx.x & 31;
    float* p = att + (size_t)row * Ln;
    float vals[16];
    float mx = -3.4e38f;
#pragma unroll
    for (int i = 0; i < 16; i++) { vals[i] = p[lane + i*32]; mx = fmaxf(mx, vals[i]); }
#pragma unroll
    for (int o = 16; o > 0; o >>= 1) mx = fmaxf(mx, __shfl_xor_sync(0xffffffffu, mx, o));
    float s = 0.f;
#pragma unroll
    for (int i = 0; i < 16; i++) { vals[i] = __expf(vals[i] - mx); s += vals[i]; }
#pragma unroll
    for (int o = 16; o > 0; o >>= 1) s += __shfl_xor_sync(0xffffffffu, s, o);
    float inv = 1.f / s;
#pragma unroll
    for (int i = 0; i < 16; i++) p[lane + i*32] = vals[i] * inv;
}

__global__ __launch_bounds__(256, 2) void attn_av(
    const float* __restrict__ att, const float* __restrict__ v,
    __nv_bfloat16* __restrict__ Ohi, __nv_bfloat16* __restrict__ Olo)
{
    int bh = blockIdx.y; int b = bh >> 3, h = bh & 7;
    const float* P  = att + (size_t)bh*Ln*Ln;
    const float* Vb = v + (size_t)b*Ln*Dn + h*DHn;
    size_t obase = (size_t)b*Ln*Dn + h*DHn;
    int m0 = blockIdx.x * 128;

    __shared__ float Ps[2][8][128];
    __shared__ float Vs[2][8][64];
    const int tid = threadIdx.x;
    const int pr = tid >> 1;
    const int pc = (tid & 1) << 2;
    const int vk = tid >> 4;
    const int vn = (tid & 15) << 2;
    const int tx = tid & 15, ty = tid >> 4;

    float acc[8][4];
#pragma unroll
    for (int i = 0; i < 8; i++)
#pragma unroll
        for (int j = 0; j < 4; j++) acc[i][j] = 0.f;

    float4 pa = *(const float4*)(P + (size_t)(m0 + pr)*Ln + pc);
    float4 va = make_float4(0.f,0.f,0.f,0.f);
    if (tid < 128) va = *(const float4*)(Vb + (size_t)vk*Dn + vn);
    Ps[0][pc+0][pr]=pa.x; Ps[0][pc+1][pr]=pa.y; Ps[0][pc+2][pr]=pa.z; Ps[0][pc+3][pr]=pa.w;
    if (tid < 128) *(float4*)&Vs[0][vk][vn] = va;
    __syncthreads();
    int buf = 0;
#pragma unroll 1
    for (int kt = 0; kt < Ln/8; kt++) {
        if (kt + 1 < Ln/8) {
            int k0 = (kt+1)*8;
            pa = *(const float4*)(P + (size_t)(m0 + pr)*Ln + k0 + pc);
            if (tid < 128) va = *(const float4*)(Vb + (size_t)(k0 + vk)*Dn + vn);
        }
#pragma unroll
        for (int kk = 0; kk < 8; kk++) {
            float4 a0 = *(const float4*)&Ps[buf][kk][ty*8];
            float4 a1 = *(const float4*)&Ps[buf][kk][ty*8 + 4];
            float4 bv = *(const float4*)&Vs[buf][kk][tx*4];
            float a[8]  = {a0.x,a0.y,a0.z,a0.w,a1.x,a1.y,a1.z,a1.w};
            float bb[4] = {bv.x,bv.y,bv.z,bv.w};
#pragma unroll
            for (int i = 0; i < 8; i++)
#pragma unroll
                for (int j = 0; j < 4; j++) acc[i][j] = fmaf(a[i], bb[j], acc[i][j]);
        }
        if (kt + 1 < Ln/8) {
            int nb = buf ^ 1;
            Ps[nb][pc+0][pr]=pa.x; Ps[nb][pc+1][pr]=pa.y; Ps[nb][pc+2][pr]=pa.z; Ps[nb][pc+3][pr]=pa.w;
            if (tid < 128) *(float4*)&Vs[nb][vk][vn] = va;
        }
        __syncthreads();
        buf ^= 1;
    }
#pragma unroll
    for (int i = 0; i < 8; i++) {
        int row = m0 + ty*8 + i;
        size_t o = obase + (size_t)row*Dn + tx*4;
        __nv_bfloat162 hh0, hh1, ll0, ll1;
        __nv_bfloat16 h0 = __float2bfloat16_rn(acc[i][0]);
        __nv_bfloat16 h1 = __float2bfloat16_rn(acc[i][1]);
        __nv_bfloat16 h2 = __float2bfloat16_rn(acc[i][2]);
        __nv_bfloat16 h3 = __float2bfloat16_rn(acc[i][3]);
        hh0.x = h0; hh0.y = h1; hh1.x = h2; hh1.y = h3;
        ll0.x = __float2bfloat16_rn(acc[i][0] - __bfloat162float(h0));
        ll0.y = __float2bfloat16_rn(acc[i][1] - __bfloat162float(h1));
        ll1.x = __float2bfloat16_rn(acc[i][2] - __bfloat162float(h2));
        ll1.y = __float2bfloat16_rn(acc[i][3] - __bfloat162float(h3));
        *(__nv_bfloat162*)(Ohi + o)     = hh0;
        *(__nv_bfloat162*)(Ohi + o + 2) = hh1;
        *(__nv_bfloat162*)(Olo + o)     = ll0;
        *(__nv_bfloat162*)(Olo + o + 2) = ll1;
    }
}

// ======================= host orchestration =======================
extern "C" void kernel_launch(void* const* d_in, const int* in_sizes, int n_in,
                              void* d_out, int out_size)
{
    (void)in_sizes; (void)n_in; (void)out_size;
    const float* x     = (const float*)d_in[0];
    const float* mask  = (const float*)d_in[1];
    const float* pe    = (const float*)d_in[2];
    const float* dw_w  = (const float*)d_in[3];
    const float* dw_b  = (const float*)d_in[4];
    const float* pw_w  = (const float*)d_in[5];
    const float* pw_b  = (const float*)d_in[6];
    const float* wq    = (const float*)d_in[7];
    const float* bq    = (const float*)d_in[8];
    const float* wk    = (const float*)d_in[9];
    const float* bk    = (const float*)d_in[10];
    const float* wv    = (const float*)d_in[11];
    const float* bv    = (const float*)d_in[12];
    const float* fc_w  = (const float*)d_in[13];
    const float* fc_b  = (const float*)d_in[14];
    const float* out_w = (const float*)d_in[15];
    const float* out_b = (const float*)d_in[16];
    const float* lnc_g = (const float*)d_in[17];
    const float* lnc_b = (const float*)d_in[18];
    const float* lna_g = (const float*)d_in[19];
    const float* lna_b = (const float*)d_in[20];
    const float* lno_g = (const float*)d_in[21];
    const float* lno_b = (const float*)d_in[22];
    float* out = (float*)d_out;

    float *x1, *x2, *q, *k, *v, *att;
    __nv_bfloat16 *pt, *px, *ws;
    cudaGetSymbolAddress((void**)&x1,  g_x1);
    cudaGetSymbolAddress((void**)&x2,  g_x2);
    cudaGetSymbolAddress((void**)&q,   g_q);
    cudaGetSymbolAddress((void**)&k,   g_k);
    cudaGetSymbolAddress((void**)&v,   g_v);
    cudaGetSymbolAddress((void**)&att, g_att);
    cudaGetSymbolAddress((void**)&pt,  g_pt);
    cudaGetSymbolAddress((void**)&px,  g_px);
    cudaGetSymbolAddress((void**)&ws,  g_wspl);

    __nv_bfloat16* pt_hi = pt;
    __nv_bfloat16* pt_lo = pt + (size_t)Mn*Dn;
    __nv_bfloat16* px_hi = px;
    __nv_bfloat16* px_lo = px + (size_t)Mn*Dn;
    auto W = [&](int i, int hl){ return ws + ((size_t)i*2 + hl) * Dn * Dn; };

    cudaFuncSetAttribute(gemm_mma<true,false,false>,  cudaFuncAttributeMaxDynamicSharedMemorySize, SMEM_SZ);
    cudaFuncSetAttribute(gemm_mma<true,true,false>,   cudaFuncAttributeMaxDynamicSharedMemorySize, SMEM_SZ);
    cudaFuncSetAttribute(gemm_mma<true,true,true>,    cudaFuncAttributeMaxDynamicSharedMemorySize, SMEM_SZ);
    cudaFuncSetAttribute(gemm_mma<false,false,false>, cudaFuncAttributeMaxDynamicSharedMemorySize, SMEM_SZ);
    cudaFuncSetAttribute(gemm_mma<false,true,true>,   cudaFuncAttributeMaxDynamicSharedMemorySize, SMEM_SZ);
    cudaFuncSetAttribute(gemm_mma<false,true,false>,  cudaFuncAttributeMaxDynamicSharedMemorySize, SMEM_SZ);

    const int NE = Mn * Dn;
    dim3 gemmGrid(Dn/128, Mn/128);   // (4, 128)
    const int WG = (Dn*Dn)/256;

    // weight splits
    split_w<<<WG, 256>>>(pw_w + 0*Dn*Dn, W(0,0), W(0,1));
    split_w<<<WG, 256>>>(pw_w + 1*Dn*Dn, W(1,0), W(1,1));
    split_w<<<WG, 256>>>(pw_w + 2*Dn*Dn, W(2,0), W(2,1));
    repack_split<<<WG, 256>>>(wq, wk, wv, W(3,0), W(3,1), W(4,0), W(4,1), W(5,0), W(5,1));
    split_w<<<WG, 256>>>(fc_w,  W(6,0), W(6,1));
    split_w<<<WG, 256>>>(out_w, W(7,0), W(7,1));

    // x = x + pe
    add_pe_k<<<NE/256, 256>>>(x, pe, x1);

    // conv layer 0
    dwconv_relu<<<NE/256, 256>>>(x1, dw_w + 0*Dn*Kn, dw_b + 0*Dn, pt_hi, pt_lo);
    gemm_mma<true,false,false><<<gemmGrid, 256, SMEM_SZ>>>(
        pt_hi, pt_lo, W(0,0), W(0,1), pw_b + 0*Dn, x2,
        nullptr, nullptr, nullptr, nullptr, nullptr);
    // conv layer 1: + LN(x2; lnc0)
    ln_stats<<<Bn, 1024>>>(x2);
    dwconv_relu<<<NE/256, 256>>>(x2, dw_w + 1*Dn*Kn, dw_b + 1*Dn, pt_hi, pt_lo);
    gemm_mma<true,true,false><<<gemmGrid, 256, SMEM_SZ>>>(
        pt_hi, pt_lo, W(1,0), W(1,1), pw_b + 1*Dn, x1,
        x2, lnc_g + 0, lnc_b + 0, nullptr, nullptr);
    // conv layer 2: + LN(x1; lnc1), emit bf16 pair for qkv
    ln_stats<<<Bn, 1024>>>(x1);
    dwconv_relu<<<NE/256, 256>>>(x1, dw_w + 2*Dn*Kn, dw_b + 2*Dn, pt_hi, pt_lo);
    gemm_mma<true,true,true><<<gemmGrid, 256, SMEM_SZ>>>(
        pt_hi, pt_lo, W(2,0), W(2,1), pw_b + 2*Dn, x2,
        x1, lnc_g + Ln*Dn, lnc_b + Ln*Dn, px_hi, px_lo);

    // qkv projections
    gemm_mma<false,false,false><<<gemmGrid, 256, SMEM_SZ>>>(
        px_hi, px_lo, W(3,0), W(3,1), bq, q, nullptr, nullptr, nullptr, nullptr, nullptr);
    gemm_mma<false,false,false><<<gemmGrid, 256, SMEM_SZ>>>(
        px_hi, px_lo, W(4,0), W(4,1), bk, k, nullptr, nullptr, nullptr, nullptr, nullptr);
    gemm_mma<false,false,false><<<gemmGrid, 256, SMEM_SZ>>>(
        px_hi, px_lo, W(5,0), W(5,1), bv, v, nullptr, nullptr, nullptr, nullptr, nullptr);

    // attention (fp32), output as bf16 pair
    qk_scores<<<dim3(Ln/128, Ln/128, Bn*Hn), 256>>>(q, k, mask, att);
    softmax_rows<<<(Bn*Hn*Ln)/8, 256>>>(att);
    attn_av<<<dim3(Ln/128, Bn*Hn), 256>>>(att, v, pt_hi, pt_lo);

    // fc + LN(x2; lna), emit pair for out gemm
    ln_stats<<<Bn, 1024>>>(x2);
    gemm_mma<false,true,true><<<gemmGrid, 256, SMEM_SZ>>>(
        pt_hi, pt_lo, W(6,0), W(6,1), fc_b, x1,
        x2, lna_g, lna_b, px_hi, px_lo);

    // out + LN(x1; lno) -> d_out
    ln_stats<<<Bn, 1024>>>(x1);
    gemm_mma<false,true,false><<<gemmGrid, 256, SMEM_SZ>>>(
        px_hi, px_lo, W(7,0), W(7,1), out_b, out,
        x1, lno_g, lno_b, nullptr, nullptr);
}

// round 6
// speedup vs baseline: 2.0422x; 1.3463x over previous
#include <cuda_runtime.h>
#include <cuda_bf16.h>
#include <cstdint>

#define Bn 32
#define Ln 512
#define Dn 512
#define Hn 8
#define DHn 64
#define Kn 7
#define Mn (Bn*Ln)
#define NEGV (-1e30f)

// ---- big-GEMM tiling ----
#define BK 32
#define PITCH 40
#define TB (128*PITCH*2)
#define BUFB (4*TB)
#define SMEM_SZ (2*BUFB)

// ---- fused attention smem layout ----
#define AP 144                      // pitch bytes for 64-col bf16 tiles (72 elems)
#define QT (128*AP)                 // 18432 B, one 128x64 bf16 tile
#define KVB (4*QT)                  // khi,klo,vhi,vlo chunk = 73728 B
#define SMEM_ATT (2*QT + 2*KVB + 1024)   // Q pair + 2 KV bufs + mask = 185344 B

// ======================= PTX helpers (base-target only) =======================
__device__ __forceinline__ uint32_t smem_u32(const void* p){
    uint32_t a;
    asm("{ .reg .u64 t; cvta.to.shared.u64 t, %1; cvt.u32.u64 %0, t; }" : "=r"(a) : "l"(p));
    return a;
}
__device__ __forceinline__ void cpasync16(uint32_t dst, const void* src){
    asm volatile("cp.async.cg.shared.global [%0], [%1], 16;" :: "r"(dst), "l"(src) : "memory");
}
#define CP_COMMIT() asm volatile("cp.async.commit_group;" ::: "memory")
#define CP_WAIT(N)  asm volatile("cp.async.wait_group %0;" :: "n"(N) : "memory")
__device__ __forceinline__ void ldsm4(uint32_t* r, uint32_t addr){
    asm volatile("ldmatrix.sync.aligned.m8n8.x4.shared.b16 {%0,%1,%2,%3}, [%4];"
        : "=r"(r[0]), "=r"(r[1]), "=r"(r[2]), "=r"(r[3]) : "r"(addr));
}
__device__ __forceinline__ void ldsm4t(uint32_t* r, uint32_t addr){
    asm volatile("ldmatrix.sync.aligned.m8n8.x4.trans.shared.b16 {%0,%1,%2,%3}, [%4];"
        : "=r"(r[0]), "=r"(r[1]), "=r"(r[2]), "=r"(r[3]) : "r"(addr));
}
__device__ __forceinline__ void mma16816(float* d, const uint32_t* a, const uint32_t* b){
    asm volatile("mma.sync.aligned.m16n8k16.row.col.f32.bf16.bf16.f32 "
        "{%0,%1,%2,%3}, {%4,%5,%6,%7}, {%8,%9}, {%0,%1,%2,%3};"
        : "+f"(d[0]), "+f"(d[1]), "+f"(d[2]), "+f"(d[3])
        : "r"(a[0]), "r"(a[1]), "r"(a[2]), "r"(a[3]), "r"(b[0]), "r"(b[1]));
}
__device__ __forceinline__ void packpair(float x, float y, uint32_t& hi, uint32_t& lo){
    __nv_bfloat16 hx = __float2bfloat16_rn(x), hy = __float2bfloat16_rn(y);
    __nv_bfloat162 h; h.x = hx; h.y = hy;
    __nv_bfloat162 l;
    l.x = __float2bfloat16_rn(x - __bfloat162float(hx));
    l.y = __float2bfloat16_rn(y - __bfloat162float(hy));
    hi = *(uint32_t*)&h; lo = *(uint32_t*)&l;
}

// ======================= scratch (device globals) =======================
__device__ float g_x1[Mn*Dn];
__device__ float g_x2[Mn*Dn];
__device__ float g_mu[Bn];
__device__ float g_rstd[Bn];
__device__ __nv_bfloat16 g_pt[2][Mn*Dn];      // activation pair T (hi, lo)
__device__ __nv_bfloat16 g_px[2][Mn*Dn];      // activation pair X (hi, lo)
__device__ __nv_bfloat16 g_qkv[6][Mn*Dn];     // q,k,v pairs (hi,lo each)
__device__ __nv_bfloat16 g_wspl[8*2*Dn*Dn];   // 8 weights x (hi, lo)

// ======================= small kernels =======================
__global__ void add_pe_k(const float* __restrict__ x, const float* __restrict__ pe,
                         float* __restrict__ y)
{
    int idx = blockIdx.x * blockDim.x + threadIdx.x;
    y[idx] = x[idx] + pe[idx & (Ln*Dn - 1)];
}

__global__ void ln_stats(const float* __restrict__ x)
{
    int b = blockIdx.x;
    const float4* p = (const float4*)(x + (size_t)b * Ln * Dn);
    float s = 0.f, s2 = 0.f;
    for (int i = threadIdx.x; i < Ln*Dn/4; i += blockDim.x) {
        float4 v = p[i];
        s  += v.x + v.y + v.z + v.w;
        s2 += v.x*v.x + v.y*v.y + v.z*v.z + v.w*v.w;
    }
#pragma unroll
    for (int o = 16; o > 0; o >>= 1) {
        s  += __shfl_xor_sync(0xffffffffu, s,  o);
        s2 += __shfl_xor_sync(0xffffffffu, s2, o);
    }
    __shared__ float sh[32], sh2[32];
    int w = threadIdx.x >> 5, lane = threadIdx.x & 31;
    if (lane == 0) { sh[w] = s; sh2[w] = s2; }
    __syncthreads();
    if (w == 0) {
        int nw = blockDim.x >> 5;
        s  = (lane < nw) ? sh[lane]  : 0.f;
        s2 = (lane < nw) ? sh2[lane] : 0.f;
#pragma unroll
        for (int o = 16; o > 0; o >>= 1) {
            s  += __shfl_xor_sync(0xffffffffu, s,  o);
            s2 += __shfl_xor_sync(0xffffffffu, s2, o);
        }
        if (lane == 0) {
            float inv = 1.f / (float)(Ln*Dn);
            float m   = s * inv;
            float var = s2 * inv - m*m;
            g_mu[b]   = m;
            g_rstd[b] = rsqrtf(var + 1e-5f);
        }
    }
}

__global__ void dwconv_relu(const float* __restrict__ x, const float* __restrict__ w,
                            const float* __restrict__ bias,
                            __nv_bfloat16* __restrict__ hi, __nv_bfloat16* __restrict__ lo)
{
    int idx = blockIdx.x * blockDim.x + threadIdx.x;
    int d = idx & (Dn - 1);
    int l = (idx >> 9) & (Ln - 1);
    int b = idx >> 18;
    float acc = bias[d];
    const float* wr = w + d * Kn;
#pragma unroll
    for (int kk = 0; kk < Kn; kk++) {
        int ll = l + kk - 3;
        if (ll >= 0 && ll < Ln)
            acc = fmaf(x[((size_t)(b*Ln + ll))*Dn + d], wr[kk], acc);
    }
    float r = fmaxf(acc, 0.f);
    __nv_bfloat16 h = __float2bfloat16_rn(r);
    hi[idx] = h;
    lo[idx] = __float2bfloat16_rn(r - __bfloat162float(h));
}

__global__ void split_w(const float* __restrict__ w,
                        __nv_bfloat16* __restrict__ hi, __nv_bfloat16* __restrict__ lo)
{
    int idx = blockIdx.x * blockDim.x + threadIdx.x;
    float a = w[idx];
    __nv_bfloat16 h = __float2bfloat16_rn(a);
    hi[idx] = h;
    lo[idx] = __float2bfloat16_rn(a - __bfloat162float(h));
}

__global__ void repack_split(const float* __restrict__ wq, const float* __restrict__ wk,
                             const float* __restrict__ wv,
                             __nv_bfloat16* __restrict__ qh, __nv_bfloat16* __restrict__ ql,
                             __nv_bfloat16* __restrict__ kh, __nv_bfloat16* __restrict__ kl,
                             __nv_bfloat16* __restrict__ vh, __nv_bfloat16* __restrict__ vl)
{
    int idx = blockIdx.x * blockDim.x + threadIdx.x;
    int n = idx >> 9, d = idx & 511;
    int src = (n >> 6) * (Dn * DHn) + d * DHn + (n & 63);
    float a;
    __nv_bfloat16 h;
    a = wq[src]; h = __float2bfloat16_rn(a); qh[idx] = h; ql[idx] = __float2bfloat16_rn(a - __bfloat162float(h));
    a = wk[src]; h = __float2bfloat16_rn(a); kh[idx] = h; kl[idx] = __float2bfloat16_rn(a - __bfloat162float(h));
    a = wv[src]; h = __float2bfloat16_rn(a); vh[idx] = h; vl[idx] = __float2bfloat16_rn(a - __bfloat162float(h));
}

// ======================= mma.sync GEMM (3-term bf16) =======================
template<bool RELU, bool ADDLN, bool SPLIT, bool WRITEC>
__global__ __launch_bounds__(256, 2) void gemm_mma(
    const __nv_bfloat16* __restrict__ Ahi, const __nv_bfloat16* __restrict__ Alo,
    const __nv_bfloat16* __restrict__ Whi, const __nv_bfloat16* __restrict__ Wlo,
    const float* __restrict__ bias, float* __restrict__ C,
    const float* __restrict__ res, const float* __restrict__ lng,
    const float* __restrict__ lnb,
    __nv_bfloat16* __restrict__ Chi, __nv_bfloat16* __restrict__ Clo)
{
    extern __shared__ __align__(16) char dsm[];
    const uint32_t sb = smem_u32(dsm);
    const int tid = threadIdx.x;
    const int wid = tid >> 5, lane = tid & 31;
    const int warpRow = wid >> 2, warpCol = wid & 3;
    const int bx = blockIdx.x, by = blockIdx.y;

    const __nv_bfloat16* srcs[4] = {Ahi, Alo, Whi, Wlo};
    const int rowb[2] = { by*128, bx*128 };

    auto PREF = [&](int kt){
        uint32_t bufb = sb + (uint32_t)(kt & 1) * BUFB;
#pragma unroll
        for (int t = 0; t < 4; t++){
            const __nv_bfloat16* src = srcs[t] + (size_t)rowb[t >> 1]*Dn + kt*BK;
            uint32_t tb = bufb + (uint32_t)t*TB;
#pragma unroll
            for (int i = 0; i < 2; i++){
                int id  = tid + i*256;
                int row = id >> 2, c = id & 3;
                cpasync16(tb + (uint32_t)(row*(PITCH*2) + c*16),
                          src + (size_t)row*Dn + c*8);
            }
        }
        CP_COMMIT();
    };

    float acc[4][4][4];
#pragma unroll
    for (int i = 0; i < 4; i++)
#pragma unroll
        for (int j = 0; j < 4; j++)
#pragma unroll
            for (int q = 0; q < 4; q++) acc[i][j][q] = 0.f;

    const uint32_t aRow = (uint32_t)(warpRow*64 + (lane & 15));
    const uint32_t aColB = (uint32_t)(((lane >> 4) << 4));
    const uint32_t bRow = (uint32_t)(warpCol*32 + (lane & 7) + ((lane >> 4) << 3));
    const uint32_t bColB = (uint32_t)((((lane >> 3) & 1) << 4));

    PREF(0);
#pragma unroll 1
    for (int kt = 0; kt < Dn/BK; kt++){
        if (kt + 1 < Dn/BK) { PREF(kt + 1); CP_WAIT(1); }
        else                { CP_WAIT(0); }
        __syncthreads();

        uint32_t bufb = sb + (uint32_t)(kt & 1) * BUFB;
        uint32_t tAhi = bufb, tAlo = bufb + TB, tWhi = bufb + 2*TB, tWlo = bufb + 3*TB;
#pragma unroll
        for (int term = 0; term < 3; term++){
            uint32_t aB = (term == 1) ? tAlo : tAhi;
            uint32_t wB = (term == 2) ? tWlo : tWhi;
#pragma unroll
            for (int kk = 0; kk < 2; kk++){
                uint32_t a[4][4], b[2][4];
#pragma unroll
                for (int mi = 0; mi < 4; mi++)
                    ldsm4(a[mi], aB + (aRow + mi*16)*(PITCH*2) + aColB + kk*32);
#pragma unroll
                for (int nt = 0; nt < 2; nt++)
                    ldsm4(b[nt], wB + (bRow + nt*16)*(PITCH*2) + bColB + kk*32);
#pragma unroll
                for (int mi = 0; mi < 4; mi++)
#pragma unroll
                    for (int nj = 0; nj < 4; nj++)
                        mma16816(acc[mi][nj], a[mi], &b[nj >> 1][(nj & 1) << 1]);
            }
        }
        __syncthreads();
    }

    float muv = 0.f, rsv = 0.f;
    if (ADDLN) { int bb = (by*128) >> 9; muv = g_mu[bb]; rsv = g_rstd[bb]; }
    const int r0base = by*128 + warpRow*64;
    const int c0base = bx*128 + warpCol*32;
#pragma unroll
    for (int mi = 0; mi < 4; mi++){
#pragma unroll
        for (int rp = 0; rp < 2; rp++){
            int grow = r0base + mi*16 + (lane >> 2) + rp*8;
            int lrow = grow & (Ln - 1);
#pragma unroll
            for (int nj = 0; nj < 4; nj++){
                int col = c0base + nj*8 + (lane & 3)*2;
                float vx = acc[mi][nj][rp*2 + 0];
                float vy = acc[mi][nj][rp*2 + 1];
                float2 bs = *(const float2*)(bias + col);
                vx += bs.x; vy += bs.y;
                if (RELU) { vx = fmaxf(vx, 0.f); vy = fmaxf(vy, 0.f); }
                if (ADDLN) {
                    float2 rr = *(const float2*)(res + (size_t)grow*Dn + col);
                    float2 gg = *(const float2*)(lng + (size_t)lrow*Dn + col);
                    float2 bb = *(const float2*)(lnb + (size_t)lrow*Dn + col);
                    vx += (rr.x - muv)*rsv*gg.x + bb.x;
                    vy += (rr.y - muv)*rsv*gg.y + bb.y;
                }
                if (WRITEC) {
                    float2 o; o.x = vx; o.y = vy;
                    *(float2*)(C + (size_t)grow*Dn + col) = o;
                }
                if (SPLIT) {
                    size_t off = (size_t)grow*Dn + col;
                    uint32_t hi, lo;
                    packpair(vx, vy, hi, lo);
                    *(uint32_t*)(Chi + off) = hi;
                    *(uint32_t*)(Clo + off) = lo;
                }
            }
        }
    }
}

// ======================= fused flash attention (bf16 HMMA, 3-term) =======================
// grid (Ln/128, Bn*Hn), 256 threads. Warp w owns rows [w*16, w*16+16) of the Q tile.
__global__ __launch_bounds__(256, 1) void attn_fused(
    const __nv_bfloat16* __restrict__ qh, const __nv_bfloat16* __restrict__ ql,
    const __nv_bfloat16* __restrict__ kh, const __nv_bfloat16* __restrict__ kl,
    const __nv_bfloat16* __restrict__ vh, const __nv_bfloat16* __restrict__ vl,
    const float* __restrict__ mask,
    __nv_bfloat16* __restrict__ Ohi, __nv_bfloat16* __restrict__ Olo)
{
    extern __shared__ __align__(16) char dsm[];
    const uint32_t sb = smem_u32(dsm);
    const int tid = threadIdx.x, wid = tid >> 5, lane = tid & 31;
    const int bh = blockIdx.y, b = bh >> 3, h = bh & 7;
    const int i0 = blockIdx.x * 128;
    const size_t qoff = ((size_t)(b*Ln + i0))*Dn + h*DHn;
    const size_t koff = ((size_t)(b*Ln))*Dn + h*DHn;

    const uint32_t smQh = sb, smQl = sb + QT;
    const uint32_t smKV0 = sb + 2*QT;
    const uint32_t smMaskOff = 2*QT + 2*KVB;

    auto LOADC = [&](int c){
        uint32_t base = smKV0 + (uint32_t)(c & 1)*KVB;
        size_t g0 = koff + (size_t)(c*128)*Dn;
#pragma unroll
        for (int i = 0; i < 4; i++){
            int id = tid + i*256; int row = id >> 3, seg = id & 7;
            size_t go = g0 + (size_t)row*Dn + seg*8;
            uint32_t so = (uint32_t)(row*AP + seg*16);
            cpasync16(base + so,        kh + go);
            cpasync16(base + QT + so,   kl + go);
            cpasync16(base + 2*QT + so, vh + go);
            cpasync16(base + 3*QT + so, vl + go);
        }
        if (tid < 32)
            cpasync16(sb + smMaskOff + (uint32_t)(c & 1)*512 + tid*16,
                      mask + b*Ln + c*128 + tid*4);
        CP_COMMIT();
    };

    // issue Q + chunk0 (group 0), chunk1 (group 1)
#pragma unroll
    for (int i = 0; i < 4; i++){
        int id = tid + i*256; int row = id >> 3, seg = id & 7;
        size_t go = qoff + (size_t)row*Dn + seg*8;
        uint32_t so = (uint32_t)(row*AP + seg*16);
        cpasync16(smQh + so, qh + go);
        cpasync16(smQl + so, ql + go);
    }
    LOADC(0);
    LOADC(1);

    const int g = lane >> 2, t4 = lane & 3;
    float mi0 = mask[b*Ln + i0 + wid*16 + g];
    float mi1 = mask[b*Ln + i0 + wid*16 + g + 8];

    float m0 = -3.0e38f, m1 = -3.0e38f, l0 = 0.f, l1 = 0.f;
    float o[8][4];
#pragma unroll
    for (int i = 0; i < 8; i++)
#pragma unroll
        for (int j = 0; j < 4; j++) o[i][j] = 0.f;

    const uint32_t aQoff = (uint32_t)((wid*16 + (lane & 15))*AP + ((lane >> 4) << 4));
    const uint32_t bKoff = (uint32_t)(((lane & 7) + ((lane >> 4) << 3))*AP + (((lane >> 3) & 1) << 4));
    const uint32_t vOff  = (uint32_t)((lane & 15)*AP + ((lane >> 4) << 4));

#pragma unroll 1
    for (int c = 0; c < 4; c++){
        if (c < 3) { CP_WAIT(1); } else { CP_WAIT(0); }
        __syncthreads();
        const uint32_t kb = smKV0 + (uint32_t)(c & 1)*KVB;
        const float* mjp = (const float*)(dsm + smMaskOff + (c & 1)*512);

        // ---- S = Q K^T (3-term) ----
        float s[16][4];
#pragma unroll
        for (int nj = 0; nj < 16; nj++)
#pragma unroll
            for (int q = 0; q < 4; q++) s[nj][q] = 0.f;
#pragma unroll
        for (int ss = 0; ss < 4; ss++){
            uint32_t ah[4], al[4];
            ldsm4(ah, smQh + aQoff + ss*32);
            ldsm4(al, smQl + aQoff + ss*32);
#pragma unroll
            for (int njp = 0; njp < 8; njp++){
                uint32_t bhh[4], bll[4];
                uint32_t ra = kb + (uint32_t)(njp*16)*AP + bKoff + ss*32;
                ldsm4(bhh, ra);
                ldsm4(bll, ra + QT);
                mma16816(s[2*njp],   ah, &bhh[0]);
                mma16816(s[2*njp],   al, &bhh[0]);
                mma16816(s[2*njp],   ah, &bll[0]);
                mma16816(s[2*njp+1], ah, &bhh[2]);
                mma16816(s[2*njp+1], al, &bhh[2]);
                mma16816(s[2*njp+1], ah, &bll[2]);
            }
        }

        // ---- scale + mask + row max ----
        float rm0 = -3.0e38f, rm1 = -3.0e38f;
#pragma unroll
        for (int nj = 0; nj < 16; nj++){
            int colb = nj*8 + t4*2;
            float mj0 = mjp[colb], mj1 = mjp[colb+1];
            float mm;
            mm = mi0*mj0; s[nj][0] = s[nj][0]*0.125f*mm + NEGV*(1.f - mm);
            mm = mi0*mj1; s[nj][1] = s[nj][1]*0.125f*mm + NEGV*(1.f - mm);
            mm = mi1*mj0; s[nj][2] = s[nj][2]*0.125f*mm + NEGV*(1.f - mm);
            mm = mi1*mj1; s[nj][3] = s[nj][3]*0.125f*mm + NEGV*(1.f - mm);
            rm0 = fmaxf(rm0, fmaxf(s[nj][0], s[nj][1]));
            rm1 = fmaxf(rm1, fmaxf(s[nj][2], s[nj][3]));
        }
        rm0 = fmaxf(rm0, __shfl_xor_sync(0xffffffffu, rm0, 1));
        rm0 = fmaxf(rm0, __shfl_xor_sync(0xffffffffu, rm0, 2));
        rm1 = fmaxf(rm1, __shfl_xor_sync(0xffffffffu, rm1, 1));
        rm1 = fmaxf(rm1, __shfl_xor_sync(0xffffffffu, rm1, 2));
        float nm0 = fmaxf(m0, rm0), nm1 = fmaxf(m1, rm1);
        float al0 = __expf(m0 - nm0), al1 = __expf(m1 - nm1);
        m0 = nm0; m1 = nm1;
#pragma unroll
        for (int nd = 0; nd < 8; nd++){
            o[nd][0] *= al0; o[nd][1] *= al0;
            o[nd][2] *= al1; o[nd][3] *= al1;
        }

        // ---- P = exp(S - m), O += P V (3-term) ----
        float sum0 = 0.f, sum1 = 0.f;
#pragma unroll
        for (int ss = 0; ss < 8; ss++){
            float p00 = __expf(s[2*ss][0]   - nm0), p01 = __expf(s[2*ss][1]   - nm0);
            float p02 = __expf(s[2*ss][2]   - nm1), p03 = __expf(s[2*ss][3]   - nm1);
            float p10 = __expf(s[2*ss+1][0] - nm0), p11 = __expf(s[2*ss+1][1] - nm0);
            float p12 = __expf(s[2*ss+1][2] - nm1), p13 = __expf(s[2*ss+1][3] - nm1);
            sum0 += p00 + p01 + p10 + p11;
            sum1 += p02 + p03 + p12 + p13;
            uint32_t pah[4], pal[4];
            packpair(p00, p01, pah[0], pal[0]);
            packpair(p02, p03, pah[1], pal[1]);
            packpair(p10, p11, pah[2], pal[2]);
            packpair(p12, p13, pah[3], pal[3]);
#pragma unroll
            for (int ndp = 0; ndp < 4; ndp++){
                uint32_t vhh[4], vll[4];
                uint32_t va = kb + 2*QT + (uint32_t)(ss*16)*AP + vOff + ndp*32;
                ldsm4t(vhh, va);
                ldsm4t(vll, va + QT);
                mma16816(o[2*ndp],   pah, &vhh[0]);
                mma16816(o[2*ndp],   pal, &vhh[0]);
                mma16816(o[2*ndp],   pah, &vll[0]);
                mma16816(o[2*ndp+1], pah, &vhh[2]);
                mma16816(o[2*ndp+1], pal, &vhh[2]);
                mma16816(o[2*ndp+1], pah, &vll[2]);
            }
        }
        sum0 += __shfl_xor_sync(0xffffffffu, sum0, 1);
        sum0 += __shfl_xor_sync(0xffffffffu, sum0, 2);
        sum1 += __shfl_xor_sync(0xffffffffu, sum1, 1);
        sum1 += __shfl_xor_sync(0xffffffffu, sum1, 2);
        l0 = l0*al0 + sum0;
        l1 = l1*al1 + sum1;

        if (c < 2){ __syncthreads(); LOADC(c + 2); }
    }

    // ---- epilogue: O/l -> bf16 pair ----
    float inv0 = 1.f / l0, inv1 = 1.f / l1;
    int r0 = i0 + wid*16 + g, r1 = r0 + 8;
    size_t ob = ((size_t)(b*Ln))*Dn + h*DHn;
#pragma unroll
    for (int nd = 0; nd < 8; nd++){
        int col = nd*8 + t4*2;
        uint32_t hi0, lo0, hi1, lo1;
        packpair(o[nd][0]*inv0, o[nd][1]*inv0, hi0, lo0);
        packpair(o[nd][2]*inv1, o[nd][3]*inv1, hi1, lo1);
        *(uint32_t*)(Ohi + ob + (size_t)r0*Dn + col) = hi0;
        *(uint32_t*)(Olo + ob + (size_t)r0*Dn + col) = lo0;
        *(uint32_t*)(Ohi + ob + (size_t)r1*Dn + col) = hi1;
        *(uint32_t*)(Olo + ob + (size_t)r1*Dn + col) = lo1;
    }
}

// ======================= host orchestration =======================
extern "C" void kernel_launch(void* const* d_in, const int* in_sizes, int n_in,
                              void* d_out, int out_size)
{
    (void)in_sizes; (void)n_in; (void)out_size;
    const float* x     = (const float*)d_in[0];
    const float* mask  = (const float*)d_in[1];
    const float* pe    = (const float*)d_in[2];
    const float* dw_w  = (const float*)d_in[3];
    const float* dw_b  = (const float*)d_in[4];
    const float* pw_w  = (const float*)d_in[5];
    const float* pw_b  = (const float*)d_in[6];
    const float* wq    = (const float*)d_in[7];
    const float* bq    = (const float*)d_in[8];
    const float* wk    = (const float*)d_in[9];
    const float* bk    = (const float*)d_in[10];
    const float* wv    = (const float*)d_in[11];
    const float* bv    = (const float*)d_in[12];
    const float* fc_w  = (const float*)d_in[13];
    const float* fc_b  = (const float*)d_in[14];
    const float* out_w = (const float*)d_in[15];
    const float* out_b = (const float*)d_in[16];
    const float* lnc_g = (const float*)d_in[17];
    const float* lnc_b = (const float*)d_in[18];
    const float* lna_g = (const float*)d_in[19];
    const float* lna_b = (const float*)d_in[20];
    const float* lno_g = (const float*)d_in[21];
    const float* lno_b = (const float*)d_in[22];
    float* out = (float*)d_out;

    float *x1, *x2;
    __nv_bfloat16 *pt, *px, *qkv, *ws;
    cudaGetSymbolAddress((void**)&x1,  g_x1);
    cudaGetSymbolAddress((void**)&x2,  g_x2);
    cudaGetSymbolAddress((void**)&pt,  g_pt);
    cudaGetSymbolAddress((void**)&px,  g_px);
    cudaGetSymbolAddress((void**)&qkv, g_qkv);
    cudaGetSymbolAddress((void**)&ws,  g_wspl);

    __nv_bfloat16* pt_hi = pt;
    __nv_bfloat16* pt_lo = pt + (size_t)Mn*Dn;
    __nv_bfloat16* px_hi = px;
    __nv_bfloat16* px_lo = px + (size_t)Mn*Dn;
    auto QKV = [&](int i){ return qkv + (size_t)i * Mn * Dn; };
    auto W = [&](int i, int hl){ return ws + ((size_t)i*2 + hl) * Dn * Dn; };

    cudaFuncSetAttribute(gemm_mma<true,false,false,true>,  cudaFuncAttributeMaxDynamicSharedMemorySize, SMEM_SZ);
    cudaFuncSetAttribute(gemm_mma<true,true,false,true>,   cudaFuncAttributeMaxDynamicSharedMemorySize, SMEM_SZ);
    cudaFuncSetAttribute(gemm_mma<true,true,true,true>,    cudaFuncAttributeMaxDynamicSharedMemorySize, SMEM_SZ);
    cudaFuncSetAttribute(gemm_mma<false,false,true,false>, cudaFuncAttributeMaxDynamicSharedMemorySize, SMEM_SZ);
    cudaFuncSetAttribute(gemm_mma<false,true,true,true>,   cudaFuncAttributeMaxDynamicSharedMemorySize, SMEM_SZ);
    cudaFuncSetAttribute(gemm_mma<false,true,false,true>,  cudaFuncAttributeMaxDynamicSharedMemorySize, SMEM_SZ);
    cudaFuncSetAttribute(attn_fused, cudaFuncAttributeMaxDynamicSharedMemorySize, SMEM_ATT);

    const int NE = Mn * Dn;
    dim3 gemmGrid(Dn/128, Mn/128);
    const int WG = (Dn*Dn)/256;

    // weight splits
    split_w<<<WG, 256>>>(pw_w + 0*Dn*Dn, W(0,0), W(0,1));
    split_w<<<WG, 256>>>(pw_w + 1*Dn*Dn, W(1,0), W(1,1));
    split_w<<<WG, 256>>>(pw_w + 2*Dn*Dn, W(2,0), W(2,1));
    repack_split<<<WG, 256>>>(wq, wk, wv, W(3,0), W(3,1), W(4,0), W(4,1), W(5,0), W(5,1));
    split_w<<<WG, 256>>>(fc_w,  W(6,0), W(6,1));
    split_w<<<WG, 256>>>(out_w, W(7,0), W(7,1));

    // x = x + pe
    add_pe_k<<<NE/256, 256>>>(x, pe, x1);

    // conv layer 0
    dwconv_relu<<<NE/256, 256>>>(x1, dw_w + 0*Dn*Kn, dw_b + 0*Dn, pt_hi, pt_lo);
    gemm_mma<true,false,false,true><<<gemmGrid, 256, SMEM_SZ>>>(
        pt_hi, pt_lo, W(0,0), W(0,1), pw_b + 0*Dn, x2,
        nullptr, nullptr, nullptr, nullptr, nullptr);
    // conv layer 1: + LN(x2; lnc0)
    ln_stats<<<Bn, 1024>>>(x2);
    dwconv_relu<<<NE/256, 256>>>(x2, dw_w + 1*Dn*Kn, dw_b + 1*Dn, pt_hi, pt_lo);
    gemm_mma<true,true,false,true><<<gemmGrid, 256, SMEM_SZ>>>(
        pt_hi, pt_lo, W(1,0), W(1,1), pw_b + 1*Dn, x1,
        x2, lnc_g + 0, lnc_b + 0, nullptr, nullptr);
    // conv layer 2: + LN(x1; lnc1), emit pair for qkv
    ln_stats<<<Bn, 1024>>>(x1);
    dwconv_relu<<<NE/256, 256>>>(x1, dw_w + 2*Dn*Kn, dw_b + 2*Dn, pt_hi, pt_lo);
    gemm_mma<true,true,true,true><<<gemmGrid, 256, SMEM_SZ>>>(
        pt_hi, pt_lo, W(2,0), W(2,1), pw_b + 2*Dn, x2,
        x1, lnc_g + Ln*Dn, lnc_b + Ln*Dn, px_hi, px_lo);

    // qkv projections -> bf16 pairs only
    gemm_mma<false,false,true,false><<<gemmGrid, 256, SMEM_SZ>>>(
        px_hi, px_lo, W(3,0), W(3,1), bq, nullptr, nullptr, nullptr, nullptr, QKV(0), QKV(1));
    gemm_mma<false,false,true,false><<<gemmGrid, 256, SMEM_SZ>>>(
        px_hi, px_lo, W(4,0), W(4,1), bk, nullptr, nullptr, nullptr, nullptr, QKV(2), QKV(3));
    gemm_mma<false,false,true,false><<<gemmGrid, 256, SMEM_SZ>>>(
        px_hi, px_lo, W(5,0), W(5,1), bv, nullptr, nullptr, nullptr, nullptr, QKV(4), QKV(5));

    // fused flash attention -> pt pair
    attn_fused<<<dim3(Ln/128, Bn*Hn), 256, SMEM_ATT>>>(
        QKV(0), QKV(1), QKV(2), QKV(3), QKV(4), QKV(5), mask, pt_hi, pt_lo);

    // fc + LN(x2; lna), emit pair for out gemm
    ln_stats<<<Bn, 1024>>>(x2);
    gemm_mma<false,true,true,true><<<gemmGrid, 256, SMEM_SZ>>>(
        pt_hi, pt_lo, W(6,0), W(6,1), fc_b, x1,
        x2, lna_g, lna_b, px_hi, px_lo);

    // out + LN(x1; lno) -> d_out
    ln_stats<<<Bn, 1024>>>(x1);
    gemm_mma<false,true,false,true><<<gemmGrid, 256, SMEM_SZ>>>(
        px_hi, px_lo, W(7,0), W(7,1), out_b, out,
        x1, lno_g, lno_b, nullptr, nullptr);
}

// round 7
// speedup vs baseline: 2.5090x; 1.2286x over previous
#include <cuda_runtime.h>
#include <cuda_fp16.h>
#include <cstdint>

#define Bn 32
#define Ln 512
#define Dn 512
#define Hn 8
#define DHn 64
#define Kn 7
#define Mn (Bn*Ln)
#define NEGV (-1e30f)

// ---- big-GEMM tiling ----
#define BK 32
#define PITCH 40                    // fp16 elems per smem row (80 B)
#define TB (128*PITCH*2)            // 10240 B per 128x32 tile
#define BUFB (3*TB)                 // Ahi, Alo, Whi
#define SMEM_SZ (2*BUFB)            // 61440 B

// ---- fused attention smem ----
#define AP 144                      // pitch bytes for 64-col fp16 tiles
#define QT (128*AP)                 // 18432 B
#define KVB (2*QT)                  // Khi + Vhi per chunk
#define SMEM_ATT (2*QT + 2*KVB + 1024)   // 111616 B

// ======================= PTX helpers =======================
__device__ __forceinline__ uint32_t smem_u32(const void* p){
    uint32_t a;
    asm("{ .reg .u64 t; cvta.to.shared.u64 t, %1; cvt.u32.u64 %0, t; }" : "=r"(a) : "l"(p));
    return a;
}
__device__ __forceinline__ void cpasync16(uint32_t dst, const void* src){
    asm volatile("cp.async.cg.shared.global [%0], [%1], 16;" :: "r"(dst), "l"(src) : "memory");
}
#define CP_COMMIT() asm volatile("cp.async.commit_group;" ::: "memory")
#define CP_WAIT(N)  asm volatile("cp.async.wait_group %0;" :: "n"(N) : "memory")
__device__ __forceinline__ void ldsm4(uint32_t* r, uint32_t addr){
    asm volatile("ldmatrix.sync.aligned.m8n8.x4.shared.b16 {%0,%1,%2,%3}, [%4];"
        : "=r"(r[0]), "=r"(r[1]), "=r"(r[2]), "=r"(r[3]) : "r"(addr));
}
__device__ __forceinline__ void ldsm4t(uint32_t* r, uint32_t addr){
    asm volatile("ldmatrix.sync.aligned.m8n8.x4.trans.shared.b16 {%0,%1,%2,%3}, [%4];"
        : "=r"(r[0]), "=r"(r[1]), "=r"(r[2]), "=r"(r[3]) : "r"(addr));
}
__device__ __forceinline__ void mma16816(float* d, const uint32_t* a, const uint32_t* b){
    asm volatile("mma.sync.aligned.m16n8k16.row.col.f32.f16.f16.f32 "
        "{%0,%1,%2,%3}, {%4,%5,%6,%7}, {%8,%9}, {%0,%1,%2,%3};"
        : "+f"(d[0]), "+f"(d[1]), "+f"(d[2]), "+f"(d[3])
        : "r"(a[0]), "r"(a[1]), "r"(a[2]), "r"(a[3]), "r"(b[0]), "r"(b[1]));
}
__device__ __forceinline__ void packpair(float x, float y, uint32_t& hi, uint32_t& lo){
    __half hx = __float2half_rn(x), hy = __float2half_rn(y);
    __half2 h; h.x = hx; h.y = hy;
    __half2 l;
    l.x = __float2half_rn(x - __half2float(hx));
    l.y = __float2half_rn(y - __half2float(hy));
    hi = *(uint32_t*)&h; lo = *(uint32_t*)&l;
}
__device__ __forceinline__ uint32_t packhi(float x, float y){
    __half2 h; h.x = __float2half_rn(x); h.y = __float2half_rn(y);
    return *(uint32_t*)&h;
}

// ======================= scratch =======================
__device__ float g_x1[Mn*Dn];
__device__ float g_x2[Mn*Dn];
__device__ float g_mu[Bn];
__device__ float g_rstd[Bn];
__device__ float2 g_part[Bn*8];
__device__ __half g_pt[2][Mn*Dn];      // activation pair T (hi, lo)
__device__ __half g_px[2][Mn*Dn];      // activation pair X (hi, lo)
__device__ __half g_qkv[4][Mn*Dn];     // qhi, qlo, khi, vhi
__device__ __half g_w[8][Dn*Dn];       // weights hi only (B operand)

// ======================= small kernels =======================
// two-stage LayerNorm([L,D]) stats
__global__ void ln_part(const float* __restrict__ x)
{
    int blk = blockIdx.x, b = blk >> 3, seg = blk & 7;
    const float4* p = (const float4*)(x + (size_t)b*Ln*Dn) + seg*(Ln*Dn/32);
    float s = 0.f, s2 = 0.f;
    for (int i = threadIdx.x; i < Ln*Dn/32; i += 256){
        float4 v = p[i];
        s  += v.x + v.y + v.z + v.w;
        s2 += v.x*v.x + v.y*v.y + v.z*v.z + v.w*v.w;
    }
#pragma unroll
    for (int o = 16; o > 0; o >>= 1){
        s  += __shfl_xor_sync(0xffffffffu, s,  o);
        s2 += __shfl_xor_sync(0xffffffffu, s2, o);
    }
    __shared__ float sh[8], sh2[8];
    int w = threadIdx.x >> 5, lane = threadIdx.x & 31;
    if (lane == 0){ sh[w] = s; sh2[w] = s2; }
    __syncthreads();
    if (threadIdx.x == 0){
        float ts = 0.f, ts2 = 0.f;
#pragma unroll
        for (int i = 0; i < 8; i++){ ts += sh[i]; ts2 += sh2[i]; }
        g_part[blk] = make_float2(ts, ts2);
    }
}
__global__ void ln_fin()
{
    int b = threadIdx.x;
    if (b < Bn){
        float s = 0.f, s2 = 0.f;
#pragma unroll
        for (int i = 0; i < 8; i++){ float2 p = g_part[b*8 + i]; s += p.x; s2 += p.y; }
        float inv = 1.f / (float)(Ln*Dn);
        float m = s * inv;
        float var = s2 * inv - m*m;
        g_mu[b] = m;
        g_rstd[b] = rsqrtf(var + 1e-5f);
    }
}

// depthwise conv (+ optional PE) + relu, float4, emits fp16 hi/lo pair
template<bool PE>
__global__ void dwconv_relu(const float* __restrict__ x, const float* __restrict__ pe,
                            const float* __restrict__ w, const float* __restrict__ bias,
                            __half* __restrict__ hi, __half* __restrict__ lo)
{
    int idx4 = blockIdx.x * blockDim.x + threadIdx.x;    // over Mn*Dn/4
    int d = (idx4 & (Dn/4 - 1)) << 2;
    int l = (idx4 >> 7) & (Ln - 1);
    int b = idx4 >> 16;
    float4 acc = *(const float4*)(bias + d);
    const float* wr = w + d * Kn;
#pragma unroll
    for (int kk = 0; kk < Kn; kk++){
        int ll = l + kk - 3;
        if (ll >= 0 && ll < Ln){
            float4 xv = *(const float4*)(x + ((size_t)(b*Ln + ll))*Dn + d);
            if (PE){
                float4 pv = *(const float4*)(pe + (size_t)ll*Dn + d);
                xv.x += pv.x; xv.y += pv.y; xv.z += pv.z; xv.w += pv.w;
            }
            acc.x = fmaf(xv.x, wr[0*Kn + kk], acc.x);
            acc.y = fmaf(xv.y, wr[1*Kn + kk], acc.y);
            acc.z = fmaf(xv.z, wr[2*Kn + kk], acc.z);
            acc.w = fmaf(xv.w, wr[3*Kn + kk], acc.w);
        }
    }
    acc.x = fmaxf(acc.x, 0.f); acc.y = fmaxf(acc.y, 0.f);
    acc.z = fmaxf(acc.z, 0.f); acc.w = fmaxf(acc.w, 0.f);
    size_t o = (size_t)idx4 * 4;
    uint32_t h0, l0, h1, l1;
    packpair(acc.x, acc.y, h0, l0);
    packpair(acc.z, acc.w, h1, l1);
    *(uint32_t*)(hi + o)     = h0;
    *(uint32_t*)(hi + o + 2) = h1;
    *(uint32_t*)(lo + o)     = l0;
    *(uint32_t*)(lo + o + 2) = l1;
}

// weight -> fp16 hi only (B operand never needs lo)
__global__ void split_w(const float* __restrict__ w, __half* __restrict__ hi)
{
    int idx = blockIdx.x * blockDim.x + threadIdx.x;
    hi[idx] = __float2half_rn(w[idx]);
}

// repack qkv weights [H,D,DH] -> W'[n,d], hi only
__global__ void repack_split(const float* __restrict__ wq, const float* __restrict__ wk,
                             const float* __restrict__ wv,
                             __half* __restrict__ qh, __half* __restrict__ kh,
                             __half* __restrict__ vh)
{
    int idx = blockIdx.x * blockDim.x + threadIdx.x;
    int n = idx >> 9, d = idx & 511;
    int src = (n >> 6) * (Dn * DHn) + d * DHn + (n & 63);
    qh[idx] = __float2half_rn(wq[src]);
    kh[idx] = __float2half_rn(wk[src]);
    vh[idx] = __float2half_rn(wv[src]);
}

// ======================= mma.sync GEMM (fp16 2-term) =======================
// C = A*W^T: A corrected (hi+lo), W hi only.  SPL: 0 none, 1 hi, 2 hi+lo.
template<bool RELU, bool ADDLN, int SPL, bool WRITEC>
__global__ __launch_bounds__(256, 2) void gemm_mma(
    const __half* __restrict__ Ahi, const __half* __restrict__ Alo,
    const __half* __restrict__ Whi,
    const float* __restrict__ bias, float* __restrict__ C,
    const float* __restrict__ res, const float* __restrict__ lng,
    const float* __restrict__ lnb,
    __half* __restrict__ Chi, __half* __restrict__ Clo)
{
    extern __shared__ __align__(16) char dsm[];
    const uint32_t sb = smem_u32(dsm);
    const int tid = threadIdx.x;
    const int wid = tid >> 5, lane = tid & 31;
    const int warpRow = wid >> 2, warpCol = wid & 3;
    const int bx = blockIdx.x, by = blockIdx.y;

    const __half* srcs[3] = {Ahi, Alo, Whi};
    const int rowb[3] = { by*128, by*128, bx*128 };

    auto PREF = [&](int kt){
        uint32_t bufb = sb + (uint32_t)(kt & 1) * BUFB;
#pragma unroll
        for (int t = 0; t < 3; t++){
            const __half* src = srcs[t] + (size_t)rowb[t]*Dn + kt*BK;
            uint32_t tb = bufb + (uint32_t)t*TB;
#pragma unroll
            for (int i = 0; i < 2; i++){
                int id  = tid + i*256;
                int row = id >> 2, c = id & 3;
                cpasync16(tb + (uint32_t)(row*(PITCH*2) + c*16),
                          src + (size_t)row*Dn + c*8);
            }
        }
        CP_COMMIT();
    };

    float acc[4][4][4];
#pragma unroll
    for (int i = 0; i < 4; i++)
#pragma unroll
        for (int j = 0; j < 4; j++)
#pragma unroll
            for (int q = 0; q < 4; q++) acc[i][j][q] = 0.f;

    const uint32_t aRow = (uint32_t)(warpRow*64 + (lane & 15));
    const uint32_t aColB = (uint32_t)(((lane >> 4) << 4));
    const uint32_t bRow = (uint32_t)(warpCol*32 + (lane & 7) + ((lane >> 4) << 3));
    const uint32_t bColB = (uint32_t)((((lane >> 3) & 1) << 4));

    PREF(0);
#pragma unroll 1
    for (int kt = 0; kt < Dn/BK; kt++){
        if (kt + 1 < Dn/BK) { PREF(kt + 1); CP_WAIT(1); }
        else                { CP_WAIT(0); }
        __syncthreads();

        uint32_t bufb = sb + (uint32_t)(kt & 1) * BUFB;
        uint32_t tAhi = bufb, tAlo = bufb + TB, tWhi = bufb + 2*TB;
#pragma unroll
        for (int kk = 0; kk < 2; kk++){
            uint32_t ah[4][4], al[4][4], bh[2][4];
#pragma unroll
            for (int mi = 0; mi < 4; mi++){
                ldsm4(ah[mi], tAhi + (aRow + mi*16)*(PITCH*2) + aColB + kk*32);
                ldsm4(al[mi], tAlo + (aRow + mi*16)*(PITCH*2) + aColB + kk*32);
            }
#pragma unroll
            for (int nt = 0; nt < 2; nt++)
                ldsm4(bh[nt], tWhi + (bRow + nt*16)*(PITCH*2) + bColB + kk*32);
#pragma unroll
            for (int mi = 0; mi < 4; mi++)
#pragma unroll
                for (int nj = 0; nj < 4; nj++){
                    mma16816(acc[mi][nj], ah[mi], &bh[nj >> 1][(nj & 1) << 1]);
                    mma16816(acc[mi][nj], al[mi], &bh[nj >> 1][(nj & 1) << 1]);
                }
        }
        __syncthreads();
    }

    float muv = 0.f, rsv = 0.f;
    if (ADDLN) { int bb = (by*128) >> 9; muv = g_mu[bb]; rsv = g_rstd[bb]; }
    const int r0base = by*128 + warpRow*64;
    const int c0base = bx*128 + warpCol*32;
#pragma unroll
    for (int mi = 0; mi < 4; mi++){
#pragma unroll
        for (int rp = 0; rp < 2; rp++){
            int grow = r0base + mi*16 + (lane >> 2) + rp*8;
            int lrow = grow & (Ln - 1);
#pragma unroll
            for (int nj = 0; nj < 4; nj++){
                int col = c0base + nj*8 + (lane & 3)*2;
                float vx = acc[mi][nj][rp*2 + 0];
                float vy = acc[mi][nj][rp*2 + 1];
                float2 bs = *(const float2*)(bias + col);
                vx += bs.x; vy += bs.y;
                if (RELU) { vx = fmaxf(vx, 0.f); vy = fmaxf(vy, 0.f); }
                if (ADDLN) {
                    float2 rr = *(const float2*)(res + (size_t)grow*Dn + col);
                    float2 gg = *(const float2*)(lng + (size_t)lrow*Dn + col);
                    float2 bb = *(const float2*)(lnb + (size_t)lrow*Dn + col);
                    vx += (rr.x - muv)*rsv*gg.x + bb.x;
                    vy += (rr.y - muv)*rsv*gg.y + bb.y;
                }
                if (WRITEC) {
                    float2 o; o.x = vx; o.y = vy;
                    *(float2*)(C + (size_t)grow*Dn + col) = o;
                }
                if (SPL == 1) {
                    *(uint32_t*)(Chi + (size_t)grow*Dn + col) = packhi(vx, vy);
                } else if (SPL == 2) {
                    size_t off = (size_t)grow*Dn + col;
                    uint32_t hi, lo;
                    packpair(vx, vy, hi, lo);
                    *(uint32_t*)(Chi + off) = hi;
                    *(uint32_t*)(Clo + off) = lo;
                }
            }
        }
    }
}

// ======================= fused flash attention (fp16 2-term) =======================
__global__ __launch_bounds__(256, 1) void attn_fused(
    const __half* __restrict__ qh, const __half* __restrict__ ql,
    const __half* __restrict__ kh, const __half* __restrict__ vh,
    const float* __restrict__ mask,
    __half* __restrict__ Ohi, __half* __restrict__ Olo)
{
    extern __shared__ __align__(16) char dsm[];
    const uint32_t sb = smem_u32(dsm);
    const int tid = threadIdx.x, wid = tid >> 5, lane = tid & 31;
    const int bh = blockIdx.y, b = bh >> 3, h = bh & 7;
    const int i0 = blockIdx.x * 128;
    const size_t qoff = ((size_t)(b*Ln + i0))*Dn + h*DHn;
    const size_t koff = ((size_t)(b*Ln))*Dn + h*DHn;

    const uint32_t smQh = sb, smQl = sb + QT;
    const uint32_t smKV0 = sb + 2*QT;
    const uint32_t smMaskOff = 2*QT + 2*KVB;

    auto LOADC = [&](int c){
        uint32_t base = smKV0 + (uint32_t)(c & 1)*KVB;
        size_t g0 = koff + (size_t)(c*128)*Dn;
#pragma unroll
        for (int i = 0; i < 4; i++){
            int id = tid + i*256; int row = id >> 3, seg = id & 7;
            size_t go = g0 + (size_t)row*Dn + seg*8;
            uint32_t so = (uint32_t)(row*AP + seg*16);
            cpasync16(base + so,      kh + go);
            cpasync16(base + QT + so, vh + go);
        }
        if (tid < 32)
            cpasync16(sb + smMaskOff + (uint32_t)(c & 1)*512 + tid*16,
                      mask + b*Ln + c*128 + tid*4);
        CP_COMMIT();
    };

#pragma unroll
    for (int i = 0; i < 4; i++){
        int id = tid + i*256; int row = id >> 3, seg = id & 7;
        size_t go = qoff + (size_t)row*Dn + seg*8;
        uint32_t so = (uint32_t)(row*AP + seg*16);
        cpasync16(smQh + so, qh + go);
        cpasync16(smQl + so, ql + go);
    }
    LOADC(0);
    LOADC(1);

    const int g = lane >> 2, t4 = lane & 3;
    float mi0 = mask[b*Ln + i0 + wid*16 + g];
    float mi1 = mask[b*Ln + i0 + wid*16 + g + 8];

    float m0 = -3.0e38f, m1 = -3.0e38f, l0 = 0.f, l1 = 0.f;
    float o[8][4];
#pragma unroll
    for (int i = 0; i < 8; i++)
#pragma unroll
        for (int j = 0; j < 4; j++) o[i][j] = 0.f;

    const uint32_t aQoff = (uint32_t)((wid*16 + (lane & 15))*AP + ((lane >> 4) << 4));
    const uint32_t bKoff = (uint32_t)(((lane & 7) + ((lane >> 4) << 3))*AP + (((lane >> 3) & 1) << 4));
    const uint32_t vOff  = (uint32_t)((lane & 15)*AP + ((lane >> 4) << 4));

#pragma unroll 1
    for (int c = 0; c < 4; c++){
        if (c < 3) { CP_WAIT(1); } else { CP_WAIT(0); }
        __syncthreads();
        const uint32_t kb = smKV0 + (uint32_t)(c & 1)*KVB;
        const float* mjp = (const float*)(dsm + smMaskOff + (c & 1)*512);

        // ---- S = Q K^T (Q corrected, K hi) ----
        float s[16][4];
#pragma unroll
        for (int nj = 0; nj < 16; nj++)
#pragma unroll
            for (int q = 0; q < 4; q++) s[nj][q] = 0.f;
#pragma unroll
        for (int ss = 0; ss < 4; ss++){
            uint32_t ah[4], al[4];
            ldsm4(ah, smQh + aQoff + ss*32);
            ldsm4(al, smQl + aQoff + ss*32);
#pragma unroll
            for (int njp = 0; njp < 8; njp++){
                uint32_t bhh[4];
                ldsm4(bhh, kb + (uint32_t)(njp*16)*AP + bKoff + ss*32);
                mma16816(s[2*njp],   ah, &bhh[0]);
                mma16816(s[2*njp],   al, &bhh[0]);
                mma16816(s[2*njp+1], ah, &bhh[2]);
                mma16816(s[2*njp+1], al, &bhh[2]);
            }
        }

        // ---- scale + mask + row max ----
        float rm0 = -3.0e38f, rm1 = -3.0e38f;
#pragma unroll
        for (int nj = 0; nj < 16; nj++){
            int colb = nj*8 + t4*2;
            float mj0 = mjp[colb], mj1 = mjp[colb+1];
            float mm;
            mm = mi0*mj0; s[nj][0] = s[nj][0]*0.125f*mm + NEGV*(1.f - mm);
            mm = mi0*mj1; s[nj][1] = s[nj][1]*0.125f*mm + NEGV*(1.f - mm);
            mm = mi1*mj0; s[nj][2] = s[nj][2]*0.125f*mm + NEGV*(1.f - mm);
            mm = mi1*mj1; s[nj][3] = s[nj][3]*0.125f*mm + NEGV*(1.f - mm);
            rm0 = fmaxf(rm0, fmaxf(s[nj][0], s[nj][1]));
            rm1 = fmaxf(rm1, fmaxf(s[nj][2], s[nj][3]));
        }
        rm0 = fmaxf(rm0, __shfl_xor_sync(0xffffffffu, rm0, 1));
        rm0 = fmaxf(rm0, __shfl_xor_sync(0xffffffffu, rm0, 2));
        rm1 = fmaxf(rm1, __shfl_xor_sync(0xffffffffu, rm1, 1));
        rm1 = fmaxf(rm1, __shfl_xor_sync(0xffffffffu, rm1, 2));
        float nm0 = fmaxf(m0, rm0), nm1 = fmaxf(m1, rm1);
        float al0 = __expf(m0 - nm0), al1 = __expf(m1 - nm1);
        m0 = nm0; m1 = nm1;
#pragma unroll
        for (int nd = 0; nd < 8; nd++){
            o[nd][0] *= al0; o[nd][1] *= al0;
            o[nd][2] *= al1; o[nd][3] *= al1;
        }

        // ---- P = exp(S-m) (corrected), O += P V (V hi) ----
        float sum0 = 0.f, sum1 = 0.f;
#pragma unroll
        for (int ss = 0; ss < 8; ss++){
            float p00 = __expf(s[2*ss][0]   - nm0), p01 = __expf(s[2*ss][1]   - nm0);
            float p02 = __expf(s[2*ss][2]   - nm1), p03 = __expf(s[2*ss][3]   - nm1);
            float p10 = __expf(s[2*ss+1][0] - nm0), p11 = __expf(s[2*ss+1][1] - nm0);
            float p12 = __expf(s[2*ss+1][2] - nm1), p13 = __expf(s[2*ss+1][3] - nm1);
            sum0 += p00 + p01 + p10 + p11;
            sum1 += p02 + p03 + p12 + p13;
            uint32_t pah[4], pal[4];
            packpair(p00, p01, pah[0], pal[0]);
            packpair(p02, p03, pah[1], pal[1]);
            packpair(p10, p11, pah[2], pal[2]);
            packpair(p12, p13, pah[3], pal[3]);
#pragma unroll
            for (int ndp = 0; ndp < 4; ndp++){
                uint32_t vhh[4];
                ldsm4t(vhh, kb + QT + (uint32_t)(ss*16)*AP + vOff + ndp*32);
                mma16816(o[2*ndp],   pah, &vhh[0]);
                mma16816(o[2*ndp],   pal, &vhh[0]);
                mma16816(o[2*ndp+1], pah, &vhh[2]);
                mma16816(o[2*ndp+1], pal, &vhh[2]);
            }
        }
        sum0 += __shfl_xor_sync(0xffffffffu, sum0, 1);
        sum0 += __shfl_xor_sync(0xffffffffu, sum0, 2);
        sum1 += __shfl_xor_sync(0xffffffffu, sum1, 1);
        sum1 += __shfl_xor_sync(0xffffffffu, sum1, 2);
        l0 = l0*al0 + sum0;
        l1 = l1*al1 + sum1;

        if (c < 2){ __syncthreads(); LOADC(c + 2); }
    }

    float inv0 = 1.f / l0, inv1 = 1.f / l1;
    int r0 = i0 + wid*16 + g, r1 = r0 + 8;
    size_t ob = ((size_t)(b*Ln))*Dn + h*DHn;
#pragma unroll
    for (int nd = 0; nd < 8; nd++){
        int col = nd*8 + t4*2;
        uint32_t hi0, lo0, hi1, lo1;
        packpair(o[nd][0]*inv0, o[nd][1]*inv0, hi0, lo0);
        packpair(o[nd][2]*inv1, o[nd][3]*inv1, hi1, lo1);
        *(uint32_t*)(Ohi + ob + (size_t)r0*Dn + col) = hi0;
        *(uint32_t*)(Olo + ob + (size_t)r0*Dn + col) = lo0;
        *(uint32_t*)(Ohi + ob + (size_t)r1*Dn + col) = hi1;
        *(uint32_t*)(Olo + ob + (size_t)r1*Dn + col) = lo1;
    }
}

// ======================= host orchestration =======================
extern "C" void kernel_launch(void* const* d_in, const int* in_sizes, int n_in,
                              void* d_out, int out_size)
{
    (void)in_sizes; (void)n_in; (void)out_size;
    const float* x     = (const float*)d_in[0];
    const float* mask  = (const float*)d_in[1];
    const float* pe    = (const float*)d_in[2];
    const float* dw_w  = (const float*)d_in[3];
    const float* dw_b  = (const float*)d_in[4];
    const float* pw_w  = (const float*)d_in[5];
    const float* pw_b  = (const float*)d_in[6];
    const float* wq    = (const float*)d_in[7];
    const float* bq    = (const float*)d_in[8];
    const float* wk    = (const float*)d_in[9];
    const float* bk    = (const float*)d_in[10];
    const float* wv    = (const float*)d_in[11];
    const float* bv    = (const float*)d_in[12];
    const float* fc_w  = (const float*)d_in[13];
    const float* fc_b  = (const float*)d_in[14];
    const float* out_w = (const float*)d_in[15];
    const float* out_b = (const float*)d_in[16];
    const float* lnc_g = (const float*)d_in[17];
    const float* lnc_b = (const float*)d_in[18];
    const float* lna_g = (const float*)d_in[19];
    const float* lna_b = (const float*)d_in[20];
    const float* lno_g = (const float*)d_in[21];
    const float* lno_b = (const float*)d_in[22];
    float* out = (float*)d_out;

    float *x1, *x2;
    __half *pt, *px, *qkv, *ws;
    cudaGetSymbolAddress((void**)&x1,  g_x1);
    cudaGetSymbolAddress((void**)&x2,  g_x2);
    cudaGetSymbolAddress((void**)&pt,  g_pt);
    cudaGetSymbolAddress((void**)&px,  g_px);
    cudaGetSymbolAddress((void**)&qkv, g_qkv);
    cudaGetSymbolAddress((void**)&ws,  g_w);

    __half* pt_hi = pt;
    __half* pt_lo = pt + (size_t)Mn*Dn;
    __half* px_hi = px;
    __half* px_lo = px + (size_t)Mn*Dn;
    __half* q_hi = qkv;
    __half* q_lo = qkv + (size_t)Mn*Dn;
    __half* k_hi = qkv + 2*(size_t)Mn*Dn;
    __half* v_hi = qkv + 3*(size_t)Mn*Dn;
    auto W = [&](int i){ return ws + (size_t)i * Dn * Dn; };

    cudaFuncSetAttribute(gemm_mma<true,false,0,true>,  cudaFuncAttributeMaxDynamicSharedMemorySize, SMEM_SZ);
    cudaFuncSetAttribute(gemm_mma<true,true,0,true>,   cudaFuncAttributeMaxDynamicSharedMemorySize, SMEM_SZ);
    cudaFuncSetAttribute(gemm_mma<true,true,2,true>,   cudaFuncAttributeMaxDynamicSharedMemorySize, SMEM_SZ);
    cudaFuncSetAttribute(gemm_mma<false,false,2,false>,cudaFuncAttributeMaxDynamicSharedMemorySize, SMEM_SZ);
    cudaFuncSetAttribute(gemm_mma<false,false,1,false>,cudaFuncAttributeMaxDynamicSharedMemorySize, SMEM_SZ);
    cudaFuncSetAttribute(gemm_mma<false,true,2,true>,  cudaFuncAttributeMaxDynamicSharedMemorySize, SMEM_SZ);
    cudaFuncSetAttribute(gemm_mma<false,true,0,true>,  cudaFuncAttributeMaxDynamicSharedMemorySize, SMEM_SZ);
    cudaFuncSetAttribute(attn_fused, cudaFuncAttributeMaxDynamicSharedMemorySize, SMEM_ATT);

    const int NE4 = Mn * Dn / 4;
    dim3 gemmGrid(Dn/128, Mn/128);
    const int WG = (Dn*Dn)/256;

    // weight conversions (hi only)
    split_w<<<WG, 256>>>(pw_w + 0*Dn*Dn, W(0));
    split_w<<<WG, 256>>>(pw_w + 1*Dn*Dn, W(1));
    split_w<<<WG, 256>>>(pw_w + 2*Dn*Dn, W(2));
    repack_split<<<WG, 256>>>(wq, wk, wv, W(3), W(4), W(5));
    split_w<<<WG, 256>>>(fc_w,  W(6));
    split_w<<<WG, 256>>>(out_w, W(7));

    // conv layer 0 (PE fused into dwconv)
    dwconv_relu<true><<<NE4/256, 256>>>(x, pe, dw_w + 0*Dn*Kn, dw_b + 0*Dn, pt_hi, pt_lo);
    gemm_mma<true,false,0,true><<<gemmGrid, 256, SMEM_SZ>>>(
        pt_hi, pt_lo, W(0), pw_b + 0*Dn, x2,
        nullptr, nullptr, nullptr, nullptr, nullptr);
    // conv layer 1: + LN(x2; lnc0)
    ln_part<<<Bn*8, 256>>>(x2);  ln_fin<<<1, 32>>>();
    dwconv_relu<false><<<NE4/256, 256>>>(x2, nullptr, dw_w + 1*Dn*Kn, dw_b + 1*Dn, pt_hi, pt_lo);
    gemm_mma<true,true,0,true><<<gemmGrid, 256, SMEM_SZ>>>(
        pt_hi, pt_lo, W(1), pw_b + 1*Dn, x1,
        x2, lnc_g + 0, lnc_b + 0, nullptr, nullptr);
    // conv layer 2: + LN(x1; lnc1), emit px pair for qkv
    ln_part<<<Bn*8, 256>>>(x1);  ln_fin<<<1, 32>>>();
    dwconv_relu<false><<<NE4/256, 256>>>(x1, nullptr, dw_w + 2*Dn*Kn, dw_b + 2*Dn, pt_hi, pt_lo);
    gemm_mma<true,true,2,true><<<gemmGrid, 256, SMEM_SZ>>>(
        pt_hi, pt_lo, W(2), pw_b + 2*Dn, x2,
        x1, lnc_g + Ln*Dn, lnc_b + Ln*Dn, px_hi, px_lo);

    // qkv projections: q -> hi+lo, k/v -> hi only
    gemm_mma<false,false,2,false><<<gemmGrid, 256, SMEM_SZ>>>(
        px_hi, px_lo, W(3), bq, nullptr, nullptr, nullptr, nullptr, q_hi, q_lo);
    gemm_mma<false,false,1,false><<<gemmGrid, 256, SMEM_SZ>>>(
        px_hi, px_lo, W(4), bk, nullptr, nullptr, nullptr, nullptr, k_hi, nullptr);
    gemm_mma<false,false,1,false><<<gemmGrid, 256, SMEM_SZ>>>(
        px_hi, px_lo, W(5), bv, nullptr, nullptr, nullptr, nullptr, v_hi, nullptr);

    // fused flash attention -> pt pair
    attn_fused<<<dim3(Ln/128, Bn*Hn), 256, SMEM_ATT>>>(
        q_hi, q_lo, k_hi, v_hi, mask, pt_hi, pt_lo);

    // fc + LN(x2; lna), emit pair for out gemm
    ln_part<<<Bn*8, 256>>>(x2);  ln_fin<<<1, 32>>>();
    gemm_mma<false,true,2,true><<<gemmGrid, 256, SMEM_SZ>>>(
        pt_hi, pt_lo, W(6), fc_b, x1,
        x2, lna_g, lna_b, px_hi, px_lo);

    // out + LN(x1; lno) -> d_out
    ln_part<<<Bn*8, 256>>>(x1);  ln_fin<<<1, 32>>>();
    gemm_mma<false,true,0,true><<<gemmGrid, 256, SMEM_SZ>>>(
        px_hi, px_lo, W(7), out_b, out,
        x1, lno_g, lno_b, nullptr, nullptr);
}

// round 8
// speedup vs baseline: 2.6203x; 1.0444x over previous
#include <cuda_runtime.h>
#include <cuda_fp16.h>
#include <cstdint>

#define Bn 32
#define Ln 512
#define Dn 512
#define Hn 8
#define DHn 64
#define Kn 7
#define Mn (Bn*Ln)
#define NEGV (-1e30f)

// ---- big-GEMM tiling ----
#define BK 32
#define PITCH 40                    // fp16 elems per smem row (80 B)
#define TB (128*PITCH*2)            // 10240 B per 128x32 tile
#define BUFB (3*TB)                 // Ahi, Alo, Whi
#define SMEM_SZ (2*BUFB)            // 61440 B

// ---- fused attention smem ----
#define AP 144
#define QT (128*AP)
#define KVB (2*QT)
#define SMEM_ATT (2*QT + 2*KVB + 1024)

// ======================= PTX helpers =======================
__device__ __forceinline__ uint32_t smem_u32(const void* p){
    uint32_t a;
    asm("{ .reg .u64 t; cvta.to.shared.u64 t, %1; cvt.u32.u64 %0, t; }" : "=r"(a) : "l"(p));
    return a;
}
__device__ __forceinline__ void cpasync16(uint32_t dst, const void* src){
    asm volatile("cp.async.cg.shared.global [%0], [%1], 16;" :: "r"(dst), "l"(src) : "memory");
}
#define CP_COMMIT() asm volatile("cp.async.commit_group;" ::: "memory")
#define CP_WAIT(N)  asm volatile("cp.async.wait_group %0;" :: "n"(N) : "memory")
__device__ __forceinline__ void ldsm4(uint32_t* r, uint32_t addr){
    asm volatile("ldmatrix.sync.aligned.m8n8.x4.shared.b16 {%0,%1,%2,%3}, [%4];"
        : "=r"(r[0]), "=r"(r[1]), "=r"(r[2]), "=r"(r[3]) : "r"(addr));
}
__device__ __forceinline__ void ldsm4t(uint32_t* r, uint32_t addr){
    asm volatile("ldmatrix.sync.aligned.m8n8.x4.trans.shared.b16 {%0,%1,%2,%3}, [%4];"
        : "=r"(r[0]), "=r"(r[1]), "=r"(r[2]), "=r"(r[3]) : "r"(addr));
}
__device__ __forceinline__ void mma16816(float* d, const uint32_t* a, const uint32_t* b){
    asm volatile("mma.sync.aligned.m16n8k16.row.col.f32.f16.f16.f32 "
        "{%0,%1,%2,%3}, {%4,%5,%6,%7}, {%8,%9}, {%0,%1,%2,%3};"
        : "+f"(d[0]), "+f"(d[1]), "+f"(d[2]), "+f"(d[3])
        : "r"(a[0]), "r"(a[1]), "r"(a[2]), "r"(a[3]), "r"(b[0]), "r"(b[1]));
}
__device__ __forceinline__ void packpair(float x, float y, uint32_t& hi, uint32_t& lo){
    __half hx = __float2half_rn(x), hy = __float2half_rn(y);
    __half2 h; h.x = hx; h.y = hy;
    __half2 l;
    l.x = __float2half_rn(x - __half2float(hx));
    l.y = __float2half_rn(y - __half2float(hy));
    hi = *(uint32_t*)&h; lo = *(uint32_t*)&l;
}
__device__ __forceinline__ float2 unpackpair(uint32_t hi, uint32_t lo){
    __half2 h = *(__half2*)&hi, l = *(__half2*)&lo;
    float2 r;
    r.x = __half2float(h.x) + __half2float(l.x);
    r.y = __half2float(h.y) + __half2float(l.y);
    return r;
}

// ======================= scratch =======================
__device__ float g_mu[Bn];
__device__ float g_rstd[Bn];
__device__ float g_pS[Bn];
__device__ float g_pS2[Bn];
__device__ __half g_pA [2][Mn*Dn];     // transient A pair (dwconv out / attn out)
__device__ __half g_pX2[2][Mn*Dn];     // x2 pair
__device__ __half g_pX1[2][Mn*Dn];     // x1 pair
__device__ __half g_qkv[4][Mn*Dn];     // qhi, qlo, khi, vhi
__device__ __half g_w[8][Dn*Dn];       // weights hi (B operand)

// ======================= weight prep (single kernel) =======================
__global__ void prep_weights(const float* __restrict__ pw_w,
                             const float* __restrict__ wq, const float* __restrict__ wk,
                             const float* __restrict__ wv,
                             const float* __restrict__ fc_w, const float* __restrict__ out_w)
{
    int task = blockIdx.x >> 10;
    int idx  = (blockIdx.x & 1023) * 256 + threadIdx.x;   // 0..262143
    if (task < 3) {
        g_w[task][idx] = __float2half_rn(pw_w[(size_t)task*Dn*Dn + idx]);
    } else if (task == 3) {
        int n = idx >> 9, d = idx & 511;
        int src = (n >> 6) * (Dn * DHn) + d * DHn + (n & 63);
        g_w[3][idx] = __float2half_rn(wq[src]);
        g_w[4][idx] = __float2half_rn(wk[src]);
        g_w[5][idx] = __float2half_rn(wv[src]);
    } else if (task == 4) {
        g_w[6][idx] = __float2half_rn(fc_w[idx]);
    } else {
        g_w[7][idx] = __float2half_rn(out_w[idx]);
    }
}

// ======================= LN finalize (and re-zero partials) =======================
__global__ void ln_fin()
{
    int b = threadIdx.x;
    if (b < Bn){
        float s = g_pS[b], s2 = g_pS2[b];
        float inv = 1.f / (float)(Ln*Dn);
        float m = s * inv;
        float var = s2 * inv - m*m;
        g_mu[b]   = m;
        g_rstd[b] = rsqrtf(var + 1e-5f);
        g_pS[b] = 0.f; g_pS2[b] = 0.f;
    }
}

// ======================= depthwise conv + relu -> pair =======================
// layer 0: fp32 input + PE.  layers 1/2: pair input.
__global__ void dwconv_pe(const float* __restrict__ x, const float* __restrict__ pe,
                          const float* __restrict__ w, const float* __restrict__ bias,
                          __half* __restrict__ hi, __half* __restrict__ lo)
{
    int idx4 = blockIdx.x * blockDim.x + threadIdx.x;
    int d = (idx4 & (Dn/4 - 1)) << 2;
    int l = (idx4 >> 7) & (Ln - 1);
    int b = idx4 >> 16;
    float4 acc = *(const float4*)(bias + d);
    const float* wr = w + d * Kn;
#pragma unroll
    for (int kk = 0; kk < Kn; kk++){
        int ll = l + kk - 3;
        if (ll >= 0 && ll < Ln){
            float4 xv = *(const float4*)(x + ((size_t)(b*Ln + ll))*Dn + d);
            float4 pv = *(const float4*)(pe + (size_t)ll*Dn + d);
            xv.x += pv.x; xv.y += pv.y; xv.z += pv.z; xv.w += pv.w;
            acc.x = fmaf(xv.x, wr[0*Kn + kk], acc.x);
            acc.y = fmaf(xv.y, wr[1*Kn + kk], acc.y);
            acc.z = fmaf(xv.z, wr[2*Kn + kk], acc.z);
            acc.w = fmaf(xv.w, wr[3*Kn + kk], acc.w);
        }
    }
    acc.x = fmaxf(acc.x, 0.f); acc.y = fmaxf(acc.y, 0.f);
    acc.z = fmaxf(acc.z, 0.f); acc.w = fmaxf(acc.w, 0.f);
    size_t o = (size_t)idx4 * 4;
    uint32_t h0, l0, h1, l1;
    packpair(acc.x, acc.y, h0, l0);
    packpair(acc.z, acc.w, h1, l1);
    *(uint32_t*)(hi + o)     = h0;
    *(uint32_t*)(hi + o + 2) = h1;
    *(uint32_t*)(lo + o)     = l0;
    *(uint32_t*)(lo + o + 2) = l1;
}

__global__ void dwconv_pair(const __half* __restrict__ xh, const __half* __restrict__ xl,
                            const float* __restrict__ w, const float* __restrict__ bias,
                            __half* __restrict__ hi, __half* __restrict__ lo)
{
    int idx4 = blockIdx.x * blockDim.x + threadIdx.x;
    int d = (idx4 & (Dn/4 - 1)) << 2;
    int l = (idx4 >> 7) & (Ln - 1);
    int b = idx4 >> 16;
    float4 acc = *(const float4*)(bias + d);
    const float* wr = w + d * Kn;
#pragma unroll
    for (int kk = 0; kk < Kn; kk++){
        int ll = l + kk - 3;
        if (ll >= 0 && ll < Ln){
            size_t base = ((size_t)(b*Ln + ll))*Dn + d;
            uint32_t h0 = *(const uint32_t*)(xh + base);
            uint32_t h1 = *(const uint32_t*)(xh + base + 2);
            uint32_t l0 = *(const uint32_t*)(xl + base);
            uint32_t l1 = *(const uint32_t*)(xl + base + 2);
            float2 a0 = unpackpair(h0, l0);
            float2 a1 = unpackpair(h1, l1);
            acc.x = fmaf(a0.x, wr[0*Kn + kk], acc.x);
            acc.y = fmaf(a0.y, wr[1*Kn + kk], acc.y);
            acc.z = fmaf(a1.x, wr[2*Kn + kk], acc.z);
            acc.w = fmaf(a1.y, wr[3*Kn + kk], acc.w);
        }
    }
    acc.x = fmaxf(acc.x, 0.f); acc.y = fmaxf(acc.y, 0.f);
    acc.z = fmaxf(acc.z, 0.f); acc.w = fmaxf(acc.w, 0.f);
    size_t o = (size_t)idx4 * 4;
    uint32_t h0, l0, h1, l1;
    packpair(acc.x, acc.y, h0, l0);
    packpair(acc.z, acc.w, h1, l1);
    *(uint32_t*)(hi + o)     = h0;
    *(uint32_t*)(hi + o + 2) = h1;
    *(uint32_t*)(lo + o)     = l0;
    *(uint32_t*)(lo + o + 2) = l1;
}

// ======================= mma.sync GEMM (fp16 2-term) =======================
// C = A*W^T. A pair, W hi. Residual given as pair. Optional fused LN-stats accumulation.
template<bool RELU, bool ADDLN, bool SPL, bool WRITEC, bool STATS>
__global__ __launch_bounds__(256, 2) void gemm_mma(
    const __half* __restrict__ Ahi, const __half* __restrict__ Alo,
    const __half* __restrict__ Whi,
    const float* __restrict__ bias, float* __restrict__ C,
    const __half* __restrict__ Rhi, const __half* __restrict__ Rlo,
    const float* __restrict__ lng, const float* __restrict__ lnb,
    __half* __restrict__ Chi, __half* __restrict__ Clo)
{
    extern __shared__ __align__(16) char dsm[];
    const uint32_t sb = smem_u32(dsm);
    const int tid = threadIdx.x;
    const int wid = tid >> 5, lane = tid & 31;
    const int warpRow = wid >> 2, warpCol = wid & 3;
    const int bx = blockIdx.x, by = blockIdx.y;

    const __half* srcs[3] = {Ahi, Alo, Whi};
    const int rowb[3] = { by*128, by*128, bx*128 };

    auto PREF = [&](int kt){
        uint32_t bufb = sb + (uint32_t)(kt & 1) * BUFB;
#pragma unroll
        for (int t = 0; t < 3; t++){
            const __half* src = srcs[t] + (size_t)rowb[t]*Dn + kt*BK;
            uint32_t tb = bufb + (uint32_t)t*TB;
#pragma unroll
            for (int i = 0; i < 2; i++){
                int id  = tid + i*256;
                int row = id >> 2, c = id & 3;
                cpasync16(tb + (uint32_t)(row*(PITCH*2) + c*16),
                          src + (size_t)row*Dn + c*8);
            }
        }
        CP_COMMIT();
    };

    float acc[4][4][4];
#pragma unroll
    for (int i = 0; i < 4; i++)
#pragma unroll
        for (int j = 0; j < 4; j++)
#pragma unroll
            for (int q = 0; q < 4; q++) acc[i][j][q] = 0.f;

    const uint32_t aRow = (uint32_t)(warpRow*64 + (lane & 15));
    const uint32_t aColB = (uint32_t)(((lane >> 4) << 4));
    const uint32_t bRow = (uint32_t)(warpCol*32 + (lane & 7) + ((lane >> 4) << 3));
    const uint32_t bColB = (uint32_t)((((lane >> 3) & 1) << 4));

    PREF(0);
#pragma unroll 1
    for (int kt = 0; kt < Dn/BK; kt++){
        if (kt + 1 < Dn/BK) { PREF(kt + 1); CP_WAIT(1); }
        else                { CP_WAIT(0); }
        __syncthreads();

        uint32_t bufb = sb + (uint32_t)(kt & 1) * BUFB;
        uint32_t tAhi = bufb, tAlo = bufb + TB, tWhi = bufb + 2*TB;
#pragma unroll
        for (int kk = 0; kk < 2; kk++){
            uint32_t ah[4][4], al[4][4], bh[2][4];
#pragma unroll
            for (int mi = 0; mi < 4; mi++){
                ldsm4(ah[mi], tAhi + (aRow + mi*16)*(PITCH*2) + aColB + kk*32);
                ldsm4(al[mi], tAlo + (aRow + mi*16)*(PITCH*2) + aColB + kk*32);
            }
#pragma unroll
            for (int nt = 0; nt < 2; nt++)
                ldsm4(bh[nt], tWhi + (bRow + nt*16)*(PITCH*2) + bColB + kk*32);
#pragma unroll
            for (int mi = 0; mi < 4; mi++)
#pragma unroll
                for (int nj = 0; nj < 4; nj++){
                    mma16816(acc[mi][nj], ah[mi], &bh[nj >> 1][(nj & 1) << 1]);
                    mma16816(acc[mi][nj], al[mi], &bh[nj >> 1][(nj & 1) << 1]);
                }
        }
        __syncthreads();
    }

    float muv = 0.f, rsv = 0.f;
    if (ADDLN) { int bb = (by*128) >> 9; muv = g_mu[bb]; rsv = g_rstd[bb]; }
    const int r0base = by*128 + warpRow*64;
    const int c0base = bx*128 + warpCol*32;
    float ts = 0.f, ts2 = 0.f;
#pragma unroll
    for (int mi = 0; mi < 4; mi++){
#pragma unroll
        for (int rp = 0; rp < 2; rp++){
            int grow = r0base + mi*16 + (lane >> 2) + rp*8;
            int lrow = grow & (Ln - 1);
#pragma unroll
            for (int nj = 0; nj < 4; nj++){
                int col = c0base + nj*8 + (lane & 3)*2;
                float vx = acc[mi][nj][rp*2 + 0];
                float vy = acc[mi][nj][rp*2 + 1];
                float2 bs = *(const float2*)(bias + col);
                vx += bs.x; vy += bs.y;
                if (RELU) { vx = fmaxf(vx, 0.f); vy = fmaxf(vy, 0.f); }
                size_t off = (size_t)grow*Dn + col;
                if (ADDLN) {
                    float2 rr = unpackpair(*(const uint32_t*)(Rhi + off),
                                           *(const uint32_t*)(Rlo + off));
                    float2 gg = *(const float2*)(lng + (size_t)lrow*Dn + col);
                    float2 bb = *(const float2*)(lnb + (size_t)lrow*Dn + col);
                    vx += (rr.x - muv)*rsv*gg.x + bb.x;
                    vy += (rr.y - muv)*rsv*gg.y + bb.y;
                }
                if (STATS) { ts += vx + vy; ts2 += vx*vx + vy*vy; }
                if (WRITEC) {
                    float2 o; o.x = vx; o.y = vy;
                    *(float2*)(C + off) = o;
                }
                if (SPL) {
                    uint32_t hi, lo;
                    packpair(vx, vy, hi, lo);
                    *(uint32_t*)(Chi + off) = hi;
                    *(uint32_t*)(Clo + off) = lo;
                }
            }
        }
    }
    if (STATS) {
#pragma unroll
        for (int o = 16; o > 0; o >>= 1){
            ts  += __shfl_xor_sync(0xffffffffu, ts,  o);
            ts2 += __shfl_xor_sync(0xffffffffu, ts2, o);
        }
        __shared__ float sred[2][8];
        if (lane == 0){ sred[0][wid] = ts; sred[1][wid] = ts2; }
        __syncthreads();
        if (tid == 0){
            float a = 0.f, b2 = 0.f;
#pragma unroll
            for (int i = 0; i < 8; i++){ a += sred[0][i]; b2 += sred[1][i]; }
            int batch = by >> 2;
            atomicAdd(&g_pS[batch],  a);
            atomicAdd(&g_pS2[batch], b2);
        }
    }
}

// ======================= merged qkv GEMM (N=1536, segment epilogue) =======================
__global__ __launch_bounds__(256, 2) void gemm_qkv(
    const __half* __restrict__ Ahi, const __half* __restrict__ Alo,
    const float* __restrict__ bq, const float* __restrict__ bk, const float* __restrict__ bv)
{
    extern __shared__ __align__(16) char dsm[];
    const uint32_t sb = smem_u32(dsm);
    const int tid = threadIdx.x;
    const int wid = tid >> 5, lane = tid & 31;
    const int warpRow = wid >> 2, warpCol = wid & 3;
    const int bx = blockIdx.x, by = blockIdx.y;
    const int seg = bx >> 2, bxl = bx & 3;

    const __half* Whi = g_w[3 + seg];
    const float* bias = (seg == 0) ? bq : ((seg == 1) ? bk : bv);
    __half* Ch = (seg == 0) ? g_qkv[0] : ((seg == 1) ? g_qkv[2] : g_qkv[3]);
    __half* Cl = g_qkv[1];                       // only used for seg==0

    const __half* srcs[3] = {Ahi, Alo, Whi};
    const int rowb[3] = { by*128, by*128, bxl*128 };

    auto PREF = [&](int kt){
        uint32_t bufb = sb + (uint32_t)(kt & 1) * BUFB;
#pragma unroll
        for (int t = 0; t < 3; t++){
            const __half* src = srcs[t] + (size_t)rowb[t]*Dn + kt*BK;
            uint32_t tb = bufb + (uint32_t)t*TB;
#pragma unroll
            for (int i = 0; i < 2; i++){
                int id  = tid + i*256;
                int row = id >> 2, c = id & 3;
                cpasync16(tb + (uint32_t)(row*(PITCH*2) + c*16),
                          src + (size_t)row*Dn + c*8);
            }
        }
        CP_COMMIT();
    };

    float acc[4][4][4];
#pragma unroll
    for (int i = 0; i < 4; i++)
#pragma unroll
        for (int j = 0; j < 4; j++)
#pragma unroll
            for (int q = 0; q < 4; q++) acc[i][j][q] = 0.f;

    const uint32_t aRow = (uint32_t)(warpRow*64 + (lane & 15));
    const uint32_t aColB = (uint32_t)(((lane >> 4) << 4));
    const uint32_t bRow = (uint32_t)(warpCol*32 + (lane & 7) + ((lane >> 4) << 3));
    const uint32_t bColB = (uint32_t)((((lane >> 3) & 1) << 4));

    PREF(0);
#pragma unroll 1
    for (int kt = 0; kt < Dn/BK; kt++){
        if (kt + 1 < Dn/BK) { PREF(kt + 1); CP_WAIT(1); }
        else                { CP_WAIT(0); }
        __syncthreads();

        uint32_t bufb = sb + (uint32_t)(kt & 1) * BUFB;
        uint32_t tAhi = bufb, tAlo = bufb + TB, tWhi = bufb + 2*TB;
#pragma unroll
        for (int kk = 0; kk < 2; kk++){
            uint32_t ah[4][4], al[4][4], bh[2][4];
#pragma unroll
            for (int mi = 0; mi < 4; mi++){
                ldsm4(ah[mi], tAhi + (aRow + mi*16)*(PITCH*2) + aColB + kk*32);
                ldsm4(al[mi], tAlo + (aRow + mi*16)*(PITCH*2) + aColB + kk*32);
            }
#pragma unroll
            for (int nt = 0; nt < 2; nt++)
                ldsm4(bh[nt], tWhi + (bRow + nt*16)*(PITCH*2) + bColB + kk*32);
#pragma unroll
            for (int mi = 0; mi < 4; mi++)
#pragma unroll
                for (int nj = 0; nj < 4; nj++){
                    mma16816(acc[mi][nj], ah[mi], &bh[nj >> 1][(nj & 1) << 1]);
                    mma16816(acc[mi][nj], al[mi], &bh[nj >> 1][(nj & 1) << 1]);
                }
        }
        __syncthreads();
    }

    const int r0base = by*128 + warpRow*64;
    const int c0base = bxl*128 + warpCol*32;
    const bool wlo = (seg == 0);
#pragma unroll
    for (int mi = 0; mi < 4; mi++){
#pragma unroll
        for (int rp = 0; rp < 2; rp++){
            int grow = r0base + mi*16 + (lane >> 2) + rp*8;
#pragma unroll
            for (int nj = 0; nj < 4; nj++){
                int col = c0base + nj*8 + (lane & 3)*2;
                float vx = acc[mi][nj][rp*2 + 0];
                float vy = acc[mi][nj][rp*2 + 1];
                float2 bs = *(const float2*)(bias + col);
                vx += bs.x; vy += bs.y;
                size_t off = (size_t)grow*Dn + col;
                uint32_t hi, lo;
                packpair(vx, vy, hi, lo);
                *(uint32_t*)(Ch + off) = hi;
                if (wlo) *(uint32_t*)(Cl + off) = lo;
            }
        }
    }
}

// ======================= fused flash attention (fp16 2-term) =======================
__global__ __launch_bounds__(256, 1) void attn_fused(
    const __half* __restrict__ qh, const __half* __restrict__ ql,
    const __half* __restrict__ kh, const __half* __restrict__ vh,
    const float* __restrict__ mask,
    __half* __restrict__ Ohi, __half* __restrict__ Olo)
{
    extern __shared__ __align__(16) char dsm[];
    const uint32_t sb = smem_u32(dsm);
    const int tid = threadIdx.x, wid = tid >> 5, lane = tid & 31;
    const int bh = blockIdx.y, b = bh >> 3, h = bh & 7;
    const int i0 = blockIdx.x * 128;
    const size_t qoff = ((size_t)(b*Ln + i0))*Dn + h*DHn;
    const size_t koff = ((size_t)(b*Ln))*Dn + h*DHn;

    const uint32_t smQh = sb, smQl = sb + QT;
    const uint32_t smKV0 = sb + 2*QT;
    const uint32_t smMaskOff = 2*QT + 2*KVB;

    auto LOADC = [&](int c){
        uint32_t base = smKV0 + (uint32_t)(c & 1)*KVB;
        size_t g0 = koff + (size_t)(c*128)*Dn;
#pragma unroll
        for (int i = 0; i < 4; i++){
            int id = tid + i*256; int row = id >> 3, seg = id & 7;
            size_t go = g0 + (size_t)row*Dn + seg*8;
            uint32_t so = (uint32_t)(row*AP + seg*16);
            cpasync16(base + so,      kh + go);
            cpasync16(base + QT + so, vh + go);
        }
        if (tid < 32)
            cpasync16(sb + smMaskOff + (uint32_t)(c & 1)*512 + tid*16,
                      mask + b*Ln + c*128 + tid*4);
        CP_COMMIT();
    };

#pragma unroll
    for (int i = 0; i < 4; i++){
        int id = tid + i*256; int row = id >> 3, seg = id & 7;
        size_t go = qoff + (size_t)row*Dn + seg*8;
        uint32_t so = (uint32_t)(row*AP + seg*16);
        cpasync16(smQh + so, qh + go);
        cpasync16(smQl + so, ql + go);
    }
    LOADC(0);
    LOADC(1);

    const int g = lane >> 2, t4 = lane & 3;
    float mi0 = mask[b*Ln + i0 + wid*16 + g];
    float mi1 = mask[b*Ln + i0 + wid*16 + g + 8];

    float m0 = -3.0e38f, m1 = -3.0e38f, l0 = 0.f, l1 = 0.f;
    float o[8][4];
#pragma unroll
    for (int i = 0; i < 8; i++)
#pragma unroll
        for (int j = 0; j < 4; j++) o[i][j] = 0.f;

    const uint32_t aQoff = (uint32_t)((wid*16 + (lane & 15))*AP + ((lane >> 4) << 4));
    const uint32_t bKoff = (uint32_t)(((lane & 7) + ((lane >> 4) << 3))*AP + (((lane >> 3) & 1) << 4));
    const uint32_t vOff  = (uint32_t)((lane & 15)*AP + ((lane >> 4) << 4));

#pragma unroll 1
    for (int c = 0; c < 4; c++){
        if (c < 3) { CP_WAIT(1); } else { CP_WAIT(0); }
        __syncthreads();
        const uint32_t kb = smKV0 + (uint32_t)(c & 1)*KVB;
        const float* mjp = (const float*)(dsm + smMaskOff + (c & 1)*512);

        float s[16][4];
#pragma unroll
        for (int nj = 0; nj < 16; nj++)
#pragma unroll
            for (int q = 0; q < 4; q++) s[nj][q] = 0.f;
#pragma unroll
        for (int ss = 0; ss < 4; ss++){
            uint32_t ah[4], al[4];
            ldsm4(ah, smQh + aQoff + ss*32);
            ldsm4(al, smQl + aQoff + ss*32);
#pragma unroll
            for (int njp = 0; njp < 8; njp++){
                uint32_t bhh[4];
                ldsm4(bhh, kb + (uint32_t)(njp*16)*AP + bKoff + ss*32);
                mma16816(s[2*njp],   ah, &bhh[0]);
                mma16816(s[2*njp],   al, &bhh[0]);
                mma16816(s[2*njp+1], ah, &bhh[2]);
                mma16816(s[2*njp+1], al, &bhh[2]);
            }
        }

        float rm0 = -3.0e38f, rm1 = -3.0e38f;
#pragma unroll
        for (int nj = 0; nj < 16; nj++){
            int colb = nj*8 + t4*2;
            float mj0 = mjp[colb], mj1 = mjp[colb+1];
            float mm;
            mm = mi0*mj0; s[nj][0] = s[nj][0]*0.125f*mm + NEGV*(1.f - mm);
            mm = mi0*mj1; s[nj][1] = s[nj][1]*0.125f*mm + NEGV*(1.f - mm);
            mm = mi1*mj0; s[nj][2] = s[nj][2]*0.125f*mm + NEGV*(1.f - mm);
            mm = mi1*mj1; s[nj][3] = s[nj][3]*0.125f*mm + NEGV*(1.f - mm);
            rm0 = fmaxf(rm0, fmaxf(s[nj][0], s[nj][1]));
            rm1 = fmaxf(rm1, fmaxf(s[nj][2], s[nj][3]));
        }
        rm0 = fmaxf(rm0, __shfl_xor_sync(0xffffffffu, rm0, 1));
        rm0 = fmaxf(rm0, __shfl_xor_sync(0xffffffffu, rm0, 2));
        rm1 = fmaxf(rm1, __shfl_xor_sync(0xffffffffu, rm1, 1));
        rm1 = fmaxf(rm1, __shfl_xor_sync(0xffffffffu, rm1, 2));
        float nm0 = fmaxf(m0, rm0), nm1 = fmaxf(m1, rm1);
        float al0 = __expf(m0 - nm0), al1 = __expf(m1 - nm1);
        m0 = nm0; m1 = nm1;
#pragma unroll
        for (int nd = 0; nd < 8; nd++){
            o[nd][0] *= al0; o[nd][1] *= al0;
            o[nd][2] *= al1; o[nd][3] *= al1;
        }

        float sum0 = 0.f, sum1 = 0.f;
#pragma unroll
        for (int ss = 0; ss < 8; ss++){
            float p00 = __expf(s[2*ss][0]   - nm0), p01 = __expf(s[2*ss][1]   - nm0);
            float p02 = __expf(s[2*ss][2]   - nm1), p03 = __expf(s[2*ss][3]   - nm1);
            float p10 = __expf(s[2*ss+1][0] - nm0), p11 = __expf(s[2*ss+1][1] - nm0);
            float p12 = __expf(s[2*ss+1][2] - nm1), p13 = __expf(s[2*ss+1][3] - nm1);
            sum0 += p00 + p01 + p10 + p11;
            sum1 += p02 + p03 + p12 + p13;
            uint32_t pah[4], pal[4];
            packpair(p00, p01, pah[0], pal[0]);
            packpair(p02, p03, pah[1], pal[1]);
            packpair(p10, p11, pah[2], pal[2]);
            packpair(p12, p13, pah[3], pal[3]);
#pragma unroll
            for (int ndp = 0; ndp < 4; ndp++){
                uint32_t vhh[4];
                ldsm4t(vhh, kb + QT + (uint32_t)(ss*16)*AP + vOff + ndp*32);
                mma16816(o[2*ndp],   pah, &vhh[0]);
                mma16816(o[2*ndp],   pal, &vhh[0]);
                mma16816(o[2*ndp+1], pah, &vhh[2]);
                mma16816(o[2*ndp+1], pal, &vhh[2]);
            }
        }
        sum0 += __shfl_xor_sync(0xffffffffu, sum0, 1);
        sum0 += __shfl_xor_sync(0xffffffffu, sum0, 2);
        sum1 += __shfl_xor_sync(0xffffffffu, sum1, 1);
        sum1 += __shfl_xor_sync(0xffffffffu, sum1, 2);
        l0 = l0*al0 + sum0;
        l1 = l1*al1 + sum1;

        if (c < 2){ __syncthreads(); LOADC(c + 2); }
    }

    float inv0 = 1.f / l0, inv1 = 1.f / l1;
    int r0 = i0 + wid*16 + g, r1 = r0 + 8;
    size_t ob = ((size_t)(b*Ln))*Dn + h*DHn;
#pragma unroll
    for (int nd = 0; nd < 8; nd++){
        int col = nd*8 + t4*2;
        uint32_t hi0, lo0, hi1, lo1;
        packpair(o[nd][0]*inv0, o[nd][1]*inv0, hi0, lo0);
        packpair(o[nd][2]*inv1, o[nd][3]*inv1, hi1, lo1);
        *(uint32_t*)(Ohi + ob + (size_t)r0*Dn + col) = hi0;
        *(uint32_t*)(Olo + ob + (size_t)r0*Dn + col) = lo0;
        *(uint32_t*)(Ohi + ob + (size_t)r1*Dn + col) = hi1;
        *(uint32_t*)(Olo + ob + (size_t)r1*Dn + col) = lo1;
    }
}

// ======================= host orchestration =======================
extern "C" void kernel_launch(void* const* d_in, const int* in_sizes, int n_in,
                              void* d_out, int out_size)
{
    (void)in_sizes; (void)n_in; (void)out_size;
    const float* x     = (const float*)d_in[0];
    const float* mask  = (const float*)d_in[1];
    const float* pe    = (const float*)d_in[2];
    const float* dw_w  = (const float*)d_in[3];
    const float* dw_b  = (const float*)d_in[4];
    const float* pw_w  = (const float*)d_in[5];
    const float* pw_b  = (const float*)d_in[6];
    const float* wq    = (const float*)d_in[7];
    const float* bq    = (const float*)d_in[8];
    const float* wk    = (const float*)d_in[9];
    const float* bk    = (const float*)d_in[10];
    const float* wv    = (const float*)d_in[11];
    const float* bv    = (const float*)d_in[12];
    const float* fc_w  = (const float*)d_in[13];
    const float* fc_b  = (const float*)d_in[14];
    const float* out_w = (const float*)d_in[15];
    const float* out_b = (const float*)d_in[16];
    const float* lnc_g = (const float*)d_in[17];
    const float* lnc_b = (const float*)d_in[18];
    const float* lna_g = (const float*)d_in[19];
    const float* lna_b = (const float*)d_in[20];
    const float* lno_g = (const float*)d_in[21];
    const float* lno_b = (const float*)d_in[22];
    float* out = (float*)d_out;

    __half *pA, *pX2, *pX1, *qkv, *wsym;
    cudaGetSymbolAddress((void**)&pA,  g_pA);
    cudaGetSymbolAddress((void**)&pX2, g_pX2);
    cudaGetSymbolAddress((void**)&pX1, g_pX1);
    cudaGetSymbolAddress((void**)&qkv, g_qkv);
    cudaGetSymbolAddress((void**)&wsym, g_w);

    const size_t NN = (size_t)Mn*Dn;
    __half *pA_h = pA,  *pA_l = pA + NN;
    __half *x2_h = pX2, *x2_l = pX2 + NN;
    __half *x1_h = pX1, *x1_l = pX1 + NN;
    __half *q_h = qkv, *q_l = qkv + NN, *k_h = qkv + 2*NN, *v_h = qkv + 3*NN;
    auto W = [&](int i){ return wsym + (size_t)i * Dn * Dn; };

    cudaFuncSetAttribute(gemm_mma<true,false,true,false,true>, cudaFuncAttributeMaxDynamicSharedMemorySize, SMEM_SZ);
    cudaFuncSetAttribute(gemm_mma<true,true,true,false,true>,  cudaFuncAttributeMaxDynamicSharedMemorySize, SMEM_SZ);
    cudaFuncSetAttribute(gemm_mma<false,true,true,false,true>, cudaFuncAttributeMaxDynamicSharedMemorySize, SMEM_SZ);
    cudaFuncSetAttribute(gemm_mma<false,true,false,true,false>,cudaFuncAttributeMaxDynamicSharedMemorySize, SMEM_SZ);
    cudaFuncSetAttribute(gemm_qkv, cudaFuncAttributeMaxDynamicSharedMemorySize, SMEM_SZ);
    cudaFuncSetAttribute(attn_fused, cudaFuncAttributeMaxDynamicSharedMemorySize, SMEM_ATT);

    const int NE4 = Mn * Dn / 4;
    dim3 gemmGrid(Dn/128, Mn/128);      // (4, 128)
    dim3 qkvGrid(12, Mn/128);           // N = 1536

    // 1. all weight prep in one kernel
    prep_weights<<<6*1024, 256>>>(pw_w, wq, wk, wv, fc_w, out_w);

    // 2-3. conv layer 0 (PE fused); stats for lnc0
    dwconv_pe<<<NE4/256, 256>>>(x, pe, dw_w + 0*Dn*Kn, dw_b + 0*Dn, pA_h, pA_l);
    gemm_mma<true,false,true,false,true><<<gemmGrid, 256, SMEM_SZ>>>(
        pA_h, pA_l, W(0), pw_b + 0*Dn, nullptr,
        nullptr, nullptr, nullptr, nullptr, x2_h, x2_l);
    // 4. finalize lnc0 stats
    ln_fin<<<1, 32>>>();
    // 5-6. conv layer 1: + LN(x2; lnc0); stats for lnc1
    dwconv_pair<<<NE4/256, 256>>>(x2_h, x2_l, dw_w + 1*Dn*Kn, dw_b + 1*Dn, pA_h, pA_l);
    gemm_mma<true,true,true,false,true><<<gemmGrid, 256, SMEM_SZ>>>(
        pA_h, pA_l, W(1), pw_b + 1*Dn, nullptr,
        x2_h, x2_l, lnc_g + 0, lnc_b + 0, x1_h, x1_l);
    // 7. finalize lnc1
    ln_fin<<<1, 32>>>();
    // 8-9. conv layer 2: + LN(x1; lnc1); stats for lna
    dwconv_pair<<<NE4/256, 256>>>(x1_h, x1_l, dw_w + 2*Dn*Kn, dw_b + 2*Dn, pA_h, pA_l);
    gemm_mma<true,true,true,false,true><<<gemmGrid, 256, SMEM_SZ>>>(
        pA_h, pA_l, W(2), pw_b + 2*Dn, nullptr,
        x1_h, x1_l, lnc_g + Ln*Dn, lnc_b + Ln*Dn, x2_h, x2_l);
    // 10. finalize lna
    ln_fin<<<1, 32>>>();

    // 11. merged qkv projection (q pair, k/v hi)
    gemm_qkv<<<qkvGrid, 256, SMEM_SZ>>>(x2_h, x2_l, bq, bk, bv);

    // 12. fused flash attention -> pA pair
    attn_fused<<<dim3(Ln/128, Bn*Hn), 256, SMEM_ATT>>>(
        q_h, q_l, k_h, v_h, mask, pA_h, pA_l);

    // 13. fc + LN(x2; lna) -> x1 pair; stats for lno
    gemm_mma<false,true,true,false,true><<<gemmGrid, 256, SMEM_SZ>>>(
        pA_h, pA_l, W(6), fc_b, nullptr,
        x2_h, x2_l, lna_g, lna_b, x1_h, x1_l);
    // 14. finalize lno
    ln_fin<<<1, 32>>>();

    // 15. out + LN(x1; lno) -> d_out (fp32)
    gemm_mma<false,true,false,true,false><<<gemmGrid, 256, SMEM_SZ>>>(
        x1_h, x1_l, W(7), out_b, out,
        x1_h, x1_l, lno_g, lno_b, nullptr, nullptr);
}

// round 9
// speedup vs baseline: 2.6871x; 1.0255x over previous
#include <cuda_runtime.h>
#include <cuda_fp16.h>
#include <cstdint>

#define Bn 32
#define Ln 512
#define Dn 512
#define Hn 8
#define DHn 64
#define Kn 7
#define Mn (Bn*Ln)
#define NEGV (-1e30f)
#define LDINV (1.0f/(float)(Ln*Dn))

// ---- big-GEMM tiling ----
#define BK 32
#define PITCH 40                    // fp16 elems per smem row (80 B)
#define TB (128*PITCH*2)            // 10240 B per 128x32 tile
#define BUFB (3*TB)                 // Ahi, Alo, Whi
#define SMEM_SZ (3*BUFB)            // 3-stage pipeline = 92160 B

// ---- fused attention smem ----
#define AP 144
#define QT (128*AP)
#define KVB (2*QT)
#define SMEM_ATT (2*QT + 2*KVB + 1024)

// ======================= PTX helpers =======================
__device__ __forceinline__ uint32_t smem_u32(const void* p){
    uint32_t a;
    asm("{ .reg .u64 t; cvta.to.shared.u64 t, %1; cvt.u32.u64 %0, t; }" : "=r"(a) : "l"(p));
    return a;
}
__device__ __forceinline__ void cpasync16(uint32_t dst, const void* src){
    asm volatile("cp.async.cg.shared.global [%0], [%1], 16;" :: "r"(dst), "l"(src) : "memory");
}
#define CP_COMMIT() asm volatile("cp.async.commit_group;" ::: "memory")
#define CP_WAIT(N)  asm volatile("cp.async.wait_group %0;" :: "n"(N) : "memory")
__device__ __forceinline__ void ldsm4(uint32_t* r, uint32_t addr){
    asm volatile("ldmatrix.sync.aligned.m8n8.x4.shared.b16 {%0,%1,%2,%3}, [%4];"
        : "=r"(r[0]), "=r"(r[1]), "=r"(r[2]), "=r"(r[3]) : "r"(addr));
}
__device__ __forceinline__ void ldsm4t(uint32_t* r, uint32_t addr){
    asm volatile("ldmatrix.sync.aligned.m8n8.x4.trans.shared.b16 {%0,%1,%2,%3}, [%4];"
        : "=r"(r[0]), "=r"(r[1]), "=r"(r[2]), "=r"(r[3]) : "r"(addr));
}
__device__ __forceinline__ void mma16816(float* d, const uint32_t* a, const uint32_t* b){
    asm volatile("mma.sync.aligned.m16n8k16.row.col.f32.f16.f16.f32 "
        "{%0,%1,%2,%3}, {%4,%5,%6,%7}, {%8,%9}, {%0,%1,%2,%3};"
        : "+f"(d[0]), "+f"(d[1]), "+f"(d[2]), "+f"(d[3])
        : "r"(a[0]), "r"(a[1]), "r"(a[2]), "r"(a[3]), "r"(b[0]), "r"(b[1]));
}
__device__ __forceinline__ void packpair(float x, float y, uint32_t& hi, uint32_t& lo){
    __half hx = __float2half_rn(x), hy = __float2half_rn(y);
    __half2 h; h.x = hx; h.y = hy;
    __half2 l;
    l.x = __float2half_rn(x - __half2float(hx));
    l.y = __float2half_rn(y - __half2float(hy));
    hi = *(uint32_t*)&h; lo = *(uint32_t*)&l;
}
__device__ __forceinline__ float2 unpackpair(uint32_t hi, uint32_t lo){
    __half2 h = *(__half2*)&hi, l = *(__half2*)&lo;
    float2 r;
    r.x = __half2float(h.x) + __half2float(l.x);
    r.y = __half2float(h.y) + __half2float(l.y);
    return r;
}

// ======================= scratch =======================
__device__ float g_pS [4][Bn];         // LN partial sums, slot-indexed
__device__ float g_pS2[4][Bn];
__device__ __half g_pA [2][Mn*Dn];     // transient A pair
__device__ __half g_pX2[2][Mn*Dn];     // x2 pair
__device__ __half g_pX1[2][Mn*Dn];     // x1 pair
__device__ __half g_qkv[4][Mn*Dn];     // qhi, qlo, khi, vhi
__device__ __half g_w[8][Dn*Dn];       // weights hi (B operand)

// ======================= weight prep + LN-partial zeroing =======================
__global__ void prep_weights(const float* __restrict__ pw_w,
                             const float* __restrict__ wq, const float* __restrict__ wk,
                             const float* __restrict__ wv,
                             const float* __restrict__ fc_w, const float* __restrict__ out_w)
{
    if (blockIdx.x == 0 && threadIdx.x < 4*Bn) {
        (&g_pS[0][0])[threadIdx.x]  = 0.f;
        (&g_pS2[0][0])[threadIdx.x] = 0.f;
    }
    int task = blockIdx.x >> 10;
    int idx  = (blockIdx.x & 1023) * 256 + threadIdx.x;
    if (task < 3) {
        g_w[task][idx] = __float2half_rn(pw_w[(size_t)task*Dn*Dn + idx]);
    } else if (task == 3) {
        int n = idx >> 9, d = idx & 511;
        int src = (n >> 6) * (Dn * DHn) + d * DHn + (n & 63);
        g_w[3][idx] = __float2half_rn(wq[src]);
        g_w[4][idx] = __float2half_rn(wk[src]);
        g_w[5][idx] = __float2half_rn(wv[src]);
    } else if (task == 4) {
        g_w[6][idx] = __float2half_rn(fc_w[idx]);
    } else {
        g_w[7][idx] = __float2half_rn(out_w[idx]);
    }
}

// ======================= depthwise conv + relu -> pair =======================
__global__ void dwconv_pe(const float* __restrict__ x, const float* __restrict__ pe,
                          const float* __restrict__ w, const float* __restrict__ bias,
                          __half* __restrict__ hi, __half* __restrict__ lo)
{
    int idx4 = blockIdx.x * blockDim.x + threadIdx.x;
    int d = (idx4 & (Dn/4 - 1)) << 2;
    int l = (idx4 >> 7) & (Ln - 1);
    int b = idx4 >> 16;
    float4 acc = *(const float4*)(bias + d);
    const float* wr = w + d * Kn;
#pragma unroll
    for (int kk = 0; kk < Kn; kk++){
        int ll = l + kk - 3;
        if (ll >= 0 && ll < Ln){
            float4 xv = *(const float4*)(x + ((size_t)(b*Ln + ll))*Dn + d);
            float4 pv = *(const float4*)(pe + (size_t)ll*Dn + d);
            xv.x += pv.x; xv.y += pv.y; xv.z += pv.z; xv.w += pv.w;
            acc.x = fmaf(xv.x, wr[0*Kn + kk], acc.x);
            acc.y = fmaf(xv.y, wr[1*Kn + kk], acc.y);
            acc.z = fmaf(xv.z, wr[2*Kn + kk], acc.z);
            acc.w = fmaf(xv.w, wr[3*Kn + kk], acc.w);
        }
    }
    acc.x = fmaxf(acc.x, 0.f); acc.y = fmaxf(acc.y, 0.f);
    acc.z = fmaxf(acc.z, 0.f); acc.w = fmaxf(acc.w, 0.f);
    size_t o = (size_t)idx4 * 4;
    uint32_t h0, l0, h1, l1;
    packpair(acc.x, acc.y, h0, l0);
    packpair(acc.z, acc.w, h1, l1);
    *(uint32_t*)(hi + o)     = h0;
    *(uint32_t*)(hi + o + 2) = h1;
    *(uint32_t*)(lo + o)     = l0;
    *(uint32_t*)(lo + o + 2) = l1;
}

__global__ void dwconv_pair(const __half* __restrict__ xh, const __half* __restrict__ xl,
                            const float* __restrict__ w, const float* __restrict__ bias,
                            __half* __restrict__ hi, __half* __restrict__ lo)
{
    int idx4 = blockIdx.x * blockDim.x + threadIdx.x;
    int d = (idx4 & (Dn/4 - 1)) << 2;
    int l = (idx4 >> 7) & (Ln - 1);
    int b = idx4 >> 16;
    float4 acc = *(const float4*)(bias + d);
    const float* wr = w + d * Kn;
#pragma unroll
    for (int kk = 0; kk < Kn; kk++){
        int ll = l + kk - 3;
        if (ll >= 0 && ll < Ln){
            size_t base = ((size_t)(b*Ln + ll))*Dn + d;
            uint32_t h0 = *(const uint32_t*)(xh + base);
            uint32_t h1 = *(const uint32_t*)(xh + base + 2);
            uint32_t l0 = *(const uint32_t*)(xl + base);
            uint32_t l1 = *(const uint32_t*)(xl + base + 2);
            float2 a0 = unpackpair(h0, l0);
            float2 a1 = unpackpair(h1, l1);
            acc.x = fmaf(a0.x, wr[0*Kn + kk], acc.x);
            acc.y = fmaf(a0.y, wr[1*Kn + kk], acc.y);
            acc.z = fmaf(a1.x, wr[2*Kn + kk], acc.z);
            acc.w = fmaf(a1.y, wr[3*Kn + kk], acc.w);
        }
    }
    acc.x = fmaxf(acc.x, 0.f); acc.y = fmaxf(acc.y, 0.f);
    acc.z = fmaxf(acc.z, 0.f); acc.w = fmaxf(acc.w, 0.f);
    size_t o = (size_t)idx4 * 4;
    uint32_t h0, l0, h1, l1;
    packpair(acc.x, acc.y, h0, l0);
    packpair(acc.z, acc.w, h1, l1);
    *(uint32_t*)(hi + o)     = h0;
    *(uint32_t*)(hi + o + 2) = h1;
    *(uint32_t*)(lo + o)     = l0;
    *(uint32_t*)(lo + o + 2) = l1;
}

// ======================= mma.sync GEMM (fp16 2-term, 3-stage pipeline) =======================
// LNIN: slot for residual-LN input stats (-1 = no LN). LNOUT: slot for output stats (-1 none).
template<bool RELU, int LNIN, int LNOUT, bool SPL, bool WRITEC>
__global__ __launch_bounds__(256, 2) void gemm_mma(
    const __half* __restrict__ Ahi, const __half* __restrict__ Alo,
    const __half* __restrict__ Whi,
    const float* __restrict__ bias, float* __restrict__ C,
    const __half* __restrict__ Rhi, const __half* __restrict__ Rlo,
    const float* __restrict__ lng, const float* __restrict__ lnb,
    __half* __restrict__ Chi, __half* __restrict__ Clo)
{
    extern __shared__ __align__(16) char dsm[];
    const uint32_t sb = smem_u32(dsm);
    const int tid = threadIdx.x;
    const int wid = tid >> 5, lane = tid & 31;
    const int warpRow = wid >> 2, warpCol = wid & 3;
    const int bx = blockIdx.x, by = blockIdx.y;

    const __half* srcs[3] = {Ahi, Alo, Whi};
    const int rowb[3] = { by*128, by*128, bx*128 };

    auto PREF = [&](int kt){
        uint32_t bufb = sb + (uint32_t)(kt % 3) * BUFB;
#pragma unroll
        for (int t = 0; t < 3; t++){
            const __half* src = srcs[t] + (size_t)rowb[t]*Dn + kt*BK;
            uint32_t tb = bufb + (uint32_t)t*TB;
#pragma unroll
            for (int i = 0; i < 2; i++){
                int id  = tid + i*256;
                int row = id >> 2, c = id & 3;
                cpasync16(tb + (uint32_t)(row*(PITCH*2) + c*16),
                          src + (size_t)row*Dn + c*8);
            }
        }
        CP_COMMIT();
    };

    float acc[4][4][4];
#pragma unroll
    for (int i = 0; i < 4; i++)
#pragma unroll
        for (int j = 0; j < 4; j++)
#pragma unroll
            for (int q = 0; q < 4; q++) acc[i][j][q] = 0.f;

    const uint32_t aRow = (uint32_t)(warpRow*64 + (lane & 15));
    const uint32_t aColB = (uint32_t)(((lane >> 4) << 4));
    const uint32_t bRow = (uint32_t)(warpCol*32 + (lane & 7) + ((lane >> 4) << 3));
    const uint32_t bColB = (uint32_t)((((lane >> 3) & 1) << 4));

    PREF(0);
    PREF(1);
#pragma unroll 1
    for (int kt = 0; kt < Dn/BK; kt++){
        if (kt + 1 < Dn/BK) { CP_WAIT(1); } else { CP_WAIT(0); }
        __syncthreads();                       // data visible + everyone done reading buf (kt+2)%3
        if (kt + 2 < Dn/BK) PREF(kt + 2);

        uint32_t bufb = sb + (uint32_t)(kt % 3) * BUFB;
        uint32_t tAhi = bufb, tAlo = bufb + TB, tWhi = bufb + 2*TB;
#pragma unroll
        for (int kk = 0; kk < 2; kk++){
            uint32_t ah[4][4], al[4][4], bh[2][4];
#pragma unroll
            for (int mi = 0; mi < 4; mi++){
                ldsm4(ah[mi], tAhi + (aRow + mi*16)*(PITCH*2) + aColB + kk*32);
                ldsm4(al[mi], tAlo + (aRow + mi*16)*(PITCH*2) + aColB + kk*32);
            }
#pragma unroll
            for (int nt = 0; nt < 2; nt++)
                ldsm4(bh[nt], tWhi + (bRow + nt*16)*(PITCH*2) + bColB + kk*32);
#pragma unroll
            for (int mi = 0; mi < 4; mi++)
#pragma unroll
                for (int nj = 0; nj < 4; nj++){
                    mma16816(acc[mi][nj], ah[mi], &bh[nj >> 1][(nj & 1) << 1]);
                    mma16816(acc[mi][nj], al[mi], &bh[nj >> 1][(nj & 1) << 1]);
                }
        }
    }

    float muv = 0.f, rsv = 0.f;
    if (LNIN >= 0) {
        int bb = (by*128) >> 9;
        float s = g_pS[LNIN][bb], s2 = g_pS2[LNIN][bb];
        muv = s * LDINV;
        rsv = rsqrtf(s2 * LDINV - muv*muv + 1e-5f);
    }
    const int r0base = by*128 + warpRow*64;
    const int c0base = bx*128 + warpCol*32;
    float ts = 0.f, ts2 = 0.f;
#pragma unroll
    for (int mi = 0; mi < 4; mi++){
#pragma unroll
        for (int rp = 0; rp < 2; rp++){
            int grow = r0base + mi*16 + (lane >> 2) + rp*8;
            int lrow = grow & (Ln - 1);
#pragma unroll
            for (int nj = 0; nj < 4; nj++){
                int col = c0base + nj*8 + (lane & 3)*2;
                float vx = acc[mi][nj][rp*2 + 0];
                float vy = acc[mi][nj][rp*2 + 1];
                float2 bs = *(const float2*)(bias + col);
                vx += bs.x; vy += bs.y;
                if (RELU) { vx = fmaxf(vx, 0.f); vy = fmaxf(vy, 0.f); }
                size_t off = (size_t)grow*Dn + col;
                if (LNIN >= 0) {
                    float2 rr = unpackpair(*(const uint32_t*)(Rhi + off),
                                           *(const uint32_t*)(Rlo + off));
                    float2 gg = *(const float2*)(lng + (size_t)lrow*Dn + col);
                    float2 bb = *(const float2*)(lnb + (size_t)lrow*Dn + col);
                    vx += (rr.x - muv)*rsv*gg.x + bb.x;
                    vy += (rr.y - muv)*rsv*gg.y + bb.y;
                }
                if (LNOUT >= 0) { ts += vx + vy; ts2 += vx*vx + vy*vy; }
                if (WRITEC) {
                    float2 o; o.x = vx; o.y = vy;
                    *(float2*)(C + off) = o;
                }
                if (SPL) {
                    uint32_t hi, lo;
                    packpair(vx, vy, hi, lo);
                    *(uint32_t*)(Chi + off) = hi;
                    *(uint32_t*)(Clo + off) = lo;
                }
            }
        }
    }
    if (LNOUT >= 0) {
#pragma unroll
        for (int o = 16; o > 0; o >>= 1){
            ts  += __shfl_xor_sync(0xffffffffu, ts,  o);
            ts2 += __shfl_xor_sync(0xffffffffu, ts2, o);
        }
        __shared__ float sred[2][8];
        if (lane == 0){ sred[0][wid] = ts; sred[1][wid] = ts2; }
        __syncthreads();
        if (tid == 0){
            float a = 0.f, b2 = 0.f;
#pragma unroll
            for (int i = 0; i < 8; i++){ a += sred[0][i]; b2 += sred[1][i]; }
            int batch = by >> 2;
            atomicAdd(&g_pS[LNOUT][batch],  a);
            atomicAdd(&g_pS2[LNOUT][batch], b2);
        }
    }
}

// ======================= merged qkv GEMM (N=1536, 3-stage pipeline) =======================
__global__ __launch_bounds__(256, 2) void gemm_qkv(
    const __half* __restrict__ Ahi, const __half* __restrict__ Alo,
    const float* __restrict__ bq, const float* __restrict__ bk, const float* __restrict__ bv)
{
    extern __shared__ __align__(16) char dsm[];
    const uint32_t sb = smem_u32(dsm);
    const int tid = threadIdx.x;
    const int wid = tid >> 5, lane = tid & 31;
    const int warpRow = wid >> 2, warpCol = wid & 3;
    const int bx = blockIdx.x, by = blockIdx.y;
    const int seg = bx >> 2, bxl = bx & 3;

    const __half* Whi = g_w[3 + seg];
    const float* bias = (seg == 0) ? bq : ((seg == 1) ? bk : bv);
    __half* Ch = (seg == 0) ? g_qkv[0] : ((seg == 1) ? g_qkv[2] : g_qkv[3]);
    __half* Cl = g_qkv[1];

    const __half* srcs[3] = {Ahi, Alo, Whi};
    const int rowb[3] = { by*128, by*128, bxl*128 };

    auto PREF = [&](int kt){
        uint32_t bufb = sb + (uint32_t)(kt % 3) * BUFB;
#pragma unroll
        for (int t = 0; t < 3; t++){
            const __half* src = srcs[t] + (size_t)rowb[t]*Dn + kt*BK;
            uint32_t tb = bufb + (uint32_t)t*TB;
#pragma unroll
            for (int i = 0; i < 2; i++){
                int id  = tid + i*256;
                int row = id >> 2, c = id & 3;
                cpasync16(tb + (uint32_t)(row*(PITCH*2) + c*16),
                          src + (size_t)row*Dn + c*8);
            }
        }
        CP_COMMIT();
    };

    float acc[4][4][4];
#pragma unroll
    for (int i = 0; i < 4; i++)
#pragma unroll
        for (int j = 0; j < 4; j++)
#pragma unroll
            for (int q = 0; q < 4; q++) acc[i][j][q] = 0.f;

    const uint32_t aRow = (uint32_t)(warpRow*64 + (lane & 15));
    const uint32_t aColB = (uint32_t)(((lane >> 4) << 4));
    const uint32_t bRow = (uint32_t)(warpCol*32 + (lane & 7) + ((lane >> 4) << 3));
    const uint32_t bColB = (uint32_t)((((lane >> 3) & 1) << 4));

    PREF(0);
    PREF(1);
#pragma unroll 1
    for (int kt = 0; kt < Dn/BK; kt++){
        if (kt + 1 < Dn/BK) { CP_WAIT(1); } else { CP_WAIT(0); }
        __syncthreads();
        if (kt + 2 < Dn/BK) PREF(kt + 2);

        uint32_t bufb = sb + (uint32_t)(kt % 3) * BUFB;
        uint32_t tAhi = bufb, tAlo = bufb + TB, tWhi = bufb + 2*TB;
#pragma unroll
        for (int kk = 0; kk < 2; kk++){
            uint32_t ah[4][4], al[4][4], bh[2][4];
#pragma unroll
            for (int mi = 0; mi < 4; mi++){
                ldsm4(ah[mi], tAhi + (aRow + mi*16)*(PITCH*2) + aColB + kk*32);
                ldsm4(al[mi], tAlo + (aRow + mi*16)*(PITCH*2) + aColB + kk*32);
            }
#pragma unroll
            for (int nt = 0; nt < 2; nt++)
                ldsm4(bh[nt], tWhi + (bRow + nt*16)*(PITCH*2) + bColB + kk*32);
#pragma unroll
            for (int mi = 0; mi < 4; mi++)
#pragma unroll
                for (int nj = 0; nj < 4; nj++){
                    mma16816(acc[mi][nj], ah[mi], &bh[nj >> 1][(nj & 1) << 1]);
                    mma16816(acc[mi][nj], al[mi], &bh[nj >> 1][(nj & 1) << 1]);
                }
        }
    }

    const int r0base = by*128 + warpRow*64;
    const int c0base = bxl*128 + warpCol*32;
    const bool wlo = (seg == 0);
#pragma unroll
    for (int mi = 0; mi < 4; mi++){
#pragma unroll
        for (int rp = 0; rp < 2; rp++){
            int grow = r0base + mi*16 + (lane >> 2) + rp*8;
#pragma unroll
            for (int nj = 0; nj < 4; nj++){
                int col = c0base + nj*8 + (lane & 3)*2;
                float vx = acc[mi][nj][rp*2 + 0];
                float vy = acc[mi][nj][rp*2 + 1];
                float2 bs = *(const float2*)(bias + col);
                vx += bs.x; vy += bs.y;
                size_t off = (size_t)grow*Dn + col;
                uint32_t hi, lo;
                packpair(vx, vy, hi, lo);
                *(uint32_t*)(Ch + off) = hi;
                if (wlo) *(uint32_t*)(Cl + off) = lo;
            }
        }
    }
}

// ======================= fused flash attention (fp16 2-term) =======================
__global__ __launch_bounds__(256, 1) void attn_fused(
    const __half* __restrict__ qh, const __half* __restrict__ ql,
    const __half* __restrict__ kh, const __half* __restrict__ vh,
    const float* __restrict__ mask,
    __half* __restrict__ Ohi, __half* __restrict__ Olo)
{
    extern __shared__ __align__(16) char dsm[];
    const uint32_t sb = smem_u32(dsm);
    const int tid = threadIdx.x, wid = tid >> 5, lane = tid & 31;
    const int bh = blockIdx.y, b = bh >> 3, h = bh & 7;
    const int i0 = blockIdx.x * 128;
    const size_t qoff = ((size_t)(b*Ln + i0))*Dn + h*DHn;
    const size_t koff = ((size_t)(b*Ln))*Dn + h*DHn;

    const uint32_t smQh = sb, smQl = sb + QT;
    const uint32_t smKV0 = sb + 2*QT;
    const uint32_t smMaskOff = 2*QT + 2*KVB;

    auto LOADC = [&](int c){
        uint32_t base = smKV0 + (uint32_t)(c & 1)*KVB;
        size_t g0 = koff + (size_t)(c*128)*Dn;
#pragma unroll
        for (int i = 0; i < 4; i++){
            int id = tid + i*256; int row = id >> 3, seg = id & 7;
            size_t go = g0 + (size_t)row*Dn + seg*8;
            uint32_t so = (uint32_t)(row*AP + seg*16);
            cpasync16(base + so,      kh + go);
            cpasync16(base + QT + so, vh + go);
        }
        if (tid < 32)
            cpasync16(sb + smMaskOff + (uint32_t)(c & 1)*512 + tid*16,
                      mask + b*Ln + c*128 + tid*4);
        CP_COMMIT();
    };

#pragma unroll
    for (int i = 0; i < 4; i++){
        int id = tid + i*256; int row = id >> 3, seg = id & 7;
        size_t go = qoff + (size_t)row*Dn + seg*8;
        uint32_t so = (uint32_t)(row*AP + seg*16);
        cpasync16(smQh + so, qh + go);
        cpasync16(smQl + so, ql + go);
    }
    LOADC(0);
    LOADC(1);

    const int g = lane >> 2, t4 = lane & 3;
    float mi0 = mask[b*Ln + i0 + wid*16 + g];
    float mi1 = mask[b*Ln + i0 + wid*16 + g + 8];

    float m0 = -3.0e38f, m1 = -3.0e38f, l0 = 0.f, l1 = 0.f;
    float o[8][4];
#pragma unroll
    for (int i = 0; i < 8; i++)
#pragma unroll
        for (int j = 0; j < 4; j++) o[i][j] = 0.f;

    const uint32_t aQoff = (uint32_t)((wid*16 + (lane & 15))*AP + ((lane >> 4) << 4));
    const uint32_t bKoff = (uint32_t)(((lane & 7) + ((lane >> 4) << 3))*AP + (((lane >> 3) & 1) << 4));
    const uint32_t vOff  = (uint32_t)((lane & 15)*AP + ((lane >> 4) << 4));

#pragma unroll 1
    for (int c = 0; c < 4; c++){
        if (c < 3) { CP_WAIT(1); } else { CP_WAIT(0); }
        __syncthreads();
        const uint32_t kb = smKV0 + (uint32_t)(c & 1)*KVB;
        const float* mjp = (const float*)(dsm + smMaskOff + (c & 1)*512);

        float s[16][4];
#pragma unroll
        for (int nj = 0; nj < 16; nj++)
#pragma unroll
            for (int q = 0; q < 4; q++) s[nj][q] = 0.f;
#pragma unroll
        for (int ss = 0; ss < 4; ss++){
            uint32_t ah[4], al[4];
            ldsm4(ah, smQh + aQoff + ss*32);
            ldsm4(al, smQl + aQoff + ss*32);
#pragma unroll
            for (int njp = 0; njp < 8; njp++){
                uint32_t bhh[4];
                ldsm4(bhh, kb + (uint32_t)(njp*16)*AP + bKoff + ss*32);
                mma16816(s[2*njp],   ah, &bhh[0]);
                mma16816(s[2*njp],   al, &bhh[0]);
                mma16816(s[2*njp+1], ah, &bhh[2]);
                mma16816(s[2*njp+1], al, &bhh[2]);
            }
        }

        float rm0 = -3.0e38f, rm1 = -3.0e38f;
#pragma unroll
        for (int nj = 0; nj < 16; nj++){
            int colb = nj*8 + t4*2;
            float mj0 = mjp[colb], mj1 = mjp[colb+1];
            float mm;
            mm = mi0*mj0; s[nj][0] = s[nj][0]*0.125f*mm + NEGV*(1.f - mm);
            mm = mi0*mj1; s[nj][1] = s[nj][1]*0.125f*mm + NEGV*(1.f - mm);
            mm = mi1*mj0; s[nj][2] = s[nj][2]*0.125f*mm + NEGV*(1.f - mm);
            mm = mi1*mj1; s[nj][3] = s[nj][3]*0.125f*mm + NEGV*(1.f - mm);
            rm0 = fmaxf(rm0, fmaxf(s[nj][0], s[nj][1]));
            rm1 = fmaxf(rm1, fmaxf(s[nj][2], s[nj][3]));
        }
        rm0 = fmaxf(rm0, __shfl_xor_sync(0xffffffffu, rm0, 1));
        rm0 = fmaxf(rm0, __shfl_xor_sync(0xffffffffu, rm0, 2));
        rm1 = fmaxf(rm1, __shfl_xor_sync(0xffffffffu, rm1, 1));
        rm1 = fmaxf(rm1, __shfl_xor_sync(0xffffffffu, rm1, 2));
        float nm0 = fmaxf(m0, rm0), nm1 = fmaxf(m1, rm1);
        float al0 = __expf(m0 - nm0), al1 = __expf(m1 - nm1);
        m0 = nm0; m1 = nm1;
#pragma unroll
        for (int nd = 0; nd < 8; nd++){
            o[nd][0] *= al0; o[nd][1] *= al0;
            o[nd][2] *= al1; o[nd][3] *= al1;
        }

        float sum0 = 0.f, sum1 = 0.f;
#pragma unroll
        for (int ss = 0; ss < 8; ss++){
            float p00 = __expf(s[2*ss][0]   - nm0), p01 = __expf(s[2*ss][1]   - nm0);
            float p02 = __expf(s[2*ss][2]   - nm1), p03 = __expf(s[2*ss][3]   - nm1);
            float p10 = __expf(s[2*ss+1][0] - nm0), p11 = __expf(s[2*ss+1][1] - nm0);
            float p12 = __expf(s[2*ss+1][2] - nm1), p13 = __expf(s[2*ss+1][3] - nm1);
            sum0 += p00 + p01 + p10 + p11;
            sum1 += p02 + p03 + p12 + p13;
            uint32_t pah[4], pal[4];
            packpair(p00, p01, pah[0], pal[0]);
            packpair(p02, p03, pah[1], pal[1]);
            packpair(p10, p11, pah[2], pal[2]);
            packpair(p12, p13, pah[3], pal[3]);
#pragma unroll
            for (int ndp = 0; ndp < 4; ndp++){
                uint32_t vhh[4];
                ldsm4t(vhh, kb + QT + (uint32_t)(ss*16)*AP + vOff + ndp*32);
                mma16816(o[2*ndp],   pah, &vhh[0]);
                mma16816(o[2*ndp],   pal, &vhh[0]);
                mma16816(o[2*ndp+1], pah, &vhh[2]);
                mma16816(o[2*ndp+1], pal, &vhh[2]);
            }
        }
        sum0 += __shfl_xor_sync(0xffffffffu, sum0, 1);
        sum0 += __shfl_xor_sync(0xffffffffu, sum0, 2);
        sum1 += __shfl_xor_sync(0xffffffffu, sum1, 1);
        sum1 += __shfl_xor_sync(0xffffffffu, sum1, 2);
        l0 = l0*al0 + sum0;
        l1 = l1*al1 + sum1;

        if (c < 2){ __syncthreads(); LOADC(c + 2); }
    }

    float inv0 = 1.f / l0, inv1 = 1.f / l1;
    int r0 = i0 + wid*16 + g, r1 = r0 + 8;
    size_t ob = ((size_t)(b*Ln))*Dn + h*DHn;
#pragma unroll
    for (int nd = 0; nd < 8; nd++){
        int col = nd*8 + t4*2;
        uint32_t hi0, lo0, hi1, lo1;
        packpair(o[nd][0]*inv0, o[nd][1]*inv0, hi0, lo0);
        packpair(o[nd][2]*inv1, o[nd][3]*inv1, hi1, lo1);
        *(uint32_t*)(Ohi + ob + (size_t)r0*Dn + col) = hi0;
        *(uint32_t*)(Olo + ob + (size_t)r0*Dn + col) = lo0;
        *(uint32_t*)(Ohi + ob + (size_t)r1*Dn + col) = hi1;
        *(uint32_t*)(Olo + ob + (size_t)r1*Dn + col) = lo1;
    }
}

// ======================= host orchestration =======================
extern "C" void kernel_launch(void* const* d_in, const int* in_sizes, int n_in,
                              void* d_out, int out_size)
{
    (void)in_sizes; (void)n_in; (void)out_size;
    const float* x     = (const float*)d_in[0];
    const float* mask  = (const float*)d_in[1];
    const float* pe    = (const float*)d_in[2];
    const float* dw_w  = (const float*)d_in[3];
    const float* dw_b  = (const float*)d_in[4];
    const float* pw_w  = (const float*)d_in[5];
    const float* pw_b  = (const float*)d_in[6];
    const float* wq    = (const float*)d_in[7];
    const float* bq    = (const float*)d_in[8];
    const float* wk    = (const float*)d_in[9];
    const float* bk    = (const float*)d_in[10];
    const float* wv    = (const float*)d_in[11];
    const float* bv    = (const float*)d_in[12];
    const float* fc_w  = (const float*)d_in[13];
    const float* fc_b  = (const float*)d_in[14];
    const float* out_w = (const float*)d_in[15];
    const float* out_b = (const float*)d_in[16];
    const float* lnc_g = (const float*)d_in[17];
    const float* lnc_b = (const float*)d_in[18];
    const float* lna_g = (const float*)d_in[19];
    const float* lna_b = (const float*)d_in[20];
    const float* lno_g = (const float*)d_in[21];
    const float* lno_b = (const float*)d_in[22];
    float* out = (float*)d_out;

    __half *pA, *pX2, *pX1, *qkv;
    cudaGetSymbolAddress((void**)&pA,  g_pA);
    cudaGetSymbolAddress((void**)&pX2, g_pX2);
    cudaGetSymbolAddress((void**)&pX1, g_pX1);
    cudaGetSymbolAddress((void**)&qkv, g_qkv);
    __half* wsym;
    cudaGetSymbolAddress((void**)&wsym, g_w);

    const size_t NN = (size_t)Mn*Dn;
    __half *pA_h = pA,  *pA_l = pA + NN;
    __half *x2_h = pX2, *x2_l = pX2 + NN;
    __half *x1_h = pX1, *x1_l = pX1 + NN;
    __half *q_h = qkv, *q_l = qkv + NN, *k_h = qkv + 2*NN, *v_h = qkv + 3*NN;
    auto W = [&](int i){ return wsym + (size_t)i * Dn * Dn; };

    cudaFuncSetAttribute(gemm_mma<true,-1,0,true,false>,  cudaFuncAttributeMaxDynamicSharedMemorySize, SMEM_SZ);
    cudaFuncSetAttribute(gemm_mma<true,0,1,true,false>,   cudaFuncAttributeMaxDynamicSharedMemorySize, SMEM_SZ);
    cudaFuncSetAttribute(gemm_mma<true,1,2,true,false>,   cudaFuncAttributeMaxDynamicSharedMemorySize, SMEM_SZ);
    cudaFuncSetAttribute(gemm_mma<false,2,3,true,false>,  cudaFuncAttributeMaxDynamicSharedMemorySize, SMEM_SZ);
    cudaFuncSetAttribute(gemm_mma<false,3,-1,false,true>, cudaFuncAttributeMaxDynamicSharedMemorySize, SMEM_SZ);
    cudaFuncSetAttribute(gemm_qkv, cudaFuncAttributeMaxDynamicSharedMemorySize, SMEM_SZ);
    cudaFuncSetAttribute(attn_fused, cudaFuncAttributeMaxDynamicSharedMemorySize, SMEM_ATT);

    const int NE4 = Mn * Dn / 4;
    dim3 gemmGrid(Dn/128, Mn/128);      // (4, 128)
    dim3 qkvGrid(12, Mn/128);           // N = 1536

    // 1. weight prep + LN-partial zeroing
    prep_weights<<<6*1024, 256>>>(pw_w, wq, wk, wv, fc_w, out_w);

    // 2-3. conv layer 0 (PE fused); stats -> slot 0 (lnc0)
    dwconv_pe<<<NE4/256, 256>>>(x, pe, dw_w + 0*Dn*Kn, dw_b + 0*Dn, pA_h, pA_l);
    gemm_mma<true,-1,0,true,false><<<gemmGrid, 256, SMEM_SZ>>>(
        pA_h, pA_l, W(0), pw_b + 0*Dn, nullptr,
        nullptr, nullptr, nullptr, nullptr, x2_h, x2_l);
    // 4-5. conv layer 1: + LN(x2; lnc0, slot 0); stats -> slot 1 (lnc1)
    dwconv_pair<<<NE4/256, 256>>>(x2_h, x2_l, dw_w + 1*Dn*Kn, dw_b + 1*Dn, pA_h, pA_l);
    gemm_mma<true,0,1,true,false><<<gemmGrid, 256, SMEM_SZ>>>(
        pA_h, pA_l, W(1), pw_b + 1*Dn, nullptr,
        x2_h, x2_l, lnc_g + 0, lnc_b + 0, x1_h, x1_l);
    // 6-7. conv layer 2: + LN(x1; lnc1, slot 1); stats -> slot 2 (lna)
    dwconv_pair<<<NE4/256, 256>>>(x1_h, x1_l, dw_w + 2*Dn*Kn, dw_b + 2*Dn, pA_h, pA_l);
    gemm_mma<true,1,2,true,false><<<gemmGrid, 256, SMEM_SZ>>>(
        pA_h, pA_l, W(2), pw_b + 2*Dn, nullptr,
        x1_h, x1_l, lnc_g + Ln*Dn, lnc_b + Ln*Dn, x2_h, x2_l);

    // 8. merged qkv projection
    gemm_qkv<<<qkvGrid, 256, SMEM_SZ>>>(x2_h, x2_l, bq, bk, bv);

    // 9. fused flash attention -> pA pair
    attn_fused<<<dim3(Ln/128, Bn*Hn), 256, SMEM_ATT>>>(
        q_h, q_l, k_h, v_h, mask, pA_h, pA_l);

    // 10. fc + LN(x2; lna, slot 2) -> x1 pair; stats -> slot 3 (lno)
    gemm_mma<false,2,3,true,false><<<gemmGrid, 256, SMEM_SZ>>>(
        pA_h, pA_l, W(6), fc_b, nullptr,
        x2_h, x2_l, lna_g, lna_b, x1_h, x1_l);

    // 11. out + LN(x1; lno, slot 3) -> d_out (fp32)
    gemm_mma<false,3,-1,false,true><<<gemmGrid, 256, SMEM_SZ>>>(
        x1_h, x1_l, W(7), out_b, out,
        x1_h, x1_l, lno_g, lno_b, nullptr, nullptr);
}

// round 10
// speedup vs baseline: 3.1087x; 1.1569x over previous
#include <cuda_runtime.h>
#include <cuda_fp16.h>
#include <cstdint>

#define Bn 32
#define Ln 512
#define Dn 512
#define Hn 8
#define DHn 64
#define Kn 7
#define Mn (Bn*Ln)
#define NEGV (-1e30f)
#define LDINV (1.0f/(float)(Ln*Dn))
#define TLC 8                       // L positions per dwconv thread

// ---- big-GEMM tiling ----
#define BK 32
#define PITCH 40
#define TB (128*PITCH*2)
#define BUFB (3*TB)
#define SMEM_SZ (3*BUFB)            // 3-stage pipeline = 92160 B

// ---- fused attention smem ----
#define AP 144
#define QT (128*AP)
#define KVB (2*QT)
#define SMEM_ATT (2*QT + 2*KVB + 1024)

// ======================= PTX helpers =======================
__device__ __forceinline__ uint32_t smem_u32(const void* p){
    uint32_t a;
    asm("{ .reg .u64 t; cvta.to.shared.u64 t, %1; cvt.u32.u64 %0, t; }" : "=r"(a) : "l"(p));
    return a;
}
__device__ __forceinline__ void cpasync16(uint32_t dst, const void* src){
    asm volatile("cp.async.cg.shared.global [%0], [%1], 16;" :: "r"(dst), "l"(src) : "memory");
}
#define CP_COMMIT() asm volatile("cp.async.commit_group;" ::: "memory")
#define CP_WAIT(N)  asm volatile("cp.async.wait_group %0;" :: "n"(N) : "memory")
__device__ __forceinline__ void ldsm4(uint32_t* r, uint32_t addr){
    asm volatile("ldmatrix.sync.aligned.m8n8.x4.shared.b16 {%0,%1,%2,%3}, [%4];"
        : "=r"(r[0]), "=r"(r[1]), "=r"(r[2]), "=r"(r[3]) : "r"(addr));
}
__device__ __forceinline__ void ldsm4t(uint32_t* r, uint32_t addr){
    asm volatile("ldmatrix.sync.aligned.m8n8.x4.trans.shared.b16 {%0,%1,%2,%3}, [%4];"
        : "=r"(r[0]), "=r"(r[1]), "=r"(r[2]), "=r"(r[3]) : "r"(addr));
}
__device__ __forceinline__ void mma16816(float* d, const uint32_t* a, const uint32_t* b){
    asm volatile("mma.sync.aligned.m16n8k16.row.col.f32.f16.f16.f32 "
        "{%0,%1,%2,%3}, {%4,%5,%6,%7}, {%8,%9}, {%0,%1,%2,%3};"
        : "+f"(d[0]), "+f"(d[1]), "+f"(d[2]), "+f"(d[3])
        : "r"(a[0]), "r"(a[1]), "r"(a[2]), "r"(a[3]), "r"(b[0]), "r"(b[1]));
}
__device__ __forceinline__ void packpair(float x, float y, uint32_t& hi, uint32_t& lo){
    __half hx = __float2half_rn(x), hy = __float2half_rn(y);
    __half2 h; h.x = hx; h.y = hy;
    __half2 l;
    l.x = __float2half_rn(x - __half2float(hx));
    l.y = __float2half_rn(y - __half2float(hy));
    hi = *(uint32_t*)&h; lo = *(uint32_t*)&l;
}
__device__ __forceinline__ float2 unpackpair(uint32_t hi, uint32_t lo){
    __half2 h = *(__half2*)&hi, l = *(__half2*)&lo;
    float2 r;
    r.x = __half2float(h.x) + __half2float(l.x);
    r.y = __half2float(h.y) + __half2float(l.y);
    return r;
}

// ======================= scratch =======================
__device__ float g_pS [4][Bn];
__device__ float g_pS2[4][Bn];
__device__ __half g_pA [2][Mn*Dn];
__device__ __half g_pX2[2][Mn*Dn];
__device__ __half g_pX1[2][Mn*Dn];
__device__ __half g_qkv[4][Mn*Dn];
__device__ __half g_w[8][Dn*Dn];

// ======================= weight prep + LN-partial zeroing =======================
__global__ void prep_weights(const float* __restrict__ pw_w,
                             const float* __restrict__ wq, const float* __restrict__ wk,
                             const float* __restrict__ wv,
                             const float* __restrict__ fc_w, const float* __restrict__ out_w)
{
    if (blockIdx.x == 0 && threadIdx.x < 4*Bn) {
        (&g_pS[0][0])[threadIdx.x]  = 0.f;
        (&g_pS2[0][0])[threadIdx.x] = 0.f;
    }
    int task = blockIdx.x >> 10;
    int idx  = (blockIdx.x & 1023) * 256 + threadIdx.x;
    if (task < 3) {
        g_w[task][idx] = __float2half_rn(pw_w[(size_t)task*Dn*Dn + idx]);
    } else if (task == 3) {
        int n = idx >> 9, d = idx & 511;
        int src = (n >> 6) * (Dn * DHn) + d * DHn + (n & 63);
        g_w[3][idx] = __float2half_rn(wq[src]);
        g_w[4][idx] = __float2half_rn(wk[src]);
        g_w[5][idx] = __float2half_rn(wv[src]);
    } else if (task == 4) {
        g_w[6][idx] = __float2half_rn(fc_w[idx]);
    } else {
        g_w[7][idx] = __float2half_rn(out_w[idx]);
    }
}

// ======================= sliding-window depthwise conv =======================
// each thread: 8 consecutive L positions x 4 channels; input rows loaded once.
__global__ void dwconv_pe(const float* __restrict__ x, const float* __restrict__ pe,
                          const float* __restrict__ w, const float* __restrict__ bias,
                          __half* __restrict__ hi, __half* __restrict__ lo)
{
    int idx = blockIdx.x * 256 + threadIdx.x;      // over Bn*(Ln/8)*(Dn/4) = 262144
    int d  = (idx & 127) << 2;
    int l0 = ((idx >> 7) & 63) << 3;
    int b  = idx >> 13;

    float wr[4][Kn];
#pragma unroll
    for (int c = 0; c < 4; c++)
#pragma unroll
        for (int kk = 0; kk < Kn; kk++) wr[c][kk] = w[(d + c)*Kn + kk];

    float4 bs = *(const float4*)(bias + d);
    float4 acc[TLC];
#pragma unroll
    for (int j = 0; j < TLC; j++) acc[j] = bs;

#pragma unroll
    for (int i = 0; i < TLC + 6; i++){
        int ll = l0 - 3 + i;
        if (ll >= 0 && ll < Ln){
            float4 xv = *(const float4*)(x + ((size_t)(b*Ln + ll))*Dn + d);
            float4 pv = *(const float4*)(pe + (size_t)ll*Dn + d);
            xv.x += pv.x; xv.y += pv.y; xv.z += pv.z; xv.w += pv.w;
#pragma unroll
            for (int kk = 0; kk < Kn; kk++){
                int j = i - kk;
                if (j >= 0 && j < TLC){
                    acc[j].x = fmaf(xv.x, wr[0][kk], acc[j].x);
                    acc[j].y = fmaf(xv.y, wr[1][kk], acc[j].y);
                    acc[j].z = fmaf(xv.z, wr[2][kk], acc[j].z);
                    acc[j].w = fmaf(xv.w, wr[3][kk], acc[j].w);
                }
            }
        }
    }
#pragma unroll
    for (int j = 0; j < TLC; j++){
        float vx = fmaxf(acc[j].x, 0.f), vy = fmaxf(acc[j].y, 0.f);
        float vz = fmaxf(acc[j].z, 0.f), vw = fmaxf(acc[j].w, 0.f);
        size_t o = ((size_t)(b*Ln + l0 + j))*Dn + d;
        uint32_t h0, lw0, h1, lw1;
        packpair(vx, vy, h0, lw0);
        packpair(vz, vw, h1, lw1);
        uint2 hv; hv.x = h0;  hv.y = h1;
        uint2 lv; lv.x = lw0; lv.y = lw1;
        *(uint2*)(hi + o) = hv;
        *(uint2*)(lo + o) = lv;
    }
}

__global__ void dwconv_pair(const __half* __restrict__ xh, const __half* __restrict__ xl,
                            const float* __restrict__ w, const float* __restrict__ bias,
                            __half* __restrict__ hi, __half* __restrict__ lo)
{
    int idx = blockIdx.x * 256 + threadIdx.x;
    int d  = (idx & 127) << 2;
    int l0 = ((idx >> 7) & 63) << 3;
    int b  = idx >> 13;

    float wr[4][Kn];
#pragma unroll
    for (int c = 0; c < 4; c++)
#pragma unroll
        for (int kk = 0; kk < Kn; kk++) wr[c][kk] = w[(d + c)*Kn + kk];

    float4 bs = *(const float4*)(bias + d);
    float4 acc[TLC];
#pragma unroll
    for (int j = 0; j < TLC; j++) acc[j] = bs;

#pragma unroll
    for (int i = 0; i < TLC + 6; i++){
        int ll = l0 - 3 + i;
        if (ll >= 0 && ll < Ln){
            size_t base = ((size_t)(b*Ln + ll))*Dn + d;
            uint2 hv = *(const uint2*)(xh + base);
            uint2 lv = *(const uint2*)(xl + base);
            float2 a0 = unpackpair(hv.x, lv.x);
            float2 a1 = unpackpair(hv.y, lv.y);
            float4 xv; xv.x = a0.x; xv.y = a0.y; xv.z = a1.x; xv.w = a1.y;
#pragma unroll
            for (int kk = 0; kk < Kn; kk++){
                int j = i - kk;
                if (j >= 0 && j < TLC){
                    acc[j].x = fmaf(xv.x, wr[0][kk], acc[j].x);
                    acc[j].y = fmaf(xv.y, wr[1][kk], acc[j].y);
                    acc[j].z = fmaf(xv.z, wr[2][kk], acc[j].z);
                    acc[j].w = fmaf(xv.w, wr[3][kk], acc[j].w);
                }
            }
        }
    }
#pragma unroll
    for (int j = 0; j < TLC; j++){
        float vx = fmaxf(acc[j].x, 0.f), vy = fmaxf(acc[j].y, 0.f);
        float vz = fmaxf(acc[j].z, 0.f), vw = fmaxf(acc[j].w, 0.f);
        size_t o = ((size_t)(b*Ln + l0 + j))*Dn + d;
        uint32_t h0, lw0, h1, lw1;
        packpair(vx, vy, h0, lw0);
        packpair(vz, vw, h1, lw1);
        uint2 hv; hv.x = h0;  hv.y = h1;
        uint2 lv; lv.x = lw0; lv.y = lw1;
        *(uint2*)(hi + o) = hv;
        *(uint2*)(lo + o) = lv;
    }
}

// ======================= mma.sync GEMM (fp16 2-term, 3-stage pipeline) =======================
template<bool RELU, int LNIN, int LNOUT, bool SPL, bool WRITEC>
__global__ __launch_bounds__(256, 2) void gemm_mma(
    const __half* __restrict__ Ahi, const __half* __restrict__ Alo,
    const __half* __restrict__ Whi,
    const float* __restrict__ bias, float* __restrict__ C,
    const __half* __restrict__ Rhi, const __half* __restrict__ Rlo,
    const float* __restrict__ lng, const float* __restrict__ lnb,
    __half* __restrict__ Chi, __half* __restrict__ Clo)
{
    extern __shared__ __align__(16) char dsm[];
    const uint32_t sb = smem_u32(dsm);
    const int tid = threadIdx.x;
    const int wid = tid >> 5, lane = tid & 31;
    const int warpRow = wid >> 2, warpCol = wid & 3;
    const int bx = blockIdx.x, by = blockIdx.y;

    const __half* srcs[3] = {Ahi, Alo, Whi};
    const int rowb[3] = { by*128, by*128, bx*128 };

    auto PREF = [&](int kt){
        uint32_t bufb = sb + (uint32_t)(kt % 3) * BUFB;
#pragma unroll
        for (int t = 0; t < 3; t++){
            const __half* src = srcs[t] + (size_t)rowb[t]*Dn + kt*BK;
            uint32_t tb = bufb + (uint32_t)t*TB;
#pragma unroll
            for (int i = 0; i < 2; i++){
                int id  = tid + i*256;
                int row = id >> 2, c = id & 3;
                cpasync16(tb + (uint32_t)(row*(PITCH*2) + c*16),
                          src + (size_t)row*Dn + c*8);
            }
        }
        CP_COMMIT();
    };

    float acc[4][4][4];
#pragma unroll
    for (int i = 0; i < 4; i++)
#pragma unroll
        for (int j = 0; j < 4; j++)
#pragma unroll
            for (int q = 0; q < 4; q++) acc[i][j][q] = 0.f;

    const uint32_t aRow = (uint32_t)(warpRow*64 + (lane & 15));
    const uint32_t aColB = (uint32_t)(((lane >> 4) << 4));
    const uint32_t bRow = (uint32_t)(warpCol*32 + (lane & 7) + ((lane >> 4) << 3));
    const uint32_t bColB = (uint32_t)((((lane >> 3) & 1) << 4));

    PREF(0);
    PREF(1);
#pragma unroll 1
    for (int kt = 0; kt < Dn/BK; kt++){
        if (kt + 1 < Dn/BK) { CP_WAIT(1); } else { CP_WAIT(0); }
        __syncthreads();
        if (kt + 2 < Dn/BK) PREF(kt + 2);

        uint32_t bufb = sb + (uint32_t)(kt % 3) * BUFB;
        uint32_t tAhi = bufb, tAlo = bufb + TB, tWhi = bufb + 2*TB;
#pragma unroll
        for (int kk = 0; kk < 2; kk++){
            uint32_t ah[4][4], al[4][4], bh[2][4];
#pragma unroll
            for (int mi = 0; mi < 4; mi++){
                ldsm4(ah[mi], tAhi + (aRow + mi*16)*(PITCH*2) + aColB + kk*32);
                ldsm4(al[mi], tAlo + (aRow + mi*16)*(PITCH*2) + aColB + kk*32);
            }
#pragma unroll
            for (int nt = 0; nt < 2; nt++)
                ldsm4(bh[nt], tWhi + (bRow + nt*16)*(PITCH*2) + bColB + kk*32);
#pragma unroll
            for (int mi = 0; mi < 4; mi++)
#pragma unroll
                for (int nj = 0; nj < 4; nj++){
                    mma16816(acc[mi][nj], ah[mi], &bh[nj >> 1][(nj & 1) << 1]);
                    mma16816(acc[mi][nj], al[mi], &bh[nj >> 1][(nj & 1) << 1]);
                }
        }
    }

    float muv = 0.f, rsv = 0.f;
    if (LNIN >= 0) {
        int bb = (by*128) >> 9;
        float s = g_pS[LNIN][bb], s2 = g_pS2[LNIN][bb];
        muv = s * LDINV;
        rsv = rsqrtf(s2 * LDINV - muv*muv + 1e-5f);
    }
    const int r0base = by*128 + warpRow*64;
    const int c0base = bx*128 + warpCol*32;
    float ts = 0.f, ts2 = 0.f;
#pragma unroll
    for (int mi = 0; mi < 4; mi++){
#pragma unroll
        for (int rp = 0; rp < 2; rp++){
            int grow = r0base + mi*16 + (lane >> 2) + rp*8;
            int lrow = grow & (Ln - 1);
#pragma unroll
            for (int nj = 0; nj < 4; nj++){
                int col = c0base + nj*8 + (lane & 3)*2;
                float vx = acc[mi][nj][rp*2 + 0];
                float vy = acc[mi][nj][rp*2 + 1];
                float2 bs = *(const float2*)(bias + col);
                vx += bs.x; vy += bs.y;
                if (RELU) { vx = fmaxf(vx, 0.f); vy = fmaxf(vy, 0.f); }
                size_t off = (size_t)grow*Dn + col;
                if (LNIN >= 0) {
                    float2 rr = unpackpair(*(const uint32_t*)(Rhi + off),
                                           *(const uint32_t*)(Rlo + off));
                    float2 gg = *(const float2*)(lng + (size_t)lrow*Dn + col);
                    float2 bb = *(const float2*)(lnb + (size_t)lrow*Dn + col);
                    vx += (rr.x - muv)*rsv*gg.x + bb.x;
                    vy += (rr.y - muv)*rsv*gg.y + bb.y;
                }
                if (LNOUT >= 0) { ts += vx + vy; ts2 += vx*vx + vy*vy; }
                if (WRITEC) {
                    float2 o; o.x = vx; o.y = vy;
                    *(float2*)(C + off) = o;
                }
                if (SPL) {
                    uint32_t hi, lo;
                    packpair(vx, vy, hi, lo);
                    *(uint32_t*)(Chi + off) = hi;
                    *(uint32_t*)(Clo + off) = lo;
                }
            }
        }
    }
    if (LNOUT >= 0) {
#pragma unroll
        for (int o = 16; o > 0; o >>= 1){
            ts  += __shfl_xor_sync(0xffffffffu, ts,  o);
            ts2 += __shfl_xor_sync(0xffffffffu, ts2, o);
        }
        __shared__ float sred[2][8];
        if (lane == 0){ sred[0][wid] = ts; sred[1][wid] = ts2; }
        __syncthreads();
        if (tid == 0){
            float a = 0.f, b2 = 0.f;
#pragma unroll
            for (int i = 0; i < 8; i++){ a += sred[0][i]; b2 += sred[1][i]; }
            int batch = by >> 2;
            atomicAdd(&g_pS[LNOUT][batch],  a);
            atomicAdd(&g_pS2[LNOUT][batch], b2);
        }
    }
}

// ======================= merged qkv GEMM (N=1536, 3-stage pipeline) =======================
__global__ __launch_bounds__(256, 2) void gemm_qkv(
    const __half* __restrict__ Ahi, const __half* __restrict__ Alo,
    const float* __restrict__ bq, const float* __restrict__ bk, const float* __restrict__ bv)
{
    extern __shared__ __align__(16) char dsm[];
    const uint32_t sb = smem_u32(dsm);
    const int tid = threadIdx.x;
    const int wid = tid >> 5, lane = tid & 31;
    const int warpRow = wid >> 2, warpCol = wid & 3;
    const int bx = blockIdx.x, by = blockIdx.y;
    const int seg = bx >> 2, bxl = bx & 3;

    const __half* Whi = g_w[3 + seg];
    const float* bias = (seg == 0) ? bq : ((seg == 1) ? bk : bv);
    __half* Ch = (seg == 0) ? g_qkv[0] : ((seg == 1) ? g_qkv[2] : g_qkv[3]);
    __half* Cl = g_qkv[1];

    const __half* srcs[3] = {Ahi, Alo, Whi};
    const int rowb[3] = { by*128, by*128, bxl*128 };

    auto PREF = [&](int kt){
        uint32_t bufb = sb + (uint32_t)(kt % 3) * BUFB;
#pragma unroll
        for (int t = 0; t < 3; t++){
            const __half* src = srcs[t] + (size_t)rowb[t]*Dn + kt*BK;
            uint32_t tb = bufb + (uint32_t)t*TB;
#pragma unroll
            for (int i = 0; i < 2; i++){
                int id  = tid + i*256;
                int row = id >> 2, c = id & 3;
                cpasync16(tb + (uint32_t)(row*(PITCH*2) + c*16),
                          src + (size_t)row*Dn + c*8);
            }
        }
        CP_COMMIT();
    };

    float acc[4][4][4];
#pragma unroll
    for (int i = 0; i < 4; i++)
#pragma unroll
        for (int j = 0; j < 4; j++)
#pragma unroll
            for (int q = 0; q < 4; q++) acc[i][j][q] = 0.f;

    const uint32_t aRow = (uint32_t)(warpRow*64 + (lane & 15));
    const uint32_t aColB = (uint32_t)(((lane >> 4) << 4));
    const uint32_t bRow = (uint32_t)(warpCol*32 + (lane & 7) + ((lane >> 4) << 3));
    const uint32_t bColB = (uint32_t)((((lane >> 3) & 1) << 4));

    PREF(0);
    PREF(1);
#pragma unroll 1
    for (int kt = 0; kt < Dn/BK; kt++){
        if (kt + 1 < Dn/BK) { CP_WAIT(1); } else { CP_WAIT(0); }
        __syncthreads();
        if (kt + 2 < Dn/BK) PREF(kt + 2);

        uint32_t bufb = sb + (uint32_t)(kt % 3) * BUFB;
        uint32_t tAhi = bufb, tAlo = bufb + TB, tWhi = bufb + 2*TB;
#pragma unroll
        for (int kk = 0; kk < 2; kk++){
            uint32_t ah[4][4], al[4][4], bh[2][4];
#pragma unroll
            for (int mi = 0; mi < 4; mi++){
                ldsm4(ah[mi], tAhi + (aRow + mi*16)*(PITCH*2) + aColB + kk*32);
                ldsm4(al[mi], tAlo + (aRow + mi*16)*(PITCH*2) + aColB + kk*32);
            }
#pragma unroll
            for (int nt = 0; nt < 2; nt++)
                ldsm4(bh[nt], tWhi + (bRow + nt*16)*(PITCH*2) + bColB + kk*32);
#pragma unroll
            for (int mi = 0; mi < 4; mi++)
#pragma unroll
                for (int nj = 0; nj < 4; nj++){
                    mma16816(acc[mi][nj], ah[mi], &bh[nj >> 1][(nj & 1) << 1]);
                    mma16816(acc[mi][nj], al[mi], &bh[nj >> 1][(nj & 1) << 1]);
                }
        }
    }

    const int r0base = by*128 + warpRow*64;
    const int c0base = bxl*128 + warpCol*32;
    const bool wlo = (seg == 0);
#pragma unroll
    for (int mi = 0; mi < 4; mi++){
#pragma unroll
        for (int rp = 0; rp < 2; rp++){
            int grow = r0base + mi*16 + (lane >> 2) + rp*8;
#pragma unroll
            for (int nj = 0; nj < 4; nj++){
                int col = c0base + nj*8 + (lane & 3)*2;
                float vx = acc[mi][nj][rp*2 + 0];
                float vy = acc[mi][nj][rp*2 + 1];
                float2 bs = *(const float2*)(bias + col);
                vx += bs.x; vy += bs.y;
                size_t off = (size_t)grow*Dn + col;
                uint32_t hi, lo;
                packpair(vx, vy, hi, lo);
                *(uint32_t*)(Ch + off) = hi;
                if (wlo) *(uint32_t*)(Cl + off) = lo;
            }
        }
    }
}

// ======================= fused flash attention (fp16 2-term) =======================
__global__ __launch_bounds__(256, 1) void attn_fused(
    const __half* __restrict__ qh, const __half* __restrict__ ql,
    const __half* __restrict__ kh, const __half* __restrict__ vh,
    const float* __restrict__ mask,
    __half* __restrict__ Ohi, __half* __restrict__ Olo)
{
    extern __shared__ __align__(16) char dsm[];
    const uint32_t sb = smem_u32(dsm);
    const int tid = threadIdx.x, wid = tid >> 5, lane = tid & 31;
    const int bh = blockIdx.y, b = bh >> 3, h = bh & 7;
    const int i0 = blockIdx.x * 128;
    const size_t qoff = ((size_t)(b*Ln + i0))*Dn + h*DHn;
    const size_t koff = ((size_t)(b*Ln))*Dn + h*DHn;

    const uint32_t smQh = sb, smQl = sb + QT;
    const uint32_t smKV0 = sb + 2*QT;
    const uint32_t smMaskOff = 2*QT + 2*KVB;

    auto LOADC = [&](int c){
        uint32_t base = smKV0 + (uint32_t)(c & 1)*KVB;
        size_t g0 = koff + (size_t)(c*128)*Dn;
#pragma unroll
        for (int i = 0; i < 4; i++){
            int id = tid + i*256; int row = id >> 3, seg = id & 7;
            size_t go = g0 + (size_t)row*Dn + seg*8;
            uint32_t so = (uint32_t)(row*AP + seg*16);
            cpasync16(base + so,      kh + go);
            cpasync16(base + QT + so, vh + go);
        }
        if (tid < 32)
            cpasync16(sb + smMaskOff + (uint32_t)(c & 1)*512 + tid*16,
                      mask + b*Ln + c*128 + tid*4);
        CP_COMMIT();
    };

#pragma unroll
    for (int i = 0; i < 4; i++){
        int id = tid + i*256; int row = id >> 3, seg = id & 7;
        size_t go = qoff + (size_t)row*Dn + seg*8;
        uint32_t so = (uint32_t)(row*AP + seg*16);
        cpasync16(smQh + so, qh + go);
        cpasync16(smQl + so, ql + go);
    }
    LOADC(0);
    LOADC(1);

    const int g = lane >> 2, t4 = lane & 3;
    float mi0 = mask[b*Ln + i0 + wid*16 + g];
    float mi1 = mask[b*Ln + i0 + wid*16 + g + 8];

    float m0 = -3.0e38f, m1 = -3.0e38f, l0 = 0.f, l1 = 0.f;
    float o[8][4];
#pragma unroll
    for (int i = 0; i < 8; i++)
#pragma unroll
        for (int j = 0; j < 4; j++) o[i][j] = 0.f;

    const uint32_t aQoff = (uint32_t)((wid*16 + (lane & 15))*AP + ((lane >> 4) << 4));
    const uint32_t bKoff = (uint32_t)(((lane & 7) + ((lane >> 4) << 3))*AP + (((lane >> 3) & 1) << 4));
    const uint32_t vOff  = (uint32_t)((lane & 15)*AP + ((lane >> 4) << 4));

#pragma unroll 1
    for (int c = 0; c < 4; c++){
        if (c < 3) { CP_WAIT(1); } else { CP_WAIT(0); }
        __syncthreads();
        const uint32_t kb = smKV0 + (uint32_t)(c & 1)*KVB;
        const float* mjp = (const float*)(dsm + smMaskOff + (c & 1)*512);

        float s[16][4];
#pragma unroll
        for (int nj = 0; nj < 16; nj++)
#pragma unroll
            for (int q = 0; q < 4; q++) s[nj][q] = 0.f;
#pragma unroll
        for (int ss = 0; ss < 4; ss++){
            uint32_t ah[4], al[4];
            ldsm4(ah, smQh + aQoff + ss*32);
            ldsm4(al, smQl + aQoff + ss*32);
#pragma unroll
            for (int njp = 0; njp < 8; njp++){
                uint32_t bhh[4];
                ldsm4(bhh, kb + (uint32_t)(njp*16)*AP + bKoff + ss*32);
                mma16816(s[2*njp],   ah, &bhh[0]);
                mma16816(s[2*njp],   al, &bhh[0]);
                mma16816(s[2*njp+1], ah, &bhh[2]);
                mma16816(s[2*njp+1], al, &bhh[2]);
            }
        }

        float rm0 = -3.0e38f, rm1 = -3.0e38f;
#pragma unroll
        for (int nj = 0; nj < 16; nj++){
            int colb = nj*8 + t4*2;
            float mj0 = mjp[colb], mj1 = mjp[colb+1];
            float mm;
            mm = mi0*mj0; s[nj][0] = s[nj][0]*0.125f*mm + NEGV*(1.f - mm);
            mm = mi0*mj1; s[nj][1] = s[nj][1]*0.125f*mm + NEGV*(1.f - mm);
            mm = mi1*mj0; s[nj][2] = s[nj][2]*0.125f*mm + NEGV*(1.f - mm);
            mm = mi1*mj1; s[nj][3] = s[nj][3]*0.125f*mm + NEGV*(1.f - mm);
            rm0 = fmaxf(rm0, fmaxf(s[nj][0], s[nj][1]));
            rm1 = fmaxf(rm1, fmaxf(s[nj][2], s[nj][3]));
        }
        rm0 = fmaxf(rm0, __shfl_xor_sync(0xffffffffu, rm0, 1));
        rm0 = fmaxf(rm0, __shfl_xor_sync(0xffffffffu, rm0, 2));
        rm1 = fmaxf(rm1, __shfl_xor_sync(0xffffffffu, rm1, 1));
        rm1 = fmaxf(rm1, __shfl_xor_sync(0xffffffffu, rm1, 2));
        float nm0 = fmaxf(m0, rm0), nm1 = fmaxf(m1, rm1);
        float al0 = __expf(m0 - nm0), al1 = __expf(m1 - nm1);
        m0 = nm0; m1 = nm1;
#pragma unroll
        for (int nd = 0; nd < 8; nd++){
            o[nd][0] *= al0; o[nd][1] *= al0;
            o[nd][2] *= al1; o[nd][3] *= al1;
        }

        float sum0 = 0.f, sum1 = 0.f;
#pragma unroll
        for (int ss = 0; ss < 8; ss++){
            float p00 = __expf(s[2*ss][0]   - nm0), p01 = __expf(s[2*ss][1]   - nm0);
            float p02 = __expf(s[2*ss][2]   - nm1), p03 = __expf(s[2*ss][3]   - nm1);
            float p10 = __expf(s[2*ss+1][0] - nm0), p11 = __expf(s[2*ss+1][1] - nm0);
            float p12 = __expf(s[2*ss+1][2] - nm1), p13 = __expf(s[2*ss+1][3] - nm1);
            sum0 += p00 + p01 + p10 + p11;
            sum1 += p02 + p03 + p12 + p13;
            uint32_t pah[4], pal[4];
            packpair(p00, p01, pah[0], pal[0]);
            packpair(p02, p03, pah[1], pal[1]);
            packpair(p10, p11, pah[2], pal[2]);
            packpair(p12, p13, pah[3], pal[3]);
#pragma unroll
            for (int ndp = 0; ndp < 4; ndp++){
                uint32_t vhh[4];
                ldsm4t(vhh, kb + QT + (uint32_t)(ss*16)*AP + vOff + ndp*32);
                mma16816(o[2*ndp],   pah, &vhh[0]);
                mma16816(o[2*ndp],   pal, &vhh[0]);
                mma16816(o[2*ndp+1], pah, &vhh[2]);
                mma16816(o[2*ndp+1], pal, &vhh[2]);
            }
        }
        sum0 += __shfl_xor_sync(0xffffffffu, sum0, 1);
        sum0 += __shfl_xor_sync(0xffffffffu, sum0, 2);
        sum1 += __shfl_xor_sync(0xffffffffu, sum1, 1);
        sum1 += __shfl_xor_sync(0xffffffffu, sum1, 2);
        l0 = l0*al0 + sum0;
        l1 = l1*al1 + sum1;

        if (c < 2){ __syncthreads(); LOADC(c + 2); }
    }

    float inv0 = 1.f / l0, inv1 = 1.f / l1;
    int r0 = i0 + wid*16 + g, r1 = r0 + 8;
    size_t ob = ((size_t)(b*Ln))*Dn + h*DHn;
#pragma unroll
    for (int nd = 0; nd < 8; nd++){
        int col = nd*8 + t4*2;
        uint32_t hi0, lo0, hi1, lo1;
        packpair(o[nd][0]*inv0, o[nd][1]*inv0, hi0, lo0);
        packpair(o[nd][2]*inv1, o[nd][3]*inv1, hi1, lo1);
        *(uint32_t*)(Ohi + ob + (size_t)r0*Dn + col) = hi0;
        *(uint32_t*)(Olo + ob + (size_t)r0*Dn + col) = lo0;
        *(uint32_t*)(Ohi + ob + (size_t)r1*Dn + col) = hi1;
        *(uint32_t*)(Olo + ob + (size_t)r1*Dn + col) = lo1;
    }
}

// ======================= host orchestration =======================
extern "C" void kernel_launch(void* const* d_in, const int* in_sizes, int n_in,
                              void* d_out, int out_size)
{
    (void)in_sizes; (void)n_in; (void)out_size;
    const float* x     = (const float*)d_in[0];
    const float* mask  = (const float*)d_in[1];
    const float* pe    = (const float*)d_in[2];
    const float* dw_w  = (const float*)d_in[3];
    const float* dw_b  = (const float*)d_in[4];
    const float* pw_w  = (const float*)d_in[5];
    const float* pw_b  = (const float*)d_in[6];
    const float* wq    = (const float*)d_in[7];
    const float* bq    = (const float*)d_in[8];
    const float* wk    = (const float*)d_in[9];
    const float* bk    = (const float*)d_in[10];
    const float* wv    = (const float*)d_in[11];
    const float* bv    = (const float*)d_in[12];
    const float* fc_w  = (const float*)d_in[13];
    const float* fc_b  = (const float*)d_in[14];
    const float* out_w = (const float*)d_in[15];
    const float* out_b = (const float*)d_in[16];
    const float* lnc_g = (const float*)d_in[17];
    const float* lnc_b = (const float*)d_in[18];
    const float* lna_g = (const float*)d_in[19];
    const float* lna_b = (const float*)d_in[20];
    const float* lno_g = (const float*)d_in[21];
    const float* lno_b = (const float*)d_in[22];
    float* out = (float*)d_out;

    __half *pA, *pX2, *pX1, *qkv;
    cudaGetSymbolAddress((void**)&pA,  g_pA);
    cudaGetSymbolAddress((void**)&pX2, g_pX2);
    cudaGetSymbolAddress((void**)&pX1, g_pX1);
    cudaGetSymbolAddress((void**)&qkv, g_qkv);
    __half* wsym;
    cudaGetSymbolAddress((void**)&wsym, g_w);

    const size_t NN = (size_t)Mn*Dn;
    __half *pA_h = pA,  *pA_l = pA + NN;
    __half *x2_h = pX2, *x2_l = pX2 + NN;
    __half *x1_h = pX1, *x1_l = pX1 + NN;
    __half *q_h = qkv, *q_l = qkv + NN, *k_h = qkv + 2*NN, *v_h = qkv + 3*NN;
    auto W = [&](int i){ return wsym + (size_t)i * Dn * Dn; };

    cudaFuncSetAttribute(gemm_mma<true,-1,0,true,false>,  cudaFuncAttributeMaxDynamicSharedMemorySize, SMEM_SZ);
    cudaFuncSetAttribute(gemm_mma<true,0,1,true,false>,   cudaFuncAttributeMaxDynamicSharedMemorySize, SMEM_SZ);
    cudaFuncSetAttribute(gemm_mma<true,1,2,true,false>,   cudaFuncAttributeMaxDynamicSharedMemorySize, SMEM_SZ);
    cudaFuncSetAttribute(gemm_mma<false,2,3,true,false>,  cudaFuncAttributeMaxDynamicSharedMemorySize, SMEM_SZ);
    cudaFuncSetAttribute(gemm_mma<false,3,-1,false,true>, cudaFuncAttributeMaxDynamicSharedMemorySize, SMEM_SZ);
    cudaFuncSetAttribute(gemm_qkv, cudaFuncAttributeMaxDynamicSharedMemorySize, SMEM_SZ);
    cudaFuncSetAttribute(attn_fused, cudaFuncAttributeMaxDynamicSharedMemorySize, SMEM_ATT);

    const int DWB = (Bn * (Ln/TLC) * (Dn/4)) / 256;   // 1024 blocks
    dim3 gemmGrid(Dn/128, Mn/128);      // (4, 128)
    dim3 qkvGrid(12, Mn/128);           // N = 1536

    // 1. weight prep + LN-partial zeroing
    prep_weights<<<6*1024, 256>>>(pw_w, wq, wk, wv, fc_w, out_w);

    // 2-3. conv layer 0 (PE fused); stats -> slot 0 (lnc0)
    dwconv_pe<<<DWB, 256>>>(x, pe, dw_w + 0*Dn*Kn, dw_b + 0*Dn, pA_h, pA_l);
    gemm_mma<true,-1,0,true,false><<<gemmGrid, 256, SMEM_SZ>>>(
        pA_h, pA_l, W(0), pw_b + 0*Dn, nullptr,
        nullptr, nullptr, nullptr, nullptr, x2_h, x2_l);
    // 4-5. conv layer 1: + LN(x2; lnc0, slot 0); stats -> slot 1 (lnc1)
    dwconv_pair<<<DWB, 256>>>(x2_h, x2_l, dw_w + 1*Dn*Kn, dw_b + 1*Dn, pA_h, pA_l);
    gemm_mma<true,0,1,true,false><<<gemmGrid, 256, SMEM_SZ>>>(
        pA_h, pA_l, W(1), pw_b + 1*Dn, nullptr,
        x2_h, x2_l, lnc_g + 0, lnc_b + 0, x1_h, x1_l);
    // 6-7. conv layer 2: + LN(x1; lnc1, slot 1); stats -> slot 2 (lna)
    dwconv_pair<<<DWB, 256>>>(x1_h, x1_l, dw_w + 2*Dn*Kn, dw_b + 2*Dn, pA_h, pA_l);
    gemm_mma<true,1,2,true,false><<<gemmGrid, 256, SMEM_SZ>>>(
        pA_h, pA_l, W(2), pw_b + 2*Dn, nullptr,
        x1_h, x1_l, lnc_g + Ln*Dn, lnc_b + Ln*Dn, x2_h, x2_l);

    // 8. merged qkv projection
    gemm_qkv<<<qkvGrid, 256, SMEM_SZ>>>(x2_h, x2_l, bq, bk, bv);

    // 9. fused flash attention -> pA pair
    attn_fused<<<dim3(Ln/128, Bn*Hn), 256, SMEM_ATT>>>(
        q_h, q_l, k_h, v_h, mask, pA_h, pA_l);

    // 10. fc + LN(x2; lna, slot 2) -> x1 pair; stats -> slot 3 (lno)
    gemm_mma<false,2,3,true,false><<<gemmGrid, 256, SMEM_SZ>>>(
        pA_h, pA_l, W(6), fc_b, nullptr,
        x2_h, x2_l, lna_g, lna_b, x1_h, x1_l);

    // 11. out + LN(x1; lno, slot 3) -> d_out (fp32)
    gemm_mma<false,3,-1,false,true><<<gemmGrid, 256, SMEM_SZ>>>(
        x1_h, x1_l, W(7), out_b, out,
        x1_h, x1_l, lno_g, lno_b, nullptr, nullptr);
}

// round 11
// speedup vs baseline: 3.1308x; 1.0071x over previous
#include <cuda_runtime.h>
#include <cuda_fp16.h>
#include <cstdint>

#define Bn 32
#define Ln 512
#define Dn 512
#define Hn 8
#define DHn 64
#define Kn 7
#define Mn (Bn*Ln)
#define NEGV (-1e30f)
#define LDINV (1.0f/(float)(Ln*Dn))
#define TLC 4                       // L positions per dwconv thread

// ---- big-GEMM tiling ----
#define BK 32
#define PITCH 40
#define TB (128*PITCH*2)
#define BUFB (3*TB)
#define SMEM_SZ (3*BUFB)            // 3-stage pipeline = 92160 B

// ---- fused attention smem ----
#define AP 144
#define QT (128*AP)
#define KVB (2*QT)
#define SMEM_ATT (2*QT + 2*KVB + 1024)

// ======================= PTX helpers =======================
__device__ __forceinline__ uint32_t smem_u32(const void* p){
    uint32_t a;
    asm("{ .reg .u64 t; cvta.to.shared.u64 t, %1; cvt.u32.u64 %0, t; }" : "=r"(a) : "l"(p));
    return a;
}
__device__ __forceinline__ void cpasync16(uint32_t dst, const void* src){
    asm volatile("cp.async.cg.shared.global [%0], [%1], 16;" :: "r"(dst), "l"(src) : "memory");
}
#define CP_COMMIT() asm volatile("cp.async.commit_group;" ::: "memory")
#define CP_WAIT(N)  asm volatile("cp.async.wait_group %0;" :: "n"(N) : "memory")
__device__ __forceinline__ void ldsm4(uint32_t* r, uint32_t addr){
    asm volatile("ldmatrix.sync.aligned.m8n8.x4.shared.b16 {%0,%1,%2,%3}, [%4];"
        : "=r"(r[0]), "=r"(r[1]), "=r"(r[2]), "=r"(r[3]) : "r"(addr));
}
__device__ __forceinline__ void ldsm4t(uint32_t* r, uint32_t addr){
    asm volatile("ldmatrix.sync.aligned.m8n8.x4.trans.shared.b16 {%0,%1,%2,%3}, [%4];"
        : "=r"(r[0]), "=r"(r[1]), "=r"(r[2]), "=r"(r[3]) : "r"(addr));
}
__device__ __forceinline__ void mma16816(float* d, const uint32_t* a, const uint32_t* b){
    asm volatile("mma.sync.aligned.m16n8k16.row.col.f32.f16.f16.f32 "
        "{%0,%1,%2,%3}, {%4,%5,%6,%7}, {%8,%9}, {%0,%1,%2,%3};"
        : "+f"(d[0]), "+f"(d[1]), "+f"(d[2]), "+f"(d[3])
        : "r"(a[0]), "r"(a[1]), "r"(a[2]), "r"(a[3]), "r"(b[0]), "r"(b[1]));
}
__device__ __forceinline__ void packpair(float x, float y, uint32_t& hi, uint32_t& lo){
    __half hx = __float2half_rn(x), hy = __float2half_rn(y);
    __half2 h; h.x = hx; h.y = hy;
    __half2 l;
    l.x = __float2half_rn(x - __half2float(hx));
    l.y = __float2half_rn(y - __half2float(hy));
    hi = *(uint32_t*)&h; lo = *(uint32_t*)&l;
}
__device__ __forceinline__ uint32_t packhi(float x, float y){
    __half2 h; h.x = __float2half_rn(x); h.y = __float2half_rn(y);
    return *(uint32_t*)&h;
}
__device__ __forceinline__ float2 unpackpair(uint32_t hi, uint32_t lo){
    __half2 h = *(__half2*)&hi, l = *(__half2*)&lo;
    float2 r;
    r.x = __half2float(h.x) + __half2float(l.x);
    r.y = __half2float(h.y) + __half2float(l.y);
    return r;
}

// ======================= scratch =======================
__device__ float g_pS [4][Bn];
__device__ float g_pS2[4][Bn];
__device__ __half g_pA [2][Mn*Dn];
__device__ __half g_pX2[2][Mn*Dn];
__device__ __half g_pX1[2][Mn*Dn];
__device__ __half g_qkv[4][Mn*Dn];
__device__ __half g_w[8][Dn*Dn];

// ======================= weight prep + LN-partial zeroing =======================
__global__ void prep_weights(const float* __restrict__ pw_w,
                             const float* __restrict__ wq, const float* __restrict__ wk,
                             const float* __restrict__ wv,
                             const float* __restrict__ fc_w, const float* __restrict__ out_w)
{
    if (blockIdx.x == 0 && threadIdx.x < 4*Bn) {
        (&g_pS[0][0])[threadIdx.x]  = 0.f;
        (&g_pS2[0][0])[threadIdx.x] = 0.f;
    }
    int task = blockIdx.x >> 10;
    int idx  = (blockIdx.x & 1023) * 256 + threadIdx.x;
    if (task < 3) {
        g_w[task][idx] = __float2half_rn(pw_w[(size_t)task*Dn*Dn + idx]);
    } else if (task == 3) {
        int n = idx >> 9, d = idx & 511;
        int src = (n >> 6) * (Dn * DHn) + d * DHn + (n & 63);
        g_w[3][idx] = __float2half_rn(wq[src]);
        g_w[4][idx] = __float2half_rn(wk[src]);
        g_w[5][idx] = __float2half_rn(wv[src]);
    } else if (task == 4) {
        g_w[6][idx] = __float2half_rn(fc_w[idx]);
    } else {
        g_w[7][idx] = __float2half_rn(out_w[idx]);
    }
}

// ======================= sliding-window depthwise conv (TLC=4) =======================
__global__ void dwconv_pe(const float* __restrict__ x, const float* __restrict__ pe,
                          const float* __restrict__ w, const float* __restrict__ bias,
                          __half* __restrict__ hi, __half* __restrict__ lo)
{
    int idx = blockIdx.x * 256 + threadIdx.x;      // over Bn*(Ln/4)*(Dn/4) = 524288
    int d  = (idx & 127) << 2;
    int l0 = ((idx >> 7) & 127) << 2;
    int b  = idx >> 14;

    float wr[4][Kn];
#pragma unroll
    for (int c = 0; c < 4; c++)
#pragma unroll
        for (int kk = 0; kk < Kn; kk++) wr[c][kk] = w[(d + c)*Kn + kk];

    float4 bs = *(const float4*)(bias + d);
    float4 acc[TLC];
#pragma unroll
    for (int j = 0; j < TLC; j++) acc[j] = bs;

#pragma unroll
    for (int i = 0; i < TLC + 6; i++){
        int ll = l0 - 3 + i;
        if (ll >= 0 && ll < Ln){
            float4 xv = *(const float4*)(x + ((size_t)(b*Ln + ll))*Dn + d);
            float4 pv = *(const float4*)(pe + (size_t)ll*Dn + d);
            xv.x += pv.x; xv.y += pv.y; xv.z += pv.z; xv.w += pv.w;
#pragma unroll
            for (int kk = 0; kk < Kn; kk++){
                int j = i - kk;
                if (j >= 0 && j < TLC){
                    acc[j].x = fmaf(xv.x, wr[0][kk], acc[j].x);
                    acc[j].y = fmaf(xv.y, wr[1][kk], acc[j].y);
                    acc[j].z = fmaf(xv.z, wr[2][kk], acc[j].z);
                    acc[j].w = fmaf(xv.w, wr[3][kk], acc[j].w);
                }
            }
        }
    }
#pragma unroll
    for (int j = 0; j < TLC; j++){
        float vx = fmaxf(acc[j].x, 0.f), vy = fmaxf(acc[j].y, 0.f);
        float vz = fmaxf(acc[j].z, 0.f), vw = fmaxf(acc[j].w, 0.f);
        size_t o = ((size_t)(b*Ln + l0 + j))*Dn + d;
        uint32_t h0, lw0, h1, lw1;
        packpair(vx, vy, h0, lw0);
        packpair(vz, vw, h1, lw1);
        uint2 hv; hv.x = h0;  hv.y = h1;
        uint2 lv; lv.x = lw0; lv.y = lw1;
        *(uint2*)(hi + o) = hv;
        *(uint2*)(lo + o) = lv;
    }
}

__global__ void dwconv_pair(const __half* __restrict__ xh, const __half* __restrict__ xl,
                            const float* __restrict__ w, const float* __restrict__ bias,
                            __half* __restrict__ hi, __half* __restrict__ lo)
{
    int idx = blockIdx.x * 256 + threadIdx.x;
    int d  = (idx & 127) << 2;
    int l0 = ((idx >> 7) & 127) << 2;
    int b  = idx >> 14;

    float wr[4][Kn];
#pragma unroll
    for (int c = 0; c < 4; c++)
#pragma unroll
        for (int kk = 0; kk < Kn; kk++) wr[c][kk] = w[(d + c)*Kn + kk];

    float4 bs = *(const float4*)(bias + d);
    float4 acc[TLC];
#pragma unroll
    for (int j = 0; j < TLC; j++) acc[j] = bs;

#pragma unroll
    for (int i = 0; i < TLC + 6; i++){
        int ll = l0 - 3 + i;
        if (ll >= 0 && ll < Ln){
            size_t base = ((size_t)(b*Ln + ll))*Dn + d;
            uint2 hv = *(const uint2*)(xh + base);
            uint2 lv = *(const uint2*)(xl + base);
            float2 a0 = unpackpair(hv.x, lv.x);
            float2 a1 = unpackpair(hv.y, lv.y);
            float4 xv; xv.x = a0.x; xv.y = a0.y; xv.z = a1.x; xv.w = a1.y;
#pragma unroll
            for (int kk = 0; kk < Kn; kk++){
                int j = i - kk;
                if (j >= 0 && j < TLC){
                    acc[j].x = fmaf(xv.x, wr[0][kk], acc[j].x);
                    acc[j].y = fmaf(xv.y, wr[1][kk], acc[j].y);
                    acc[j].z = fmaf(xv.z, wr[2][kk], acc[j].z);
                    acc[j].w = fmaf(xv.w, wr[3][kk], acc[j].w);
                }
            }
        }
    }
#pragma unroll
    for (int j = 0; j < TLC; j++){
        float vx = fmaxf(acc[j].x, 0.f), vy = fmaxf(acc[j].y, 0.f);
        float vz = fmaxf(acc[j].z, 0.f), vw = fmaxf(acc[j].w, 0.f);
        size_t o = ((size_t)(b*Ln + l0 + j))*Dn + d;
        uint32_t h0, lw0, h1, lw1;
        packpair(vx, vy, h0, lw0);
        packpair(vz, vw, h1, lw1);
        uint2 hv; hv.x = h0;  hv.y = h1;
        uint2 lv; lv.x = lw0; lv.y = lw1;
        *(uint2*)(hi + o) = hv;
        *(uint2*)(lo + o) = lv;
    }
}

// ======================= mma.sync GEMM (fp16 2-term, 3-stage pipeline) =======================
template<bool RELU, int LNIN, int LNOUT, bool SPL, bool WRITEC>
__global__ __launch_bounds__(256, 2) void gemm_mma(
    const __half* __restrict__ Ahi, const __half* __restrict__ Alo,
    const __half* __restrict__ Whi,
    const float* __restrict__ bias, float* __restrict__ C,
    const __half* __restrict__ Rhi, const __half* __restrict__ Rlo,
    const float* __restrict__ lng, const float* __restrict__ lnb,
    __half* __restrict__ Chi, __half* __restrict__ Clo)
{
    extern __shared__ __align__(16) char dsm[];
    const uint32_t sb = smem_u32(dsm);
    const int tid = threadIdx.x;
    const int wid = tid >> 5, lane = tid & 31;
    const int warpRow = wid >> 2, warpCol = wid & 3;
    const int bx = blockIdx.x, by = blockIdx.y;

    const __half* srcs[3] = {Ahi, Alo, Whi};
    const int rowb[3] = { by*128, by*128, bx*128 };

    auto PREF = [&](int kt){
        uint32_t bufb = sb + (uint32_t)(kt % 3) * BUFB;
#pragma unroll
        for (int t = 0; t < 3; t++){
            const __half* src = srcs[t] + (size_t)rowb[t]*Dn + kt*BK;
            uint32_t tb = bufb + (uint32_t)t*TB;
#pragma unroll
            for (int i = 0; i < 2; i++){
                int id  = tid + i*256;
                int row = id >> 2, c = id & 3;
                cpasync16(tb + (uint32_t)(row*(PITCH*2) + c*16),
                          src + (size_t)row*Dn + c*8);
            }
        }
        CP_COMMIT();
    };

    float acc[4][4][4];
#pragma unroll
    for (int i = 0; i < 4; i++)
#pragma unroll
        for (int j = 0; j < 4; j++)
#pragma unroll
            for (int q = 0; q < 4; q++) acc[i][j][q] = 0.f;

    const uint32_t aRow = (uint32_t)(warpRow*64 + (lane & 15));
    const uint32_t aColB = (uint32_t)(((lane >> 4) << 4));
    const uint32_t bRow = (uint32_t)(warpCol*32 + (lane & 7) + ((lane >> 4) << 3));
    const uint32_t bColB = (uint32_t)((((lane >> 3) & 1) << 4));

    PREF(0);
    PREF(1);
#pragma unroll 1
    for (int kt = 0; kt < Dn/BK; kt++){
        if (kt + 1 < Dn/BK) { CP_WAIT(1); } else { CP_WAIT(0); }
        __syncthreads();
        if (kt + 2 < Dn/BK) PREF(kt + 2);

        uint32_t bufb = sb + (uint32_t)(kt % 3) * BUFB;
        uint32_t tAhi = bufb, tAlo = bufb + TB, tWhi = bufb + 2*TB;
#pragma unroll
        for (int kk = 0; kk < 2; kk++){
            uint32_t ah[4][4], al[4][4], bh[2][4];
#pragma unroll
            for (int mi = 0; mi < 4; mi++){
                ldsm4(ah[mi], tAhi + (aRow + mi*16)*(PITCH*2) + aColB + kk*32);
                ldsm4(al[mi], tAlo + (aRow + mi*16)*(PITCH*2) + aColB + kk*32);
            }
#pragma unroll
            for (int nt = 0; nt < 2; nt++)
                ldsm4(bh[nt], tWhi + (bRow + nt*16)*(PITCH*2) + bColB + kk*32);
#pragma unroll
            for (int mi = 0; mi < 4; mi++)
#pragma unroll
                for (int nj = 0; nj < 4; nj++){
                    mma16816(acc[mi][nj], ah[mi], &bh[nj >> 1][(nj & 1) << 1]);
                    mma16816(acc[mi][nj], al[mi], &bh[nj >> 1][(nj & 1) << 1]);
                }
        }
    }

    float muv = 0.f, rsv = 0.f;
    if (LNIN >= 0) {
        int bb = (by*128) >> 9;
        float s = g_pS[LNIN][bb], s2 = g_pS2[LNIN][bb];
        muv = s * LDINV;
        rsv = rsqrtf(s2 * LDINV - muv*muv + 1e-5f);
    }
    const int r0base = by*128 + warpRow*64;
    const int c0base = bx*128 + warpCol*32;
    float ts = 0.f, ts2 = 0.f;
#pragma unroll
    for (int mi = 0; mi < 4; mi++){
#pragma unroll
        for (int rp = 0; rp < 2; rp++){
            int grow = r0base + mi*16 + (lane >> 2) + rp*8;
            int lrow = grow & (Ln - 1);
#pragma unroll
            for (int nj = 0; nj < 4; nj++){
                int col = c0base + nj*8 + (lane & 3)*2;
                float vx = acc[mi][nj][rp*2 + 0];
                float vy = acc[mi][nj][rp*2 + 1];
                float2 bs = *(const float2*)(bias + col);
                vx += bs.x; vy += bs.y;
                if (RELU) { vx = fmaxf(vx, 0.f); vy = fmaxf(vy, 0.f); }
                size_t off = (size_t)grow*Dn + col;
                if (LNIN >= 0) {
                    float2 rr = unpackpair(*(const uint32_t*)(Rhi + off),
                                           *(const uint32_t*)(Rlo + off));
                    float2 gg = *(const float2*)(lng + (size_t)lrow*Dn + col);
                    float2 bb = *(const float2*)(lnb + (size_t)lrow*Dn + col);
                    vx += (rr.x - muv)*rsv*gg.x + bb.x;
                    vy += (rr.y - muv)*rsv*gg.y + bb.y;
                }
                if (LNOUT >= 0) { ts += vx + vy; ts2 += vx*vx + vy*vy; }
                if (WRITEC) {
                    float2 o; o.x = vx; o.y = vy;
                    *(float2*)(C + off) = o;
                }
                if (SPL) {
                    uint32_t hi, lo;
                    packpair(vx, vy, hi, lo);
                    *(uint32_t*)(Chi + off) = hi;
                    *(uint32_t*)(Clo + off) = lo;
                }
            }
        }
    }
    if (LNOUT >= 0) {
#pragma unroll
        for (int o = 16; o > 0; o >>= 1){
            ts  += __shfl_xor_sync(0xffffffffu, ts,  o);
            ts2 += __shfl_xor_sync(0xffffffffu, ts2, o);
        }
        __shared__ float sred[2][8];
        if (lane == 0){ sred[0][wid] = ts; sred[1][wid] = ts2; }
        __syncthreads();
        if (tid == 0){
            float a = 0.f, b2 = 0.f;
#pragma unroll
            for (int i = 0; i < 8; i++){ a += sred[0][i]; b2 += sred[1][i]; }
            int batch = by >> 2;
            atomicAdd(&g_pS[LNOUT][batch],  a);
            atomicAdd(&g_pS2[LNOUT][batch], b2);
        }
    }
}

// ======================= merged qkv GEMM (N=1536, 3-stage pipeline) =======================
__global__ __launch_bounds__(256, 2) void gemm_qkv(
    const __half* __restrict__ Ahi, const __half* __restrict__ Alo,
    const float* __restrict__ bq, const float* __restrict__ bk, const float* __restrict__ bv)
{
    extern __shared__ __align__(16) char dsm[];
    const uint32_t sb = smem_u32(dsm);
    const int tid = threadIdx.x;
    const int wid = tid >> 5, lane = tid & 31;
    const int warpRow = wid >> 2, warpCol = wid & 3;
    const int bx = blockIdx.x, by = blockIdx.y;
    const int seg = bx >> 2, bxl = bx & 3;

    const __half* Whi = g_w[3 + seg];
    const float* bias = (seg == 0) ? bq : ((seg == 1) ? bk : bv);
    __half* Ch = (seg == 0) ? g_qkv[0] : ((seg == 1) ? g_qkv[2] : g_qkv[3]);
    __half* Cl = g_qkv[1];

    const __half* srcs[3] = {Ahi, Alo, Whi};
    const int rowb[3] = { by*128, by*128, bxl*128 };

    auto PREF = [&](int kt){
        uint32_t bufb = sb + (uint32_t)(kt % 3) * BUFB;
#pragma unroll
        for (int t = 0; t < 3; t++){
            const __half* src = srcs[t] + (size_t)rowb[t]*Dn + kt*BK;
            uint32_t tb = bufb + (uint32_t)t*TB;
#pragma unroll
            for (int i = 0; i < 2; i++){
                int id  = tid + i*256;
                int row = id >> 2, c = id & 3;
                cpasync16(tb + (uint32_t)(row*(PITCH*2) + c*16),
                          src + (size_t)row*Dn + c*8);
            }
        }
        CP_COMMIT();
    };

    float acc[4][4][4];
#pragma unroll
    for (int i = 0; i < 4; i++)
#pragma unroll
        for (int j = 0; j < 4; j++)
#pragma unroll
            for (int q = 0; q < 4; q++) acc[i][j][q] = 0.f;

    const uint32_t aRow = (uint32_t)(warpRow*64 + (lane & 15));
    const uint32_t aColB = (uint32_t)(((lane >> 4) << 4));
    const uint32_t bRow = (uint32_t)(warpCol*32 + (lane & 7) + ((lane >> 4) << 3));
    const uint32_t bColB = (uint32_t)((((lane >> 3) & 1) << 4));

    PREF(0);
    PREF(1);
#pragma unroll 1
    for (int kt = 0; kt < Dn/BK; kt++){
        if (kt + 1 < Dn/BK) { CP_WAIT(1); } else { CP_WAIT(0); }
        __syncthreads();
        if (kt + 2 < Dn/BK) PREF(kt + 2);

        uint32_t bufb = sb + (uint32_t)(kt % 3) * BUFB;
        uint32_t tAhi = bufb, tAlo = bufb + TB, tWhi = bufb + 2*TB;
#pragma unroll
        for (int kk = 0; kk < 2; kk++){
            uint32_t ah[4][4], al[4][4], bh[2][4];
#pragma unroll
            for (int mi = 0; mi < 4; mi++){
                ldsm4(ah[mi], tAhi + (aRow + mi*16)*(PITCH*2) + aColB + kk*32);
                ldsm4(al[mi], tAlo + (aRow + mi*16)*(PITCH*2) + aColB + kk*32);
            }
#pragma unroll
            for (int nt = 0; nt < 2; nt++)
                ldsm4(bh[nt], tWhi + (bRow + nt*16)*(PITCH*2) + bColB + kk*32);
#pragma unroll
            for (int mi = 0; mi < 4; mi++)
#pragma unroll
                for (int nj = 0; nj < 4; nj++){
                    mma16816(acc[mi][nj], ah[mi], &bh[nj >> 1][(nj & 1) << 1]);
                    mma16816(acc[mi][nj], al[mi], &bh[nj >> 1][(nj & 1) << 1]);
                }
        }
    }

    const int r0base = by*128 + warpRow*64;
    const int c0base = bxl*128 + warpCol*32;
    const bool wlo = (seg == 0);
#pragma unroll
    for (int mi = 0; mi < 4; mi++){
#pragma unroll
        for (int rp = 0; rp < 2; rp++){
            int grow = r0base + mi*16 + (lane >> 2) + rp*8;
#pragma unroll
            for (int nj = 0; nj < 4; nj++){
                int col = c0base + nj*8 + (lane & 3)*2;
                float vx = acc[mi][nj][rp*2 + 0];
                float vy = acc[mi][nj][rp*2 + 1];
                float2 bs = *(const float2*)(bias + col);
                vx += bs.x; vy += bs.y;
                size_t off = (size_t)grow*Dn + col;
                uint32_t hi, lo;
                packpair(vx, vy, hi, lo);
                *(uint32_t*)(Ch + off) = hi;
                if (wlo) *(uint32_t*)(Cl + off) = lo;
            }
        }
    }
}

// ======================= fused flash attention (QK 2-term, PV 1-term) =======================
__global__ __launch_bounds__(256, 1) void attn_fused(
    const __half* __restrict__ qh, const __half* __restrict__ ql,
    const __half* __restrict__ kh, const __half* __restrict__ vh,
    const float* __restrict__ mask,
    __half* __restrict__ Ohi, __half* __restrict__ Olo)
{
    extern __shared__ __align__(16) char dsm[];
    const uint32_t sb = smem_u32(dsm);
    const int tid = threadIdx.x, wid = tid >> 5, lane = tid & 31;
    const int bh = blockIdx.y, b = bh >> 3, h = bh & 7;
    const int i0 = blockIdx.x * 128;
    const size_t qoff = ((size_t)(b*Ln + i0))*Dn + h*DHn;
    const size_t koff = ((size_t)(b*Ln))*Dn + h*DHn;

    const uint32_t smQh = sb, smQl = sb + QT;
    const uint32_t smKV0 = sb + 2*QT;
    const uint32_t smMaskOff = 2*QT + 2*KVB;

    auto LOADC = [&](int c){
        uint32_t base = smKV0 + (uint32_t)(c & 1)*KVB;
        size_t g0 = koff + (size_t)(c*128)*Dn;
#pragma unroll
        for (int i = 0; i < 4; i++){
            int id = tid + i*256; int row = id >> 3, seg = id & 7;
            size_t go = g0 + (size_t)row*Dn + seg*8;
            uint32_t so = (uint32_t)(row*AP + seg*16);
            cpasync16(base + so,      kh + go);
            cpasync16(base + QT + so, vh + go);
        }
        if (tid < 32)
            cpasync16(sb + smMaskOff + (uint32_t)(c & 1)*512 + tid*16,
                      mask + b*Ln + c*128 + tid*4);
        CP_COMMIT();
    };

#pragma unroll
    for (int i = 0; i < 4; i++){
        int id = tid + i*256; int row = id >> 3, seg = id & 7;
        size_t go = qoff + (size_t)row*Dn + seg*8;
        uint32_t so = (uint32_t)(row*AP + seg*16);
        cpasync16(smQh + so, qh + go);
        cpasync16(smQl + so, ql + go);
    }
    LOADC(0);
    LOADC(1);

    const int g = lane >> 2, t4 = lane & 3;
    float mi0 = mask[b*Ln + i0 + wid*16 + g];
    float mi1 = mask[b*Ln + i0 + wid*16 + g + 8];

    float m0 = -3.0e38f, m1 = -3.0e38f, l0 = 0.f, l1 = 0.f;
    float o[8][4];
#pragma unroll
    for (int i = 0; i < 8; i++)
#pragma unroll
        for (int j = 0; j < 4; j++) o[i][j] = 0.f;

    const uint32_t aQoff = (uint32_t)((wid*16 + (lane & 15))*AP + ((lane >> 4) << 4));
    const uint32_t bKoff = (uint32_t)(((lane & 7) + ((lane >> 4) << 3))*AP + (((lane >> 3) & 1) << 4));
    const uint32_t vOff  = (uint32_t)((lane & 15)*AP + ((lane >> 4) << 4));

#pragma unroll 1
    for (int c = 0; c < 4; c++){
        if (c < 3) { CP_WAIT(1); } else { CP_WAIT(0); }
        __syncthreads();
        const uint32_t kb = smKV0 + (uint32_t)(c & 1)*KVB;
        const float* mjp = (const float*)(dsm + smMaskOff + (c & 1)*512);

        float s[16][4];
#pragma unroll
        for (int nj = 0; nj < 16; nj++)
#pragma unroll
            for (int q = 0; q < 4; q++) s[nj][q] = 0.f;
#pragma unroll
        for (int ss = 0; ss < 4; ss++){
            uint32_t ah[4], al[4];
            ldsm4(ah, smQh + aQoff + ss*32);
            ldsm4(al, smQl + aQoff + ss*32);
#pragma unroll
            for (int njp = 0; njp < 8; njp++){
                uint32_t bhh[4];
                ldsm4(bhh, kb + (uint32_t)(njp*16)*AP + bKoff + ss*32);
                mma16816(s[2*njp],   ah, &bhh[0]);
                mma16816(s[2*njp],   al, &bhh[0]);
                mma16816(s[2*njp+1], ah, &bhh[2]);
                mma16816(s[2*njp+1], al, &bhh[2]);
            }
        }

        float rm0 = -3.0e38f, rm1 = -3.0e38f;
#pragma unroll
        for (int nj = 0; nj < 16; nj++){
            int colb = nj*8 + t4*2;
            float mj0 = mjp[colb], mj1 = mjp[colb+1];
            float mm;
            mm = mi0*mj0; s[nj][0] = s[nj][0]*0.125f*mm + NEGV*(1.f - mm);
            mm = mi0*mj1; s[nj][1] = s[nj][1]*0.125f*mm + NEGV*(1.f - mm);
            mm = mi1*mj0; s[nj][2] = s[nj][2]*0.125f*mm + NEGV*(1.f - mm);
            mm = mi1*mj1; s[nj][3] = s[nj][3]*0.125f*mm + NEGV*(1.f - mm);
            rm0 = fmaxf(rm0, fmaxf(s[nj][0], s[nj][1]));
            rm1 = fmaxf(rm1, fmaxf(s[nj][2], s[nj][3]));
        }
        rm0 = fmaxf(rm0, __shfl_xor_sync(0xffffffffu, rm0, 1));
        rm0 = fmaxf(rm0, __shfl_xor_sync(0xffffffffu, rm0, 2));
        rm1 = fmaxf(rm1, __shfl_xor_sync(0xffffffffu, rm1, 1));
        rm1 = fmaxf(rm1, __shfl_xor_sync(0xffffffffu, rm1, 2));
        float nm0 = fmaxf(m0, rm0), nm1 = fmaxf(m1, rm1);
        float al0 = __expf(m0 - nm0), al1 = __expf(m1 - nm1);
        m0 = nm0; m1 = nm1;
#pragma unroll
        for (int nd = 0; nd < 8; nd++){
            o[nd][0] *= al0; o[nd][1] *= al0;
            o[nd][2] *= al1; o[nd][3] *= al1;
        }

        float sum0 = 0.f, sum1 = 0.f;
#pragma unroll
        for (int ss = 0; ss < 8; ss++){
            float p00 = __expf(s[2*ss][0]   - nm0), p01 = __expf(s[2*ss][1]   - nm0);
            float p02 = __expf(s[2*ss][2]   - nm1), p03 = __expf(s[2*ss][3]   - nm1);
            float p10 = __expf(s[2*ss+1][0] - nm0), p11 = __expf(s[2*ss+1][1] - nm0);
            float p12 = __expf(s[2*ss+1][2] - nm1), p13 = __expf(s[2*ss+1][3] - nm1);
            sum0 += p00 + p01 + p10 + p11;
            sum1 += p02 + p03 + p12 + p13;
            uint32_t pah[4];
            pah[0] = packhi(p00, p01);
            pah[1] = packhi(p02, p03);
            pah[2] = packhi(p10, p11);
            pah[3] = packhi(p12, p13);
#pragma unroll
            for (int ndp = 0; ndp < 4; ndp++){
                uint32_t vhh[4];
                ldsm4t(vhh, kb + QT + (uint32_t)(ss*16)*AP + vOff + ndp*32);
                mma16816(o[2*ndp],   pah, &vhh[0]);
                mma16816(o[2*ndp+1], pah, &vhh[2]);
            }
        }
        sum0 += __shfl_xor_sync(0xffffffffu, sum0, 1);
        sum0 += __shfl_xor_sync(0xffffffffu, sum0, 2);
        sum1 += __shfl_xor_sync(0xffffffffu, sum1, 1);
        sum1 += __shfl_xor_sync(0xffffffffu, sum1, 2);
        l0 = l0*al0 + sum0;
        l1 = l1*al1 + sum1;

        if (c < 2){ __syncthreads(); LOADC(c + 2); }
    }

    float inv0 = 1.f / l0, inv1 = 1.f / l1;
    int r0 = i0 + wid*16 + g, r1 = r0 + 8;
    size_t ob = ((size_t)(b*Ln))*Dn + h*DHn;
#pragma unroll
    for (int nd = 0; nd < 8; nd++){
        int col = nd*8 + t4*2;
        uint32_t hi0, lo0, hi1, lo1;
        packpair(o[nd][0]*inv0, o[nd][1]*inv0, hi0, lo0);
        packpair(o[nd][2]*inv1, o[nd][3]*inv1, hi1, lo1);
        *(uint32_t*)(Ohi + ob + (size_t)r0*Dn + col) = hi0;
        *(uint32_t*)(Olo + ob + (size_t)r0*Dn + col) = lo0;
        *(uint32_t*)(Ohi + ob + (size_t)r1*Dn + col) = hi1;
        *(uint32_t*)(Olo + ob + (size_t)r1*Dn + col) = lo1;
    }
}

// ======================= host orchestration =======================
extern "C" void kernel_launch(void* const* d_in, const int* in_sizes, int n_in,
                              void* d_out, int out_size)
{
    (void)in_sizes; (void)n_in; (void)out_size;
    const float* x     = (const float*)d_in[0];
    const float* mask  = (const float*)d_in[1];
    const float* pe    = (const float*)d_in[2];
    const float* dw_w  = (const float*)d_in[3];
    const float* dw_b  = (const float*)d_in[4];
    const float* pw_w  = (const float*)d_in[5];
    const float* pw_b  = (const float*)d_in[6];
    const float* wq    = (const float*)d_in[7];
    const float* bq    = (const float*)d_in[8];
    const float* wk    = (const float*)d_in[9];
    const float* bk    = (const float*)d_in[10];
    const float* wv    = (const float*)d_in[11];
    const float* bv    = (const float*)d_in[12];
    const float* fc_w  = (const float*)d_in[13];
    const float* fc_b  = (const float*)d_in[14];
    const float* out_w = (const float*)d_in[15];
    const float* out_b = (const float*)d_in[16];
    const float* lnc_g = (const float*)d_in[17];
    const float* lnc_b = (const float*)d_in[18];
    const float* lna_g = (const float*)d_in[19];
    const float* lna_b = (const float*)d_in[20];
    const float* lno_g = (const float*)d_in[21];
    const float* lno_b = (const float*)d_in[22];
    float* out = (float*)d_out;

    __half *pA, *pX2, *pX1, *qkv;
    cudaGetSymbolAddress((void**)&pA,  g_pA);
    cudaGetSymbolAddress((void**)&pX2, g_pX2);
    cudaGetSymbolAddress((void**)&pX1, g_pX1);
    cudaGetSymbolAddress((void**)&qkv, g_qkv);
    __half* wsym;
    cudaGetSymbolAddress((void**)&wsym, g_w);

    const size_t NN = (size_t)Mn*Dn;
    __half *pA_h = pA,  *pA_l = pA + NN;
    __half *x2_h = pX2, *x2_l = pX2 + NN;
    __half *x1_h = pX1, *x1_l = pX1 + NN;
    __half *q_h = qkv, *q_l = qkv + NN, *k_h = qkv + 2*NN, *v_h = qkv + 3*NN;
    auto W = [&](int i){ return wsym + (size_t)i * Dn * Dn; };

    cudaFuncSetAttribute(gemm_mma<true,-1,0,true,false>,  cudaFuncAttributeMaxDynamicSharedMemorySize, SMEM_SZ);
    cudaFuncSetAttribute(gemm_mma<true,0,1,true,false>,   cudaFuncAttributeMaxDynamicSharedMemorySize, SMEM_SZ);
    cudaFuncSetAttribute(gemm_mma<true,1,2,true,false>,   cudaFuncAttributeMaxDynamicSharedMemorySize, SMEM_SZ);
    cudaFuncSetAttribute(gemm_mma<false,2,3,true,false>,  cudaFuncAttributeMaxDynamicSharedMemorySize, SMEM_SZ);
    cudaFuncSetAttribute(gemm_mma<false,3,-1,false,true>, cudaFuncAttributeMaxDynamicSharedMemorySize, SMEM_SZ);
    cudaFuncSetAttribute(gemm_qkv, cudaFuncAttributeMaxDynamicSharedMemorySize, SMEM_SZ);
    cudaFuncSetAttribute(attn_fused, cudaFuncAttributeMaxDynamicSharedMemorySize, SMEM_ATT);

    const int DWB = (Bn * (Ln/TLC) * (Dn/4)) / 256;   // 2048 blocks
    dim3 gemmGrid(Dn/128, Mn/128);      // (4, 128)
    dim3 qkvGrid(12, Mn/128);           // N = 1536

    // 1. weight prep + LN-partial zeroing
    prep_weights<<<6*1024, 256>>>(pw_w, wq, wk, wv, fc_w, out_w);

    // 2-3. conv layer 0 (PE fused); stats -> slot 0 (lnc0)
    dwconv_pe<<<DWB, 256>>>(x, pe, dw_w + 0*Dn*Kn, dw_b + 0*Dn, pA_h, pA_l);
    gemm_mma<true,-1,0,true,false><<<gemmGrid, 256, SMEM_SZ>>>(
        pA_h, pA_l, W(0), pw_b + 0*Dn, nullptr,
        nullptr, nullptr, nullptr, nullptr, x2_h, x2_l);
    // 4-5. conv layer 1: + LN(x2; lnc0, slot 0); stats -> slot 1 (lnc1)
    dwconv_pair<<<DWB, 256>>>(x2_h, x2_l, dw_w + 1*Dn*Kn, dw_b + 1*Dn, pA_h, pA_l);
    gemm_mma<true,0,1,true,false><<<gemmGrid, 256, SMEM_SZ>>>(
        pA_h, pA_l, W(1), pw_b + 1*Dn, nullptr,
        x2_h, x2_l, lnc_g + 0, lnc_b + 0, x1_h, x1_l);
    // 6-7. conv layer 2: + LN(x1; lnc1, slot 1); stats -> slot 2 (lna)
    dwconv_pair<<<DWB, 256>>>(x1_h, x1_l, dw_w + 2*Dn*Kn, dw_b + 2*Dn, pA_h, pA_l);
    gemm_mma<true,1,2,true,false><<<gemmGrid, 256, SMEM_SZ>>>(
        pA_h, pA_l, W(2), pw_b + 2*Dn, nullptr,
        x1_h, x1_l, lnc_g + Ln*Dn, lnc_b + Ln*Dn, x2_h, x2_l);

    // 8. merged qkv projection
    gemm_qkv<<<qkvGrid, 256, SMEM_SZ>>>(x2_h, x2_l, bq, bk, bv);

    // 9. fused flash attention -> pA pair
    attn_fused<<<dim3(Ln/128, Bn*Hn), 256, SMEM_ATT>>>(
        q_h, q_l, k_h, v_h, mask, pA_h, pA_l);

    // 10. fc + LN(x2; lna, slot 2) -> x1 pair; stats -> slot 3 (lno)
    gemm_mma<false,2,3,true,false><<<gemmGrid, 256, SMEM_SZ>>>(
        pA_h, pA_l, W(6), fc_b, nullptr,
        x2_h, x2_l, lna_g, lna_b, x1_h, x1_l);

    // 11. out + LN(x1; lno, slot 3) -> d_out (fp32)
    gemm_mma<false,3,-1,false,true><<<gemmGrid, 256, SMEM_SZ>>>(
        x1_h, x1_l, W(7), out_b, out,
        x1_h, x1_l, lno_g, lno_b, nullptr, nullptr);
}

// round 12
// speedup vs baseline: 3.3060x; 1.0560x over previous
#include <cuda_runtime.h>
#include <cuda_fp16.h>
#include <cstdint>

#define Bn 32
#define Ln 512
#define Dn 512
#define Hn 8
#define DHn 64
#define Kn 7
#define Mn (Bn*Ln)
#define NEGV (-1e30f)
#define LDINV (1.0f/(float)(Ln*Dn))
#define TLC 8                       // L positions per dwconv thread (R10 proven)

// ---- big-GEMM tiling ----
#define BK 32
#define PITCH 40
#define TB (128*PITCH*2)
#define BUFB (3*TB)
#define SMEM_SZ (3*BUFB)            // 3-stage pipeline = 92160 B

// ---- fused attention smem ----
#define AP 144
#define QT (128*AP)
#define KVB (2*QT)
#define SMEM_ATT (2*QT + 2*KVB + 1024)

// ======================= PTX helpers =======================
__device__ __forceinline__ uint32_t smem_u32(const void* p){
    uint32_t a;
    asm("{ .reg .u64 t; cvta.to.shared.u64 t, %1; cvt.u32.u64 %0, t; }" : "=r"(a) : "l"(p));
    return a;
}
__device__ __forceinline__ void cpasync16(uint32_t dst, const void* src){
    asm volatile("cp.async.cg.shared.global [%0], [%1], 16;" :: "r"(dst), "l"(src) : "memory");
}
#define CP_COMMIT() asm volatile("cp.async.commit_group;" ::: "memory")
#define CP_WAIT(N)  asm volatile("cp.async.wait_group %0;" :: "n"(N) : "memory")
__device__ __forceinline__ void ldsm4(uint32_t* r, uint32_t addr){
    asm volatile("ldmatrix.sync.aligned.m8n8.x4.shared.b16 {%0,%1,%2,%3}, [%4];"
        : "=r"(r[0]), "=r"(r[1]), "=r"(r[2]), "=r"(r[3]) : "r"(addr));
}
__device__ __forceinline__ void ldsm4t(uint32_t* r, uint32_t addr){
    asm volatile("ldmatrix.sync.aligned.m8n8.x4.trans.shared.b16 {%0,%1,%2,%3}, [%4];"
        : "=r"(r[0]), "=r"(r[1]), "=r"(r[2]), "=r"(r[3]) : "r"(addr));
}
__device__ __forceinline__ void mma16816(float* d, const uint32_t* a, const uint32_t* b){
    asm volatile("mma.sync.aligned.m16n8k16.row.col.f32.f16.f16.f32 "
        "{%0,%1,%2,%3}, {%4,%5,%6,%7}, {%8,%9}, {%0,%1,%2,%3};"
        : "+f"(d[0]), "+f"(d[1]), "+f"(d[2]), "+f"(d[3])
        : "r"(a[0]), "r"(a[1]), "r"(a[2]), "r"(a[3]), "r"(b[0]), "r"(b[1]));
}
__device__ __forceinline__ void packpair(float x, float y, uint32_t& hi, uint32_t& lo){
    __half hx = __float2half_rn(x), hy = __float2half_rn(y);
    __half2 h; h.x = hx; h.y = hy;
    __half2 l;
    l.x = __float2half_rn(x - __half2float(hx));
    l.y = __float2half_rn(y - __half2float(hy));
    hi = *(uint32_t*)&h; lo = *(uint32_t*)&l;
}
__device__ __forceinline__ uint32_t packhi(float x, float y){
    __half2 h; h.x = __float2half_rn(x); h.y = __float2half_rn(y);
    return *(uint32_t*)&h;
}
__device__ __forceinline__ float2 unpackpair(uint32_t hi, uint32_t lo){
    __half2 h = *(__half2*)&hi, l = *(__half2*)&lo;
    float2 r;
    r.x = __half2float(h.x) + __half2float(l.x);
    r.y = __half2float(h.y) + __half2float(l.y);
    return r;
}

// ======================= scratch =======================
__device__ float g_pS [4][Bn];
__device__ float g_pS2[4][Bn];
__device__ __half g_pA [2][Mn*Dn];
__device__ __half g_pX2[2][Mn*Dn];
__device__ __half g_pX1[2][Mn*Dn];
__device__ __half g_qkv[4][Mn*Dn];
__device__ __half g_w[8][Dn*Dn];

// ======================= weight prep + LN-partial zeroing =======================
__global__ void prep_weights(const float* __restrict__ pw_w,
                             const float* __restrict__ wq, const float* __restrict__ wk,
                             const float* __restrict__ wv,
                             const float* __restrict__ fc_w, const float* __restrict__ out_w)
{
    if (blockIdx.x == 0 && threadIdx.x < 4*Bn) {
        (&g_pS[0][0])[threadIdx.x]  = 0.f;
        (&g_pS2[0][0])[threadIdx.x] = 0.f;
    }
    int task = blockIdx.x >> 10;
    int idx  = (blockIdx.x & 1023) * 256 + threadIdx.x;
    if (task < 3) {
        g_w[task][idx] = __float2half_rn(pw_w[(size_t)task*Dn*Dn + idx]);
    } else if (task == 3) {
        int n = idx >> 9, d = idx & 511;
        int src = (n >> 6) * (Dn * DHn) + d * DHn + (n & 63);
        g_w[3][idx] = __float2half_rn(wq[src]);
        g_w[4][idx] = __float2half_rn(wk[src]);
        g_w[5][idx] = __float2half_rn(wv[src]);
    } else if (task == 4) {
        g_w[6][idx] = __float2half_rn(fc_w[idx]);
    } else {
        g_w[7][idx] = __float2half_rn(out_w[idx]);
    }
}

// ======================= sliding-window depthwise conv (TLC=8) =======================
__global__ void dwconv_pe(const float* __restrict__ x, const float* __restrict__ pe,
                          const float* __restrict__ w, const float* __restrict__ bias,
                          __half* __restrict__ hi, __half* __restrict__ lo)
{
    int idx = blockIdx.x * 256 + threadIdx.x;      // over Bn*(Ln/8)*(Dn/4) = 262144
    int d  = (idx & 127) << 2;
    int l0 = ((idx >> 7) & 63) << 3;
    int b  = idx >> 13;

    float wr[4][Kn];
#pragma unroll
    for (int c = 0; c < 4; c++)
#pragma unroll
        for (int kk = 0; kk < Kn; kk++) wr[c][kk] = w[(d + c)*Kn + kk];

    float4 bs = *(const float4*)(bias + d);
    float4 acc[TLC];
#pragma unroll
    for (int j = 0; j < TLC; j++) acc[j] = bs;

#pragma unroll
    for (int i = 0; i < TLC + 6; i++){
        int ll = l0 - 3 + i;
        if (ll >= 0 && ll < Ln){
            float4 xv = *(const float4*)(x + ((size_t)(b*Ln + ll))*Dn + d);
            float4 pv = *(const float4*)(pe + (size_t)ll*Dn + d);
            xv.x += pv.x; xv.y += pv.y; xv.z += pv.z; xv.w += pv.w;
#pragma unroll
            for (int kk = 0; kk < Kn; kk++){
                int j = i - kk;
                if (j >= 0 && j < TLC){
                    acc[j].x = fmaf(xv.x, wr[0][kk], acc[j].x);
                    acc[j].y = fmaf(xv.y, wr[1][kk], acc[j].y);
                    acc[j].z = fmaf(xv.z, wr[2][kk], acc[j].z);
                    acc[j].w = fmaf(xv.w, wr[3][kk], acc[j].w);
                }
            }
        }
    }
#pragma unroll
    for (int j = 0; j < TLC; j++){
        float vx = fmaxf(acc[j].x, 0.f), vy = fmaxf(acc[j].y, 0.f);
        float vz = fmaxf(acc[j].z, 0.f), vw = fmaxf(acc[j].w, 0.f);
        size_t o = ((size_t)(b*Ln + l0 + j))*Dn + d;
        uint32_t h0, lw0, h1, lw1;
        packpair(vx, vy, h0, lw0);
        packpair(vz, vw, h1, lw1);
        uint2 hv; hv.x = h0;  hv.y = h1;
        uint2 lv; lv.x = lw0; lv.y = lw1;
        *(uint2*)(hi + o) = hv;
        *(uint2*)(lo + o) = lv;
    }
}

__global__ void dwconv_pair(const __half* __restrict__ xh, const __half* __restrict__ xl,
                            const float* __restrict__ w, const float* __restrict__ bias,
                            __half* __restrict__ hi, __half* __restrict__ lo)
{
    int idx = blockIdx.x * 256 + threadIdx.x;
    int d  = (idx & 127) << 2;
    int l0 = ((idx >> 7) & 63) << 3;
    int b  = idx >> 13;

    float wr[4][Kn];
#pragma unroll
    for (int c = 0; c < 4; c++)
#pragma unroll
        for (int kk = 0; kk < Kn; kk++) wr[c][kk] = w[(d + c)*Kn + kk];

    float4 bs = *(const float4*)(bias + d);
    float4 acc[TLC];
#pragma unroll
    for (int j = 0; j < TLC; j++) acc[j] = bs;

#pragma unroll
    for (int i = 0; i < TLC + 6; i++){
        int ll = l0 - 3 + i;
        if (ll >= 0 && ll < Ln){
            size_t base = ((size_t)(b*Ln + ll))*Dn + d;
            uint2 hv = *(const uint2*)(xh + base);
            uint2 lv = *(const uint2*)(xl + base);
            float2 a0 = unpackpair(hv.x, lv.x);
            float2 a1 = unpackpair(hv.y, lv.y);
            float4 xv; xv.x = a0.x; xv.y = a0.y; xv.z = a1.x; xv.w = a1.y;
#pragma unroll
            for (int kk = 0; kk < Kn; kk++){
                int j = i - kk;
                if (j >= 0 && j < TLC){
                    acc[j].x = fmaf(xv.x, wr[0][kk], acc[j].x);
                    acc[j].y = fmaf(xv.y, wr[1][kk], acc[j].y);
                    acc[j].z = fmaf(xv.z, wr[2][kk], acc[j].z);
                    acc[j].w = fmaf(xv.w, wr[3][kk], acc[j].w);
                }
            }
        }
    }
#pragma unroll
    for (int j = 0; j < TLC; j++){
        float vx = fmaxf(acc[j].x, 0.f), vy = fmaxf(acc[j].y, 0.f);
        float vz = fmaxf(acc[j].z, 0.f), vw = fmaxf(acc[j].w, 0.f);
        size_t o = ((size_t)(b*Ln + l0 + j))*Dn + d;
        uint32_t h0, lw0, h1, lw1;
        packpair(vx, vy, h0, lw0);
        packpair(vz, vw, h1, lw1);
        uint2 hv; hv.x = h0;  hv.y = h1;
        uint2 lv; lv.x = lw0; lv.y = lw1;
        *(uint2*)(hi + o) = hv;
        *(uint2*)(lo + o) = lv;
    }
}

// ======================= mma.sync GEMM (fp16 2-term, 4x2 warp layout) =======================
// warp tile 32x64: A (2-term) fragments small, B (1-term) fragments wide.
template<bool RELU, int LNIN, int LNOUT, bool SPL, bool WRITEC>
__global__ __launch_bounds__(256, 2) void gemm_mma(
    const __half* __restrict__ Ahi, const __half* __restrict__ Alo,
    const __half* __restrict__ Whi,
    const float* __restrict__ bias, float* __restrict__ C,
    const __half* __restrict__ Rhi, const __half* __restrict__ Rlo,
    const float* __restrict__ lng, const float* __restrict__ lnb,
    __half* __restrict__ Chi, __half* __restrict__ Clo)
{
    extern __shared__ __align__(16) char dsm[];
    const uint32_t sb = smem_u32(dsm);
    const int tid = threadIdx.x;
    const int wid = tid >> 5, lane = tid & 31;
    const int warpRow = wid & 3, warpCol = wid >> 2;   // 4x2
    const int bx = blockIdx.x, by = blockIdx.y;

    const __half* srcs[3] = {Ahi, Alo, Whi};
    const int rowb[3] = { by*128, by*128, bx*128 };

    auto PREF = [&](int kt){
        uint32_t bufb = sb + (uint32_t)(kt % 3) * BUFB;
#pragma unroll
        for (int t = 0; t < 3; t++){
            const __half* src = srcs[t] + (size_t)rowb[t]*Dn + kt*BK;
            uint32_t tb = bufb + (uint32_t)t*TB;
#pragma unroll
            for (int i = 0; i < 2; i++){
                int id  = tid + i*256;
                int row = id >> 2, c = id & 3;
                cpasync16(tb + (uint32_t)(row*(PITCH*2) + c*16),
                          src + (size_t)row*Dn + c*8);
            }
        }
        CP_COMMIT();
    };

    float acc[2][8][4];
#pragma unroll
    for (int i = 0; i < 2; i++)
#pragma unroll
        for (int j = 0; j < 8; j++)
#pragma unroll
            for (int q = 0; q < 4; q++) acc[i][j][q] = 0.f;

    const uint32_t aRow = (uint32_t)(warpRow*32 + (lane & 15));
    const uint32_t aColB = (uint32_t)(((lane >> 4) << 4));
    const uint32_t bRow = (uint32_t)(warpCol*64 + (lane & 7) + ((lane >> 4) << 3));
    const uint32_t bColB = (uint32_t)((((lane >> 3) & 1) << 4));

    PREF(0);
    PREF(1);
#pragma unroll 1
    for (int kt = 0; kt < Dn/BK; kt++){
        if (kt + 1 < Dn/BK) { CP_WAIT(1); } else { CP_WAIT(0); }
        __syncthreads();
        if (kt + 2 < Dn/BK) PREF(kt + 2);

        uint32_t bufb = sb + (uint32_t)(kt % 3) * BUFB;
        uint32_t tAhi = bufb, tAlo = bufb + TB, tWhi = bufb + 2*TB;
#pragma unroll
        for (int kk = 0; kk < 2; kk++){
            uint32_t ah[2][4], al[2][4], bh[4][4];
#pragma unroll
            for (int mi = 0; mi < 2; mi++){
                ldsm4(ah[mi], tAhi + (aRow + mi*16)*(PITCH*2) + aColB + kk*32);
                ldsm4(al[mi], tAlo + (aRow + mi*16)*(PITCH*2) + aColB + kk*32);
            }
#pragma unroll
            for (int nt = 0; nt < 4; nt++)
                ldsm4(bh[nt], tWhi + (bRow + nt*16)*(PITCH*2) + bColB + kk*32);
#pragma unroll
            for (int mi = 0; mi < 2; mi++)
#pragma unroll
                for (int nj = 0; nj < 8; nj++){
                    mma16816(acc[mi][nj], ah[mi], &bh[nj >> 1][(nj & 1) << 1]);
                    mma16816(acc[mi][nj], al[mi], &bh[nj >> 1][(nj & 1) << 1]);
                }
        }
    }

    float muv = 0.f, rsv = 0.f;
    if (LNIN >= 0) {
        int bb = (by*128) >> 9;
        float s = g_pS[LNIN][bb], s2 = g_pS2[LNIN][bb];
        muv = s * LDINV;
        rsv = rsqrtf(s2 * LDINV - muv*muv + 1e-5f);
    }
    const int r0base = by*128 + warpRow*32;
    const int c0base = bx*128 + warpCol*64;
    float ts = 0.f, ts2 = 0.f;
#pragma unroll
    for (int mi = 0; mi < 2; mi++){
#pragma unroll
        for (int rp = 0; rp < 2; rp++){
            int grow = r0base + mi*16 + (lane >> 2) + rp*8;
            int lrow = grow & (Ln - 1);
#pragma unroll
            for (int nj = 0; nj < 8; nj++){
                int col = c0base + nj*8 + (lane & 3)*2;
                float vx = acc[mi][nj][rp*2 + 0];
                float vy = acc[mi][nj][rp*2 + 1];
                float2 bs = *(const float2*)(bias + col);
                vx += bs.x; vy += bs.y;
                if (RELU) { vx = fmaxf(vx, 0.f); vy = fmaxf(vy, 0.f); }
                size_t off = (size_t)grow*Dn + col;
                if (LNIN >= 0) {
                    float2 rr = unpackpair(*(const uint32_t*)(Rhi + off),
                                           *(const uint32_t*)(Rlo + off));
                    float2 gg = *(const float2*)(lng + (size_t)lrow*Dn + col);
                    float2 bb = *(const float2*)(lnb + (size_t)lrow*Dn + col);
                    vx += (rr.x - muv)*rsv*gg.x + bb.x;
                    vy += (rr.y - muv)*rsv*gg.y + bb.y;
                }
                if (LNOUT >= 0) { ts += vx + vy; ts2 += vx*vx + vy*vy; }
                if (WRITEC) {
                    float2 o; o.x = vx; o.y = vy;
                    *(float2*)(C + off) = o;
                }
                if (SPL) {
                    uint32_t hi, lo;
                    packpair(vx, vy, hi, lo);
                    *(uint32_t*)(Chi + off) = hi;
                    *(uint32_t*)(Clo + off) = lo;
                }
            }
        }
    }
    if (LNOUT >= 0) {
#pragma unroll
        for (int o = 16; o > 0; o >>= 1){
            ts  += __shfl_xor_sync(0xffffffffu, ts,  o);
            ts2 += __shfl_xor_sync(0xffffffffu, ts2, o);
        }
        __shared__ float sred[2][8];
        if (lane == 0){ sred[0][wid] = ts; sred[1][wid] = ts2; }
        __syncthreads();
        if (tid == 0){
            float a = 0.f, b2 = 0.f;
#pragma unroll
            for (int i = 0; i < 8; i++){ a += sred[0][i]; b2 += sred[1][i]; }
            int batch = by >> 2;
            atomicAdd(&g_pS[LNOUT][batch],  a);
            atomicAdd(&g_pS2[LNOUT][batch], b2);
        }
    }
}

// ======================= merged qkv GEMM (N=1536, 4x2 warp layout) =======================
__global__ __launch_bounds__(256, 2) void gemm_qkv(
    const __half* __restrict__ Ahi, const __half* __restrict__ Alo,
    const float* __restrict__ bq, const float* __restrict__ bk, const float* __restrict__ bv)
{
    extern __shared__ __align__(16) char dsm[];
    const uint32_t sb = smem_u32(dsm);
    const int tid = threadIdx.x;
    const int wid = tid >> 5, lane = tid & 31;
    const int warpRow = wid & 3, warpCol = wid >> 2;
    const int bx = blockIdx.x, by = blockIdx.y;
    const int seg = bx >> 2, bxl = bx & 3;

    const __half* Whi = g_w[3 + seg];
    const float* bias = (seg == 0) ? bq : ((seg == 1) ? bk : bv);
    __half* Ch = (seg == 0) ? g_qkv[0] : ((seg == 1) ? g_qkv[2] : g_qkv[3]);
    __half* Cl = g_qkv[1];

    const __half* srcs[3] = {Ahi, Alo, Whi};
    const int rowb[3] = { by*128, by*128, bxl*128 };

    auto PREF = [&](int kt){
        uint32_t bufb = sb + (uint32_t)(kt % 3) * BUFB;
#pragma unroll
        for (int t = 0; t < 3; t++){
            const __half* src = srcs[t] + (size_t)rowb[t]*Dn + kt*BK;
            uint32_t tb = bufb + (uint32_t)t*TB;
#pragma unroll
            for (int i = 0; i < 2; i++){
                int id  = tid + i*256;
                int row = id >> 2, c = id & 3;
                cpasync16(tb + (uint32_t)(row*(PITCH*2) + c*16),
                          src + (size_t)row*Dn + c*8);
            }
        }
        CP_COMMIT();
    };

    float acc[2][8][4];
#pragma unroll
    for (int i = 0; i < 2; i++)
#pragma unroll
        for (int j = 0; j < 8; j++)
#pragma unroll
            for (int q = 0; q < 4; q++) acc[i][j][q] = 0.f;

    const uint32_t aRow = (uint32_t)(warpRow*32 + (lane & 15));
    const uint32_t aColB = (uint32_t)(((lane >> 4) << 4));
    const uint32_t bRow = (uint32_t)(warpCol*64 + (lane & 7) + ((lane >> 4) << 3));
    const uint32_t bColB = (uint32_t)((((lane >> 3) & 1) << 4));

    PREF(0);
    PREF(1);
#pragma unroll 1
    for (int kt = 0; kt < Dn/BK; kt++){
        if (kt + 1 < Dn/BK) { CP_WAIT(1); } else { CP_WAIT(0); }
        __syncthreads();
        if (kt + 2 < Dn/BK) PREF(kt + 2);

        uint32_t bufb = sb + (uint32_t)(kt % 3) * BUFB;
        uint32_t tAhi = bufb, tAlo = bufb + TB, tWhi = bufb + 2*TB;
#pragma unroll
        for (int kk = 0; kk < 2; kk++){
            uint32_t ah[2][4], al[2][4], bh[4][4];
#pragma unroll
            for (int mi = 0; mi < 2; mi++){
                ldsm4(ah[mi], tAhi + (aRow + mi*16)*(PITCH*2) + aColB + kk*32);
                ldsm4(al[mi], tAlo + (aRow + mi*16)*(PITCH*2) + aColB + kk*32);
            }
#pragma unroll
            for (int nt = 0; nt < 4; nt++)
                ldsm4(bh[nt], tWhi + (bRow + nt*16)*(PITCH*2) + bColB + kk*32);
#pragma unroll
            for (int mi = 0; mi < 2; mi++)
#pragma unroll
                for (int nj = 0; nj < 8; nj++){
                    mma16816(acc[mi][nj], ah[mi], &bh[nj >> 1][(nj & 1) << 1]);
                    mma16816(acc[mi][nj], al[mi], &bh[nj >> 1][(nj & 1) << 1]);
                }
        }
    }

    const int r0base = by*128 + warpRow*32;
    const int c0base = bxl*128 + warpCol*64;
    const bool wlo = (seg == 0);
#pragma unroll
    for (int mi = 0; mi < 2; mi++){
#pragma unroll
        for (int rp = 0; rp < 2; rp++){
            int grow = r0base + mi*16 + (lane >> 2) + rp*8;
#pragma unroll
            for (int nj = 0; nj < 8; nj++){
                int col = c0base + nj*8 + (lane & 3)*2;
                float vx = acc[mi][nj][rp*2 + 0];
                float vy = acc[mi][nj][rp*2 + 1];
                float2 bs = *(const float2*)(bias + col);
                vx += bs.x; vy += bs.y;
                size_t off = (size_t)grow*Dn + col;
                uint32_t hi, lo;
                packpair(vx, vy, hi, lo);
                *(uint32_t*)(Ch + off) = hi;
                if (wlo) *(uint32_t*)(Cl + off) = lo;
            }
        }
    }
}

// ======================= fused flash attention (QK 2-term, PV 1-term) =======================
__global__ __launch_bounds__(256, 1) void attn_fused(
    const __half* __restrict__ qh, const __half* __restrict__ ql,
    const __half* __restrict__ kh, const __half* __restrict__ vh,
    const float* __restrict__ mask,
    __half* __restrict__ Ohi, __half* __restrict__ Olo)
{
    extern __shared__ __align__(16) char dsm[];
    const uint32_t sb = smem_u32(dsm);
    const int tid = threadIdx.x, wid = tid >> 5, lane = tid & 31;
    const int bh = blockIdx.y, b = bh >> 3, h = bh & 7;
    const int i0 = blockIdx.x * 128;
    const size_t qoff = ((size_t)(b*Ln + i0))*Dn + h*DHn;
    const size_t koff = ((size_t)(b*Ln))*Dn + h*DHn;

    const uint32_t smQh = sb, smQl = sb + QT;
    const uint32_t smKV0 = sb + 2*QT;
    const uint32_t smMaskOff = 2*QT + 2*KVB;

    auto LOADC = [&](int c){
        uint32_t base = smKV0 + (uint32_t)(c & 1)*KVB;
        size_t g0 = koff + (size_t)(c*128)*Dn;
#pragma unroll
        for (int i = 0; i < 4; i++){
            int id = tid + i*256; int row = id >> 3, seg = id & 7;
            size_t go = g0 + (size_t)row*Dn + seg*8;
            uint32_t so = (uint32_t)(row*AP + seg*16);
            cpasync16(base + so,      kh + go);
            cpasync16(base + QT + so, vh + go);
        }
        if (tid < 32)
            cpasync16(sb + smMaskOff + (uint32_t)(c & 1)*512 + tid*16,
                      mask + b*Ln + c*128 + tid*4);
        CP_COMMIT();
    };

#pragma unroll
    for (int i = 0; i < 4; i++){
        int id = tid + i*256; int row = id >> 3, seg = id & 7;
        size_t go = qoff + (size_t)row*Dn + seg*8;
        uint32_t so = (uint32_t)(row*AP + seg*16);
        cpasync16(smQh + so, qh + go);
        cpasync16(smQl + so, ql + go);
    }
    LOADC(0);
    LOADC(1);

    const int g = lane >> 2, t4 = lane & 3;
    float mi0 = mask[b*Ln + i0 + wid*16 + g];
    float mi1 = mask[b*Ln + i0 + wid*16 + g + 8];

    float m0 = -3.0e38f, m1 = -3.0e38f, l0 = 0.f, l1 = 0.f;
    float o[8][4];
#pragma unroll
    for (int i = 0; i < 8; i++)
#pragma unroll
        for (int j = 0; j < 4; j++) o[i][j] = 0.f;

    const uint32_t aQoff = (uint32_t)((wid*16 + (lane & 15))*AP + ((lane >> 4) << 4));
    const uint32_t bKoff = (uint32_t)(((lane & 7) + ((lane >> 4) << 3))*AP + (((lane >> 3) & 1) << 4));
    const uint32_t vOff  = (uint32_t)((lane & 15)*AP + ((lane >> 4) << 4));

#pragma unroll 1
    for (int c = 0; c < 4; c++){
        if (c < 3) { CP_WAIT(1); } else { CP_WAIT(0); }
        __syncthreads();
        const uint32_t kb = smKV0 + (uint32_t)(c & 1)*KVB;
        const float* mjp = (const float*)(dsm + smMaskOff + (c & 1)*512);

        float s[16][4];
#pragma unroll
        for (int nj = 0; nj < 16; nj++)
#pragma unroll
            for (int q = 0; q < 4; q++) s[nj][q] = 0.f;
#pragma unroll
        for (int ss = 0; ss < 4; ss++){
            uint32_t ah[4], al[4];
            ldsm4(ah, smQh + aQoff + ss*32);
            ldsm4(al, smQl + aQoff + ss*32);
#pragma unroll
            for (int njp = 0; njp < 8; njp++){
                uint32_t bhh[4];
                ldsm4(bhh, kb + (uint32_t)(njp*16)*AP + bKoff + ss*32);
                mma16816(s[2*njp],   ah, &bhh[0]);
                mma16816(s[2*njp],   al, &bhh[0]);
                mma16816(s[2*njp+1], ah, &bhh[2]);
                mma16816(s[2*njp+1], al, &bhh[2]);
            }
        }

        float rm0 = -3.0e38f, rm1 = -3.0e38f;
#pragma unroll
        for (int nj = 0; nj < 16; nj++){
            int colb = nj*8 + t4*2;
            float mj0 = mjp[colb], mj1 = mjp[colb+1];
            float mm;
            mm = mi0*mj0; s[nj][0] = s[nj][0]*0.125f*mm + NEGV*(1.f - mm);
            mm = mi0*mj1; s[nj][1] = s[nj][1]*0.125f*mm + NEGV*(1.f - mm);
            mm = mi1*mj0; s[nj][2] = s[nj][2]*0.125f*mm + NEGV*(1.f - mm);
            mm = mi1*mj1; s[nj][3] = s[nj][3]*0.125f*mm + NEGV*(1.f - mm);
            rm0 = fmaxf(rm0, fmaxf(s[nj][0], s[nj][1]));
            rm1 = fmaxf(rm1, fmaxf(s[nj][2], s[nj][3]));
        }
        rm0 = fmaxf(rm0, __shfl_xor_sync(0xffffffffu, rm0, 1));
        rm0 = fmaxf(rm0, __shfl_xor_sync(0xffffffffu, rm0, 2));
        rm1 = fmaxf(rm1, __shfl_xor_sync(0xffffffffu, rm1, 1));
        rm1 = fmaxf(rm1, __shfl_xor_sync(0xffffffffu, rm1, 2));
        float nm0 = fmaxf(m0, rm0), nm1 = fmaxf(m1, rm1);
        float al0 = __expf(m0 - nm0), al1 = __expf(m1 - nm1);
        m0 = nm0; m1 = nm1;
#pragma unroll
        for (int nd = 0; nd < 8; nd++){
            o[nd][0] *= al0; o[nd][1] *= al0;
            o[nd][2] *= al1; o[nd][3] *= al1;
        }

        float sum0 = 0.f, sum1 = 0.f;
#pragma unroll
        for (int ss = 0; ss < 8; ss++){
            float p00 = __expf(s[2*ss][0]   - nm0), p01 = __expf(s[2*ss][1]   - nm0);
            float p02 = __expf(s[2*ss][2]   - nm1), p03 = __expf(s[2*ss][3]   - nm1);
            float p10 = __expf(s[2*ss+1][0] - nm0), p11 = __expf(s[2*ss+1][1] - nm0);
            float p12 = __expf(s[2*ss+1][2] - nm1), p13 = __expf(s[2*ss+1][3] - nm1);
            sum0 += p00 + p01 + p10 + p11;
            sum1 += p02 + p03 + p12 + p13;
            uint32_t pah[4];
            pah[0] = packhi(p00, p01);
            pah[1] = packhi(p02, p03);
            pah[2] = packhi(p10, p11);
            pah[3] = packhi(p12, p13);
#pragma unroll
            for (int ndp = 0; ndp < 4; ndp++){
                uint32_t vhh[4];
                ldsm4t(vhh, kb + QT + (uint32_t)(ss*16)*AP + vOff + ndp*32);
                mma16816(o[2*ndp],   pah, &vhh[0]);
                mma16816(o[2*ndp+1], pah, &vhh[2]);
            }
        }
        sum0 += __shfl_xor_sync(0xffffffffu, sum0, 1);
        sum0 += __shfl_xor_sync(0xffffffffu, sum0, 2);
        sum1 += __shfl_xor_sync(0xffffffffu, sum1, 1);
        sum1 += __shfl_xor_sync(0xffffffffu, sum1, 2);
        l0 = l0*al0 + sum0;
        l1 = l1*al1 + sum1;

        if (c < 2){ __syncthreads(); LOADC(c + 2); }
    }

    float inv0 = 1.f / l0, inv1 = 1.f / l1;
    int r0 = i0 + wid*16 + g, r1 = r0 + 8;
    size_t ob = ((size_t)(b*Ln))*Dn + h*DHn;
#pragma unroll
    for (int nd = 0; nd < 8; nd++){
        int col = nd*8 + t4*2;
        uint32_t hi0, lo0, hi1, lo1;
        packpair(o[nd][0]*inv0, o[nd][1]*inv0, hi0, lo0);
        packpair(o[nd][2]*inv1, o[nd][3]*inv1, hi1, lo1);
        *(uint32_t*)(Ohi + ob + (size_t)r0*Dn + col) = hi0;
        *(uint32_t*)(Olo + ob + (size_t)r0*Dn + col) = lo0;
        *(uint32_t*)(Ohi + ob + (size_t)r1*Dn + col) = hi1;
        *(uint32_t*)(Olo + ob + (size_t)r1*Dn + col) = lo1;
    }
}

// ======================= host orchestration =======================
extern "C" void kernel_launch(void* const* d_in, const int* in_sizes, int n_in,
                              void* d_out, int out_size)
{
    (void)in_sizes; (void)n_in; (void)out_size;
    const float* x     = (const float*)d_in[0];
    const float* mask  = (const float*)d_in[1];
    const float* pe    = (const float*)d_in[2];
    const float* dw_w  = (const float*)d_in[3];
    const float* dw_b  = (const float*)d_in[4];
    const float* pw_w  = (const float*)d_in[5];
    const float* pw_b  = (const float*)d_in[6];
    const float* wq    = (const float*)d_in[7];
    const float* bq    = (const float*)d_in[8];
    const float* wk    = (const float*)d_in[9];
    const float* bk    = (const float*)d_in[10];
    const float* wv    = (const float*)d_in[11];
    const float* bv    = (const float*)d_in[12];
    const float* fc_w  = (const float*)d_in[13];
    const float* fc_b  = (const float*)d_in[14];
    const float* out_w = (const float*)d_in[15];
    const float* out_b = (const float*)d_in[16];
    const float* lnc_g = (const float*)d_in[17];
    const float* lnc_b = (const float*)d_in[18];
    const float* lna_g = (const float*)d_in[19];
    const float* lna_b = (const float*)d_in[20];
    const float* lno_g = (const float*)d_in[21];
    const float* lno_b = (const float*)d_in[22];
    float* out = (float*)d_out;

    __half *pA, *pX2, *pX1, *qkv;
    cudaGetSymbolAddress((void**)&pA,  g_pA);
    cudaGetSymbolAddress((void**)&pX2, g_pX2);
    cudaGetSymbolAddress((void**)&pX1, g_pX1);
    cudaGetSymbolAddress((void**)&qkv, g_qkv);
    __half* wsym;
    cudaGetSymbolAddress((void**)&wsym, g_w);

    const size_t NN = (size_t)Mn*Dn;
    __half *pA_h = pA,  *pA_l = pA + NN;
    __half *x2_h = pX2, *x2_l = pX2 + NN;
    __half *x1_h = pX1, *x1_l = pX1 + NN;
    __half *q_h = qkv, *q_l = qkv + NN, *k_h = qkv + 2*NN, *v_h = qkv + 3*NN;
    auto W = [&](int i){ return wsym + (size_t)i * Dn * Dn; };

    cudaFuncSetAttribute(gemm_mma<true,-1,0,true,false>,  cudaFuncAttributeMaxDynamicSharedMemorySize, SMEM_SZ);
    cudaFuncSetAttribute(gemm_mma<true,0,1,true,false>,   cudaFuncAttributeMaxDynamicSharedMemorySize, SMEM_SZ);
    cudaFuncSetAttribute(gemm_mma<true,1,2,true,false>,   cudaFuncAttributeMaxDynamicSharedMemorySize, SMEM_SZ);
    cudaFuncSetAttribute(gemm_mma<false,2,3,true,false>,  cudaFuncAttributeMaxDynamicSharedMemorySize, SMEM_SZ);
    cudaFuncSetAttribute(gemm_mma<false,3,-1,false,true>, cudaFuncAttributeMaxDynamicSharedMemorySize, SMEM_SZ);
    cudaFuncSetAttribute(gemm_qkv, cudaFuncAttributeMaxDynamicSharedMemorySize, SMEM_SZ);
    cudaFuncSetAttribute(attn_fused, cudaFuncAttributeMaxDynamicSharedMemorySize, SMEM_ATT);

    const int DWB = (Bn * (Ln/TLC) * (Dn/4)) / 256;   // 1024 blocks
    dim3 gemmGrid(Dn/128, Mn/128);      // (4, 128)
    dim3 qkvGrid(12, Mn/128);           // N = 1536

    // 1. weight prep + LN-partial zeroing
    prep_weights<<<6*1024, 256>>>(pw_w, wq, wk, wv, fc_w, out_w);

    // 2-3. conv layer 0 (PE fused); stats -> slot 0 (lnc0)
    dwconv_pe<<<DWB, 256>>>(x, pe, dw_w + 0*Dn*Kn, dw_b + 0*Dn, pA_h, pA_l);
    gemm_mma<true,-1,0,true,false><<<gemmGrid, 256, SMEM_SZ>>>(
        pA_h, pA_l, W(0), pw_b + 0*Dn, nullptr,
        nullptr, nullptr, nullptr, nullptr, x2_h, x2_l);
    // 4-5. conv layer 1: + LN(x2; lnc0, slot 0); stats -> slot 1 (lnc1)
    dwconv_pair<<<DWB, 256>>>(x2_h, x2_l, dw_w + 1*Dn*Kn, dw_b + 1*Dn, pA_h, pA_l);
    gemm_mma<true,0,1,true,false><<<gemmGrid, 256, SMEM_SZ>>>(
        pA_h, pA_l, W(1), pw_b + 1*Dn, nullptr,
        x2_h, x2_l, lnc_g + 0, lnc_b + 0, x1_h, x1_l);
    // 6-7. conv layer 2: + LN(x1; lnc1, slot 1); stats -> slot 2 (lna)
    dwconv_pair<<<DWB, 256>>>(x1_h, x1_l, dw_w + 2*Dn*Kn, dw_b + 2*Dn, pA_h, pA_l);
    gemm_mma<true,1,2,true,false><<<gemmGrid, 256, SMEM_SZ>>>(
        pA_h, pA_l, W(2), pw_b + 2*Dn, nullptr,
        x1_h, x1_l, lnc_g + Ln*Dn, lnc_b + Ln*Dn, x2_h, x2_l);

    // 8. merged qkv projection
    gemm_qkv<<<qkvGrid, 256, SMEM_SZ>>>(x2_h, x2_l, bq, bk, bv);

    // 9. fused flash attention -> pA pair
    attn_fused<<<dim3(Ln/128, Bn*Hn), 256, SMEM_ATT>>>(
        q_h, q_l, k_h, v_h, mask, pA_h, pA_l);

    // 10. fc + LN(x2; lna, slot 2) -> x1 pair; stats -> slot 3 (lno)
    gemm_mma<false,2,3,true,false><<<gemmGrid, 256, SMEM_SZ>>>(
        pA_h, pA_l, W(6), fc_b, nullptr,
        x2_h, x2_l, lna_g, lna_b, x1_h, x1_l);

    // 11. out + LN(x1; lno, slot 3) -> d_out (fp32)
    gemm_mma<false,3,-1,false,true><<<gemmGrid, 256, SMEM_SZ>>>(
        x1_h, x1_l, W(7), out_b, out,
        x1_h, x1_l, lno_g, lno_b, nullptr, nullptr);
}

// round 13
// speedup vs baseline: 3.3681x; 1.0188x over previous
#include <cuda_runtime.h>
#include <cuda_fp16.h>
#include <cstdint>

#define Bn 32
#define Ln 512
#define Dn 512
#define Hn 8
#define DHn 64
#define Kn 7
#define Mn (Bn*Ln)
#define NEGV (-1e30f)
#define LDINV (1.0f/(float)(Ln*Dn))
#define TLC 8

// ---- big-GEMM tiling ----
#define BK 32
#define PITCH 40
#define TB (128*PITCH*2)
#define BUFB (3*TB)
#define SMEM_SZ (3*BUFB)            // 92160 B

// ---- fused attention smem (KV chunk = 64 rows -> 2 CTAs/SM) ----
#define AP 144
#define QT (128*AP)                 // 18432 B
#define KVT (64*AP)                 // 9216 B
#define KVB (2*KVT)                 // khi+vhi = 18432 B
#define SMEM_ATT (2*QT + 2*KVB + 1024)   // 74752 B

// ======================= PTX helpers =======================
__device__ __forceinline__ uint32_t smem_u32(const void* p){
    uint32_t a;
    asm("{ .reg .u64 t; cvta.to.shared.u64 t, %1; cvt.u32.u64 %0, t; }" : "=r"(a) : "l"(p));
    return a;
}
__device__ __forceinline__ void cpasync16(uint32_t dst, const void* src){
    asm volatile("cp.async.cg.shared.global [%0], [%1], 16;" :: "r"(dst), "l"(src) : "memory");
}
#define CP_COMMIT() asm volatile("cp.async.commit_group;" ::: "memory")
#define CP_WAIT(N)  asm volatile("cp.async.wait_group %0;" :: "n"(N) : "memory")
__device__ __forceinline__ void ldsm4(uint32_t* r, uint32_t addr){
    asm volatile("ldmatrix.sync.aligned.m8n8.x4.shared.b16 {%0,%1,%2,%3}, [%4];"
        : "=r"(r[0]), "=r"(r[1]), "=r"(r[2]), "=r"(r[3]) : "r"(addr));
}
__device__ __forceinline__ void ldsm4t(uint32_t* r, uint32_t addr){
    asm volatile("ldmatrix.sync.aligned.m8n8.x4.trans.shared.b16 {%0,%1,%2,%3}, [%4];"
        : "=r"(r[0]), "=r"(r[1]), "=r"(r[2]), "=r"(r[3]) : "r"(addr));
}
__device__ __forceinline__ void mma16816(float* d, const uint32_t* a, const uint32_t* b){
    asm volatile("mma.sync.aligned.m16n8k16.row.col.f32.f16.f16.f32 "
        "{%0,%1,%2,%3}, {%4,%5,%6,%7}, {%8,%9}, {%0,%1,%2,%3};"
        : "+f"(d[0]), "+f"(d[1]), "+f"(d[2]), "+f"(d[3])
        : "r"(a[0]), "r"(a[1]), "r"(a[2]), "r"(a[3]), "r"(b[0]), "r"(b[1]));
}
__device__ __forceinline__ void packpair(float x, float y, uint32_t& hi, uint32_t& lo){
    __half hx = __float2half_rn(x), hy = __float2half_rn(y);
    __half2 h; h.x = hx; h.y = hy;
    __half2 l;
    l.x = __float2half_rn(x - __half2float(hx));
    l.y = __float2half_rn(y - __half2float(hy));
    hi = *(uint32_t*)&h; lo = *(uint32_t*)&l;
}
__device__ __forceinline__ uint32_t packhi(float x, float y){
    __half2 h; h.x = __float2half_rn(x); h.y = __float2half_rn(y);
    return *(uint32_t*)&h;
}
__device__ __forceinline__ float2 unpackpair(uint32_t hi, uint32_t lo){
    __half2 h = *(__half2*)&hi, l = *(__half2*)&lo;
    float2 r;
    r.x = __half2float(h.x) + __half2float(l.x);
    r.y = __half2float(h.y) + __half2float(l.y);
    return r;
}

// ======================= scratch =======================
__device__ float g_pS [4][Bn];
__device__ float g_pS2[4][Bn];
__device__ __half g_pA [2][Mn*Dn];
__device__ __half g_pX2[2][Mn*Dn];
__device__ __half g_pX1[2][Mn*Dn];
__device__ __half g_qkv[4][Mn*Dn];
__device__ __half g_w[8][Dn*Dn];

// ======================= weight prep + LN-partial zeroing =======================
__global__ void prep_weights(const float* __restrict__ pw_w,
                             const float* __restrict__ wq, const float* __restrict__ wk,
                             const float* __restrict__ wv,
                             const float* __restrict__ fc_w, const float* __restrict__ out_w)
{
    if (blockIdx.x == 0 && threadIdx.x < 4*Bn) {
        (&g_pS[0][0])[threadIdx.x]  = 0.f;
        (&g_pS2[0][0])[threadIdx.x] = 0.f;
    }
    int task = blockIdx.x >> 10;
    int idx  = (blockIdx.x & 1023) * 256 + threadIdx.x;
    if (task < 3) {
        g_w[task][idx] = __float2half_rn(pw_w[(size_t)task*Dn*Dn + idx]);
    } else if (task == 3) {
        int n = idx >> 9, d = idx & 511;
        int src = (n >> 6) * (Dn * DHn) + d * DHn + (n & 63);
        g_w[3][idx] = __float2half_rn(wq[src]);
        g_w[4][idx] = __float2half_rn(wk[src]);
        g_w[5][idx] = __float2half_rn(wv[src]);
    } else if (task == 4) {
        g_w[6][idx] = __float2half_rn(fc_w[idx]);
    } else {
        g_w[7][idx] = __float2half_rn(out_w[idx]);
    }
}

// ======================= sliding-window depthwise conv (TLC=8) =======================
__global__ void dwconv_pe(const float* __restrict__ x, const float* __restrict__ pe,
                          const float* __restrict__ w, const float* __restrict__ bias,
                          __half* __restrict__ hi, __half* __restrict__ lo)
{
    int idx = blockIdx.x * 256 + threadIdx.x;
    int d  = (idx & 127) << 2;
    int l0 = ((idx >> 7) & 63) << 3;
    int b  = idx >> 13;

    float wr[4][Kn];
#pragma unroll
    for (int c = 0; c < 4; c++)
#pragma unroll
        for (int kk = 0; kk < Kn; kk++) wr[c][kk] = w[(d + c)*Kn + kk];

    float4 bs = *(const float4*)(bias + d);
    float4 acc[TLC];
#pragma unroll
    for (int j = 0; j < TLC; j++) acc[j] = bs;

#pragma unroll
    for (int i = 0; i < TLC + 6; i++){
        int ll = l0 - 3 + i;
        if (ll >= 0 && ll < Ln){
            float4 xv = *(const float4*)(x + ((size_t)(b*Ln + ll))*Dn + d);
            float4 pv = *(const float4*)(pe + (size_t)ll*Dn + d);
            xv.x += pv.x; xv.y += pv.y; xv.z += pv.z; xv.w += pv.w;
#pragma unroll
            for (int kk = 0; kk < Kn; kk++){
                int j = i - kk;
                if (j >= 0 && j < TLC){
                    acc[j].x = fmaf(xv.x, wr[0][kk], acc[j].x);
                    acc[j].y = fmaf(xv.y, wr[1][kk], acc[j].y);
                    acc[j].z = fmaf(xv.z, wr[2][kk], acc[j].z);
                    acc[j].w = fmaf(xv.w, wr[3][kk], acc[j].w);
                }
            }
        }
    }
#pragma unroll
    for (int j = 0; j < TLC; j++){
        float vx = fmaxf(acc[j].x, 0.f), vy = fmaxf(acc[j].y, 0.f);
        float vz = fmaxf(acc[j].z, 0.f), vw = fmaxf(acc[j].w, 0.f);
        size_t o = ((size_t)(b*Ln + l0 + j))*Dn + d;
        uint32_t h0, lw0, h1, lw1;
        packpair(vx, vy, h0, lw0);
        packpair(vz, vw, h1, lw1);
        uint2 hv; hv.x = h0;  hv.y = h1;
        uint2 lv; lv.x = lw0; lv.y = lw1;
        *(uint2*)(hi + o) = hv;
        *(uint2*)(lo + o) = lv;
    }
}

__global__ void dwconv_pair(const __half* __restrict__ xh, const __half* __restrict__ xl,
                            const float* __restrict__ w, const float* __restrict__ bias,
                            __half* __restrict__ hi, __half* __restrict__ lo)
{
    int idx = blockIdx.x * 256 + threadIdx.x;
    int d  = (idx & 127) << 2;
    int l0 = ((idx >> 7) & 63) << 3;
    int b  = idx >> 13;

    float wr[4][Kn];
#pragma unroll
    for (int c = 0; c < 4; c++)
#pragma unroll
        for (int kk = 0; kk < Kn; kk++) wr[c][kk] = w[(d + c)*Kn + kk];

    float4 bs = *(const float4*)(bias + d);
    float4 acc[TLC];
#pragma unroll
    for (int j = 0; j < TLC; j++) acc[j] = bs;

#pragma unroll
    for (int i = 0; i < TLC + 6; i++){
        int ll = l0 - 3 + i;
        if (ll >= 0 && ll < Ln){
            size_t base = ((size_t)(b*Ln + ll))*Dn + d;
            uint2 hv = *(const uint2*)(xh + base);
            uint2 lv = *(const uint2*)(xl + base);
            float2 a0 = unpackpair(hv.x, lv.x);
            float2 a1 = unpackpair(hv.y, lv.y);
            float4 xv; xv.x = a0.x; xv.y = a0.y; xv.z = a1.x; xv.w = a1.y;
#pragma unroll
            for (int kk = 0; kk < Kn; kk++){
                int j = i - kk;
                if (j >= 0 && j < TLC){
                    acc[j].x = fmaf(xv.x, wr[0][kk], acc[j].x);
                    acc[j].y = fmaf(xv.y, wr[1][kk], acc[j].y);
                    acc[j].z = fmaf(xv.z, wr[2][kk], acc[j].z);
                    acc[j].w = fmaf(xv.w, wr[3][kk], acc[j].w);
                }
            }
        }
    }
#pragma unroll
    for (int j = 0; j < TLC; j++){
        float vx = fmaxf(acc[j].x, 0.f), vy = fmaxf(acc[j].y, 0.f);
        float vz = fmaxf(acc[j].z, 0.f), vw = fmaxf(acc[j].w, 0.f);
        size_t o = ((size_t)(b*Ln + l0 + j))*Dn + d;
        uint32_t h0, lw0, h1, lw1;
        packpair(vx, vy, h0, lw0);
        packpair(vz, vw, h1, lw1);
        uint2 hv; hv.x = h0;  hv.y = h1;
        uint2 lv; lv.x = lw0; lv.y = lw1;
        *(uint2*)(hi + o) = hv;
        *(uint2*)(lo + o) = lv;
    }
}

// ======================= mma.sync GEMM (fp16 2-term, 4x2 warp layout) =======================
template<bool RELU, int LNIN, int LNOUT, bool SPL, bool WRITEC>
__global__ __launch_bounds__(256, 2) void gemm_mma(
    const __half* __restrict__ Ahi, const __half* __restrict__ Alo,
    const __half* __restrict__ Whi,
    const float* __restrict__ bias, float* __restrict__ C,
    const __half* __restrict__ Rhi, const __half* __restrict__ Rlo,
    const float* __restrict__ lng, const float* __restrict__ lnb,
    __half* __restrict__ Chi, __half* __restrict__ Clo)
{
    extern __shared__ __align__(16) char dsm[];
    const uint32_t sb = smem_u32(dsm);
    const int tid = threadIdx.x;
    const int wid = tid >> 5, lane = tid & 31;
    const int warpRow = wid & 3, warpCol = wid >> 2;
    const int bx = blockIdx.x, by = blockIdx.y;

    const __half* srcs[3] = {Ahi, Alo, Whi};
    const int rowb[3] = { by*128, by*128, bx*128 };

    auto PREF = [&](int kt){
        uint32_t bufb = sb + (uint32_t)(kt % 3) * BUFB;
#pragma unroll
        for (int t = 0; t < 3; t++){
            const __half* src = srcs[t] + (size_t)rowb[t]*Dn + kt*BK;
            uint32_t tb = bufb + (uint32_t)t*TB;
#pragma unroll
            for (int i = 0; i < 2; i++){
                int id  = tid + i*256;
                int row = id >> 2, c = id & 3;
                cpasync16(tb + (uint32_t)(row*(PITCH*2) + c*16),
                          src + (size_t)row*Dn + c*8);
            }
        }
        CP_COMMIT();
    };

    float acc[2][8][4];
#pragma unroll
    for (int i = 0; i < 2; i++)
#pragma unroll
        for (int j = 0; j < 8; j++)
#pragma unroll
            for (int q = 0; q < 4; q++) acc[i][j][q] = 0.f;

    const uint32_t aRow = (uint32_t)(warpRow*32 + (lane & 15));
    const uint32_t aColB = (uint32_t)(((lane >> 4) << 4));
    const uint32_t bRow = (uint32_t)(warpCol*64 + (lane & 7) + ((lane >> 4) << 3));
    const uint32_t bColB = (uint32_t)((((lane >> 3) & 1) << 4));

    PREF(0);
    PREF(1);
#pragma unroll 1
    for (int kt = 0; kt < Dn/BK; kt++){
        if (kt + 1 < Dn/BK) { CP_WAIT(1); } else { CP_WAIT(0); }
        __syncthreads();
        if (kt + 2 < Dn/BK) PREF(kt + 2);

        uint32_t bufb = sb + (uint32_t)(kt % 3) * BUFB;
        uint32_t tAhi = bufb, tAlo = bufb + TB, tWhi = bufb + 2*TB;
#pragma unroll
        for (int kk = 0; kk < 2; kk++){
            uint32_t ah[2][4], al[2][4], bh[4][4];
#pragma unroll
            for (int mi = 0; mi < 2; mi++){
                ldsm4(ah[mi], tAhi + (aRow + mi*16)*(PITCH*2) + aColB + kk*32);
                ldsm4(al[mi], tAlo + (aRow + mi*16)*(PITCH*2) + aColB + kk*32);
            }
#pragma unroll
            for (int nt = 0; nt < 4; nt++)
                ldsm4(bh[nt], tWhi + (bRow + nt*16)*(PITCH*2) + bColB + kk*32);
#pragma unroll
            for (int mi = 0; mi < 2; mi++)
#pragma unroll
                for (int nj = 0; nj < 8; nj++){
                    mma16816(acc[mi][nj], ah[mi], &bh[nj >> 1][(nj & 1) << 1]);
                    mma16816(acc[mi][nj], al[mi], &bh[nj >> 1][(nj & 1) << 1]);
                }
        }
    }

    float muv = 0.f, rsv = 0.f;
    if (LNIN >= 0) {
        int bb = (by*128) >> 9;
        float s = g_pS[LNIN][bb], s2 = g_pS2[LNIN][bb];
        muv = s * LDINV;
        rsv = rsqrtf(s2 * LDINV - muv*muv + 1e-5f);
    }
    const int r0base = by*128 + warpRow*32;
    const int c0base = bx*128 + warpCol*64;
    float ts = 0.f, ts2 = 0.f;
#pragma unroll
    for (int mi = 0; mi < 2; mi++){
#pragma unroll
        for (int rp = 0; rp < 2; rp++){
            int grow = r0base + mi*16 + (lane >> 2) + rp*8;
            int lrow = grow & (Ln - 1);
#pragma unroll
            for (int nj = 0; nj < 8; nj++){
                int col = c0base + nj*8 + (lane & 3)*2;
                float vx = acc[mi][nj][rp*2 + 0];
                float vy = acc[mi][nj][rp*2 + 1];
                float2 bs = *(const float2*)(bias + col);
                vx += bs.x; vy += bs.y;
                if (RELU) { vx = fmaxf(vx, 0.f); vy = fmaxf(vy, 0.f); }
                size_t off = (size_t)grow*Dn + col;
                if (LNIN >= 0) {
                    float2 rr = unpackpair(*(const uint32_t*)(Rhi + off),
                                           *(const uint32_t*)(Rlo + off));
                    float2 gg = *(const float2*)(lng + (size_t)lrow*Dn + col);
                    float2 bb = *(const float2*)(lnb + (size_t)lrow*Dn + col);
                    vx += (rr.x - muv)*rsv*gg.x + bb.x;
                    vy += (rr.y - muv)*rsv*gg.y + bb.y;
                }
                if (LNOUT >= 0) { ts += vx + vy; ts2 += vx*vx + vy*vy; }
                if (WRITEC) {
                    float2 o; o.x = vx; o.y = vy;
                    *(float2*)(C + off) = o;
                }
                if (SPL) {
                    uint32_t hi, lo;
                    packpair(vx, vy, hi, lo);
                    *(uint32_t*)(Chi + off) = hi;
                    *(uint32_t*)(Clo + off) = lo;
                }
            }
        }
    }
    if (LNOUT >= 0) {
#pragma unroll
        for (int o = 16; o > 0; o >>= 1){
            ts  += __shfl_xor_sync(0xffffffffu, ts,  o);
            ts2 += __shfl_xor_sync(0xffffffffu, ts2, o);
        }
        __shared__ float sred[2][8];
        if (lane == 0){ sred[0][wid] = ts; sred[1][wid] = ts2; }
        __syncthreads();
        if (tid == 0){
            float a = 0.f, b2 = 0.f;
#pragma unroll
            for (int i = 0; i < 8; i++){ a += sred[0][i]; b2 += sred[1][i]; }
            int batch = by >> 2;
            atomicAdd(&g_pS[LNOUT][batch],  a);
            atomicAdd(&g_pS2[LNOUT][batch], b2);
        }
    }
}

// ======================= merged qkv GEMM (k/v segments: 1-term A) =======================
__global__ __launch_bounds__(256, 2) void gemm_qkv(
    const __half* __restrict__ Ahi, const __half* __restrict__ Alo,
    const float* __restrict__ bq, const float* __restrict__ bk, const float* __restrict__ bv)
{
    extern __shared__ __align__(16) char dsm[];
    const uint32_t sb = smem_u32(dsm);
    const int tid = threadIdx.x;
    const int wid = tid >> 5, lane = tid & 31;
    const int warpRow = wid & 3, warpCol = wid >> 2;
    const int bx = blockIdx.x, by = blockIdx.y;
    const int seg = bx >> 2, bxl = bx & 3;
    const bool two = (seg == 0);        // q needs 2-term; k/v are fp16-hi consumers

    const __half* Whi = g_w[3 + seg];
    const float* bias = (seg == 0) ? bq : ((seg == 1) ? bk : bv);
    __half* Ch = (seg == 0) ? g_qkv[0] : ((seg == 1) ? g_qkv[2] : g_qkv[3]);
    __half* Cl = g_qkv[1];

    const __half* srcs[3] = {Ahi, Alo, Whi};
    const int rowb[3] = { by*128, by*128, bxl*128 };

    auto PREF = [&](int kt){
        uint32_t bufb = sb + (uint32_t)(kt % 3) * BUFB;
#pragma unroll
        for (int t = 0; t < 3; t++){
            const __half* src = srcs[t] + (size_t)rowb[t]*Dn + kt*BK;
            uint32_t tb = bufb + (uint32_t)t*TB;
#pragma unroll
            for (int i = 0; i < 2; i++){
                int id  = tid + i*256;
                int row = id >> 2, c = id & 3;
                cpasync16(tb + (uint32_t)(row*(PITCH*2) + c*16),
                          src + (size_t)row*Dn + c*8);
            }
        }
        CP_COMMIT();
    };

    float acc[2][8][4];
#pragma unroll
    for (int i = 0; i < 2; i++)
#pragma unroll
        for (int j = 0; j < 8; j++)
#pragma unroll
            for (int q = 0; q < 4; q++) acc[i][j][q] = 0.f;

    const uint32_t aRow = (uint32_t)(warpRow*32 + (lane & 15));
    const uint32_t aColB = (uint32_t)(((lane >> 4) << 4));
    const uint32_t bRow = (uint32_t)(warpCol*64 + (lane & 7) + ((lane >> 4) << 3));
    const uint32_t bColB = (uint32_t)((((lane >> 3) & 1) << 4));

    PREF(0);
    PREF(1);
#pragma unroll 1
    for (int kt = 0; kt < Dn/BK; kt++){
        if (kt + 1 < Dn/BK) { CP_WAIT(1); } else { CP_WAIT(0); }
        __syncthreads();
        if (kt + 2 < Dn/BK) PREF(kt + 2);

        uint32_t bufb = sb + (uint32_t)(kt % 3) * BUFB;
        uint32_t tAhi = bufb, tAlo = bufb + TB, tWhi = bufb + 2*TB;
#pragma unroll
        for (int kk = 0; kk < 2; kk++){
            uint32_t ah[2][4], al[2][4], bh[4][4];
#pragma unroll
            for (int mi = 0; mi < 2; mi++){
                ldsm4(ah[mi], tAhi + (aRow + mi*16)*(PITCH*2) + aColB + kk*32);
                if (two) ldsm4(al[mi], tAlo + (aRow + mi*16)*(PITCH*2) + aColB + kk*32);
            }
#pragma unroll
            for (int nt = 0; nt < 4; nt++)
                ldsm4(bh[nt], tWhi + (bRow + nt*16)*(PITCH*2) + bColB + kk*32);
#pragma unroll
            for (int mi = 0; mi < 2; mi++)
#pragma unroll
                for (int nj = 0; nj < 8; nj++){
                    mma16816(acc[mi][nj], ah[mi], &bh[nj >> 1][(nj & 1) << 1]);
                    if (two) mma16816(acc[mi][nj], al[mi], &bh[nj >> 1][(nj & 1) << 1]);
                }
        }
    }

    const int r0base = by*128 + warpRow*32;
    const int c0base = bxl*128 + warpCol*64;
#pragma unroll
    for (int mi = 0; mi < 2; mi++){
#pragma unroll
        for (int rp = 0; rp < 2; rp++){
            int grow = r0base + mi*16 + (lane >> 2) + rp*8;
#pragma unroll
            for (int nj = 0; nj < 8; nj++){
                int col = c0base + nj*8 + (lane & 3)*2;
                float vx = acc[mi][nj][rp*2 + 0];
                float vy = acc[mi][nj][rp*2 + 1];
                float2 bs = *(const float2*)(bias + col);
                vx += bs.x; vy += bs.y;
                size_t off = (size_t)grow*Dn + col;
                if (two) {
                    uint32_t hi, lo;
                    packpair(vx, vy, hi, lo);
                    *(uint32_t*)(Ch + off) = hi;
                    *(uint32_t*)(Cl + off) = lo;
                } else {
                    *(uint32_t*)(Ch + off) = packhi(vx, vy);
                }
            }
        }
    }
}

// ======================= fused flash attention (KV chunk 64, 2 CTAs/SM) =======================
__global__ __launch_bounds__(256, 2) void attn_fused(
    const __half* __restrict__ qh, const __half* __restrict__ ql,
    const __half* __restrict__ kh, const __half* __restrict__ vh,
    const float* __restrict__ mask,
    __half* __restrict__ Ohi, __half* __restrict__ Olo)
{
    extern __shared__ __align__(16) char dsm[];
    const uint32_t sb = smem_u32(dsm);
    const int tid = threadIdx.x, wid = tid >> 5, lane = tid & 31;
    const int bh = blockIdx.y, b = bh >> 3, h = bh & 7;
    const int i0 = blockIdx.x * 128;
    const size_t qoff = ((size_t)(b*Ln + i0))*Dn + h*DHn;
    const size_t koff = ((size_t)(b*Ln))*Dn + h*DHn;

    const uint32_t smQh = sb, smQl = sb + QT;
    const uint32_t smKV0 = sb + 2*QT;
    const uint32_t smMaskOff = 2*QT + 2*KVB;

    auto LOADC = [&](int c){
        uint32_t base = smKV0 + (uint32_t)(c & 1)*KVB;
        size_t g0 = koff + (size_t)(c*64)*Dn;
#pragma unroll
        for (int i = 0; i < 2; i++){
            int id = tid + i*256; int row = id >> 3, seg = id & 7;
            size_t go = g0 + (size_t)row*Dn + seg*8;
            uint32_t so = (uint32_t)(row*AP + seg*16);
            cpasync16(base + so,       kh + go);
            cpasync16(base + KVT + so, vh + go);
        }
        if (tid < 16)
            cpasync16(sb + smMaskOff + (uint32_t)(c & 1)*256 + tid*16,
                      mask + b*Ln + c*64 + tid*4);
        CP_COMMIT();
    };

#pragma unroll
    for (int i = 0; i < 4; i++){
        int id = tid + i*256; int row = id >> 3, seg = id & 7;
        size_t go = qoff + (size_t)row*Dn + seg*8;
        uint32_t so = (uint32_t)(row*AP + seg*16);
        cpasync16(smQh + so, qh + go);
        cpasync16(smQl + so, ql + go);
    }
    LOADC(0);
    LOADC(1);

    const int g = lane >> 2, t4 = lane & 3;
    float mi0 = mask[b*Ln + i0 + wid*16 + g];
    float mi1 = mask[b*Ln + i0 + wid*16 + g + 8];

    float m0 = -3.0e38f, m1 = -3.0e38f, l0 = 0.f, l1 = 0.f;
    float o[8][4];
#pragma unroll
    for (int i = 0; i < 8; i++)
#pragma unroll
        for (int j = 0; j < 4; j++) o[i][j] = 0.f;

    const uint32_t aQoff = (uint32_t)((wid*16 + (lane & 15))*AP + ((lane >> 4) << 4));
    const uint32_t bKoff = (uint32_t)(((lane & 7) + ((lane >> 4) << 3))*AP + (((lane >> 3) & 1) << 4));
    const uint32_t vOff  = (uint32_t)((lane & 15)*AP + ((lane >> 4) << 4));

#pragma unroll 1
    for (int c = 0; c < 8; c++){
        if (c < 7) { CP_WAIT(1); } else { CP_WAIT(0); }
        __syncthreads();
        const uint32_t kb = smKV0 + (uint32_t)(c & 1)*KVB;
        const float* mjp = (const float*)(dsm + smMaskOff + (c & 1)*256);

        // ---- S = Q K^T over 64 K-rows (Q 2-term, K hi) ----
        float s[8][4];
#pragma unroll
        for (int nj = 0; nj < 8; nj++)
#pragma unroll
            for (int q = 0; q < 4; q++) s[nj][q] = 0.f;
#pragma unroll
        for (int ss = 0; ss < 4; ss++){
            uint32_t ah[4], al[4];
            ldsm4(ah, smQh + aQoff + ss*32);
            ldsm4(al, smQl + aQoff + ss*32);
#pragma unroll
            for (int njp = 0; njp < 4; njp++){
                uint32_t bhh[4];
                ldsm4(bhh, kb + (uint32_t)(njp*16)*AP + bKoff + ss*32);
                mma16816(s[2*njp],   ah, &bhh[0]);
                mma16816(s[2*njp],   al, &bhh[0]);
                mma16816(s[2*njp+1], ah, &bhh[2]);
                mma16816(s[2*njp+1], al, &bhh[2]);
            }
        }

        // ---- scale + mask + row max ----
        float rm0 = -3.0e38f, rm1 = -3.0e38f;
#pragma unroll
        for (int nj = 0; nj < 8; nj++){
            int colb = nj*8 + t4*2;
            float mj0 = mjp[colb], mj1 = mjp[colb+1];
            float mm;
            mm = mi0*mj0; s[nj][0] = s[nj][0]*0.125f*mm + NEGV*(1.f - mm);
            mm = mi0*mj1; s[nj][1] = s[nj][1]*0.125f*mm + NEGV*(1.f - mm);
            mm = mi1*mj0; s[nj][2] = s[nj][2]*0.125f*mm + NEGV*(1.f - mm);
            mm = mi1*mj1; s[nj][3] = s[nj][3]*0.125f*mm + NEGV*(1.f - mm);
            rm0 = fmaxf(rm0, fmaxf(s[nj][0], s[nj][1]));
            rm1 = fmaxf(rm1, fmaxf(s[nj][2], s[nj][3]));
        }
        rm0 = fmaxf(rm0, __shfl_xor_sync(0xffffffffu, rm0, 1));
        rm0 = fmaxf(rm0, __shfl_xor_sync(0xffffffffu, rm0, 2));
        rm1 = fmaxf(rm1, __shfl_xor_sync(0xffffffffu, rm1, 1));
        rm1 = fmaxf(rm1, __shfl_xor_sync(0xffffffffu, rm1, 2));
        float nm0 = fmaxf(m0, rm0), nm1 = fmaxf(m1, rm1);
        float al0 = __expf(m0 - nm0), al1 = __expf(m1 - nm1);
        m0 = nm0; m1 = nm1;
#pragma unroll
        for (int nd = 0; nd < 8; nd++){
            o[nd][0] *= al0; o[nd][1] *= al0;
            o[nd][2] *= al1; o[nd][3] *= al1;
        }

        // ---- P = exp(S-m), O += P V (P 1-term, V hi) ----
        float sum0 = 0.f, sum1 = 0.f;
#pragma unroll
        for (int ss = 0; ss < 4; ss++){
            float p00 = __expf(s[2*ss][0]   - nm0), p01 = __expf(s[2*ss][1]   - nm0);
            float p02 = __expf(s[2*ss][2]   - nm1), p03 = __expf(s[2*ss][3]   - nm1);
            float p10 = __expf(s[2*ss+1][0] - nm0), p11 = __expf(s[2*ss+1][1] - nm0);
            float p12 = __expf(s[2*ss+1][2] - nm1), p13 = __expf(s[2*ss+1][3] - nm1);
            sum0 += p00 + p01 + p10 + p11;
            sum1 += p02 + p03 + p12 + p13;
            uint32_t pah[4];
            pah[0] = packhi(p00, p01);
            pah[1] = packhi(p02, p03);
            pah[2] = packhi(p10, p11);
            pah[3] = packhi(p12, p13);
#pragma unroll
            for (int ndp = 0; ndp < 4; ndp++){
                uint32_t vhh[4];
                ldsm4t(vhh, kb + KVT + (uint32_t)(ss*16)*AP + vOff + ndp*32);
                mma16816(o[2*ndp],   pah, &vhh[0]);
                mma16816(o[2*ndp+1], pah, &vhh[2]);
            }
        }
        sum0 += __shfl_xor_sync(0xffffffffu, sum0, 1);
        sum0 += __shfl_xor_sync(0xffffffffu, sum0, 2);
        sum1 += __shfl_xor_sync(0xffffffffu, sum1, 1);
        sum1 += __shfl_xor_sync(0xffffffffu, sum1, 2);
        l0 = l0*al0 + sum0;
        l1 = l1*al1 + sum1;

        if (c < 6){ __syncthreads(); LOADC(c + 2); }
    }

    float inv0 = 1.f / l0, inv1 = 1.f / l1;
    int r0 = i0 + wid*16 + g, r1 = r0 + 8;
    size_t ob = ((size_t)(b*Ln))*Dn + h*DHn;
#pragma unroll
    for (int nd = 0; nd < 8; nd++){
        int col = nd*8 + t4*2;
        uint32_t hi0, lo0, hi1, lo1;
        packpair(o[nd][0]*inv0, o[nd][1]*inv0, hi0, lo0);
        packpair(o[nd][2]*inv1, o[nd][3]*inv1, hi1, lo1);
        *(uint32_t*)(Ohi + ob + (size_t)r0*Dn + col) = hi0;
        *(uint32_t*)(Olo + ob + (size_t)r0*Dn + col) = lo0;
        *(uint32_t*)(Ohi + ob + (size_t)r1*Dn + col) = hi1;
        *(uint32_t*)(Olo + ob + (size_t)r1*Dn + col) = lo1;
    }
}

// ======================= host orchestration =======================
extern "C" void kernel_launch(void* const* d_in, const int* in_sizes, int n_in,
                              void* d_out, int out_size)
{
    (void)in_sizes; (void)n_in; (void)out_size;
    const float* x     = (const float*)d_in[0];
    const float* mask  = (const float*)d_in[1];
    const float* pe    = (const float*)d_in[2];
    const float* dw_w  = (const float*)d_in[3];
    const float* dw_b  = (const float*)d_in[4];
    const float* pw_w  = (const float*)d_in[5];
    const float* pw_b  = (const float*)d_in[6];
    const float* wq    = (const float*)d_in[7];
    const float* bq    = (const float*)d_in[8];
    const float* wk    = (const float*)d_in[9];
    const float* bk    = (const float*)d_in[10];
    const float* wv    = (const float*)d_in[11];
    const float* bv    = (const float*)d_in[12];
    const float* fc_w  = (const float*)d_in[13];
    const float* fc_b  = (const float*)d_in[14];
    const float* out_w = (const float*)d_in[15];
    const float* out_b = (const float*)d_in[16];
    const float* lnc_g = (const float*)d_in[17];
    const float* lnc_b = (const float*)d_in[18];
    const float* lna_g = (const float*)d_in[19];
    const float* lna_b = (const float*)d_in[20];
    const float* lno_g = (const float*)d_in[21];
    const float* lno_b = (const float*)d_in[22];
    float* out = (float*)d_out;

    __half *pA, *pX2, *pX1, *qkv;
    cudaGetSymbolAddress((void**)&pA,  g_pA);
    cudaGetSymbolAddress((void**)&pX2, g_pX2);
    cudaGetSymbolAddress((void**)&pX1, g_pX1);
    cudaGetSymbolAddress((void**)&qkv, g_qkv);
    __half* wsym;
    cudaGetSymbolAddress((void**)&wsym, g_w);

    const size_t NN = (size_t)Mn*Dn;
    __half *pA_h = pA,  *pA_l = pA + NN;
    __half *x2_h = pX2, *x2_l = pX2 + NN;
    __half *x1_h = pX1, *x1_l = pX1 + NN;
    __half *q_h = qkv, *q_l = qkv + NN, *k_h = qkv + 2*NN, *v_h = qkv + 3*NN;
    auto W = [&](int i){ return wsym + (size_t)i * Dn * Dn; };

    cudaFuncSetAttribute(gemm_mma<true,-1,0,true,false>,  cudaFuncAttributeMaxDynamicSharedMemorySize, SMEM_SZ);
    cudaFuncSetAttribute(gemm_mma<true,0,1,true,false>,   cudaFuncAttributeMaxDynamicSharedMemorySize, SMEM_SZ);
    cudaFuncSetAttribute(gemm_mma<true,1,2,true,false>,   cudaFuncAttributeMaxDynamicSharedMemorySize, SMEM_SZ);
    cudaFuncSetAttribute(gemm_mma<false,2,3,true,false>,  cudaFuncAttributeMaxDynamicSharedMemorySize, SMEM_SZ);
    cudaFuncSetAttribute(gemm_mma<false,3,-1,false,true>, cudaFuncAttributeMaxDynamicSharedMemorySize, SMEM_SZ);
    cudaFuncSetAttribute(gemm_qkv, cudaFuncAttributeMaxDynamicSharedMemorySize, SMEM_SZ);
    cudaFuncSetAttribute(attn_fused, cudaFuncAttributeMaxDynamicSharedMemorySize, SMEM_ATT);

    const int DWB = (Bn * (Ln/TLC) * (Dn/4)) / 256;   // 1024 blocks
    dim3 gemmGrid(Dn/128, Mn/128);      // (4, 128)
    dim3 qkvGrid(12, Mn/128);           // N = 1536

    // 1. weight prep + LN-partial zeroing
    prep_weights<<<6*1024, 256>>>(pw_w, wq, wk, wv, fc_w, out_w);

    // 2-3. conv layer 0 (PE fused); stats -> slot 0 (lnc0)
    dwconv_pe<<<DWB, 256>>>(x, pe, dw_w + 0*Dn*Kn, dw_b + 0*Dn, pA_h, pA_l);
    gemm_mma<true,-1,0,true,false><<<gemmGrid, 256, SMEM_SZ>>>(
        pA_h, pA_l, W(0), pw_b + 0*Dn, nullptr,
        nullptr, nullptr, nullptr, nullptr, x2_h, x2_l);
    // 4-5. conv layer 1: + LN(x2; lnc0, slot 0); stats -> slot 1 (lnc1)
    dwconv_pair<<<DWB, 256>>>(x2_h, x2_l, dw_w + 1*Dn*Kn, dw_b + 1*Dn, pA_h, pA_l);
    gemm_mma<true,0,1,true,false><<<gemmGrid, 256, SMEM_SZ>>>(
        pA_h, pA_l, W(1), pw_b + 1*Dn, nullptr,
        x2_h, x2_l, lnc_g + 0, lnc_b + 0, x1_h, x1_l);
    // 6-7. conv layer 2: + LN(x1; lnc1, slot 1); stats -> slot 2 (lna)
    dwconv_pair<<<DWB, 256>>>(x1_h, x1_l, dw_w + 2*Dn*Kn, dw_b + 2*Dn, pA_h, pA_l);
    gemm_mma<true,1,2,true,false><<<gemmGrid, 256, SMEM_SZ>>>(
        pA_h, pA_l, W(2), pw_b + 2*Dn, nullptr,
        x1_h, x1_l, lnc_g + Ln*Dn, lnc_b + Ln*Dn, x2_h, x2_l);

    // 8. merged qkv projection (q 2-term, k/v 1-term)
    gemm_qkv<<<qkvGrid, 256, SMEM_SZ>>>(x2_h, x2_l, bq, bk, bv);

    // 9. fused flash attention -> pA pair
    attn_fused<<<dim3(Ln/128, Bn*Hn), 256, SMEM_ATT>>>(
        q_h, q_l, k_h, v_h, mask, pA_h, pA_l);

    // 10. fc + LN(x2; lna, slot 2) -> x1 pair; stats -> slot 3 (lno)
    gemm_mma<false,2,3,true,false><<<gemmGrid, 256, SMEM_SZ>>>(
        pA_h, pA_l, W(6), fc_b, nullptr,
        x2_h, x2_l, lna_g, lna_b, x1_h, x1_l);

    // 11. out + LN(x1; lno, slot 3) -> d_out (fp32)
    gemm_mma<false,3,-1,false,true><<<gemmGrid, 256, SMEM_SZ>>>(
        x1_h, x1_l, W(7), out_b, out,
        x1_h, x1_l, lno_g, lno_b, nullptr, nullptr);
}

// round 14
// speedup vs baseline: 4.2186x; 1.2525x over previous
#include <cuda_runtime.h>
#include <cuda_fp16.h>
#include <cstdint>

#define Bn 32
#define Ln 512
#define Dn 512
#define Hn 8
#define DHn 64
#define Kn 7
#define Mn (Bn*Ln)
#define NEGV (-1e30f)
#define LDINV (1.0f/(float)(Ln*Dn))
#define TLC 8

// ---- big-GEMM tiling ----
#define BK 32
#define PITCH 40
#define TB (128*PITCH*2)
#define BUFB (3*TB)
#define SMEM_SZ (3*BUFB)            // 92160 B

// ---- fused attention smem (Q hi-only, KV chunk 64) ----
#define AP 144
#define QT (128*AP)                 // 18432 B
#define KVT (64*AP)                 // 9216 B
#define KVB (2*KVT)                 // khi+vhi = 18432 B
#define SMEM_ATT (QT + 2*KVB + 1024)    // 56320 B

// ======================= PTX helpers =======================
__device__ __forceinline__ uint32_t smem_u32(const void* p){
    uint32_t a;
    asm("{ .reg .u64 t; cvta.to.shared.u64 t, %1; cvt.u32.u64 %0, t; }" : "=r"(a) : "l"(p));
    return a;
}
__device__ __forceinline__ void cpasync16(uint32_t dst, const void* src){
    asm volatile("cp.async.cg.shared.global [%0], [%1], 16;" :: "r"(dst), "l"(src) : "memory");
}
#define CP_COMMIT() asm volatile("cp.async.commit_group;" ::: "memory")
#define CP_WAIT(N)  asm volatile("cp.async.wait_group %0;" :: "n"(N) : "memory")
__device__ __forceinline__ void ldsm4(uint32_t* r, uint32_t addr){
    asm volatile("ldmatrix.sync.aligned.m8n8.x4.shared.b16 {%0,%1,%2,%3}, [%4];"
        : "=r"(r[0]), "=r"(r[1]), "=r"(r[2]), "=r"(r[3]) : "r"(addr));
}
__device__ __forceinline__ void ldsm4t(uint32_t* r, uint32_t addr){
    asm volatile("ldmatrix.sync.aligned.m8n8.x4.trans.shared.b16 {%0,%1,%2,%3}, [%4];"
        : "=r"(r[0]), "=r"(r[1]), "=r"(r[2]), "=r"(r[3]) : "r"(addr));
}
__device__ __forceinline__ void mma16816(float* d, const uint32_t* a, const uint32_t* b){
    asm volatile("mma.sync.aligned.m16n8k16.row.col.f32.f16.f16.f32 "
        "{%0,%1,%2,%3}, {%4,%5,%6,%7}, {%8,%9}, {%0,%1,%2,%3};"
        : "+f"(d[0]), "+f"(d[1]), "+f"(d[2]), "+f"(d[3])
        : "r"(a[0]), "r"(a[1]), "r"(a[2]), "r"(a[3]), "r"(b[0]), "r"(b[1]));
}
__device__ __forceinline__ void packpair(float x, float y, uint32_t& hi, uint32_t& lo){
    __half hx = __float2half_rn(x), hy = __float2half_rn(y);
    __half2 h; h.x = hx; h.y = hy;
    __half2 l;
    l.x = __float2half_rn(x - __half2float(hx));
    l.y = __float2half_rn(y - __half2float(hy));
    hi = *(uint32_t*)&h; lo = *(uint32_t*)&l;
}
__device__ __forceinline__ uint32_t packhi(float x, float y){
    __half2 h; h.x = __float2half_rn(x); h.y = __float2half_rn(y);
    return *(uint32_t*)&h;
}
__device__ __forceinline__ float2 unpackpair(uint32_t hi, uint32_t lo){
    __half2 h = *(__half2*)&hi, l = *(__half2*)&lo;
    float2 r;
    r.x = __half2float(h.x) + __half2float(l.x);
    r.y = __half2float(h.y) + __half2float(l.y);
    return r;
}

// ======================= scratch =======================
__device__ float g_pS [4][Bn];
__device__ float g_pS2[4][Bn];
__device__ __half g_pA [2][Mn*Dn];     // [0]=hi (dwconv out / attn out hi), [1]=lo (attn out lo)
__device__ __half g_pX2[2][Mn*Dn];
__device__ __half g_pX1[2][Mn*Dn];
__device__ __half g_qkv[3][Mn*Dn];     // qhi, khi, vhi
__device__ __half g_w[8][Dn*Dn];

// ======================= weight prep + LN-partial zeroing =======================
__global__ void prep_weights(const float* __restrict__ pw_w,
                             const float* __restrict__ wq, const float* __restrict__ wk,
                             const float* __restrict__ wv,
                             const float* __restrict__ fc_w, const float* __restrict__ out_w)
{
    if (blockIdx.x == 0 && threadIdx.x < 4*Bn) {
        (&g_pS[0][0])[threadIdx.x]  = 0.f;
        (&g_pS2[0][0])[threadIdx.x] = 0.f;
    }
    int task = blockIdx.x >> 10;
    int idx  = (blockIdx.x & 1023) * 256 + threadIdx.x;
    if (task < 3) {
        g_w[task][idx] = __float2half_rn(pw_w[(size_t)task*Dn*Dn + idx]);
    } else if (task == 3) {
        int n = idx >> 9, d = idx & 511;
        int src = (n >> 6) * (Dn * DHn) + d * DHn + (n & 63);
        g_w[3][idx] = __float2half_rn(wq[src]);
        g_w[4][idx] = __float2half_rn(wk[src]);
        g_w[5][idx] = __float2half_rn(wv[src]);
    } else if (task == 4) {
        g_w[6][idx] = __float2half_rn(fc_w[idx]);
    } else {
        g_w[7][idx] = __float2half_rn(out_w[idx]);
    }
}

// ======================= sliding-window depthwise conv (hi-only output) =======================
__global__ void dwconv_pe(const float* __restrict__ x, const float* __restrict__ pe,
                          const float* __restrict__ w, const float* __restrict__ bias,
                          __half* __restrict__ hi)
{
    int idx = blockIdx.x * 256 + threadIdx.x;
    int d  = (idx & 127) << 2;
    int l0 = ((idx >> 7) & 63) << 3;
    int b  = idx >> 13;

    float wr[4][Kn];
#pragma unroll
    for (int c = 0; c < 4; c++)
#pragma unroll
        for (int kk = 0; kk < Kn; kk++) wr[c][kk] = w[(d + c)*Kn + kk];

    float4 bs = *(const float4*)(bias + d);
    float4 acc[TLC];
#pragma unroll
    for (int j = 0; j < TLC; j++) acc[j] = bs;

#pragma unroll
    for (int i = 0; i < TLC + 6; i++){
        int ll = l0 - 3 + i;
        if (ll >= 0 && ll < Ln){
            float4 xv = *(const float4*)(x + ((size_t)(b*Ln + ll))*Dn + d);
            float4 pv = *(const float4*)(pe + (size_t)ll*Dn + d);
            xv.x += pv.x; xv.y += pv.y; xv.z += pv.z; xv.w += pv.w;
#pragma unroll
            for (int kk = 0; kk < Kn; kk++){
                int j = i - kk;
                if (j >= 0 && j < TLC){
                    acc[j].x = fmaf(xv.x, wr[0][kk], acc[j].x);
                    acc[j].y = fmaf(xv.y, wr[1][kk], acc[j].y);
                    acc[j].z = fmaf(xv.z, wr[2][kk], acc[j].z);
                    acc[j].w = fmaf(xv.w, wr[3][kk], acc[j].w);
                }
            }
        }
    }
#pragma unroll
    for (int j = 0; j < TLC; j++){
        float vx = fmaxf(acc[j].x, 0.f), vy = fmaxf(acc[j].y, 0.f);
        float vz = fmaxf(acc[j].z, 0.f), vw = fmaxf(acc[j].w, 0.f);
        size_t o = ((size_t)(b*Ln + l0 + j))*Dn + d;
        uint2 hv; hv.x = packhi(vx, vy); hv.y = packhi(vz, vw);
        *(uint2*)(hi + o) = hv;
    }
}

__global__ void dwconv_pair(const __half* __restrict__ xh, const __half* __restrict__ xl,
                            const float* __restrict__ w, const float* __restrict__ bias,
                            __half* __restrict__ hi)
{
    int idx = blockIdx.x * 256 + threadIdx.x;
    int d  = (idx & 127) << 2;
    int l0 = ((idx >> 7) & 63) << 3;
    int b  = idx >> 13;

    float wr[4][Kn];
#pragma unroll
    for (int c = 0; c < 4; c++)
#pragma unroll
        for (int kk = 0; kk < Kn; kk++) wr[c][kk] = w[(d + c)*Kn + kk];

    float4 bs = *(const float4*)(bias + d);
    float4 acc[TLC];
#pragma unroll
    for (int j = 0; j < TLC; j++) acc[j] = bs;

#pragma unroll
    for (int i = 0; i < TLC + 6; i++){
        int ll = l0 - 3 + i;
        if (ll >= 0 && ll < Ln){
            size_t base = ((size_t)(b*Ln + ll))*Dn + d;
            uint2 hv = *(const uint2*)(xh + base);
            uint2 lv = *(const uint2*)(xl + base);
            float2 a0 = unpackpair(hv.x, lv.x);
            float2 a1 = unpackpair(hv.y, lv.y);
            float4 xv; xv.x = a0.x; xv.y = a0.y; xv.z = a1.x; xv.w = a1.y;
#pragma unroll
            for (int kk = 0; kk < Kn; kk++){
                int j = i - kk;
                if (j >= 0 && j < TLC){
                    acc[j].x = fmaf(xv.x, wr[0][kk], acc[j].x);
                    acc[j].y = fmaf(xv.y, wr[1][kk], acc[j].y);
                    acc[j].z = fmaf(xv.z, wr[2][kk], acc[j].z);
                    acc[j].w = fmaf(xv.w, wr[3][kk], acc[j].w);
                }
            }
        }
    }
#pragma unroll
    for (int j = 0; j < TLC; j++){
        float vx = fmaxf(acc[j].x, 0.f), vy = fmaxf(acc[j].y, 0.f);
        float vz = fmaxf(acc[j].z, 0.f), vw = fmaxf(acc[j].w, 0.f);
        size_t o = ((size_t)(b*Ln + l0 + j))*Dn + d;
        uint2 hv; hv.x = packhi(vx, vy); hv.y = packhi(vz, vw);
        *(uint2*)(hi + o) = hv;
    }
}

// ======================= mma.sync GEMM (A 1- or 2-term, 4x2 warp layout) =======================
template<bool RELU, int LNIN, int LNOUT, bool SPL, bool WRITEC, bool A2>
__global__ __launch_bounds__(256, 2) void gemm_mma(
    const __half* __restrict__ Ahi, const __half* __restrict__ Alo,
    const __half* __restrict__ Whi,
    const float* __restrict__ bias, float* __restrict__ C,
    const __half* __restrict__ Rhi, const __half* __restrict__ Rlo,
    const float* __restrict__ lng, const float* __restrict__ lnb,
    __half* __restrict__ Chi, __half* __restrict__ Clo)
{
    extern __shared__ __align__(16) char dsm[];
    const uint32_t sb = smem_u32(dsm);
    const int tid = threadIdx.x;
    const int wid = tid >> 5, lane = tid & 31;
    const int warpRow = wid & 3, warpCol = wid >> 2;
    const int bx = blockIdx.x, by = blockIdx.y;

    const __half* srcs[3] = {Ahi, Alo, Whi};
    const int rowb[3] = { by*128, by*128, bx*128 };

    auto PREF = [&](int kt){
        uint32_t bufb = sb + (uint32_t)(kt % 3) * BUFB;
#pragma unroll
        for (int t = 0; t < 3; t++){
            if (!A2 && t == 1) continue;
            const __half* src = srcs[t] + (size_t)rowb[t]*Dn + kt*BK;
            uint32_t tb = bufb + (uint32_t)t*TB;
#pragma unroll
            for (int i = 0; i < 2; i++){
                int id  = tid + i*256;
                int row = id >> 2, c = id & 3;
                cpasync16(tb + (uint32_t)(row*(PITCH*2) + c*16),
                          src + (size_t)row*Dn + c*8);
            }
        }
        CP_COMMIT();
    };

    float acc[2][8][4];
#pragma unroll
    for (int i = 0; i < 2; i++)
#pragma unroll
        for (int j = 0; j < 8; j++)
#pragma unroll
            for (int q = 0; q < 4; q++) acc[i][j][q] = 0.f;

    const uint32_t aRow = (uint32_t)(warpRow*32 + (lane & 15));
    const uint32_t aColB = (uint32_t)(((lane >> 4) << 4));
    const uint32_t bRow = (uint32_t)(warpCol*64 + (lane & 7) + ((lane >> 4) << 3));
    const uint32_t bColB = (uint32_t)((((lane >> 3) & 1) << 4));

    PREF(0);
    PREF(1);
#pragma unroll 1
    for (int kt = 0; kt < Dn/BK; kt++){
        if (kt + 1 < Dn/BK) { CP_WAIT(1); } else { CP_WAIT(0); }
        __syncthreads();
        if (kt + 2 < Dn/BK) PREF(kt + 2);

        uint32_t bufb = sb + (uint32_t)(kt % 3) * BUFB;
        uint32_t tAhi = bufb, tAlo = bufb + TB, tWhi = bufb + 2*TB;
#pragma unroll
        for (int kk = 0; kk < 2; kk++){
            uint32_t ah[2][4], al[2][4], bh[4][4];
#pragma unroll
            for (int mi = 0; mi < 2; mi++){
                ldsm4(ah[mi], tAhi + (aRow + mi*16)*(PITCH*2) + aColB + kk*32);
                if (A2) ldsm4(al[mi], tAlo + (aRow + mi*16)*(PITCH*2) + aColB + kk*32);
            }
#pragma unroll
            for (int nt = 0; nt < 4; nt++)
                ldsm4(bh[nt], tWhi + (bRow + nt*16)*(PITCH*2) + bColB + kk*32);
#pragma unroll
            for (int mi = 0; mi < 2; mi++)
#pragma unroll
                for (int nj = 0; nj < 8; nj++){
                    mma16816(acc[mi][nj], ah[mi], &bh[nj >> 1][(nj & 1) << 1]);
                    if (A2) mma16816(acc[mi][nj], al[mi], &bh[nj >> 1][(nj & 1) << 1]);
                }
        }
    }

    float muv = 0.f, rsv = 0.f;
    if (LNIN >= 0) {
        int bb = (by*128) >> 9;
        float s = g_pS[LNIN][bb], s2 = g_pS2[LNIN][bb];
        muv = s * LDINV;
        rsv = rsqrtf(s2 * LDINV - muv*muv + 1e-5f);
    }
    const int r0base = by*128 + warpRow*32;
    const int c0base = bx*128 + warpCol*64;
    float ts = 0.f, ts2 = 0.f;
#pragma unroll
    for (int mi = 0; mi < 2; mi++){
#pragma unroll
        for (int rp = 0; rp < 2; rp++){
            int grow = r0base + mi*16 + (lane >> 2) + rp*8;
            int lrow = grow & (Ln - 1);
#pragma unroll
            for (int nj = 0; nj < 8; nj++){
                int col = c0base + nj*8 + (lane & 3)*2;
                float vx = acc[mi][nj][rp*2 + 0];
                float vy = acc[mi][nj][rp*2 + 1];
                float2 bs = *(const float2*)(bias + col);
                vx += bs.x; vy += bs.y;
                if (RELU) { vx = fmaxf(vx, 0.f); vy = fmaxf(vy, 0.f); }
                size_t off = (size_t)grow*Dn + col;
                if (LNIN >= 0) {
                    float2 rr = unpackpair(*(const uint32_t*)(Rhi + off),
                                           *(const uint32_t*)(Rlo + off));
                    float2 gg = *(const float2*)(lng + (size_t)lrow*Dn + col);
                    float2 bb = *(const float2*)(lnb + (size_t)lrow*Dn + col);
                    vx += (rr.x - muv)*rsv*gg.x + bb.x;
                    vy += (rr.y - muv)*rsv*gg.y + bb.y;
                }
                if (LNOUT >= 0) { ts += vx + vy; ts2 += vx*vx + vy*vy; }
                if (WRITEC) {
                    float2 o; o.x = vx; o.y = vy;
                    *(float2*)(C + off) = o;
                }
                if (SPL) {
                    uint32_t hi, lo;
                    packpair(vx, vy, hi, lo);
                    *(uint32_t*)(Chi + off) = hi;
                    *(uint32_t*)(Clo + off) = lo;
                }
            }
        }
    }
    if (LNOUT >= 0) {
#pragma unroll
        for (int o = 16; o > 0; o >>= 1){
            ts  += __shfl_xor_sync(0xffffffffu, ts,  o);
            ts2 += __shfl_xor_sync(0xffffffffu, ts2, o);
        }
        __shared__ float sred[2][8];
        if (lane == 0){ sred[0][wid] = ts; sred[1][wid] = ts2; }
        __syncthreads();
        if (tid == 0){
            float a = 0.f, b2 = 0.f;
#pragma unroll
            for (int i = 0; i < 8; i++){ a += sred[0][i]; b2 += sred[1][i]; }
            int batch = by >> 2;
            atomicAdd(&g_pS[LNOUT][batch],  a);
            atomicAdd(&g_pS2[LNOUT][batch], b2);
        }
    }
}

// ======================= merged qkv GEMM (all 1-term A, hi-only outputs) =======================
__global__ __launch_bounds__(256, 2) void gemm_qkv(
    const __half* __restrict__ Ahi,
    const float* __restrict__ bq, const float* __restrict__ bk, const float* __restrict__ bv)
{
    extern __shared__ __align__(16) char dsm[];
    const uint32_t sb = smem_u32(dsm);
    const int tid = threadIdx.x;
    const int wid = tid >> 5, lane = tid & 31;
    const int warpRow = wid & 3, warpCol = wid >> 2;
    const int bx = blockIdx.x, by = blockIdx.y;
    const int seg = bx >> 2, bxl = bx & 3;

    const __half* Whi = g_w[3 + seg];
    const float* bias = (seg == 0) ? bq : ((seg == 1) ? bk : bv);
    __half* Ch = g_qkv[seg];

    const __half* srcs[2] = {Ahi, Whi};
    const int rowb[2] = { by*128, bxl*128 };

    auto PREF = [&](int kt){
        uint32_t bufb = sb + (uint32_t)(kt % 3) * BUFB;
#pragma unroll
        for (int t = 0; t < 2; t++){
            const __half* src = srcs[t] + (size_t)rowb[t]*Dn + kt*BK;
            uint32_t tb = bufb + (uint32_t)(t << 1)*TB;    // slots 0 and 2
#pragma unroll
            for (int i = 0; i < 2; i++){
                int id  = tid + i*256;
                int row = id >> 2, c = id & 3;
                cpasync16(tb + (uint32_t)(row*(PITCH*2) + c*16),
                          src + (size_t)row*Dn + c*8);
            }
        }
        CP_COMMIT();
    };

    float acc[2][8][4];
#pragma unroll
    for (int i = 0; i < 2; i++)
#pragma unroll
        for (int j = 0; j < 8; j++)
#pragma unroll
            for (int q = 0; q < 4; q++) acc[i][j][q] = 0.f;

    const uint32_t aRow = (uint32_t)(warpRow*32 + (lane & 15));
    const uint32_t aColB = (uint32_t)(((lane >> 4) << 4));
    const uint32_t bRow = (uint32_t)(warpCol*64 + (lane & 7) + ((lane >> 4) << 3));
    const uint32_t bColB = (uint32_t)((((lane >> 3) & 1) << 4));

    PREF(0);
    PREF(1);
#pragma unroll 1
    for (int kt = 0; kt < Dn/BK; kt++){
        if (kt + 1 < Dn/BK) { CP_WAIT(1); } else { CP_WAIT(0); }
        __syncthreads();
        if (kt + 2 < Dn/BK) PREF(kt + 2);

        uint32_t bufb = sb + (uint32_t)(kt % 3) * BUFB;
        uint32_t tAhi = bufb, tWhi = bufb + 2*TB;
#pragma unroll
        for (int kk = 0; kk < 2; kk++){
            uint32_t ah[2][4], bh[4][4];
#pragma unroll
            for (int mi = 0; mi < 2; mi++)
                ldsm4(ah[mi], tAhi + (aRow + mi*16)*(PITCH*2) + aColB + kk*32);
#pragma unroll
            for (int nt = 0; nt < 4; nt++)
                ldsm4(bh[nt], tWhi + (bRow + nt*16)*(PITCH*2) + bColB + kk*32);
#pragma unroll
            for (int mi = 0; mi < 2; mi++)
#pragma unroll
                for (int nj = 0; nj < 8; nj++)
                    mma16816(acc[mi][nj], ah[mi], &bh[nj >> 1][(nj & 1) << 1]);
        }
    }

    const int r0base = by*128 + warpRow*32;
    const int c0base = bxl*128 + warpCol*64;
#pragma unroll
    for (int mi = 0; mi < 2; mi++){
#pragma unroll
        for (int rp = 0; rp < 2; rp++){
            int grow = r0base + mi*16 + (lane >> 2) + rp*8;
#pragma unroll
            for (int nj = 0; nj < 8; nj++){
                int col = c0base + nj*8 + (lane & 3)*2;
                float vx = acc[mi][nj][rp*2 + 0];
                float vy = acc[mi][nj][rp*2 + 1];
                float2 bs = *(const float2*)(bias + col);
                vx += bs.x; vy += bs.y;
                *(uint32_t*)(Ch + (size_t)grow*Dn + col) = packhi(vx, vy);
            }
        }
    }
}

// ======================= fused flash attention (pure fp16, KV chunk 64) =======================
__global__ __launch_bounds__(256, 2) void attn_fused(
    const __half* __restrict__ qh,
    const __half* __restrict__ kh, const __half* __restrict__ vh,
    const float* __restrict__ mask,
    __half* __restrict__ Ohi, __half* __restrict__ Olo)
{
    extern __shared__ __align__(16) char dsm[];
    const uint32_t sb = smem_u32(dsm);
    const int tid = threadIdx.x, wid = tid >> 5, lane = tid & 31;
    const int bh = blockIdx.y, b = bh >> 3, h = bh & 7;
    const int i0 = blockIdx.x * 128;
    const size_t qoff = ((size_t)(b*Ln + i0))*Dn + h*DHn;
    const size_t koff = ((size_t)(b*Ln))*Dn + h*DHn;

    const uint32_t smQh = sb;
    const uint32_t smKV0 = sb + QT;
    const uint32_t smMaskOff = QT + 2*KVB;

    auto LOADC = [&](int c){
        uint32_t base = smKV0 + (uint32_t)(c & 1)*KVB;
        size_t g0 = koff + (size_t)(c*64)*Dn;
#pragma unroll
        for (int i = 0; i < 2; i++){
            int id = tid + i*256; int row = id >> 3, seg = id & 7;
            size_t go = g0 + (size_t)row*Dn + seg*8;
            uint32_t so = (uint32_t)(row*AP + seg*16);
            cpasync16(base + so,       kh + go);
            cpasync16(base + KVT + so, vh + go);
        }
        if (tid < 16)
            cpasync16(sb + smMaskOff + (uint32_t)(c & 1)*256 + tid*16,
                      mask + b*Ln + c*64 + tid*4);
        CP_COMMIT();
    };

#pragma unroll
    for (int i = 0; i < 4; i++){
        int id = tid + i*256; int row = id >> 3, seg = id & 7;
        cpasync16(smQh + (uint32_t)(row*AP + seg*16),
                  qh + qoff + (size_t)row*Dn + seg*8);
    }
    LOADC(0);
    LOADC(1);

    const int g = lane >> 2, t4 = lane & 3;
    float mi0 = mask[b*Ln + i0 + wid*16 + g];
    float mi1 = mask[b*Ln + i0 + wid*16 + g + 8];

    float m0 = -3.0e38f, m1 = -3.0e38f, l0 = 0.f, l1 = 0.f;
    float o[8][4];
#pragma unroll
    for (int i = 0; i < 8; i++)
#pragma unroll
        for (int j = 0; j < 4; j++) o[i][j] = 0.f;

    const uint32_t aQoff = (uint32_t)((wid*16 + (lane & 15))*AP + ((lane >> 4) << 4));
    const uint32_t bKoff = (uint32_t)(((lane & 7) + ((lane >> 4) << 3))*AP + (((lane >> 3) & 1) << 4));
    const uint32_t vOff  = (uint32_t)((lane & 15)*AP + ((lane >> 4) << 4));

#pragma unroll 1
    for (int c = 0; c < 8; c++){
        if (c < 7) { CP_WAIT(1); } else { CP_WAIT(0); }
        __syncthreads();
        const uint32_t kb = smKV0 + (uint32_t)(c & 1)*KVB;
        const float* mjp = (const float*)(dsm + smMaskOff + (c & 1)*256);

        // ---- S = Q K^T (fp16) ----
        float s[8][4];
#pragma unroll
        for (int nj = 0; nj < 8; nj++)
#pragma unroll
            for (int q = 0; q < 4; q++) s[nj][q] = 0.f;
#pragma unroll
        for (int ss = 0; ss < 4; ss++){
            uint32_t ah[4];
            ldsm4(ah, smQh + aQoff + ss*32);
#pragma unroll
            for (int njp = 0; njp < 4; njp++){
                uint32_t bhh[4];
                ldsm4(bhh, kb + (uint32_t)(njp*16)*AP + bKoff + ss*32);
                mma16816(s[2*njp],   ah, &bhh[0]);
                mma16816(s[2*njp+1], ah, &bhh[2]);
            }
        }

        // ---- scale + mask + row max ----
        float rm0 = -3.0e38f, rm1 = -3.0e38f;
#pragma unroll
        for (int nj = 0; nj < 8; nj++){
            int colb = nj*8 + t4*2;
            float mj0 = mjp[colb], mj1 = mjp[colb+1];
            float mm;
            mm = mi0*mj0; s[nj][0] = s[nj][0]*0.125f*mm + NEGV*(1.f - mm);
            mm = mi0*mj1; s[nj][1] = s[nj][1]*0.125f*mm + NEGV*(1.f - mm);
            mm = mi1*mj0; s[nj][2] = s[nj][2]*0.125f*mm + NEGV*(1.f - mm);
            mm = mi1*mj1; s[nj][3] = s[nj][3]*0.125f*mm + NEGV*(1.f - mm);
            rm0 = fmaxf(rm0, fmaxf(s[nj][0], s[nj][1]));
            rm1 = fmaxf(rm1, fmaxf(s[nj][2], s[nj][3]));
        }
        rm0 = fmaxf(rm0, __shfl_xor_sync(0xffffffffu, rm0, 1));
        rm0 = fmaxf(rm0, __shfl_xor_sync(0xffffffffu, rm0, 2));
        rm1 = fmaxf(rm1, __shfl_xor_sync(0xffffffffu, rm1, 1));
        rm1 = fmaxf(rm1, __shfl_xor_sync(0xffffffffu, rm1, 2));
        float nm0 = fmaxf(m0, rm0), nm1 = fmaxf(m1, rm1);
        float al0 = __expf(m0 - nm0), al1 = __expf(m1 - nm1);
        m0 = nm0; m1 = nm1;
#pragma unroll
        for (int nd = 0; nd < 8; nd++){
            o[nd][0] *= al0; o[nd][1] *= al0;
            o[nd][2] *= al1; o[nd][3] *= al1;
        }

        // ---- P = exp(S-m), O += P V ----
        float sum0 = 0.f, sum1 = 0.f;
#pragma unroll
        for (int ss = 0; ss < 4; ss++){
            float p00 = __expf(s[2*ss][0]   - nm0), p01 = __expf(s[2*ss][1]   - nm0);
            float p02 = __expf(s[2*ss][2]   - nm1), p03 = __expf(s[2*ss][3]   - nm1);
            float p10 = __expf(s[2*ss+1][0] - nm0), p11 = __expf(s[2*ss+1][1] - nm0);
            float p12 = __expf(s[2*ss+1][2] - nm1), p13 = __expf(s[2*ss+1][3] - nm1);
            sum0 += p00 + p01 + p10 + p11;
            sum1 += p02 + p03 + p12 + p13;
            uint32_t pah[4];
            pah[0] = packhi(p00, p01);
            pah[1] = packhi(p02, p03);
            pah[2] = packhi(p10, p11);
            pah[3] = packhi(p12, p13);
#pragma unroll
            for (int ndp = 0; ndp < 4; ndp++){
                uint32_t vhh[4];
                ldsm4t(vhh, kb + KVT + (uint32_t)(ss*16)*AP + vOff + ndp*32);
                mma16816(o[2*ndp],   pah, &vhh[0]);
                mma16816(o[2*ndp+1], pah, &vhh[2]);
            }
        }
        sum0 += __shfl_xor_sync(0xffffffffu, sum0, 1);
        sum0 += __shfl_xor_sync(0xffffffffu, sum0, 2);
        sum1 += __shfl_xor_sync(0xffffffffu, sum1, 1);
        sum1 += __shfl_xor_sync(0xffffffffu, sum1, 2);
        l0 = l0*al0 + sum0;
        l1 = l1*al1 + sum1;

        if (c < 6){ __syncthreads(); LOADC(c + 2); }
    }

    float inv0 = 1.f / l0, inv1 = 1.f / l1;
    int r0 = i0 + wid*16 + g, r1 = r0 + 8;
    size_t ob = ((size_t)(b*Ln))*Dn + h*DHn;
#pragma unroll
    for (int nd = 0; nd < 8; nd++){
        int col = nd*8 + t4*2;
        uint32_t hi0, lo0, hi1, lo1;
        packpair(o[nd][0]*inv0, o[nd][1]*inv0, hi0, lo0);
        packpair(o[nd][2]*inv1, o[nd][3]*inv1, hi1, lo1);
        *(uint32_t*)(Ohi + ob + (size_t)r0*Dn + col) = hi0;
        *(uint32_t*)(Olo + ob + (size_t)r0*Dn + col) = lo0;
        *(uint32_t*)(Ohi + ob + (size_t)r1*Dn + col) = hi1;
        *(uint32_t*)(Olo + ob + (size_t)r1*Dn + col) = lo1;
    }
}

// ======================= host orchestration =======================
extern "C" void kernel_launch(void* const* d_in, const int* in_sizes, int n_in,
                              void* d_out, int out_size)
{
    (void)in_sizes; (void)n_in; (void)out_size;
    const float* x     = (const float*)d_in[0];
    const float* mask  = (const float*)d_in[1];
    const float* pe    = (const float*)d_in[2];
    const float* dw_w  = (const float*)d_in[3];
    const float* dw_b  = (const float*)d_in[4];
    const float* pw_w  = (const float*)d_in[5];
    const float* pw_b  = (const float*)d_in[6];
    const float* wq    = (const float*)d_in[7];
    const float* bq    = (const float*)d_in[8];
    const float* wk    = (const float*)d_in[9];
    const float* bk    = (const float*)d_in[10];
    const float* wv    = (const float*)d_in[11];
    const float* bv    = (const float*)d_in[12];
    const float* fc_w  = (const float*)d_in[13];
    const float* fc_b  = (const float*)d_in[14];
    const float* out_w = (const float*)d_in[15];
    const float* out_b = (const float*)d_in[16];
    const float* lnc_g = (const float*)d_in[17];
    const float* lnc_b = (const float*)d_in[18];
    const float* lna_g = (const float*)d_in[19];
    const float* lna_b = (const float*)d_in[20];
    const float* lno_g = (const float*)d_in[21];
    const float* lno_b = (const float*)d_in[22];
    float* out = (float*)d_out;

    __half *pA, *pX2, *pX1, *qkv;
    cudaGetSymbolAddress((void**)&pA,  g_pA);
    cudaGetSymbolAddress((void**)&pX2, g_pX2);
    cudaGetSymbolAddress((void**)&pX1, g_pX1);
    cudaGetSymbolAddress((void**)&qkv, g_qkv);
    __half* wsym;
    cudaGetSymbolAddress((void**)&wsym, g_w);

    const size_t NN = (size_t)Mn*Dn;
    __half *pA_h = pA,  *pA_l = pA + NN;
    __half *x2_h = pX2, *x2_l = pX2 + NN;
    __half *x1_h = pX1, *x1_l = pX1 + NN;
    __half *q_h = qkv, *k_h = qkv + NN, *v_h = qkv + 2*NN;
    auto W = [&](int i){ return wsym + (size_t)i * Dn * Dn; };

    cudaFuncSetAttribute(gemm_mma<true,-1,0,true,false,false>,  cudaFuncAttributeMaxDynamicSharedMemorySize, SMEM_SZ);
    cudaFuncSetAttribute(gemm_mma<true,0,1,true,false,false>,   cudaFuncAttributeMaxDynamicSharedMemorySize, SMEM_SZ);
    cudaFuncSetAttribute(gemm_mma<true,1,2,true,false,false>,   cudaFuncAttributeMaxDynamicSharedMemorySize, SMEM_SZ);
    cudaFuncSetAttribute(gemm_mma<false,2,3,true,false,true>,   cudaFuncAttributeMaxDynamicSharedMemorySize, SMEM_SZ);
    cudaFuncSetAttribute(gemm_mma<false,3,-1,false,true,true>,  cudaFuncAttributeMaxDynamicSharedMemorySize, SMEM_SZ);
    cudaFuncSetAttribute(gemm_qkv, cudaFuncAttributeMaxDynamicSharedMemorySize, SMEM_SZ);
    cudaFuncSetAttribute(attn_fused, cudaFuncAttributeMaxDynamicSharedMemorySize, SMEM_ATT);

    const int DWB = (Bn * (Ln/TLC) * (Dn/4)) / 256;   // 1024 blocks
    dim3 gemmGrid(Dn/128, Mn/128);      // (4, 128)
    dim3 qkvGrid(12, Mn/128);           // N = 1536

    // 1. weight prep + LN-partial zeroing
    prep_weights<<<6*1024, 256>>>(pw_w, wq, wk, wv, fc_w, out_w);

    // 2-3. conv layer 0 (PE fused); A 1-term; stats -> slot 0 (lnc0)
    dwconv_pe<<<DWB, 256>>>(x, pe, dw_w + 0*Dn*Kn, dw_b + 0*Dn, pA_h);
    gemm_mma<true,-1,0,true,false,false><<<gemmGrid, 256, SMEM_SZ>>>(
        pA_h, nullptr, W(0), pw_b + 0*Dn, nullptr,
        nullptr, nullptr, nullptr, nullptr, x2_h, x2_l);
    // 4-5. conv layer 1: + LN(x2; lnc0, slot 0); stats -> slot 1 (lnc1)
    dwconv_pair<<<DWB, 256>>>(x2_h, x2_l, dw_w + 1*Dn*Kn, dw_b + 1*Dn, pA_h);
    gemm_mma<true,0,1,true,false,false><<<gemmGrid, 256, SMEM_SZ>>>(
        pA_h, nullptr, W(1), pw_b + 1*Dn, nullptr,
        x2_h, x2_l, lnc_g + 0, lnc_b + 0, x1_h, x1_l);
    // 6-7. conv layer 2: + LN(x1; lnc1, slot 1); stats -> slot 2 (lna)
    dwconv_pair<<<DWB, 256>>>(x1_h, x1_l, dw_w + 2*Dn*Kn, dw_b + 2*Dn, pA_h);
    gemm_mma<true,1,2,true,false,false><<<gemmGrid, 256, SMEM_SZ>>>(
        pA_h, nullptr, W(2), pw_b + 2*Dn, nullptr,
        x1_h, x1_l, lnc_g + Ln*Dn, lnc_b + Ln*Dn, x2_h, x2_l);

    // 8. merged qkv projection (all 1-term, hi-only outputs)
    gemm_qkv<<<qkvGrid, 256, SMEM_SZ>>>(x2_h, bq, bk, bv);

    // 9. fused flash attention (pure fp16) -> pA pair
    attn_fused<<<dim3(Ln/128, Bn*Hn), 256, SMEM_ATT>>>(
        q_h, k_h, v_h, mask, pA_h, pA_l);

    // 10. fc (A 2-term) + LN(x2; lna, slot 2) -> x1 pair; stats -> slot 3 (lno)
    gemm_mma<false,2,3,true,false,true><<<gemmGrid, 256, SMEM_SZ>>>(
        pA_h, pA_l, W(6), fc_b, nullptr,
        x2_h, x2_l, lna_g, lna_b, x1_h, x1_l);

    // 11. out (A 2-term) + LN(x1; lno, slot 3) -> d_out (fp32)
    gemm_mma<false,3,-1,false,true,true><<<gemmGrid, 256, SMEM_SZ>>>(
        x1_h, x1_l, W(7), out_b, out,
        x1_h, x1_l, lno_g, lno_b, nullptr, nullptr);
}

// round 15
// speedup vs baseline: 4.5764x; 1.0848x over previous
#include <cuda_runtime.h>
#include <cuda_fp16.h>
#include <cstdint>

#define Bn 32
#define Ln 512
#define Dn 512
#define Hn 8
#define DHn 64
#define Kn 7
#define Mn (Bn*Ln)
#define NEGV (-1e30f)
#define LDINV (1.0f/(float)(Ln*Dn))
#define TLC 8

// ---- big-GEMM tiling ----
#define BK 32
#define PITCH 40
#define TB (128*PITCH*2)
#define BUFB (3*TB)
#define SMEM_SZ (3*BUFB)            // 92160 B

// ---- fused attention smem (Q hi-only, KV chunk 64) ----
#define AP 144
#define QT (128*AP)                 // 18432 B
#define KVT (64*AP)                 // 9216 B
#define KVB (2*KVT)                 // khi+vhi = 18432 B
#define SMEM_ATT (QT + 2*KVB + 1024)    // 56320 B

// ======================= PTX helpers =======================
__device__ __forceinline__ uint32_t smem_u32(const void* p){
    uint32_t a;
    asm("{ .reg .u64 t; cvta.to.shared.u64 t, %1; cvt.u32.u64 %0, t; }" : "=r"(a) : "l"(p));
    return a;
}
__device__ __forceinline__ void cpasync16(uint32_t dst, const void* src){
    asm volatile("cp.async.cg.shared.global [%0], [%1], 16;" :: "r"(dst), "l"(src) : "memory");
}
#define CP_COMMIT() asm volatile("cp.async.commit_group;" ::: "memory")
#define CP_WAIT(N)  asm volatile("cp.async.wait_group %0;" :: "n"(N) : "memory")
__device__ __forceinline__ void ldsm4(uint32_t* r, uint32_t addr){
    asm volatile("ldmatrix.sync.aligned.m8n8.x4.shared.b16 {%0,%1,%2,%3}, [%4];"
        : "=r"(r[0]), "=r"(r[1]), "=r"(r[2]), "=r"(r[3]) : "r"(addr));
}
__device__ __forceinline__ void ldsm4t(uint32_t* r, uint32_t addr){
    asm volatile("ldmatrix.sync.aligned.m8n8.x4.trans.shared.b16 {%0,%1,%2,%3}, [%4];"
        : "=r"(r[0]), "=r"(r[1]), "=r"(r[2]), "=r"(r[3]) : "r"(addr));
}
__device__ __forceinline__ void mma16816(float* d, const uint32_t* a, const uint32_t* b){
    asm volatile("mma.sync.aligned.m16n8k16.row.col.f32.f16.f16.f32 "
        "{%0,%1,%2,%3}, {%4,%5,%6,%7}, {%8,%9}, {%0,%1,%2,%3};"
        : "+f"(d[0]), "+f"(d[1]), "+f"(d[2]), "+f"(d[3])
        : "r"(a[0]), "r"(a[1]), "r"(a[2]), "r"(a[3]), "r"(b[0]), "r"(b[1]));
}
__device__ __forceinline__ void packpair(float x, float y, uint32_t& hi, uint32_t& lo){
    __half hx = __float2half_rn(x), hy = __float2half_rn(y);
    __half2 h; h.x = hx; h.y = hy;
    __half2 l;
    l.x = __float2half_rn(x - __half2float(hx));
    l.y = __float2half_rn(y - __half2float(hy));
    hi = *(uint32_t*)&h; lo = *(uint32_t*)&l;
}
__device__ __forceinline__ uint32_t packhi(float x, float y){
    __half2 h; h.x = __float2half_rn(x); h.y = __float2half_rn(y);
    return *(uint32_t*)&h;
}
__device__ __forceinline__ float2 unpackpair(uint32_t hi, uint32_t lo){
    __half2 h = *(__half2*)&hi, l = *(__half2*)&lo;
    float2 r;
    r.x = __half2float(h.x) + __half2float(l.x);
    r.y = __half2float(h.y) + __half2float(l.y);
    return r;
}

// ======================= scratch =======================
__device__ float g_pS [4][Bn];
__device__ float g_pS2[4][Bn];
__device__ __half g_pA [Mn*Dn];        // dwconv out / attn out (hi only)
__device__ __half g_pX2[2][Mn*Dn];
__device__ __half g_pX1[2][Mn*Dn];
__device__ __half g_qkv[3][Mn*Dn];     // qhi, khi, vhi
__device__ __half g_w[8][Dn*Dn];

// ======================= weight prep + LN-partial zeroing =======================
__global__ void prep_weights(const float* __restrict__ pw_w,
                             const float* __restrict__ wq, const float* __restrict__ wk,
                             const float* __restrict__ wv,
                             const float* __restrict__ fc_w, const float* __restrict__ out_w)
{
    if (blockIdx.x == 0 && threadIdx.x < 4*Bn) {
        (&g_pS[0][0])[threadIdx.x]  = 0.f;
        (&g_pS2[0][0])[threadIdx.x] = 0.f;
    }
    int task = blockIdx.x >> 10;
    int idx  = (blockIdx.x & 1023) * 256 + threadIdx.x;
    if (task < 3) {
        g_w[task][idx] = __float2half_rn(pw_w[(size_t)task*Dn*Dn + idx]);
    } else if (task == 3) {
        int n = idx >> 9, d = idx & 511;
        int src = (n >> 6) * (Dn * DHn) + d * DHn + (n & 63);
        g_w[3][idx] = __float2half_rn(wq[src]);
        g_w[4][idx] = __float2half_rn(wk[src]);
        g_w[5][idx] = __float2half_rn(wv[src]);
    } else if (task == 4) {
        g_w[6][idx] = __float2half_rn(fc_w[idx]);
    } else {
        g_w[7][idx] = __float2half_rn(out_w[idx]);
    }
}

// ======================= sliding-window depthwise conv (hi-only output) =======================
__global__ void dwconv_pe(const float* __restrict__ x, const float* __restrict__ pe,
                          const float* __restrict__ w, const float* __restrict__ bias,
                          __half* __restrict__ hi)
{
    int idx = blockIdx.x * 256 + threadIdx.x;
    int d  = (idx & 127) << 2;
    int l0 = ((idx >> 7) & 63) << 3;
    int b  = idx >> 13;

    float wr[4][Kn];
#pragma unroll
    for (int c = 0; c < 4; c++)
#pragma unroll
        for (int kk = 0; kk < Kn; kk++) wr[c][kk] = w[(d + c)*Kn + kk];

    float4 bs = *(const float4*)(bias + d);
    float4 acc[TLC];
#pragma unroll
    for (int j = 0; j < TLC; j++) acc[j] = bs;

#pragma unroll
    for (int i = 0; i < TLC + 6; i++){
        int ll = l0 - 3 + i;
        if (ll >= 0 && ll < Ln){
            float4 xv = *(const float4*)(x + ((size_t)(b*Ln + ll))*Dn + d);
            float4 pv = *(const float4*)(pe + (size_t)ll*Dn + d);
            xv.x += pv.x; xv.y += pv.y; xv.z += pv.z; xv.w += pv.w;
#pragma unroll
            for (int kk = 0; kk < Kn; kk++){
                int j = i - kk;
                if (j >= 0 && j < TLC){
                    acc[j].x = fmaf(xv.x, wr[0][kk], acc[j].x);
                    acc[j].y = fmaf(xv.y, wr[1][kk], acc[j].y);
                    acc[j].z = fmaf(xv.z, wr[2][kk], acc[j].z);
                    acc[j].w = fmaf(xv.w, wr[3][kk], acc[j].w);
                }
            }
        }
    }
#pragma unroll
    for (int j = 0; j < TLC; j++){
        float vx = fmaxf(acc[j].x, 0.f), vy = fmaxf(acc[j].y, 0.f);
        float vz = fmaxf(acc[j].z, 0.f), vw = fmaxf(acc[j].w, 0.f);
        size_t o = ((size_t)(b*Ln + l0 + j))*Dn + d;
        uint2 hv; hv.x = packhi(vx, vy); hv.y = packhi(vz, vw);
        *(uint2*)(hi + o) = hv;
    }
}

__global__ void dwconv_pair(const __half* __restrict__ xh, const __half* __restrict__ xl,
                            const float* __restrict__ w, const float* __restrict__ bias,
                            __half* __restrict__ hi)
{
    int idx = blockIdx.x * 256 + threadIdx.x;
    int d  = (idx & 127) << 2;
    int l0 = ((idx >> 7) & 63) << 3;
    int b  = idx >> 13;

    float wr[4][Kn];
#pragma unroll
    for (int c = 0; c < 4; c++)
#pragma unroll
        for (int kk = 0; kk < Kn; kk++) wr[c][kk] = w[(d + c)*Kn + kk];

    float4 bs = *(const float4*)(bias + d);
    float4 acc[TLC];
#pragma unroll
    for (int j = 0; j < TLC; j++) acc[j] = bs;

#pragma unroll
    for (int i = 0; i < TLC + 6; i++){
        int ll = l0 - 3 + i;
        if (ll >= 0 && ll < Ln){
            size_t base = ((size_t)(b*Ln + ll))*Dn + d;
            uint2 hv = *(const uint2*)(xh + base);
            uint2 lv = *(const uint2*)(xl + base);
            float2 a0 = unpackpair(hv.x, lv.x);
            float2 a1 = unpackpair(hv.y, lv.y);
            float4 xv; xv.x = a0.x; xv.y = a0.y; xv.z = a1.x; xv.w = a1.y;
#pragma unroll
            for (int kk = 0; kk < Kn; kk++){
                int j = i - kk;
                if (j >= 0 && j < TLC){
                    acc[j].x = fmaf(xv.x, wr[0][kk], acc[j].x);
                    acc[j].y = fmaf(xv.y, wr[1][kk], acc[j].y);
                    acc[j].z = fmaf(xv.z, wr[2][kk], acc[j].z);
                    acc[j].w = fmaf(xv.w, wr[3][kk], acc[j].w);
                }
            }
        }
    }
#pragma unroll
    for (int j = 0; j < TLC; j++){
        float vx = fmaxf(acc[j].x, 0.f), vy = fmaxf(acc[j].y, 0.f);
        float vz = fmaxf(acc[j].z, 0.f), vw = fmaxf(acc[j].w, 0.f);
        size_t o = ((size_t)(b*Ln + l0 + j))*Dn + d;
        uint2 hv; hv.x = packhi(vx, vy); hv.y = packhi(vz, vw);
        *(uint2*)(hi + o) = hv;
    }
}

// ======================= mma.sync GEMM (A 1- or 2-term, 4x2 warp layout) =======================
template<bool RELU, int LNIN, int LNOUT, bool SPL, bool WRITEC, bool A2>
__global__ __launch_bounds__(256, 2) void gemm_mma(
    const __half* __restrict__ Ahi, const __half* __restrict__ Alo,
    const __half* __restrict__ Whi,
    const float* __restrict__ bias, float* __restrict__ C,
    const __half* __restrict__ Rhi, const __half* __restrict__ Rlo,
    const float* __restrict__ lng, const float* __restrict__ lnb,
    __half* __restrict__ Chi, __half* __restrict__ Clo)
{
    extern __shared__ __align__(16) char dsm[];
    const uint32_t sb = smem_u32(dsm);
    const int tid = threadIdx.x;
    const int wid = tid >> 5, lane = tid & 31;
    const int warpRow = wid & 3, warpCol = wid >> 2;
    const int bx = blockIdx.x, by = blockIdx.y;

    const __half* srcs[3] = {Ahi, Alo, Whi};
    const int rowb[3] = { by*128, by*128, bx*128 };

    auto PREF = [&](int kt){
        uint32_t bufb = sb + (uint32_t)(kt % 3) * BUFB;
#pragma unroll
        for (int t = 0; t < 3; t++){
            if (!A2 && t == 1) continue;
            const __half* src = srcs[t] + (size_t)rowb[t]*Dn + kt*BK;
            uint32_t tb = bufb + (uint32_t)t*TB;
#pragma unroll
            for (int i = 0; i < 2; i++){
                int id  = tid + i*256;
                int row = id >> 2, c = id & 3;
                cpasync16(tb + (uint32_t)(row*(PITCH*2) + c*16),
                          src + (size_t)row*Dn + c*8);
            }
        }
        CP_COMMIT();
    };

    float acc[2][8][4];
#pragma unroll
    for (int i = 0; i < 2; i++)
#pragma unroll
        for (int j = 0; j < 8; j++)
#pragma unroll
            for (int q = 0; q < 4; q++) acc[i][j][q] = 0.f;

    const uint32_t aRow = (uint32_t)(warpRow*32 + (lane & 15));
    const uint32_t aColB = (uint32_t)(((lane >> 4) << 4));
    const uint32_t bRow = (uint32_t)(warpCol*64 + (lane & 7) + ((lane >> 4) << 3));
    const uint32_t bColB = (uint32_t)((((lane >> 3) & 1) << 4));

    PREF(0);
    PREF(1);
#pragma unroll 1
    for (int kt = 0; kt < Dn/BK; kt++){
        if (kt + 1 < Dn/BK) { CP_WAIT(1); } else { CP_WAIT(0); }
        __syncthreads();
        if (kt + 2 < Dn/BK) PREF(kt + 2);

        uint32_t bufb = sb + (uint32_t)(kt % 3) * BUFB;
        uint32_t tAhi = bufb, tAlo = bufb + TB, tWhi = bufb + 2*TB;
#pragma unroll
        for (int kk = 0; kk < 2; kk++){
            uint32_t ah[2][4], al[2][4], bh[4][4];
#pragma unroll
            for (int mi = 0; mi < 2; mi++){
                ldsm4(ah[mi], tAhi + (aRow + mi*16)*(PITCH*2) + aColB + kk*32);
                if (A2) ldsm4(al[mi], tAlo + (aRow + mi*16)*(PITCH*2) + aColB + kk*32);
            }
#pragma unroll
            for (int nt = 0; nt < 4; nt++)
                ldsm4(bh[nt], tWhi + (bRow + nt*16)*(PITCH*2) + bColB + kk*32);
#pragma unroll
            for (int mi = 0; mi < 2; mi++)
#pragma unroll
                for (int nj = 0; nj < 8; nj++){
                    mma16816(acc[mi][nj], ah[mi], &bh[nj >> 1][(nj & 1) << 1]);
                    if (A2) mma16816(acc[mi][nj], al[mi], &bh[nj >> 1][(nj & 1) << 1]);
                }
        }
    }

    float muv = 0.f, rsv = 0.f;
    if (LNIN >= 0) {
        int bb = (by*128) >> 9;
        float s = g_pS[LNIN][bb], s2 = g_pS2[LNIN][bb];
        muv = s * LDINV;
        rsv = rsqrtf(s2 * LDINV - muv*muv + 1e-5f);
    }
    const int r0base = by*128 + warpRow*32;
    const int c0base = bx*128 + warpCol*64;
    float ts = 0.f, ts2 = 0.f;
#pragma unroll
    for (int mi = 0; mi < 2; mi++){
#pragma unroll
        for (int rp = 0; rp < 2; rp++){
            int grow = r0base + mi*16 + (lane >> 2) + rp*8;
            int lrow = grow & (Ln - 1);
#pragma unroll
            for (int nj = 0; nj < 8; nj++){
                int col = c0base + nj*8 + (lane & 3)*2;
                float vx = acc[mi][nj][rp*2 + 0];
                float vy = acc[mi][nj][rp*2 + 1];
                float2 bs = *(const float2*)(bias + col);
                vx += bs.x; vy += bs.y;
                if (RELU) { vx = fmaxf(vx, 0.f); vy = fmaxf(vy, 0.f); }
                size_t off = (size_t)grow*Dn + col;
                if (LNIN >= 0) {
                    float2 rr = unpackpair(*(const uint32_t*)(Rhi + off),
                                           *(const uint32_t*)(Rlo + off));
                    float2 gg = *(const float2*)(lng + (size_t)lrow*Dn + col);
                    float2 bb = *(const float2*)(lnb + (size_t)lrow*Dn + col);
                    vx += (rr.x - muv)*rsv*gg.x + bb.x;
                    vy += (rr.y - muv)*rsv*gg.y + bb.y;
                }
                if (LNOUT >= 0) { ts += vx + vy; ts2 += vx*vx + vy*vy; }
                if (WRITEC) {
                    float2 o; o.x = vx; o.y = vy;
                    *(float2*)(C + off) = o;
                }
                if (SPL) {
                    uint32_t hi, lo;
                    packpair(vx, vy, hi, lo);
                    *(uint32_t*)(Chi + off) = hi;
                    *(uint32_t*)(Clo + off) = lo;
                }
            }
        }
    }
    if (LNOUT >= 0) {
#pragma unroll
        for (int o = 16; o > 0; o >>= 1){
            ts  += __shfl_xor_sync(0xffffffffu, ts,  o);
            ts2 += __shfl_xor_sync(0xffffffffu, ts2, o);
        }
        __shared__ float sred[2][8];
        if (lane == 0){ sred[0][wid] = ts; sred[1][wid] = ts2; }
        __syncthreads();
        if (tid == 0){
            float a = 0.f, b2 = 0.f;
#pragma unroll
            for (int i = 0; i < 8; i++){ a += sred[0][i]; b2 += sred[1][i]; }
            int batch = by >> 2;
            atomicAdd(&g_pS[LNOUT][batch],  a);
            atomicAdd(&g_pS2[LNOUT][batch], b2);
        }
    }
}

// ======================= merged qkv GEMM (all 1-term A, hi-only outputs) =======================
__global__ __launch_bounds__(256, 2) void gemm_qkv(
    const __half* __restrict__ Ahi,
    const float* __restrict__ bq, const float* __restrict__ bk, const float* __restrict__ bv)
{
    extern __shared__ __align__(16) char dsm[];
    const uint32_t sb = smem_u32(dsm);
    const int tid = threadIdx.x;
    const int wid = tid >> 5, lane = tid & 31;
    const int warpRow = wid & 3, warpCol = wid >> 2;
    const int bx = blockIdx.x, by = blockIdx.y;
    const int seg = bx >> 2, bxl = bx & 3;

    const __half* Whi = g_w[3 + seg];
    const float* bias = (seg == 0) ? bq : ((seg == 1) ? bk : bv);
    __half* Ch = g_qkv[seg];

    const __half* srcs[2] = {Ahi, Whi};
    const int rowb[2] = { by*128, bxl*128 };

    auto PREF = [&](int kt){
        uint32_t bufb = sb + (uint32_t)(kt % 3) * BUFB;
#pragma unroll
        for (int t = 0; t < 2; t++){
            const __half* src = srcs[t] + (size_t)rowb[t]*Dn + kt*BK;
            uint32_t tb = bufb + (uint32_t)(t << 1)*TB;
#pragma unroll
            for (int i = 0; i < 2; i++){
                int id  = tid + i*256;
                int row = id >> 2, c = id & 3;
                cpasync16(tb + (uint32_t)(row*(PITCH*2) + c*16),
                          src + (size_t)row*Dn + c*8);
            }
        }
        CP_COMMIT();
    };

    float acc[2][8][4];
#pragma unroll
    for (int i = 0; i < 2; i++)
#pragma unroll
        for (int j = 0; j < 8; j++)
#pragma unroll
            for (int q = 0; q < 4; q++) acc[i][j][q] = 0.f;

    const uint32_t aRow = (uint32_t)(warpRow*32 + (lane & 15));
    const uint32_t aColB = (uint32_t)(((lane >> 4) << 4));
    const uint32_t bRow = (uint32_t)(warpCol*64 + (lane & 7) + ((lane >> 4) << 3));
    const uint32_t bColB = (uint32_t)((((lane >> 3) & 1) << 4));

    PREF(0);
    PREF(1);
#pragma unroll 1
    for (int kt = 0; kt < Dn/BK; kt++){
        if (kt + 1 < Dn/BK) { CP_WAIT(1); } else { CP_WAIT(0); }
        __syncthreads();
        if (kt + 2 < Dn/BK) PREF(kt + 2);

        uint32_t bufb = sb + (uint32_t)(kt % 3) * BUFB;
        uint32_t tAhi = bufb, tWhi = bufb + 2*TB;
#pragma unroll
        for (int kk = 0; kk < 2; kk++){
            uint32_t ah[2][4], bh[4][4];
#pragma unroll
            for (int mi = 0; mi < 2; mi++)
                ldsm4(ah[mi], tAhi + (aRow + mi*16)*(PITCH*2) + aColB + kk*32);
#pragma unroll
            for (int nt = 0; nt < 4; nt++)
                ldsm4(bh[nt], tWhi + (bRow + nt*16)*(PITCH*2) + bColB + kk*32);
#pragma unroll
            for (int mi = 0; mi < 2; mi++)
#pragma unroll
                for (int nj = 0; nj < 8; nj++)
                    mma16816(acc[mi][nj], ah[mi], &bh[nj >> 1][(nj & 1) << 1]);
        }
    }

    const int r0base = by*128 + warpRow*32;
    const int c0base = bxl*128 + warpCol*64;
#pragma unroll
    for (int mi = 0; mi < 2; mi++){
#pragma unroll
        for (int rp = 0; rp < 2; rp++){
            int grow = r0base + mi*16 + (lane >> 2) + rp*8;
#pragma unroll
            for (int nj = 0; nj < 8; nj++){
                int col = c0base + nj*8 + (lane & 3)*2;
                float vx = acc[mi][nj][rp*2 + 0];
                float vy = acc[mi][nj][rp*2 + 1];
                float2 bs = *(const float2*)(bias + col);
                vx += bs.x; vy += bs.y;
                *(uint32_t*)(Ch + (size_t)grow*Dn + col) = packhi(vx, vy);
            }
        }
    }
}

// ======================= fused flash attention (pure fp16, hi-only output) =======================
__global__ __launch_bounds__(256, 2) void attn_fused(
    const __half* __restrict__ qh,
    const __half* __restrict__ kh, const __half* __restrict__ vh,
    const float* __restrict__ mask,
    __half* __restrict__ Ohi)
{
    extern __shared__ __align__(16) char dsm[];
    const uint32_t sb = smem_u32(dsm);
    const int tid = threadIdx.x, wid = tid >> 5, lane = tid & 31;
    const int bh = blockIdx.y, b = bh >> 3, h = bh & 7;
    const int i0 = blockIdx.x * 128;
    const size_t qoff = ((size_t)(b*Ln + i0))*Dn + h*DHn;
    const size_t koff = ((size_t)(b*Ln))*Dn + h*DHn;

    const uint32_t smQh = sb;
    const uint32_t smKV0 = sb + QT;
    const uint32_t smMaskOff = QT + 2*KVB;

    auto LOADC = [&](int c){
        uint32_t base = smKV0 + (uint32_t)(c & 1)*KVB;
        size_t g0 = koff + (size_t)(c*64)*Dn;
#pragma unroll
        for (int i = 0; i < 2; i++){
            int id = tid + i*256; int row = id >> 3, seg = id & 7;
            size_t go = g0 + (size_t)row*Dn + seg*8;
            uint32_t so = (uint32_t)(row*AP + seg*16);
            cpasync16(base + so,       kh + go);
            cpasync16(base + KVT + so, vh + go);
        }
        if (tid < 16)
            cpasync16(sb + smMaskOff + (uint32_t)(c & 1)*256 + tid*16,
                      mask + b*Ln + c*64 + tid*4);
        CP_COMMIT();
    };

#pragma unroll
    for (int i = 0; i < 4; i++){
        int id = tid + i*256; int row = id >> 3, seg = id & 7;
        cpasync16(smQh + (uint32_t)(row*AP + seg*16),
                  qh + qoff + (size_t)row*Dn + seg*8);
    }
    LOADC(0);
    LOADC(1);

    const int g = lane >> 2, t4 = lane & 3;
    float mi0 = mask[b*Ln + i0 + wid*16 + g];
    float mi1 = mask[b*Ln + i0 + wid*16 + g + 8];

    float m0 = -3.0e38f, m1 = -3.0e38f, l0 = 0.f, l1 = 0.f;
    float o[8][4];
#pragma unroll
    for (int i = 0; i < 8; i++)
#pragma unroll
        for (int j = 0; j < 4; j++) o[i][j] = 0.f;

    const uint32_t aQoff = (uint32_t)((wid*16 + (lane & 15))*AP + ((lane >> 4) << 4));
    const uint32_t bKoff = (uint32_t)(((lane & 7) + ((lane >> 4) << 3))*AP + (((lane >> 3) & 1) << 4));
    const uint32_t vOff  = (uint32_t)((lane & 15)*AP + ((lane >> 4) << 4));

#pragma unroll 1
    for (int c = 0; c < 8; c++){
        if (c < 7) { CP_WAIT(1); } else { CP_WAIT(0); }
        __syncthreads();
        const uint32_t kb = smKV0 + (uint32_t)(c & 1)*KVB;
        const float* mjp = (const float*)(dsm + smMaskOff + (c & 1)*256);

        float s[8][4];
#pragma unroll
        for (int nj = 0; nj < 8; nj++)
#pragma unroll
            for (int q = 0; q < 4; q++) s[nj][q] = 0.f;
#pragma unroll
        for (int ss = 0; ss < 4; ss++){
            uint32_t ah[4];
            ldsm4(ah, smQh + aQoff + ss*32);
#pragma unroll
            for (int njp = 0; njp < 4; njp++){
                uint32_t bhh[4];
                ldsm4(bhh, kb + (uint32_t)(njp*16)*AP + bKoff + ss*32);
                mma16816(s[2*njp],   ah, &bhh[0]);
                mma16816(s[2*njp+1], ah, &bhh[2]);
            }
        }

        float rm0 = -3.0e38f, rm1 = -3.0e38f;
#pragma unroll
        for (int nj = 0; nj < 8; nj++){
            int colb = nj*8 + t4*2;
            float mj0 = mjp[colb], mj1 = mjp[colb+1];
            float mm;
            mm = mi0*mj0; s[nj][0] = s[nj][0]*0.125f*mm + NEGV*(1.f - mm);
            mm = mi0*mj1; s[nj][1] = s[nj][1]*0.125f*mm + NEGV*(1.f - mm);
            mm = mi1*mj0; s[nj][2] = s[nj][2]*0.125f*mm + NEGV*(1.f - mm);
            mm = mi1*mj1; s[nj][3] = s[nj][3]*0.125f*mm + NEGV*(1.f - mm);
            rm0 = fmaxf(rm0, fmaxf(s[nj][0], s[nj][1]));
            rm1 = fmaxf(rm1, fmaxf(s[nj][2], s[nj][3]));
        }
        rm0 = fmaxf(rm0, __shfl_xor_sync(0xffffffffu, rm0, 1));
        rm0 = fmaxf(rm0, __shfl_xor_sync(0xffffffffu, rm0, 2));
        rm1 = fmaxf(rm1, __shfl_xor_sync(0xffffffffu, rm1, 1));
        rm1 = fmaxf(rm1, __shfl_xor_sync(0xffffffffu, rm1, 2));
        float nm0 = fmaxf(m0, rm0), nm1 = fmaxf(m1, rm1);
        float al0 = __expf(m0 - nm0), al1 = __expf(m1 - nm1);
        m0 = nm0; m1 = nm1;
#pragma unroll
        for (int nd = 0; nd < 8; nd++){
            o[nd][0] *= al0; o[nd][1] *= al0;
            o[nd][2] *= al1; o[nd][3] *= al1;
        }

        float sum0 = 0.f, sum1 = 0.f;
#pragma unroll
        for (int ss = 0; ss < 4; ss++){
            float p00 = __expf(s[2*ss][0]   - nm0), p01 = __expf(s[2*ss][1]   - nm0);
            float p02 = __expf(s[2*ss][2]   - nm1), p03 = __expf(s[2*ss][3]   - nm1);
            float p10 = __expf(s[2*ss+1][0] - nm0), p11 = __expf(s[2*ss+1][1] - nm0);
            float p12 = __expf(s[2*ss+1][2] - nm1), p13 = __expf(s[2*ss+1][3] - nm1);
            sum0 += p00 + p01 + p10 + p11;
            sum1 += p02 + p03 + p12 + p13;
            uint32_t pah[4];
            pah[0] = packhi(p00, p01);
            pah[1] = packhi(p02, p03);
            pah[2] = packhi(p10, p11);
            pah[3] = packhi(p12, p13);
#pragma unroll
            for (int ndp = 0; ndp < 4; ndp++){
                uint32_t vhh[4];
                ldsm4t(vhh, kb + KVT + (uint32_t)(ss*16)*AP + vOff + ndp*32);
                mma16816(o[2*ndp],   pah, &vhh[0]);
                mma16816(o[2*ndp+1], pah, &vhh[2]);
            }
        }
        sum0 += __shfl_xor_sync(0xffffffffu, sum0, 1);
        sum0 += __shfl_xor_sync(0xffffffffu, sum0, 2);
        sum1 += __shfl_xor_sync(0xffffffffu, sum1, 1);
        sum1 += __shfl_xor_sync(0xffffffffu, sum1, 2);
        l0 = l0*al0 + sum0;
        l1 = l1*al1 + sum1;

        if (c < 6){ __syncthreads(); LOADC(c + 2); }
    }

    float inv0 = 1.f / l0, inv1 = 1.f / l1;
    int r0 = i0 + wid*16 + g, r1 = r0 + 8;
    size_t ob = ((size_t)(b*Ln))*Dn + h*DHn;
#pragma unroll
    for (int nd = 0; nd < 8; nd++){
        int col = nd*8 + t4*2;
        *(uint32_t*)(Ohi + ob + (size_t)r0*Dn + col) = packhi(o[nd][0]*inv0, o[nd][1]*inv0);
        *(uint32_t*)(Ohi + ob + (size_t)r1*Dn + col) = packhi(o[nd][2]*inv1, o[nd][3]*inv1);
    }
}

// ======================= host orchestration =======================
extern "C" void kernel_launch(void* const* d_in, const int* in_sizes, int n_in,
                              void* d_out, int out_size)
{
    (void)in_sizes; (void)n_in; (void)out_size;
    const float* x     = (const float*)d_in[0];
    const float* mask  = (const float*)d_in[1];
    const float* pe    = (const float*)d_in[2];
    const float* dw_w  = (const float*)d_in[3];
    const float* dw_b  = (const float*)d_in[4];
    const float* pw_w  = (const float*)d_in[5];
    const float* pw_b  = (const float*)d_in[6];
    const float* wq    = (const float*)d_in[7];
    const float* bq    = (const float*)d_in[8];
    const float* wk    = (const float*)d_in[9];
    const float* bk    = (const float*)d_in[10];
    const float* wv    = (const float*)d_in[11];
    const float* bv    = (const float*)d_in[12];
    const float* fc_w  = (const float*)d_in[13];
    const float* fc_b  = (const float*)d_in[14];
    const float* out_w = (const float*)d_in[15];
    const float* out_b = (const float*)d_in[16];
    const float* lnc_g = (const float*)d_in[17];
    const float* lnc_b = (const float*)d_in[18];
    const float* lna_g = (const float*)d_in[19];
    const float* lna_b = (const float*)d_in[20];
    const float* lno_g = (const float*)d_in[21];
    const float* lno_b = (const float*)d_in[22];
    float* out = (float*)d_out;

    __half *pA, *pX2, *pX1, *qkv;
    cudaGetSymbolAddress((void**)&pA,  g_pA);
    cudaGetSymbolAddress((void**)&pX2, g_pX2);
    cudaGetSymbolAddress((void**)&pX1, g_pX1);
    cudaGetSymbolAddress((void**)&qkv, g_qkv);
    __half* wsym;
    cudaGetSymbolAddress((void**)&wsym, g_w);

    const size_t NN = (size_t)Mn*Dn;
    __half *x2_h = pX2, *x2_l = pX2 + NN;
    __half *x1_h = pX1, *x1_l = pX1 + NN;
    __half *q_h = qkv, *k_h = qkv + NN, *v_h = qkv + 2*NN;
    auto W = [&](int i){ return wsym + (size_t)i * Dn * Dn; };

    cudaFuncSetAttribute(gemm_mma<true,-1,0,true,false,false>,  cudaFuncAttributeMaxDynamicSharedMemorySize, SMEM_SZ);
    cudaFuncSetAttribute(gemm_mma<true,0,1,true,false,false>,   cudaFuncAttributeMaxDynamicSharedMemorySize, SMEM_SZ);
    cudaFuncSetAttribute(gemm_mma<true,1,2,true,false,false>,   cudaFuncAttributeMaxDynamicSharedMemorySize, SMEM_SZ);
    cudaFuncSetAttribute(gemm_mma<false,2,3,true,false,false>,  cudaFuncAttributeMaxDynamicSharedMemorySize, SMEM_SZ);
    cudaFuncSetAttribute(gemm_mma<false,3,-1,false,true,false>, cudaFuncAttributeMaxDynamicSharedMemorySize, SMEM_SZ);
    cudaFuncSetAttribute(gemm_qkv, cudaFuncAttributeMaxDynamicSharedMemorySize, SMEM_SZ);
    cudaFuncSetAttribute(attn_fused, cudaFuncAttributeMaxDynamicSharedMemorySize, SMEM_ATT);

    const int DWB = (Bn * (Ln/TLC) * (Dn/4)) / 256;   // 1024 blocks
    dim3 gemmGrid(Dn/128, Mn/128);      // (4, 128)
    dim3 qkvGrid(12, Mn/128);           // N = 1536

    // 1. weight prep + LN-partial zeroing
    prep_weights<<<6*1024, 256>>>(pw_w, wq, wk, wv, fc_w, out_w);

    // 2-3. conv layer 0 (PE fused); A 1-term; stats -> slot 0 (lnc0)
    dwconv_pe<<<DWB, 256>>>(x, pe, dw_w + 0*Dn*Kn, dw_b + 0*Dn, pA);
    gemm_mma<true,-1,0,true,false,false><<<gemmGrid, 256, SMEM_SZ>>>(
        pA, nullptr, W(0), pw_b + 0*Dn, nullptr,
        nullptr, nullptr, nullptr, nullptr, x2_h, x2_l);
    // 4-5. conv layer 1: + LN(x2; lnc0, slot 0); stats -> slot 1 (lnc1)
    dwconv_pair<<<DWB, 256>>>(x2_h, x2_l, dw_w + 1*Dn*Kn, dw_b + 1*Dn, pA);
    gemm_mma<true,0,1,true,false,false><<<gemmGrid, 256, SMEM_SZ>>>(
        pA, nullptr, W(1), pw_b + 1*Dn, nullptr,
        x2_h, x2_l, lnc_g + 0, lnc_b + 0, x1_h, x1_l);
    // 6-7. conv layer 2: + LN(x1; lnc1, slot 1); stats -> slot 2 (lna)
    dwconv_pair<<<DWB, 256>>>(x1_h, x1_l, dw_w + 2*Dn*Kn, dw_b + 2*Dn, pA);
    gemm_mma<true,1,2,true,false,false><<<gemmGrid, 256, SMEM_SZ>>>(
        pA, nullptr, W(2), pw_b + 2*Dn, nullptr,
        x1_h, x1_l, lnc_g + Ln*Dn, lnc_b + Ln*Dn, x2_h, x2_l);

    // 8. merged qkv projection (1-term, hi-only outputs)
    gemm_qkv<<<qkvGrid, 256, SMEM_SZ>>>(x2_h, bq, bk, bv);

    // 9. fused flash attention (pure fp16) -> pA (hi only)
    attn_fused<<<dim3(Ln/128, Bn*Hn), 256, SMEM_ATT>>>(
        q_h, k_h, v_h, mask, pA);

    // 10. fc (A 1-term) + LN(x2; lna, slot 2) -> x1 pair; stats -> slot 3 (lno)
    gemm_mma<false,2,3,true,false,false><<<gemmGrid, 256, SMEM_SZ>>>(
        pA, nullptr, W(6), fc_b, nullptr,
        x2_h, x2_l, lna_g, lna_b, x1_h, x1_l);

    // 11. out (A 1-term) + LN(x1; lno, slot 3) -> d_out (fp32)
    gemm_mma<false,3,-1,false,true,false><<<gemmGrid, 256, SMEM_SZ>>>(
        x1_h, nullptr, W(7), out_b, out,
        x1_h, x1_l, lno_g, lno_b, nullptr, nullptr);
}

// round 16
// speedup vs baseline: 4.6473x; 1.0155x over previous
#include <cuda_runtime.h>
#include <cuda_fp16.h>
#include <cstdint>

#define Bn 32
#define Ln 512
#define Dn 512
#define Hn 8
#define DHn 64
#define Kn 7
#define Mn (Bn*Ln)
#define NEGV (-1e30f)
#define LDINV (1.0f/(float)(Ln*Dn))
#define TLC 8

// ---- big-GEMM tiling (BK=64, 1-term only) ----
#define BK 64
#define PITCH 72                    // fp16 elems per smem row (144 B)
#define TB (128*PITCH*2)            // 18432 B per 128x64 tile
#define BUFB (2*TB)                 // Ahi + Whi = 36864 B
#define SMEM_SZ (3*BUFB)            // 110592 B, 2 CTAs/SM

// ---- fused attention smem (Q hi-only, KV chunk 64) ----
#define AP 144
#define QT (128*AP)
#define KVT (64*AP)
#define KVB (2*KVT)
#define SMEM_ATT (QT + 2*KVB + 1024)    // 56320 B

// ======================= PTX helpers =======================
__device__ __forceinline__ uint32_t smem_u32(const void* p){
    uint32_t a;
    asm("{ .reg .u64 t; cvta.to.shared.u64 t, %1; cvt.u32.u64 %0, t; }" : "=r"(a) : "l"(p));
    return a;
}
__device__ __forceinline__ void cpasync16(uint32_t dst, const void* src){
    asm volatile("cp.async.cg.shared.global [%0], [%1], 16;" :: "r"(dst), "l"(src) : "memory");
}
#define CP_COMMIT() asm volatile("cp.async.commit_group;" ::: "memory")
#define CP_WAIT(N)  asm volatile("cp.async.wait_group %0;" :: "n"(N) : "memory")
__device__ __forceinline__ void ldsm4(uint32_t* r, uint32_t addr){
    asm volatile("ldmatrix.sync.aligned.m8n8.x4.shared.b16 {%0,%1,%2,%3}, [%4];"
        : "=r"(r[0]), "=r"(r[1]), "=r"(r[2]), "=r"(r[3]) : "r"(addr));
}
__device__ __forceinline__ void ldsm4t(uint32_t* r, uint32_t addr){
    asm volatile("ldmatrix.sync.aligned.m8n8.x4.trans.shared.b16 {%0,%1,%2,%3}, [%4];"
        : "=r"(r[0]), "=r"(r[1]), "=r"(r[2]), "=r"(r[3]) : "r"(addr));
}
__device__ __forceinline__ void mma16816(float* d, const uint32_t* a, const uint32_t* b){
    asm volatile("mma.sync.aligned.m16n8k16.row.col.f32.f16.f16.f32 "
        "{%0,%1,%2,%3}, {%4,%5,%6,%7}, {%8,%9}, {%0,%1,%2,%3};"
        : "+f"(d[0]), "+f"(d[1]), "+f"(d[2]), "+f"(d[3])
        : "r"(a[0]), "r"(a[1]), "r"(a[2]), "r"(a[3]), "r"(b[0]), "r"(b[1]));
}
__device__ __forceinline__ void packpair(float x, float y, uint32_t& hi, uint32_t& lo){
    __half hx = __float2half_rn(x), hy = __float2half_rn(y);
    __half2 h; h.x = hx; h.y = hy;
    __half2 l;
    l.x = __float2half_rn(x - __half2float(hx));
    l.y = __float2half_rn(y - __half2float(hy));
    hi = *(uint32_t*)&h; lo = *(uint32_t*)&l;
}
__device__ __forceinline__ uint32_t packhi(float x, float y){
    __half2 h; h.x = __float2half_rn(x); h.y = __float2half_rn(y);
    return *(uint32_t*)&h;
}
__device__ __forceinline__ float2 unpackpair(uint32_t hi, uint32_t lo){
    __half2 h = *(__half2*)&hi, l = *(__half2*)&lo;
    float2 r;
    r.x = __half2float(h.x) + __half2float(l.x);
    r.y = __half2float(h.y) + __half2float(l.y);
    return r;
}

// ======================= scratch =======================
__device__ float g_pS [4][Bn];
__device__ float g_pS2[4][Bn];
__device__ __half g_pA [Mn*Dn];
__device__ __half g_pX2[2][Mn*Dn];
__device__ __half g_pX1[2][Mn*Dn];
__device__ __half g_qkv[3][Mn*Dn];
__device__ __half g_w[8][Dn*Dn];

// ======================= weight prep + LN-partial zeroing =======================
__global__ void prep_weights(const float* __restrict__ pw_w,
                             const float* __restrict__ wq, const float* __restrict__ wk,
                             const float* __restrict__ wv,
                             const float* __restrict__ fc_w, const float* __restrict__ out_w)
{
    if (blockIdx.x == 0 && threadIdx.x < 4*Bn) {
        (&g_pS[0][0])[threadIdx.x]  = 0.f;
        (&g_pS2[0][0])[threadIdx.x] = 0.f;
    }
    int task = blockIdx.x >> 10;
    int idx  = (blockIdx.x & 1023) * 256 + threadIdx.x;
    if (task < 3) {
        g_w[task][idx] = __float2half_rn(pw_w[(size_t)task*Dn*Dn + idx]);
    } else if (task == 3) {
        int n = idx >> 9, d = idx & 511;
        int src = (n >> 6) * (Dn * DHn) + d * DHn + (n & 63);
        g_w[3][idx] = __float2half_rn(wq[src]);
        g_w[4][idx] = __float2half_rn(wk[src]);
        g_w[5][idx] = __float2half_rn(wv[src]);
    } else if (task == 4) {
        g_w[6][idx] = __float2half_rn(fc_w[idx]);
    } else {
        g_w[7][idx] = __float2half_rn(out_w[idx]);
    }
}

// ======================= sliding-window depthwise conv (2 channels/thread) =======================
__global__ void dwconv_pe(const float* __restrict__ x, const float* __restrict__ pe,
                          const float* __restrict__ w, const float* __restrict__ bias,
                          __half* __restrict__ hi)
{
    int idx = blockIdx.x * 256 + threadIdx.x;     // over Bn*(Ln/8)*(Dn/2) = 524288
    int d  = (idx & 255) << 1;
    int l0 = ((idx >> 8) & 63) << 3;
    int b  = idx >> 14;

    float wr[2][Kn];
#pragma unroll
    for (int c = 0; c < 2; c++)
#pragma unroll
        for (int kk = 0; kk < Kn; kk++) wr[c][kk] = w[(d + c)*Kn + kk];

    float2 bs = *(const float2*)(bias + d);
    float2 acc[TLC];
#pragma unroll
    for (int j = 0; j < TLC; j++) acc[j] = bs;

#pragma unroll
    for (int i = 0; i < TLC + 6; i++){
        int ll = l0 - 3 + i;
        if (ll >= 0 && ll < Ln){
            float2 xv = *(const float2*)(x + ((size_t)(b*Ln + ll))*Dn + d);
            float2 pv = *(const float2*)(pe + (size_t)ll*Dn + d);
            xv.x += pv.x; xv.y += pv.y;
#pragma unroll
            for (int kk = 0; kk < Kn; kk++){
                int j = i - kk;
                if (j >= 0 && j < TLC){
                    acc[j].x = fmaf(xv.x, wr[0][kk], acc[j].x);
                    acc[j].y = fmaf(xv.y, wr[1][kk], acc[j].y);
                }
            }
        }
    }
#pragma unroll
    for (int j = 0; j < TLC; j++){
        float vx = fmaxf(acc[j].x, 0.f), vy = fmaxf(acc[j].y, 0.f);
        *(uint32_t*)(hi + ((size_t)(b*Ln + l0 + j))*Dn + d) = packhi(vx, vy);
    }
}

__global__ void dwconv_pair(const __half* __restrict__ xh, const __half* __restrict__ xl,
                            const float* __restrict__ w, const float* __restrict__ bias,
                            __half* __restrict__ hi)
{
    int idx = blockIdx.x * 256 + threadIdx.x;
    int d  = (idx & 255) << 1;
    int l0 = ((idx >> 8) & 63) << 3;
    int b  = idx >> 14;

    float wr[2][Kn];
#pragma unroll
    for (int c = 0; c < 2; c++)
#pragma unroll
        for (int kk = 0; kk < Kn; kk++) wr[c][kk] = w[(d + c)*Kn + kk];

    float2 bs = *(const float2*)(bias + d);
    float2 acc[TLC];
#pragma unroll
    for (int j = 0; j < TLC; j++) acc[j] = bs;

#pragma unroll
    for (int i = 0; i < TLC + 6; i++){
        int ll = l0 - 3 + i;
        if (ll >= 0 && ll < Ln){
            size_t base = ((size_t)(b*Ln + ll))*Dn + d;
            float2 xv = unpackpair(*(const uint32_t*)(xh + base),
                                   *(const uint32_t*)(xl + base));
#pragma unroll
            for (int kk = 0; kk < Kn; kk++){
                int j = i - kk;
                if (j >= 0 && j < TLC){
                    acc[j].x = fmaf(xv.x, wr[0][kk], acc[j].x);
                    acc[j].y = fmaf(xv.y, wr[1][kk], acc[j].y);
                }
            }
        }
    }
#pragma unroll
    for (int j = 0; j < TLC; j++){
        float vx = fmaxf(acc[j].x, 0.f), vy = fmaxf(acc[j].y, 0.f);
        *(uint32_t*)(hi + ((size_t)(b*Ln + l0 + j))*Dn + d) = packhi(vx, vy);
    }
}

// ======================= mma.sync GEMM (1-term fp16, BK=64, 4x2 warps) =======================
template<bool RELU, int LNIN, int LNOUT, bool SPL, bool WRITEC>
__global__ __launch_bounds__(256, 2) void gemm_mma(
    const __half* __restrict__ Ahi, const __half* __restrict__ Whi,
    const float* __restrict__ bias, float* __restrict__ C,
    const __half* __restrict__ Rhi, const __half* __restrict__ Rlo,
    const float* __restrict__ lng, const float* __restrict__ lnb,
    __half* __restrict__ Chi, __half* __restrict__ Clo)
{
    extern __shared__ __align__(16) char dsm[];
    const uint32_t sb = smem_u32(dsm);
    const int tid = threadIdx.x;
    const int wid = tid >> 5, lane = tid & 31;
    const int warpRow = wid & 3, warpCol = wid >> 2;
    const int bx = blockIdx.x, by = blockIdx.y;

    const __half* srcs[2] = {Ahi, Whi};
    const int rowb[2] = { by*128, bx*128 };

    auto PREF = [&](int kt){
        uint32_t bufb = sb + (uint32_t)(kt % 3) * BUFB;
#pragma unroll
        for (int t = 0; t < 2; t++){
            const __half* src = srcs[t] + (size_t)rowb[t]*Dn + kt*BK;
            uint32_t tb = bufb + (uint32_t)t*TB;
#pragma unroll
            for (int i = 0; i < 4; i++){
                int id  = tid + i*256;
                int row = id >> 3, c = id & 7;
                cpasync16(tb + (uint32_t)(row*(PITCH*2) + c*16),
                          src + (size_t)row*Dn + c*8);
            }
        }
        CP_COMMIT();
    };

    float acc[2][8][4];
#pragma unroll
    for (int i = 0; i < 2; i++)
#pragma unroll
        for (int j = 0; j < 8; j++)
#pragma unroll
            for (int q = 0; q < 4; q++) acc[i][j][q] = 0.f;

    const uint32_t aRow = (uint32_t)(warpRow*32 + (lane & 15));
    const uint32_t aColB = (uint32_t)(((lane >> 4) << 4));
    const uint32_t bRow = (uint32_t)(warpCol*64 + (lane & 7) + ((lane >> 4) << 3));
    const uint32_t bColB = (uint32_t)((((lane >> 3) & 1) << 4));

    PREF(0);
    PREF(1);
#pragma unroll 1
    for (int kt = 0; kt < Dn/BK; kt++){
        if (kt + 1 < Dn/BK) { CP_WAIT(1); } else { CP_WAIT(0); }
        __syncthreads();
        if (kt + 2 < Dn/BK) PREF(kt + 2);

        uint32_t bufb = sb + (uint32_t)(kt % 3) * BUFB;
        uint32_t tAhi = bufb, tWhi = bufb + TB;
#pragma unroll
        for (int kk = 0; kk < 4; kk++){
            uint32_t ah[2][4], bh[4][4];
#pragma unroll
            for (int mi = 0; mi < 2; mi++)
                ldsm4(ah[mi], tAhi + (aRow + mi*16)*(PITCH*2) + aColB + kk*32);
#pragma unroll
            for (int nt = 0; nt < 4; nt++)
                ldsm4(bh[nt], tWhi + (bRow + nt*16)*(PITCH*2) + bColB + kk*32);
#pragma unroll
            for (int mi = 0; mi < 2; mi++)
#pragma unroll
                for (int nj = 0; nj < 8; nj++)
                    mma16816(acc[mi][nj], ah[mi], &bh[nj >> 1][(nj & 1) << 1]);
        }
    }

    float muv = 0.f, rsv = 0.f;
    if (LNIN >= 0) {
        int bb = (by*128) >> 9;
        float s = g_pS[LNIN][bb], s2 = g_pS2[LNIN][bb];
        muv = s * LDINV;
        rsv = rsqrtf(s2 * LDINV - muv*muv + 1e-5f);
    }
    const int r0base = by*128 + warpRow*32;
    const int c0base = bx*128 + warpCol*64;
    float ts = 0.f, ts2 = 0.f;
#pragma unroll
    for (int mi = 0; mi < 2; mi++){
#pragma unroll
        for (int rp = 0; rp < 2; rp++){
            int grow = r0base + mi*16 + (lane >> 2) + rp*8;
            int lrow = grow & (Ln - 1);
#pragma unroll
            for (int nj = 0; nj < 8; nj++){
                int col = c0base + nj*8 + (lane & 3)*2;
                float vx = acc[mi][nj][rp*2 + 0];
                float vy = acc[mi][nj][rp*2 + 1];
                float2 bs = *(const float2*)(bias + col);
                vx += bs.x; vy += bs.y;
                if (RELU) { vx = fmaxf(vx, 0.f); vy = fmaxf(vy, 0.f); }
                size_t off = (size_t)grow*Dn + col;
                if (LNIN >= 0) {
                    float2 rr = unpackpair(*(const uint32_t*)(Rhi + off),
                                           *(const uint32_t*)(Rlo + off));
                    float2 gg = *(const float2*)(lng + (size_t)lrow*Dn + col);
                    float2 bb = *(const float2*)(lnb + (size_t)lrow*Dn + col);
                    vx += (rr.x - muv)*rsv*gg.x + bb.x;
                    vy += (rr.y - muv)*rsv*gg.y + bb.y;
                }
                if (LNOUT >= 0) { ts += vx + vy; ts2 += vx*vx + vy*vy; }
                if (WRITEC) {
                    float2 o; o.x = vx; o.y = vy;
                    *(float2*)(C + off) = o;
                }
                if (SPL) {
                    uint32_t hi, lo;
                    packpair(vx, vy, hi, lo);
                    *(uint32_t*)(Chi + off) = hi;
                    *(uint32_t*)(Clo + off) = lo;
                }
            }
        }
    }
    if (LNOUT >= 0) {
#pragma unroll
        for (int o = 16; o > 0; o >>= 1){
            ts  += __shfl_xor_sync(0xffffffffu, ts,  o);
            ts2 += __shfl_xor_sync(0xffffffffu, ts2, o);
        }
        __shared__ float sred[2][8];
        if (lane == 0){ sred[0][wid] = ts; sred[1][wid] = ts2; }
        __syncthreads();
        if (tid == 0){
            float a = 0.f, b2 = 0.f;
#pragma unroll
            for (int i = 0; i < 8; i++){ a += sred[0][i]; b2 += sred[1][i]; }
            int batch = by >> 2;
            atomicAdd(&g_pS[LNOUT][batch],  a);
            atomicAdd(&g_pS2[LNOUT][batch], b2);
        }
    }
}

// ======================= merged qkv GEMM (1-term, BK=64) =======================
__global__ __launch_bounds__(256, 2) void gemm_qkv(
    const __half* __restrict__ Ahi,
    const float* __restrict__ bq, const float* __restrict__ bk, const float* __restrict__ bv)
{
    extern __shared__ __align__(16) char dsm[];
    const uint32_t sb = smem_u32(dsm);
    const int tid = threadIdx.x;
    const int wid = tid >> 5, lane = tid & 31;
    const int warpRow = wid & 3, warpCol = wid >> 2;
    const int bx = blockIdx.x, by = blockIdx.y;
    const int seg = bx >> 2, bxl = bx & 3;

    const __half* Whi = g_w[3 + seg];
    const float* bias = (seg == 0) ? bq : ((seg == 1) ? bk : bv);
    __half* Ch = g_qkv[seg];

    const __half* srcs[2] = {Ahi, Whi};
    const int rowb[2] = { by*128, bxl*128 };

    auto PREF = [&](int kt){
        uint32_t bufb = sb + (uint32_t)(kt % 3) * BUFB;
#pragma unroll
        for (int t = 0; t < 2; t++){
            const __half* src = srcs[t] + (size_t)rowb[t]*Dn + kt*BK;
            uint32_t tb = bufb + (uint32_t)t*TB;
#pragma unroll
            for (int i = 0; i < 4; i++){
                int id  = tid + i*256;
                int row = id >> 3, c = id & 7;
                cpasync16(tb + (uint32_t)(row*(PITCH*2) + c*16),
                          src + (size_t)row*Dn + c*8);
            }
        }
        CP_COMMIT();
    };

    float acc[2][8][4];
#pragma unroll
    for (int i = 0; i < 2; i++)
#pragma unroll
        for (int j = 0; j < 8; j++)
#pragma unroll
            for (int q = 0; q < 4; q++) acc[i][j][q] = 0.f;

    const uint32_t aRow = (uint32_t)(warpRow*32 + (lane & 15));
    const uint32_t aColB = (uint32_t)(((lane >> 4) << 4));
    const uint32_t bRow = (uint32_t)(warpCol*64 + (lane & 7) + ((lane >> 4) << 3));
    const uint32_t bColB = (uint32_t)((((lane >> 3) & 1) << 4));

    PREF(0);
    PREF(1);
#pragma unroll 1
    for (int kt = 0; kt < Dn/BK; kt++){
        if (kt + 1 < Dn/BK) { CP_WAIT(1); } else { CP_WAIT(0); }
        __syncthreads();
        if (kt + 2 < Dn/BK) PREF(kt + 2);

        uint32_t bufb = sb + (uint32_t)(kt % 3) * BUFB;
        uint32_t tAhi = bufb, tWhi = bufb + TB;
#pragma unroll
        for (int kk = 0; kk < 4; kk++){
            uint32_t ah[2][4], bh[4][4];
#pragma unroll
            for (int mi = 0; mi < 2; mi++)
                ldsm4(ah[mi], tAhi + (aRow + mi*16)*(PITCH*2) + aColB + kk*32);
#pragma unroll
            for (int nt = 0; nt < 4; nt++)
                ldsm4(bh[nt], tWhi + (bRow + nt*16)*(PITCH*2) + bColB + kk*32);
#pragma unroll
            for (int mi = 0; mi < 2; mi++)
#pragma unroll
                for (int nj = 0; nj < 8; nj++)
                    mma16816(acc[mi][nj], ah[mi], &bh[nj >> 1][(nj & 1) << 1]);
        }
    }

    const int r0base = by*128 + warpRow*32;
    const int c0base = bxl*128 + warpCol*64;
#pragma unroll
    for (int mi = 0; mi < 2; mi++){
#pragma unroll
        for (int rp = 0; rp < 2; rp++){
            int grow = r0base + mi*16 + (lane >> 2) + rp*8;
#pragma unroll
            for (int nj = 0; nj < 8; nj++){
                int col = c0base + nj*8 + (lane & 3)*2;
                float vx = acc[mi][nj][rp*2 + 0];
                float vy = acc[mi][nj][rp*2 + 1];
                float2 bs = *(const float2*)(bias + col);
                vx += bs.x; vy += bs.y;
                *(uint32_t*)(Ch + (size_t)grow*Dn + col) = packhi(vx, vy);
            }
        }
    }
}

// ======================= fused flash attention (pure fp16) =======================
__global__ __launch_bounds__(256, 2) void attn_fused(
    const __half* __restrict__ qh,
    const __half* __restrict__ kh, const __half* __restrict__ vh,
    const float* __restrict__ mask,
    __half* __restrict__ Ohi)
{
    extern __shared__ __align__(16) char dsm[];
    const uint32_t sb = smem_u32(dsm);
    const int tid = threadIdx.x, wid = tid >> 5, lane = tid & 31;
    const int bh = blockIdx.y, b = bh >> 3, h = bh & 7;
    const int i0 = blockIdx.x * 128;
    const size_t qoff = ((size_t)(b*Ln + i0))*Dn + h*DHn;
    const size_t koff = ((size_t)(b*Ln))*Dn + h*DHn;

    const uint32_t smQh = sb;
    const uint32_t smKV0 = sb + QT;
    const uint32_t smMaskOff = QT + 2*KVB;

    auto LOADC = [&](int c){
        uint32_t base = smKV0 + (uint32_t)(c & 1)*KVB;
        size_t g0 = koff + (size_t)(c*64)*Dn;
#pragma unroll
        for (int i = 0; i < 2; i++){
            int id = tid + i*256; int row = id >> 3, seg = id & 7;
            size_t go = g0 + (size_t)row*Dn + seg*8;
            uint32_t so = (uint32_t)(row*AP + seg*16);
            cpasync16(base + so,       kh + go);
            cpasync16(base + KVT + so, vh + go);
        }
        if (tid < 16)
            cpasync16(sb + smMaskOff + (uint32_t)(c & 1)*256 + tid*16,
                      mask + b*Ln + c*64 + tid*4);
        CP_COMMIT();
    };

#pragma unroll
    for (int i = 0; i < 4; i++){
        int id = tid + i*256; int row = id >> 3, seg = id & 7;
        cpasync16(smQh + (uint32_t)(row*AP + seg*16),
                  qh + qoff + (size_t)row*Dn + seg*8);
    }
    LOADC(0);
    LOADC(1);

    const int g = lane >> 2, t4 = lane & 3;
    float mi0 = mask[b*Ln + i0 + wid*16 + g];
    float mi1 = mask[b*Ln + i0 + wid*16 + g + 8];

    float m0 = -3.0e38f, m1 = -3.0e38f, l0 = 0.f, l1 = 0.f;
    float o[8][4];
#pragma unroll
    for (int i = 0; i < 8; i++)
#pragma unroll
        for (int j = 0; j < 4; j++) o[i][j] = 0.f;

    const uint32_t aQoff = (uint32_t)((wid*16 + (lane & 15))*AP + ((lane >> 4) << 4));
    const uint32_t bKoff = (uint32_t)(((lane & 7) + ((lane >> 4) << 3))*AP + (((lane >> 3) & 1) << 4));
    const uint32_t vOff  = (uint32_t)((lane & 15)*AP + ((lane >> 4) << 4));

#pragma unroll 1
    for (int c = 0; c < 8; c++){
        if (c < 7) { CP_WAIT(1); } else { CP_WAIT(0); }
        __syncthreads();
        const uint32_t kb = smKV0 + (uint32_t)(c & 1)*KVB;
        const float* mjp = (const float*)(dsm + smMaskOff + (c & 1)*256);

        float s[8][4];
#pragma unroll
        for (int nj = 0; nj < 8; nj++)
#pragma unroll
            for (int q = 0; q < 4; q++) s[nj][q] = 0.f;
#pragma unroll
        for (int ss = 0; ss < 4; ss++){
            uint32_t ah[4];
            ldsm4(ah, smQh + aQoff + ss*32);
#pragma unroll
            for (int njp = 0; njp < 4; njp++){
                uint32_t bhh[4];
                ldsm4(bhh, kb + (uint32_t)(njp*16)*AP + bKoff + ss*32);
                mma16816(s[2*njp],   ah, &bhh[0]);
                mma16816(s[2*njp+1], ah, &bhh[2]);
            }
        }

        float rm0 = -3.0e38f, rm1 = -3.0e38f;
#pragma unroll
        for (int nj = 0; nj < 8; nj++){
            int colb = nj*8 + t4*2;
            float mj0 = mjp[colb], mj1 = mjp[colb+1];
            float mm;
            mm = mi0*mj0; s[nj][0] = s[nj][0]*0.125f*mm + NEGV*(1.f - mm);
            mm = mi0*mj1; s[nj][1] = s[nj][1]*0.125f*mm + NEGV*(1.f - mm);
            mm = mi1*mj0; s[nj][2] = s[nj][2]*0.125f*mm + NEGV*(1.f - mm);
            mm = mi1*mj1; s[nj][3] = s[nj][3]*0.125f*mm + NEGV*(1.f - mm);
            rm0 = fmaxf(rm0, fmaxf(s[nj][0], s[nj][1]));
            rm1 = fmaxf(rm1, fmaxf(s[nj][2], s[nj][3]));
        }
        rm0 = fmaxf(rm0, __shfl_xor_sync(0xffffffffu, rm0, 1));
        rm0 = fmaxf(rm0, __shfl_xor_sync(0xffffffffu, rm0, 2));
        rm1 = fmaxf(rm1, __shfl_xor_sync(0xffffffffu, rm1, 1));
        rm1 = fmaxf(rm1, __shfl_xor_sync(0xffffffffu, rm1, 2));
        float nm0 = fmaxf(m0, rm0), nm1 = fmaxf(m1, rm1);
        float al0 = __expf(m0 - nm0), al1 = __expf(m1 - nm1);
        m0 = nm0; m1 = nm1;
#pragma unroll
        for (int nd = 0; nd < 8; nd++){
            o[nd][0] *= al0; o[nd][1] *= al0;
            o[nd][2] *= al1; o[nd][3] *= al1;
        }

        float sum0 = 0.f, sum1 = 0.f;
#pragma unroll
        for (int ss = 0; ss < 4; ss++){
            float p00 = __expf(s[2*ss][0]   - nm0), p01 = __expf(s[2*ss][1]   - nm0);
            float p02 = __expf(s[2*ss][2]   - nm1), p03 = __expf(s[2*ss][3]   - nm1);
            float p10 = __expf(s[2*ss+1][0] - nm0), p11 = __expf(s[2*ss+1][1] - nm0);
            float p12 = __expf(s[2*ss+1][2] - nm1), p13 = __expf(s[2*ss+1][3] - nm1);
            sum0 += p00 + p01 + p10 + p11;
            sum1 += p02 + p03 + p12 + p13;
            uint32_t pah[4];
            pah[0] = packhi(p00, p01);
            pah[1] = packhi(p02, p03);
            pah[2] = packhi(p10, p11);
            pah[3] = packhi(p12, p13);
#pragma unroll
            for (int ndp = 0; ndp < 4; ndp++){
                uint32_t vhh[4];
                ldsm4t(vhh, kb + KVT + (uint32_t)(ss*16)*AP + vOff + ndp*32);
                mma16816(o[2*ndp],   pah, &vhh[0]);
                mma16816(o[2*ndp+1], pah, &vhh[2]);
            }
        }
        sum0 += __shfl_xor_sync(0xffffffffu, sum0, 1);
        sum0 += __shfl_xor_sync(0xffffffffu, sum0, 2);
        sum1 += __shfl_xor_sync(0xffffffffu, sum1, 1);
        sum1 += __shfl_xor_sync(0xffffffffu, sum1, 2);
        l0 = l0*al0 + sum0;
        l1 = l1*al1 + sum1;

        if (c < 6){ __syncthreads(); LOADC(c + 2); }
    }

    float inv0 = 1.f / l0, inv1 = 1.f / l1;
    int r0 = i0 + wid*16 + g, r1 = r0 + 8;
    size_t ob = ((size_t)(b*Ln))*Dn + h*DHn;
#pragma unroll
    for (int nd = 0; nd < 8; nd++){
        int col = nd*8 + t4*2;
        *(uint32_t*)(Ohi + ob + (size_t)r0*Dn + col) = packhi(o[nd][0]*inv0, o[nd][1]*inv0);
        *(uint32_t*)(Ohi + ob + (size_t)r1*Dn + col) = packhi(o[nd][2]*inv1, o[nd][3]*inv1);
    }
}

// ======================= host orchestration =======================
extern "C" void kernel_launch(void* const* d_in, const int* in_sizes, int n_in,
                              void* d_out, int out_size)
{
    (void)in_sizes; (void)n_in; (void)out_size;
    const float* x     = (const float*)d_in[0];
    const float* mask  = (const float*)d_in[1];
    const float* pe    = (const float*)d_in[2];
    const float* dw_w  = (const float*)d_in[3];
    const float* dw_b  = (const float*)d_in[4];
    const float* pw_w  = (const float*)d_in[5];
    const float* pw_b  = (const float*)d_in[6];
    const float* wq    = (const float*)d_in[7];
    const float* bq    = (const float*)d_in[8];
    const float* wk    = (const float*)d_in[9];
    const float* bk    = (const float*)d_in[10];
    const float* wv    = (const float*)d_in[11];
    const float* bv    = (const float*)d_in[12];
    const float* fc_w  = (const float*)d_in[13];
    const float* fc_b  = (const float*)d_in[14];
    const float* out_w = (const float*)d_in[15];
    const float* out_b = (const float*)d_in[16];
    const float* lnc_g = (const float*)d_in[17];
    const float* lnc_b = (const float*)d_in[18];
    const float* lna_g = (const float*)d_in[19];
    const float* lna_b = (const float*)d_in[20];
    const float* lno_g = (const float*)d_in[21];
    const float* lno_b = (const float*)d_in[22];
    float* out = (float*)d_out;

    __half *pA, *pX2, *pX1, *qkv;
    cudaGetSymbolAddress((void**)&pA,  g_pA);
    cudaGetSymbolAddress((void**)&pX2, g_pX2);
    cudaGetSymbolAddress((void**)&pX1, g_pX1);
    cudaGetSymbolAddress((void**)&qkv, g_qkv);
    __half* wsym;
    cudaGetSymbolAddress((void**)&wsym, g_w);

    const size_t NN = (size_t)Mn*Dn;
    __half *x2_h = pX2, *x2_l = pX2 + NN;
    __half *x1_h = pX1, *x1_l = pX1 + NN;
    __half *q_h = qkv, *k_h = qkv + NN, *v_h = qkv + 2*NN;
    auto W = [&](int i){ return wsym + (size_t)i * Dn * Dn; };

    cudaFuncSetAttribute(gemm_mma<true,-1,0,true,false>,  cudaFuncAttributeMaxDynamicSharedMemorySize, SMEM_SZ);
    cudaFuncSetAttribute(gemm_mma<true,0,1,true,false>,   cudaFuncAttributeMaxDynamicSharedMemorySize, SMEM_SZ);
    cudaFuncSetAttribute(gemm_mma<true,1,2,true,false>,   cudaFuncAttributeMaxDynamicSharedMemorySize, SMEM_SZ);
    cudaFuncSetAttribute(gemm_mma<false,2,3,true,false>,  cudaFuncAttributeMaxDynamicSharedMemorySize, SMEM_SZ);
    cudaFuncSetAttribute(gemm_mma<false,3,-1,false,true>, cudaFuncAttributeMaxDynamicSharedMemorySize, SMEM_SZ);
    cudaFuncSetAttribute(gemm_qkv, cudaFuncAttributeMaxDynamicSharedMemorySize, SMEM_SZ);
    cudaFuncSetAttribute(attn_fused, cudaFuncAttributeMaxDynamicSharedMemorySize, SMEM_ATT);

    const int DWB = (Bn * (Ln/TLC) * (Dn/2)) / 256;   // 2048 blocks
    dim3 gemmGrid(Dn/128, Mn/128);      // (4, 128)
    dim3 qkvGrid(12, Mn/128);           // N = 1536

    // 1. weight prep + LN-partial zeroing
    prep_weights<<<6*1024, 256>>>(pw_w, wq, wk, wv, fc_w, out_w);

    // 2-3. conv layer 0 (PE fused); stats -> slot 0 (lnc0)
    dwconv_pe<<<DWB, 256>>>(x, pe, dw_w + 0*Dn*Kn, dw_b + 0*Dn, pA);
    gemm_mma<true,-1,0,true,false><<<gemmGrid, 256, SMEM_SZ>>>(
        pA, W(0), pw_b + 0*Dn, nullptr,
        nullptr, nullptr, nullptr, nullptr, x2_h, x2_l);
    // 4-5. conv layer 1: + LN(x2; lnc0, slot 0); stats -> slot 1 (lnc1)
    dwconv_pair<<<DWB, 256>>>(x2_h, x2_l, dw_w + 1*Dn*Kn, dw_b + 1*Dn, pA);
    gemm_mma<true,0,1,true,false><<<gemmGrid, 256, SMEM_SZ>>>(
        pA, W(1), pw_b + 1*Dn, nullptr,
        x2_h, x2_l, lnc_g + 0, lnc_b + 0, x1_h, x1_l);
    // 6-7. conv layer 2: + LN(x1; lnc1, slot 1); stats -> slot 2 (lna)
    dwconv_pair<<<DWB, 256>>>(x1_h, x1_l, dw_w + 2*Dn*Kn, dw_b + 2*Dn, pA);
    gemm_mma<true,1,2,true,false><<<gemmGrid, 256, SMEM_SZ>>>(
        pA, W(2), pw_b + 2*Dn, nullptr,
        x1_h, x1_l, lnc_g + Ln*Dn, lnc_b + Ln*Dn, x2_h, x2_l);

    // 8. merged qkv projection
    gemm_qkv<<<qkvGrid, 256, SMEM_SZ>>>(x2_h, bq, bk, bv);

    // 9. fused flash attention -> pA (hi only)
    attn_fused<<<dim3(Ln/128, Bn*Hn), 256, SMEM_ATT>>>(
        q_h, k_h, v_h, mask, pA);

    // 10. fc + LN(x2; lna, slot 2) -> x1 pair; stats -> slot 3 (lno)
    gemm_mma<false,2,3,true,false><<<gemmGrid, 256, SMEM_SZ>>>(
        pA, W(6), fc_b, nullptr,
        x2_h, x2_l, lna_g, lna_b, x1_h, x1_l);

    // 11. out + LN(x1; lno, slot 3) -> d_out (fp32)
    gemm_mma<false,3,-1,false,true><<<gemmGrid, 256, SMEM_SZ>>>(
        x1_h, W(7), out_b, out,
        x1_h, x1_l, lno_g, lno_b, nullptr, nullptr);
}